// round 1
// baseline (speedup 1.0000x reference)
#include <cuda_runtime.h>

#define BSZ   4
#define TOTAL 2064
#define DM    1024
#define NSN   16
#define OUTN  256
#define QLEN  272
#define NH    16
#define HD    64
#define FFND  4096
#define MAXS  2048

// Scratch (static device globals; no allocation allowed)
__device__ float g_xn  [BSZ*TOTAL*DM];
__device__ float g_q   [BSZ*QLEN*DM];
__device__ float g_k   [BSZ*TOTAL*DM];
__device__ float g_v   [BSZ*TOTAL*DM];
__device__ float g_attn[BSZ*QLEN*DM];
__device__ float g_h1  [BSZ*QLEN*DM];
__device__ float g_hn  [BSZ*QLEN*DM];
__device__ float g_ts  [BSZ*OUTN*FFND];
__device__ float g_tns [BSZ*NSN*FFND];
__device__ float g_fs  [BSZ*OUTN*DM];
__device__ float g_fns [BSZ*NSN*DM];

// ---------------- rmsnorm over rows of length 1024 ----------------
__global__ __launch_bounds__(256) void rmsnorm_kernel(const float* __restrict__ in,
        const float* __restrict__ w, float* __restrict__ out) {
    long row = blockIdx.x;
    int t = threadIdx.x;
    float4 v = reinterpret_cast<const float4*>(in + row*DM)[t];
    float ss = v.x*v.x + v.y*v.y + v.z*v.z + v.w*v.w;
    __shared__ float red[8];
    for (int o = 16; o; o >>= 1) ss += __shfl_xor_sync(0xffffffffu, ss, o);
    if ((t & 31) == 0) red[t >> 5] = ss;
    __syncthreads();
    if (t < 32) {
        float s = (t < 8) ? red[t] : 0.f;
        for (int o = 4; o; o >>= 1) s += __shfl_xor_sync(0xffffffffu, s, o);
        if (t == 0) red[0] = s;
    }
    __syncthreads();
    float rs = rsqrtf(red[0] * (1.f/DM) + 1e-6f);
    float4 wv = reinterpret_cast<const float4*>(w)[t];
    float4 o4 = make_float4(v.x*rs*wv.x, v.y*rs*wv.y, v.z*rs*wv.z, v.w*rs*wv.w);
    reinterpret_cast<float4*>(out + row*DM)[t] = o4;
}

// ---------------- h1 = x[:, -272:] + attn ; hn = rmsnorm(h1) ----------------
__global__ __launch_bounds__(256) void add_rmsnorm_kernel(const float* __restrict__ x,
        const float* __restrict__ w) {
    int row = blockIdx.x;                 // 0..BSZ*QLEN-1
    int b = row / QLEN, r = row - b*QLEN;
    int t = threadIdx.x;
    float4 xv = reinterpret_cast<const float4*>(x + ((long)b*TOTAL + (TOTAL-QLEN) + r)*DM)[t];
    float4 av = reinterpret_cast<const float4*>(g_attn + (long)row*DM)[t];
    float4 hv = make_float4(xv.x+av.x, xv.y+av.y, xv.z+av.z, xv.w+av.w);
    reinterpret_cast<float4*>(g_h1 + (long)row*DM)[t] = hv;
    float ss = hv.x*hv.x + hv.y*hv.y + hv.z*hv.z + hv.w*hv.w;
    __shared__ float red[8];
    for (int o = 16; o; o >>= 1) ss += __shfl_xor_sync(0xffffffffu, ss, o);
    if ((t & 31) == 0) red[t >> 5] = ss;
    __syncthreads();
    if (t < 32) {
        float s = (t < 8) ? red[t] : 0.f;
        for (int o = 4; o; o >>= 1) s += __shfl_xor_sync(0xffffffffu, s, o);
        if (t == 0) red[0] = s;
    }
    __syncthreads();
    float rs = rsqrtf(red[0] * (1.f/DM) + 1e-6f);
    float4 wv = reinterpret_cast<const float4*>(w)[t];
    float4 o4 = make_float4(hv.x*rs*wv.x, hv.y*rs*wv.y, hv.z*rs*wv.z, hv.w*rs*wv.w);
    reinterpret_cast<float4*>(g_hn + (long)row*DM)[t] = o4;
}

// ---------------- tiled SGEMM 128x128x8, batched row mapping ----------------
// C[row, bn0+col] = sum_k A[row, k] * Bw[k, col] + bias[col]
// rows map through batches: global row r -> A + (r/rpb)*aBatch + (r%rpb)*lda
__global__ __launch_bounds__(256) void sgemm_kernel(
    const float* __restrict__ A, int lda, long aBatch, int rpb,
    const float* __restrict__ Bw, int ldb,
    const float* __restrict__ bias,
    float* __restrict__ C, int ldc, long cBatch,
    int K, int relu)
{
    __shared__ float As[8][128];
    __shared__ float Bs[8][132];
    int t = threadIdx.x;
    int row0 = blockIdx.y * 128;
    int bn0  = blockIdx.x * 128;
    int batch = row0 / rpb;
    int rin   = row0 % rpb;
    const float* Ab = A + (long)batch*aBatch + (long)rin*lda;
    const float* Bb = Bw + bn0;
    float* Cb = C + (long)batch*cBatch + (long)rin*ldc + bn0;

    int ai = t >> 1, ak = (t & 1) * 4;
    int bk = t >> 5, bc = (t & 31) * 4;
    int ty = t >> 4, tx = t & 15;

    float acc[8][8];
    #pragma unroll
    for (int i = 0; i < 8; i++)
        #pragma unroll
        for (int j = 0; j < 8; j++) acc[i][j] = 0.f;

    for (int k0 = 0; k0 < K; k0 += 8) {
        float4 av = *reinterpret_cast<const float4*>(Ab + (long)ai*lda + k0 + ak);
        float4 bv = *reinterpret_cast<const float4*>(Bb + (long)(k0+bk)*ldb + bc);
        As[ak+0][ai] = av.x; As[ak+1][ai] = av.y; As[ak+2][ai] = av.z; As[ak+3][ai] = av.w;
        *reinterpret_cast<float4*>(&Bs[bk][bc]) = bv;
        __syncthreads();
        #pragma unroll
        for (int kk = 0; kk < 8; kk++) {
            float4 a0 = *reinterpret_cast<const float4*>(&As[kk][ty*8]);
            float4 a1 = *reinterpret_cast<const float4*>(&As[kk][ty*8+4]);
            float4 b0 = *reinterpret_cast<const float4*>(&Bs[kk][tx*8]);
            float4 b1 = *reinterpret_cast<const float4*>(&Bs[kk][tx*8+4]);
            float ar[8] = {a0.x,a0.y,a0.z,a0.w,a1.x,a1.y,a1.z,a1.w};
            float br[8] = {b0.x,b0.y,b0.z,b0.w,b1.x,b1.y,b1.z,b1.w};
            #pragma unroll
            for (int i = 0; i < 8; i++)
                #pragma unroll
                for (int j = 0; j < 8; j++) acc[i][j] += ar[i]*br[j];
        }
        __syncthreads();
    }
    float bias8[8];
    #pragma unroll
    for (int j = 0; j < 8; j++) bias8[j] = bias[bn0 + tx*8 + j];
    #pragma unroll
    for (int i = 0; i < 8; i++) {
        float cv[8];
        #pragma unroll
        for (int j = 0; j < 8; j++) {
            float vv = acc[i][j] + bias8[j];
            cv[j] = relu ? fmaxf(vv, 0.f) : vv;
        }
        float* cp = Cb + (long)(ty*8+i)*ldc + tx*8;
        *reinterpret_cast<float4*>(cp)   = make_float4(cv[0],cv[1],cv[2],cv[3]);
        *reinterpret_cast<float4*>(cp+4) = make_float4(cv[4],cv[5],cv[6],cv[7]);
    }
}

// ---------------- per-NS-position linear: Y[b,n,:] = X[b,n,:] @ W[n] + bias[n] ----------------
// Memory-bound on W; each W element read once, coalesced. X tile cached in shared.
__global__ __launch_bounds__(128) void ns_linear_kernel(
    const float* __restrict__ X, long xBatch, int xRow,
    const float* __restrict__ W, const float* __restrict__ bias,
    float* __restrict__ Y, long yBatch, int yRow,
    int K, int N, int relu)
{
    __shared__ float Xs[4][1024];
    int n = blockIdx.y;
    int t = threadIdx.x;
    int o = blockIdx.x * 128 + t;
    const float* Wn = W + (long)n*K*N + o;
    float a0=0.f, a1=0.f, a2=0.f, a3=0.f;
    for (int k0 = 0; k0 < K; k0 += 1024) {
        __syncthreads();
        for (int i = t; i < 1024; i += 128) {
            long xo = (long)n*xRow + k0 + i;
            Xs[0][i] = X[0*xBatch + xo];
            Xs[1][i] = X[1*xBatch + xo];
            Xs[2][i] = X[2*xBatch + xo];
            Xs[3][i] = X[3*xBatch + xo];
        }
        __syncthreads();
        const float* Wp = Wn + (long)k0*N;
        #pragma unroll 8
        for (int k = 0; k < 1024; k++) {
            float w = Wp[(long)k*N];
            a0 += w*Xs[0][k]; a1 += w*Xs[1][k]; a2 += w*Xs[2][k]; a3 += w*Xs[3][k];
        }
    }
    float bv = bias[(long)n*N + o];
    a0 += bv; a1 += bv; a2 += bv; a3 += bv;
    if (relu) { a0=fmaxf(a0,0.f); a1=fmaxf(a1,0.f); a2=fmaxf(a2,0.f); a3=fmaxf(a3,0.f); }
    long yo = (long)n*yRow + o;
    Y[0*yBatch+yo]=a0; Y[1*yBatch+yo]=a1; Y[2*yBatch+yo]=a2; Y[3*yBatch+yo]=a3;
}

// ---------------- RoPE in-place, head dim 64 (32 rotation pairs) ----------------
__global__ void rope_kernel(float* __restrict__ buf, int rowsPerB, int pos0, int total) {
    int idx = blockIdx.x*blockDim.x + threadIdx.x;
    if (idx >= total) return;
    int j  = idx & 31;
    int h  = (idx >> 5) & (NH-1);
    int rr = idx >> 9;
    int b  = rr / rowsPerB;
    int r  = rr - b*rowsPerB;
    double inv = pow(10000.0, -(double)j / 32.0);
    double ang = (double)(pos0 + r) * inv;
    double sd, cd;
    sincos(ang, &sd, &cd);
    float s = (float)sd, c = (float)cd;
    float* base = buf + ((long)b*rowsPerB + r)*DM + h*HD;
    float x1 = base[j], x2 = base[j+32];
    base[j]    = x1*c - x2*s;
    base[j+32] = x2*c + x1*s;
}

// ---------------- streaming-softmax attention ----------------
// block = (qtile of 64, head, batch); K tiles of 32; valid key iff kmin<=key<=1792+q
__global__ __launch_bounds__(256) void attn_kernel(
    const float* __restrict__ q, const float* __restrict__ k, const float* __restrict__ v,
    float* __restrict__ attn, const int* __restrict__ seqlen)
{
    __shared__ float qs[64][68];
    __shared__ float ks[32][68];
    __shared__ float vs[32][68];
    __shared__ float S [64][33];
    int qt = blockIdx.x, h = blockIdx.y, b = blockIdx.z;
    int tid = threadIdx.x;
    int L = seqlen[b];
    int kmin = MAXS - L;
    // load q tile
    for (int i = tid; i < 64*16; i += 256) {
        int r = i >> 4, c4 = (i & 15) * 4;
        int qg = qt*64 + r;
        float4 val = make_float4(0.f,0.f,0.f,0.f);
        if (qg < QLEN)
            val = *reinterpret_cast<const float4*>(q + ((long)b*QLEN + qg)*DM + h*HD + c4);
        *reinterpret_cast<float4*>(&qs[r][c4]) = val;
    }
    int qi = tid >> 2, dg = tid & 3;
    float m = -1e30f, l = 0.f;
    float4 acc[4];
    #pragma unroll
    for (int i = 0; i < 4; i++) acc[i] = make_float4(0.f,0.f,0.f,0.f);
    int qgmax = min(QLEN-1, qt*64 + 63);
    int t0 = kmin >> 5;
    int t1 = (MAXS - OUTN + qgmax) >> 5;
    int kiA = tid & 31, q0A = tid >> 5;
    for (int kt = t0; kt <= t1; kt++) {
        int key0 = kt * 32;
        __syncthreads();
        for (int i = tid; i < 32*16; i += 256) {
            int r = i >> 4, c4 = (i & 15) * 4;
            int key = key0 + r;
            float4 kv = make_float4(0.f,0.f,0.f,0.f), vv = kv;
            if (key < TOTAL) {
                long off = ((long)b*TOTAL + key)*DM + h*HD + c4;
                kv = *reinterpret_cast<const float4*>(k + off);
                vv = *reinterpret_cast<const float4*>(v + off);
            }
            *reinterpret_cast<float4*>(&ks[r][c4]) = kv;
            *reinterpret_cast<float4*>(&vs[r][c4]) = vv;
        }
        __syncthreads();
        // phase A: scores. thread owns key kiA, 8 q-rows {q0A + 8j}
        float sacc[8];
        #pragma unroll
        for (int j = 0; j < 8; j++) sacc[j] = 0.f;
        #pragma unroll
        for (int d4 = 0; d4 < 16; d4++) {
            float4 kk = *reinterpret_cast<const float4*>(&ks[kiA][d4*4]);
            #pragma unroll
            for (int j = 0; j < 8; j++) {
                float4 qq = *reinterpret_cast<const float4*>(&qs[q0A + j*8][d4*4]);
                sacc[j] += qq.x*kk.x + qq.y*kk.y + qq.z*kk.z + qq.w*kk.w;
            }
        }
        int key = key0 + kiA;
        #pragma unroll
        for (int j = 0; j < 8; j++) {
            int qrow = q0A + j*8;
            int qg = qt*64 + qrow;
            bool valid = (qg < QLEN) && (key < TOTAL) && (key >= kmin)
                      && (key <= MAXS - OUTN + qg);
            S[qrow][kiA] = valid ? sacc[j]*0.125f : -1e9f;
        }
        __syncthreads();
        // phase B: softmax update; thread owns (qi, dims dg*16..dg*16+15)
        float tmax = -1e30f;
        #pragma unroll
        for (int j = 0; j < 32; j++) tmax = fmaxf(tmax, S[qi][j]);
        if (tmax > -1e8f) {
            float m_new = fmaxf(m, tmax);
            float corr = __expf(m - m_new);
            l *= corr;
            #pragma unroll
            for (int i = 0; i < 4; i++) {
                acc[i].x*=corr; acc[i].y*=corr; acc[i].z*=corr; acc[i].w*=corr;
            }
            float ps = 0.f;
            #pragma unroll
            for (int j = 0; j < 32; j++) {
                float p = __expf(S[qi][j] - m_new);
                ps += p;
                #pragma unroll
                for (int i = 0; i < 4; i++) {
                    float4 vv = *reinterpret_cast<const float4*>(&vs[j][dg*16 + i*4]);
                    acc[i].x += p*vv.x; acc[i].y += p*vv.y; acc[i].z += p*vv.z; acc[i].w += p*vv.w;
                }
            }
            l += ps;
            m = m_new;
        }
    }
    int qg = qt*64 + qi;
    if (qg < QLEN) {
        float invl = 1.f / l;
        float* op = attn + ((long)b*QLEN + qg)*DM + h*HD + dg*16;
        #pragma unroll
        for (int i = 0; i < 4; i++)
            *reinterpret_cast<float4*>(op + i*4) =
                make_float4(acc[i].x*invl, acc[i].y*invl, acc[i].z*invl, acc[i].w*invl);
    }
}

// ---------------- final: out = concat(fs, fns) + h1 ; tail = min(L, OUT) ----------------
__global__ void assemble_kernel(float* __restrict__ out, const int* __restrict__ seqlen, int out_size) {
    int idx = blockIdx.x*blockDim.x + threadIdx.x;
    const int main_n = BSZ*QLEN*DM;
    if (idx < main_n) {
        int b = idx / (QLEN*DM);
        int rem = idx - b*(QLEN*DM);
        int r = rem / DM;
        int d = rem - r*DM;
        float f;
        if (r < OUTN) f = g_fs [((long)b*OUTN + r)*DM + d];
        else          f = g_fns[((long)b*NSN + (r - OUTN))*DM + d];
        out[idx] = f + g_h1[idx];
    }
    if (idx < BSZ && out_size >= main_n + BSZ) {
        int L = seqlen[idx];
        out[main_n + idx] = (float)(L < OUTN ? L : OUTN);
    }
}

extern "C" void kernel_launch(void* const* d_in, const int* in_sizes, int n_in,
                              void* d_out, int out_size) {
    (void)in_sizes; (void)n_in;
    const float* x    = (const float*)d_in[0];
    const int*   seq  = (const int*)  d_in[1];
    const float* wqkv = (const float*)d_in[2];
    const float* bqkv = (const float*)d_in[3];
    const float* wnsq = (const float*)d_in[4];
    const float* bnsq = (const float*)d_in[5];
    const float* wnsk = (const float*)d_in[6];
    const float* bnsk = (const float*)d_in[7];
    const float* wnsv = (const float*)d_in[8];
    const float* bnsv = (const float*)d_in[9];
    const float* n1w  = (const float*)d_in[10];
    const float* n2w  = (const float*)d_in[11];
    const float* fw1  = (const float*)d_in[12];
    const float* fb1  = (const float*)d_in[13];
    const float* fw2  = (const float*)d_in[14];
    const float* fb2  = (const float*)d_in[15];
    const float* w1ns = (const float*)d_in[16];
    const float* b1ns = (const float*)d_in[17];
    const float* w2ns = (const float*)d_in[18];
    const float* b2ns = (const float*)d_in[19];
    float* out = (float*)d_out;

    float *xn,*q,*k,*v,*attn,*hn,*ts,*tns,*fs,*fns;
    cudaGetSymbolAddress((void**)&xn,   g_xn);
    cudaGetSymbolAddress((void**)&q,    g_q);
    cudaGetSymbolAddress((void**)&k,    g_k);
    cudaGetSymbolAddress((void**)&v,    g_v);
    cudaGetSymbolAddress((void**)&attn, g_attn);
    cudaGetSymbolAddress((void**)&hn,   g_hn);
    cudaGetSymbolAddress((void**)&ts,   g_ts);
    cudaGetSymbolAddress((void**)&tns,  g_tns);
    cudaGetSymbolAddress((void**)&fs,   g_fs);
    cudaGetSymbolAddress((void**)&fns,  g_fns);

    const long aB = (long)TOTAL*DM;   // batch stride of xn/k/v
    const long qB = (long)QLEN*DM;    // batch stride of q/h1/hn

    // 1) xn = rmsnorm(x, norm1)
    rmsnorm_kernel<<<BSZ*TOTAL, 256>>>(x, n1w, xn);

    // 2) shared projections (K,V over all 2048 s-rows; Q over last 256)
    sgemm_kernel<<<dim3(DM/128, (BSZ*MAXS)/128), 256>>>(xn, DM, aB, MAXS,
        wqkv + DM,   3*DM, bqkv + DM,   k, DM, aB, DM, 0);
    sgemm_kernel<<<dim3(DM/128, (BSZ*MAXS)/128), 256>>>(xn, DM, aB, MAXS,
        wqkv + 2*DM, 3*DM, bqkv + 2*DM, v, DM, aB, DM, 0);
    sgemm_kernel<<<dim3(DM/128, (BSZ*OUTN)/128), 256>>>(xn + (long)(MAXS-OUTN)*DM, DM, aB, OUTN,
        wqkv,        3*DM, bqkv,        q, DM, qB, DM, 0);

    // 3) per-position NS projections (append rows 2048..2063 / 256..271)
    ns_linear_kernel<<<dim3(DM/128, NSN), 128>>>(xn + (long)MAXS*DM, aB, DM,
        wnsq, bnsq, q + (long)OUTN*DM, qB, DM, DM, DM, 0);
    ns_linear_kernel<<<dim3(DM/128, NSN), 128>>>(xn + (long)MAXS*DM, aB, DM,
        wnsk, bnsk, k + (long)MAXS*DM, aB, DM, DM, DM, 0);
    ns_linear_kernel<<<dim3(DM/128, NSN), 128>>>(xn + (long)MAXS*DM, aB, DM,
        wnsv, bnsv, v + (long)MAXS*DM, aB, DM, DM, DM, 0);

    // 4) RoPE
    {
        int totq = BSZ*QLEN*NH*32;
        rope_kernel<<<(totq+255)/256, 256>>>(q, QLEN, TOTAL-QLEN, totq);
        int totk = BSZ*TOTAL*NH*32;
        rope_kernel<<<(totk+255)/256, 256>>>(k, TOTAL, 0, totk);
    }

    // 5) attention
    attn_kernel<<<dim3((QLEN+63)/64, NH, BSZ), 256>>>(q, k, v, attn, seq);

    // 6) h1 = residual + attn ; hn = rmsnorm(h1, norm2)
    add_rmsnorm_kernel<<<BSZ*QLEN, 256>>>(x, n2w);

    // 7) shared FFN
    sgemm_kernel<<<dim3(FFND/128, (BSZ*OUTN)/128), 256>>>(hn, DM, qB, OUTN,
        fw1, FFND, fb1, ts, FFND, (long)OUTN*FFND, DM, 1);
    sgemm_kernel<<<dim3(DM/128, (BSZ*OUTN)/128), 256>>>(ts, FFND, (long)OUTN*FFND, OUTN,
        fw2, DM, fb2, fs, DM, (long)OUTN*DM, FFND, 0);

    // 8) NS FFN
    ns_linear_kernel<<<dim3(FFND/128, NSN), 128>>>(hn + (long)OUTN*DM, qB, DM,
        w1ns, b1ns, tns, (long)NSN*FFND, FFND, DM, FFND, 1);
    ns_linear_kernel<<<dim3(DM/128, NSN), 128>>>(tns, (long)NSN*FFND, FFND,
        w2ns, b2ns, fns, (long)NSN*DM, DM, FFND, DM, 0);

    // 9) assemble output (+ optional seq tail)
    assemble_kernel<<<(BSZ*QLEN*DM + 255)/256, 256>>>(out, seq, out_size);
}

// round 2
// speedup vs baseline: 1.3926x; 1.3926x over previous
#include <cuda_runtime.h>
#include <cstdint>

#define BSZ   4
#define TOTAL 2064
#define DM    1024
#define NSN   16
#define OUTN  256
#define QLEN  272
#define NH    16
#define HD    64
#define FFND  4096
#define MAXS  2048

// Scratch (static device globals; no allocation allowed)
__device__ float g_xn  [BSZ*TOTAL*DM];
__device__ float g_q   [BSZ*QLEN*DM];
__device__ float g_k   [BSZ*TOTAL*DM];
__device__ float g_v   [BSZ*TOTAL*DM];
__device__ float g_attn[BSZ*QLEN*DM];
__device__ float g_h1  [BSZ*QLEN*DM];
__device__ float g_hn  [BSZ*QLEN*DM];
__device__ float g_ts  [BSZ*OUTN*FFND];
__device__ float g_tns [BSZ*NSN*FFND];
__device__ float g_fs  [BSZ*OUTN*DM];
__device__ float g_fns [BSZ*NSN*DM];
// TF32-rounded weights
__device__ float g_wqkv[DM*3*DM];
__device__ float g_w1  [DM*FFND];
__device__ float g_w2  [FFND*DM];

__device__ __forceinline__ float rtf32(float x) {
    uint32_t u;
    asm("cvt.rna.tf32.f32 %0, %1;" : "=r"(u) : "f"(x));
    return __uint_as_float(u);
}

__device__ __forceinline__ void cpa16(uint32_t dst, const void* src) {
    asm volatile("cp.async.ca.shared.global [%0], [%1], 16;" :: "r"(dst), "l"(src));
}

// ---------------- weight rounding to tf32 ----------------
__global__ __launch_bounds__(256) void round_tf32_kernel(const float* __restrict__ in,
        float* __restrict__ out, int n4) {
    int i = blockIdx.x*blockDim.x + threadIdx.x;
    if (i >= n4) return;
    float4 v = reinterpret_cast<const float4*>(in)[i];
    v.x = rtf32(v.x); v.y = rtf32(v.y); v.z = rtf32(v.z); v.w = rtf32(v.w);
    reinterpret_cast<float4*>(out)[i] = v;
}

// ---------------- rmsnorm over rows of length 1024 (output tf32-rounded) ----------------
__global__ __launch_bounds__(256) void rmsnorm_kernel(const float* __restrict__ in,
        const float* __restrict__ w, float* __restrict__ out) {
    long row = blockIdx.x;
    int t = threadIdx.x;
    float4 v = reinterpret_cast<const float4*>(in + row*DM)[t];
    float ss = v.x*v.x + v.y*v.y + v.z*v.z + v.w*v.w;
    __shared__ float red[8];
    for (int o = 16; o; o >>= 1) ss += __shfl_xor_sync(0xffffffffu, ss, o);
    if ((t & 31) == 0) red[t >> 5] = ss;
    __syncthreads();
    if (t < 32) {
        float s = (t < 8) ? red[t] : 0.f;
        for (int o = 4; o; o >>= 1) s += __shfl_xor_sync(0xffffffffu, s, o);
        if (t == 0) red[0] = s;
    }
    __syncthreads();
    float rs = rsqrtf(red[0] * (1.f/DM) + 1e-6f);
    float4 wv = reinterpret_cast<const float4*>(w)[t];
    float4 o4 = make_float4(rtf32(v.x*rs*wv.x), rtf32(v.y*rs*wv.y),
                            rtf32(v.z*rs*wv.z), rtf32(v.w*rs*wv.w));
    reinterpret_cast<float4*>(out + row*DM)[t] = o4;
}

// ---------------- h1 = x[:, -272:] + attn ; hn = rmsnorm(h1) (hn tf32-rounded) ----------------
__global__ __launch_bounds__(256) void add_rmsnorm_kernel(const float* __restrict__ x,
        const float* __restrict__ w) {
    int row = blockIdx.x;
    int b = row / QLEN, r = row - b*QLEN;
    int t = threadIdx.x;
    float4 xv = reinterpret_cast<const float4*>(x + ((long)b*TOTAL + (TOTAL-QLEN) + r)*DM)[t];
    float4 av = reinterpret_cast<const float4*>(g_attn + (long)row*DM)[t];
    float4 hv = make_float4(xv.x+av.x, xv.y+av.y, xv.z+av.z, xv.w+av.w);
    reinterpret_cast<float4*>(g_h1 + (long)row*DM)[t] = hv;
    float ss = hv.x*hv.x + hv.y*hv.y + hv.z*hv.z + hv.w*hv.w;
    __shared__ float red[8];
    for (int o = 16; o; o >>= 1) ss += __shfl_xor_sync(0xffffffffu, ss, o);
    if ((t & 31) == 0) red[t >> 5] = ss;
    __syncthreads();
    if (t < 32) {
        float s = (t < 8) ? red[t] : 0.f;
        for (int o = 4; o; o >>= 1) s += __shfl_xor_sync(0xffffffffu, s, o);
        if (t == 0) red[0] = s;
    }
    __syncthreads();
    float rs = rsqrtf(red[0] * (1.f/DM) + 1e-6f);
    float4 wv = reinterpret_cast<const float4*>(w)[t];
    float4 o4 = make_float4(rtf32(hv.x*rs*wv.x), rtf32(hv.y*rs*wv.y),
                            rtf32(hv.z*rs*wv.z), rtf32(hv.w*rs*wv.w));
    reinterpret_cast<float4*>(g_hn + (long)row*DM)[t] = o4;
}

// ---------------- TF32 tensor-core GEMM 128x128x16 ----------------
// C[row, bn0+col] = sum_k A[row,k]*B[k,col] + bias[col]; batched row mapping via rpb.
// A,B expected pre-rounded to tf32 values (fp32 storage).
__global__ __launch_bounds__(256, 2) void mma_gemm_kernel(
    const float* __restrict__ A, int lda, long aBatch, int rpb,
    const float* __restrict__ Bw, int ldb,
    const float* __restrict__ bias,
    float* __restrict__ C, int ldc, long cBatch,
    int K, int relu, int roundOut)
{
    __shared__ float As[2][128][20];
    __shared__ float Bs[2][16][136];

    int t = threadIdx.x;
    int w = t >> 5, lane = t & 31;
    int g = lane >> 2, tig = lane & 3;
    int wm = w >> 2, wn = w & 3;

    int row0 = blockIdx.y * 128;
    int bn0  = blockIdx.x * 128;
    int batch = row0 / rpb;
    int rin   = row0 % rpb;
    const float* Ab = A + (long)batch*aBatch + (long)rin*lda;
    const float* Bb = Bw + bn0;
    float* Cb = C + (long)batch*cBatch + (long)rin*ldc + bn0;

    // global load pointers
    int aRow = t >> 1, aCol = (t & 1) * 8;
    int bRow = t >> 4, bCol = (t & 15) * 8;
    const float* ga = Ab + (long)aRow*lda + aCol;
    const float* gb = Bb + (long)bRow*ldb + bCol;

    uint32_t aSm[2], bSm[2];
    aSm[0] = (uint32_t)__cvta_generic_to_shared(&As[0][aRow][aCol]);
    aSm[1] = (uint32_t)__cvta_generic_to_shared(&As[1][aRow][aCol]);
    bSm[0] = (uint32_t)__cvta_generic_to_shared(&Bs[0][bRow][bCol]);
    bSm[1] = (uint32_t)__cvta_generic_to_shared(&Bs[1][bRow][bCol]);

    float acc[4][4][4];
    #pragma unroll
    for (int i = 0; i < 4; i++)
        #pragma unroll
        for (int j = 0; j < 4; j++)
            #pragma unroll
            for (int r = 0; r < 4; r++) acc[i][j][r] = 0.f;

    const int KT = K >> 4;
    // prologue: stage 0
    cpa16(aSm[0],      ga);
    cpa16(aSm[0] + 16, ga + 4);
    cpa16(bSm[0],      gb);
    cpa16(bSm[0] + 16, gb + 4);
    asm volatile("cp.async.commit_group;");

    int buf = 0;
    for (int kt = 0; kt < KT; kt++) {
        if (kt + 1 < KT) {
            const float* gan = ga + (kt+1)*16;
            const float* gbn = gb + (long)(kt+1)*16*ldb;
            int nb = buf ^ 1;
            cpa16(aSm[nb],      gan);
            cpa16(aSm[nb] + 16, gan + 4);
            cpa16(bSm[nb],      gbn);
            cpa16(bSm[nb] + 16, gbn + 4);
            asm volatile("cp.async.commit_group;");
            asm volatile("cp.async.wait_group 1;");
        } else {
            asm volatile("cp.async.wait_group 0;");
        }
        __syncthreads();

        #pragma unroll
        for (int ks = 0; ks < 2; ks++) {
            uint32_t afr[4][4];
            #pragma unroll
            for (int mt = 0; mt < 4; mt++) {
                const float* ap = &As[buf][wm*64 + mt*16][ks*8 + tig];
                afr[mt][0] = __float_as_uint(ap[g*20]);
                afr[mt][1] = __float_as_uint(ap[(g+8)*20]);
                afr[mt][2] = __float_as_uint(ap[g*20 + 4]);
                afr[mt][3] = __float_as_uint(ap[(g+8)*20 + 4]);
            }
            uint32_t bfr[4][2];
            #pragma unroll
            for (int nt = 0; nt < 4; nt++) {
                const float* bp = &Bs[buf][ks*8 + tig][wn*32 + nt*8 + g];
                bfr[nt][0] = __float_as_uint(bp[0]);
                bfr[nt][1] = __float_as_uint(bp[4*136]);
            }
            #pragma unroll
            for (int mt = 0; mt < 4; mt++)
                #pragma unroll
                for (int nt = 0; nt < 4; nt++) {
                    asm volatile(
                        "mma.sync.aligned.m16n8k8.row.col.f32.tf32.tf32.f32 "
                        "{%0,%1,%2,%3}, {%4,%5,%6,%7}, {%8,%9}, {%0,%1,%2,%3};\n"
                        : "+f"(acc[mt][nt][0]), "+f"(acc[mt][nt][1]),
                          "+f"(acc[mt][nt][2]), "+f"(acc[mt][nt][3])
                        : "r"(afr[mt][0]), "r"(afr[mt][1]), "r"(afr[mt][2]), "r"(afr[mt][3]),
                          "r"(bfr[nt][0]), "r"(bfr[nt][1]));
                }
        }
        __syncthreads();
        buf ^= 1;
    }

    // epilogue
    #pragma unroll
    for (int nt = 0; nt < 4; nt++) {
        int col = wn*32 + nt*8 + 2*tig;
        float bx = bias[bn0 + col], by = bias[bn0 + col + 1];
        #pragma unroll
        for (int mt = 0; mt < 4; mt++) {
            int r0 = wm*64 + mt*16 + g;
            float c0 = acc[mt][nt][0] + bx, c1 = acc[mt][nt][1] + by;
            float c2 = acc[mt][nt][2] + bx, c3 = acc[mt][nt][3] + by;
            if (relu) { c0=fmaxf(c0,0.f); c1=fmaxf(c1,0.f); c2=fmaxf(c2,0.f); c3=fmaxf(c3,0.f); }
            if (roundOut) { c0=rtf32(c0); c1=rtf32(c1); c2=rtf32(c2); c3=rtf32(c3); }
            *reinterpret_cast<float2*>(Cb + (long)r0*ldc + col)     = make_float2(c0, c1);
            *reinterpret_cast<float2*>(Cb + (long)(r0+8)*ldc + col) = make_float2(c2, c3);
        }
    }
}

// ---------------- per-NS-position linear ----------------
__global__ __launch_bounds__(128) void ns_linear_kernel(
    const float* __restrict__ X, long xBatch, int xRow,
    const float* __restrict__ W, const float* __restrict__ bias,
    float* __restrict__ Y, long yBatch, int yRow,
    int K, int N, int relu)
{
    __shared__ float Xs[4][1024];
    int n = blockIdx.y;
    int t = threadIdx.x;
    int o = blockIdx.x * 128 + t;
    const float* Wn = W + (long)n*K*N + o;
    float a0=0.f, a1=0.f, a2=0.f, a3=0.f;
    for (int k0 = 0; k0 < K; k0 += 1024) {
        __syncthreads();
        for (int i = t; i < 1024; i += 128) {
            long xo = (long)n*xRow + k0 + i;
            Xs[0][i] = X[0*xBatch + xo];
            Xs[1][i] = X[1*xBatch + xo];
            Xs[2][i] = X[2*xBatch + xo];
            Xs[3][i] = X[3*xBatch + xo];
        }
        __syncthreads();
        const float* Wp = Wn + (long)k0*N;
        #pragma unroll 8
        for (int k = 0; k < 1024; k++) {
            float w = Wp[(long)k*N];
            a0 += w*Xs[0][k]; a1 += w*Xs[1][k]; a2 += w*Xs[2][k]; a3 += w*Xs[3][k];
        }
    }
    float bv = bias[(long)n*N + o];
    a0 += bv; a1 += bv; a2 += bv; a3 += bv;
    if (relu) { a0=fmaxf(a0,0.f); a1=fmaxf(a1,0.f); a2=fmaxf(a2,0.f); a3=fmaxf(a3,0.f); }
    long yo = (long)n*yRow + o;
    Y[0*yBatch+yo]=a0; Y[1*yBatch+yo]=a1; Y[2*yBatch+yo]=a2; Y[3*yBatch+yo]=a3;
}

// ---------------- RoPE in-place ----------------
__global__ void rope_kernel(float* __restrict__ buf, int rowsPerB, int pos0, int total) {
    int idx = blockIdx.x*blockDim.x + threadIdx.x;
    if (idx >= total) return;
    int j  = idx & 31;
    int h  = (idx >> 5) & (NH-1);
    int rr = idx >> 9;
    int b  = rr / rowsPerB;
    int r  = rr - b*rowsPerB;
    double inv = pow(10000.0, -(double)j / 32.0);
    double ang = (double)(pos0 + r) * inv;
    double sd, cd;
    sincos(ang, &sd, &cd);
    float s = (float)sd, c = (float)cd;
    float* base = buf + ((long)b*rowsPerB + r)*DM + h*HD;
    float x1 = base[j], x2 = base[j+32];
    base[j]    = x1*c - x2*s;
    base[j+32] = x2*c + x1*s;
}

// ---------------- streaming-softmax attention ----------------
__global__ __launch_bounds__(256) void attn_kernel(
    const float* __restrict__ q, const float* __restrict__ k, const float* __restrict__ v,
    float* __restrict__ attn, const int* __restrict__ seqlen)
{
    __shared__ float qs[64][68];
    __shared__ float ks[32][68];
    __shared__ float vs[32][68];
    __shared__ float S [64][33];
    int qt = blockIdx.x, h = blockIdx.y, b = blockIdx.z;
    int tid = threadIdx.x;
    int L = seqlen[b];
    int kmin = MAXS - L;
    for (int i = tid; i < 64*16; i += 256) {
        int r = i >> 4, c4 = (i & 15) * 4;
        int qg = qt*64 + r;
        float4 val = make_float4(0.f,0.f,0.f,0.f);
        if (qg < QLEN)
            val = *reinterpret_cast<const float4*>(q + ((long)b*QLEN + qg)*DM + h*HD + c4);
        *reinterpret_cast<float4*>(&qs[r][c4]) = val;
    }
    int qi = tid >> 2, dg = tid & 3;
    float m = -1e30f, l = 0.f;
    float4 acc[4];
    #pragma unroll
    for (int i = 0; i < 4; i++) acc[i] = make_float4(0.f,0.f,0.f,0.f);
    int qgmax = min(QLEN-1, qt*64 + 63);
    int t0 = kmin >> 5;
    int t1 = (MAXS - OUTN + qgmax) >> 5;
    int kiA = tid & 31, q0A = tid >> 5;
    for (int kt = t0; kt <= t1; kt++) {
        int key0 = kt * 32;
        __syncthreads();
        for (int i = tid; i < 32*16; i += 256) {
            int r = i >> 4, c4 = (i & 15) * 4;
            int key = key0 + r;
            float4 kv = make_float4(0.f,0.f,0.f,0.f), vv = kv;
            if (key < TOTAL) {
                long off = ((long)b*TOTAL + key)*DM + h*HD + c4;
                kv = *reinterpret_cast<const float4*>(k + off);
                vv = *reinterpret_cast<const float4*>(v + off);
            }
            *reinterpret_cast<float4*>(&ks[r][c4]) = kv;
            *reinterpret_cast<float4*>(&vs[r][c4]) = vv;
        }
        __syncthreads();
        float sacc[8];
        #pragma unroll
        for (int j = 0; j < 8; j++) sacc[j] = 0.f;
        #pragma unroll
        for (int d4 = 0; d4 < 16; d4++) {
            float4 kk = *reinterpret_cast<const float4*>(&ks[kiA][d4*4]);
            #pragma unroll
            for (int j = 0; j < 8; j++) {
                float4 qq = *reinterpret_cast<const float4*>(&qs[q0A + j*8][d4*4]);
                sacc[j] += qq.x*kk.x + qq.y*kk.y + qq.z*kk.z + qq.w*kk.w;
            }
        }
        int key = key0 + kiA;
        #pragma unroll
        for (int j = 0; j < 8; j++) {
            int qrow = q0A + j*8;
            int qg = qt*64 + qrow;
            bool valid = (qg < QLEN) && (key < TOTAL) && (key >= kmin)
                      && (key <= MAXS - OUTN + qg);
            S[qrow][kiA] = valid ? sacc[j]*0.125f : -1e9f;
        }
        __syncthreads();
        float tmax = -1e30f;
        #pragma unroll
        for (int j = 0; j < 32; j++) tmax = fmaxf(tmax, S[qi][j]);
        if (tmax > -1e8f) {
            float m_new = fmaxf(m, tmax);
            float corr = __expf(m - m_new);
            l *= corr;
            #pragma unroll
            for (int i = 0; i < 4; i++) {
                acc[i].x*=corr; acc[i].y*=corr; acc[i].z*=corr; acc[i].w*=corr;
            }
            float ps = 0.f;
            #pragma unroll
            for (int j = 0; j < 32; j++) {
                float p = __expf(S[qi][j] - m_new);
                ps += p;
                #pragma unroll
                for (int i = 0; i < 4; i++) {
                    float4 vv = *reinterpret_cast<const float4*>(&vs[j][dg*16 + i*4]);
                    acc[i].x += p*vv.x; acc[i].y += p*vv.y; acc[i].z += p*vv.z; acc[i].w += p*vv.w;
                }
            }
            l += ps;
            m = m_new;
        }
    }
    int qg = qt*64 + qi;
    if (qg < QLEN) {
        float invl = 1.f / l;
        float* op = attn + ((long)b*QLEN + qg)*DM + h*HD + dg*16;
        #pragma unroll
        for (int i = 0; i < 4; i++)
            *reinterpret_cast<float4*>(op + i*4) =
                make_float4(acc[i].x*invl, acc[i].y*invl, acc[i].z*invl, acc[i].w*invl);
    }
}

// ---------------- final assembly ----------------
__global__ void assemble_kernel(float* __restrict__ out, const int* __restrict__ seqlen, int out_size) {
    int idx = blockIdx.x*blockDim.x + threadIdx.x;
    const int main_n = BSZ*QLEN*DM;
    if (idx < main_n) {
        int b = idx / (QLEN*DM);
        int rem = idx - b*(QLEN*DM);
        int r = rem / DM;
        int d = rem - r*DM;
        float f;
        if (r < OUTN) f = g_fs [((long)b*OUTN + r)*DM + d];
        else          f = g_fns[((long)b*NSN + (r - OUTN))*DM + d];
        out[idx] = f + g_h1[idx];
    }
    if (idx < BSZ && out_size >= main_n + BSZ) {
        int L = seqlen[idx];
        out[main_n + idx] = (float)(L < OUTN ? L : OUTN);
    }
}

extern "C" void kernel_launch(void* const* d_in, const int* in_sizes, int n_in,
                              void* d_out, int out_size) {
    (void)in_sizes; (void)n_in;
    const float* x    = (const float*)d_in[0];
    const int*   seq  = (const int*)  d_in[1];
    const float* wqkv = (const float*)d_in[2];
    const float* bqkv = (const float*)d_in[3];
    const float* wnsq = (const float*)d_in[4];
    const float* bnsq = (const float*)d_in[5];
    const float* wnsk = (const float*)d_in[6];
    const float* bnsk = (const float*)d_in[7];
    const float* wnsv = (const float*)d_in[8];
    const float* bnsv = (const float*)d_in[9];
    const float* n1w  = (const float*)d_in[10];
    const float* n2w  = (const float*)d_in[11];
    const float* fw1  = (const float*)d_in[12];
    const float* fb1  = (const float*)d_in[13];
    const float* fw2  = (const float*)d_in[14];
    const float* fb2  = (const float*)d_in[15];
    const float* w1ns = (const float*)d_in[16];
    const float* b1ns = (const float*)d_in[17];
    const float* w2ns = (const float*)d_in[18];
    const float* b2ns = (const float*)d_in[19];
    float* out = (float*)d_out;

    float *xn,*q,*k,*v,*attn,*hn,*ts,*tns,*fs,*fns,*wq_r,*w1_r,*w2_r;
    cudaGetSymbolAddress((void**)&xn,   g_xn);
    cudaGetSymbolAddress((void**)&q,    g_q);
    cudaGetSymbolAddress((void**)&k,    g_k);
    cudaGetSymbolAddress((void**)&v,    g_v);
    cudaGetSymbolAddress((void**)&attn, g_attn);
    cudaGetSymbolAddress((void**)&hn,   g_hn);
    cudaGetSymbolAddress((void**)&ts,   g_ts);
    cudaGetSymbolAddress((void**)&tns,  g_tns);
    cudaGetSymbolAddress((void**)&fs,   g_fs);
    cudaGetSymbolAddress((void**)&fns,  g_fns);
    cudaGetSymbolAddress((void**)&wq_r, g_wqkv);
    cudaGetSymbolAddress((void**)&w1_r, g_w1);
    cudaGetSymbolAddress((void**)&w2_r, g_w2);

    const long aB = (long)TOTAL*DM;
    const long qB = (long)QLEN*DM;

    // 0) round shared GEMM weights to tf32
    round_tf32_kernel<<<(DM*3*DM/4 + 255)/256, 256>>>(wqkv, wq_r, DM*3*DM/4);
    round_tf32_kernel<<<(DM*FFND/4 + 255)/256, 256>>>(fw1, w1_r, DM*FFND/4);
    round_tf32_kernel<<<(FFND*DM/4 + 255)/256, 256>>>(fw2, w2_r, FFND*DM/4);

    // 1) xn = rmsnorm(x, norm1) (tf32-rounded)
    rmsnorm_kernel<<<BSZ*TOTAL, 256>>>(x, n1w, xn);

    // 2) shared projections via tensor cores
    mma_gemm_kernel<<<dim3(DM/128, (BSZ*MAXS)/128), 256>>>(xn, DM, aB, MAXS,
        wq_r + DM,   3*DM, bqkv + DM,   k, DM, aB, DM, 0, 0);
    mma_gemm_kernel<<<dim3(DM/128, (BSZ*MAXS)/128), 256>>>(xn, DM, aB, MAXS,
        wq_r + 2*DM, 3*DM, bqkv + 2*DM, v, DM, aB, DM, 0, 0);
    mma_gemm_kernel<<<dim3(DM/128, (BSZ*OUTN)/128), 256>>>(xn + (long)(MAXS-OUTN)*DM, DM, aB, OUTN,
        wq_r,        3*DM, bqkv,        q, DM, qB, DM, 0, 0);

    // 3) per-position NS projections
    ns_linear_kernel<<<dim3(DM/128, NSN), 128>>>(xn + (long)MAXS*DM, aB, DM,
        wnsq, bnsq, q + (long)OUTN*DM, qB, DM, DM, DM, 0);
    ns_linear_kernel<<<dim3(DM/128, NSN), 128>>>(xn + (long)MAXS*DM, aB, DM,
        wnsk, bnsk, k + (long)MAXS*DM, aB, DM, DM, DM, 0);
    ns_linear_kernel<<<dim3(DM/128, NSN), 128>>>(xn + (long)MAXS*DM, aB, DM,
        wnsv, bnsv, v + (long)MAXS*DM, aB, DM, DM, DM, 0);

    // 4) RoPE
    {
        int totq = BSZ*QLEN*NH*32;
        rope_kernel<<<(totq+255)/256, 256>>>(q, QLEN, TOTAL-QLEN, totq);
        int totk = BSZ*TOTAL*NH*32;
        rope_kernel<<<(totk+255)/256, 256>>>(k, TOTAL, 0, totk);
    }

    // 5) attention
    attn_kernel<<<dim3((QLEN+63)/64, NH, BSZ), 256>>>(q, k, v, attn, seq);

    // 6) h1 = residual + attn ; hn = rmsnorm(h1, norm2)
    add_rmsnorm_kernel<<<BSZ*QLEN, 256>>>(x, n2w);

    // 7) shared FFN via tensor cores (FFN1 output rounded for FFN2's A operand)
    mma_gemm_kernel<<<dim3(FFND/128, (BSZ*OUTN)/128), 256>>>(hn, DM, qB, OUTN,
        w1_r, FFND, fb1, ts, FFND, (long)OUTN*FFND, DM, 1, 1);
    mma_gemm_kernel<<<dim3(DM/128, (BSZ*OUTN)/128), 256>>>(ts, FFND, (long)OUTN*FFND, OUTN,
        w2_r, DM, fb2, fs, DM, (long)OUTN*DM, FFND, 0, 0);

    // 8) NS FFN
    ns_linear_kernel<<<dim3(FFND/128, NSN), 128>>>(hn + (long)OUTN*DM, qB, DM,
        w1ns, b1ns, tns, (long)NSN*FFND, FFND, DM, FFND, 1);
    ns_linear_kernel<<<dim3(DM/128, NSN), 128>>>(tns, (long)NSN*FFND, FFND,
        w2ns, b2ns, fns, (long)NSN*DM, DM, FFND, DM, 0);

    // 9) assemble output
    assemble_kernel<<<(BSZ*QLEN*DM + 255)/256, 256>>>(out, seq, out_size);
}

// round 3
// speedup vs baseline: 2.0498x; 1.4719x over previous
#include <cuda_runtime.h>
#include <cstdint>

#define BSZ   4
#define TOTAL 2064
#define DM    1024
#define NSN   16
#define OUTN  256
#define QLEN  272
#define NH    16
#define HD    64
#define FFND  4096
#define MAXS  2048

// Scratch (static device globals; no allocation allowed)
__device__ float g_xn  [BSZ*TOTAL*DM];
__device__ float g_q   [BSZ*QLEN*DM];
__device__ float g_kv  [BSZ*TOTAL*2*DM];   // k = cols 0..1023, v = cols 1024..2047
__device__ float g_attn[BSZ*QLEN*DM];
__device__ float g_h1  [BSZ*QLEN*DM];
__device__ float g_hn  [BSZ*QLEN*DM];
__device__ float g_ts  [BSZ*OUTN*FFND];
__device__ float g_tns [BSZ*NSN*FFND];
__device__ float g_fs  [BSZ*OUTN*DM];
__device__ float g_fns [BSZ*NSN*DM];
__device__ float g_part[8*BSZ*NSN*DM];     // k-split partials
// TF32-rounded weights
__device__ float g_wqkv[DM*3*DM];
__device__ float g_w1  [DM*FFND];
__device__ float g_w2  [FFND*DM];

__device__ __forceinline__ float rtf32(float x) {
    uint32_t u;
    asm("cvt.rna.tf32.f32 %0, %1;" : "=r"(u) : "f"(x));
    return __uint_as_float(u);
}
__device__ __forceinline__ uint32_t f2u(float x) { return __float_as_uint(x); }

__device__ __forceinline__ void cpa16(uint32_t dst, const void* src) {
    asm volatile("cp.async.ca.shared.global [%0], [%1], 16;" :: "r"(dst), "l"(src));
}

__device__ __forceinline__ void mma_tf32(float* c,
        uint32_t a0, uint32_t a1, uint32_t a2, uint32_t a3,
        uint32_t b0, uint32_t b1) {
    asm volatile(
        "mma.sync.aligned.m16n8k8.row.col.f32.tf32.tf32.f32 "
        "{%0,%1,%2,%3}, {%4,%5,%6,%7}, {%8,%9}, {%0,%1,%2,%3};\n"
        : "+f"(c[0]), "+f"(c[1]), "+f"(c[2]), "+f"(c[3])
        : "r"(a0), "r"(a1), "r"(a2), "r"(a3), "r"(b0), "r"(b1));
}

// ---------------- weight rounding to tf32 ----------------
__global__ __launch_bounds__(256) void round_tf32_kernel(const float* __restrict__ in,
        float* __restrict__ out, int n4) {
    int i = blockIdx.x*blockDim.x + threadIdx.x;
    if (i >= n4) return;
    float4 v = reinterpret_cast<const float4*>(in)[i];
    v.x = rtf32(v.x); v.y = rtf32(v.y); v.z = rtf32(v.z); v.w = rtf32(v.w);
    reinterpret_cast<float4*>(out)[i] = v;
}

// ---------------- rmsnorm (output tf32-rounded) ----------------
__global__ __launch_bounds__(256) void rmsnorm_kernel(const float* __restrict__ in,
        const float* __restrict__ w, float* __restrict__ out) {
    long row = blockIdx.x;
    int t = threadIdx.x;
    float4 v = reinterpret_cast<const float4*>(in + row*DM)[t];
    float ss = v.x*v.x + v.y*v.y + v.z*v.z + v.w*v.w;
    __shared__ float red[8];
    for (int o = 16; o; o >>= 1) ss += __shfl_xor_sync(0xffffffffu, ss, o);
    if ((t & 31) == 0) red[t >> 5] = ss;
    __syncthreads();
    if (t < 32) {
        float s = (t < 8) ? red[t] : 0.f;
        for (int o = 4; o; o >>= 1) s += __shfl_xor_sync(0xffffffffu, s, o);
        if (t == 0) red[0] = s;
    }
    __syncthreads();
    float rs = rsqrtf(red[0] * (1.f/DM) + 1e-6f);
    float4 wv = reinterpret_cast<const float4*>(w)[t];
    float4 o4 = make_float4(rtf32(v.x*rs*wv.x), rtf32(v.y*rs*wv.y),
                            rtf32(v.z*rs*wv.z), rtf32(v.w*rs*wv.w));
    reinterpret_cast<float4*>(out + row*DM)[t] = o4;
}

// ---------------- h1 = x[:, -272:] + attn ; hn = rmsnorm(h1) ----------------
__global__ __launch_bounds__(256) void add_rmsnorm_kernel(const float* __restrict__ x,
        const float* __restrict__ w) {
    int row = blockIdx.x;
    int b = row / QLEN, r = row - b*QLEN;
    int t = threadIdx.x;
    float4 xv = reinterpret_cast<const float4*>(x + ((long)b*TOTAL + (TOTAL-QLEN) + r)*DM)[t];
    float4 av = reinterpret_cast<const float4*>(g_attn + (long)row*DM)[t];
    float4 hv = make_float4(xv.x+av.x, xv.y+av.y, xv.z+av.z, xv.w+av.w);
    reinterpret_cast<float4*>(g_h1 + (long)row*DM)[t] = hv;
    float ss = hv.x*hv.x + hv.y*hv.y + hv.z*hv.z + hv.w*hv.w;
    __shared__ float red[8];
    for (int o = 16; o; o >>= 1) ss += __shfl_xor_sync(0xffffffffu, ss, o);
    if ((t & 31) == 0) red[t >> 5] = ss;
    __syncthreads();
    if (t < 32) {
        float s = (t < 8) ? red[t] : 0.f;
        for (int o = 4; o; o >>= 1) s += __shfl_xor_sync(0xffffffffu, s, o);
        if (t == 0) red[0] = s;
    }
    __syncthreads();
    float rs = rsqrtf(red[0] * (1.f/DM) + 1e-6f);
    float4 wv = reinterpret_cast<const float4*>(w)[t];
    float4 o4 = make_float4(rtf32(hv.x*rs*wv.x), rtf32(hv.y*rs*wv.y),
                            rtf32(hv.z*rs*wv.z), rtf32(hv.w*rs*wv.w));
    reinterpret_cast<float4*>(g_hn + (long)row*DM)[t] = o4;
}

// ---------------- TF32 tensor-core GEMM 128x128x16, 2-stage cp.async ----------------
__global__ __launch_bounds__(256, 2) void mma_gemm_kernel(
    const float* __restrict__ A, int lda, long aBatch, int rpb,
    const float* __restrict__ Bw, int ldb,
    const float* __restrict__ bias,
    float* __restrict__ C, int ldc, long cBatch,
    int K, int relu, int roundOut)
{
    __shared__ float As[2][128][20];
    __shared__ float Bs[2][16][136];

    int t = threadIdx.x;
    int w = t >> 5, lane = t & 31;
    int g = lane >> 2, tig = lane & 3;
    int wm = w >> 2, wn = w & 3;

    int row0 = blockIdx.y * 128;
    int bn0  = blockIdx.x * 128;
    int batch = row0 / rpb;
    int rin   = row0 % rpb;
    const float* Ab = A + (long)batch*aBatch + (long)rin*lda;
    const float* Bb = Bw + bn0;
    float* Cb = C + (long)batch*cBatch + (long)rin*ldc + bn0;

    int aRow = t >> 1, aCol = (t & 1) * 8;
    int bRow = t >> 4, bCol = (t & 15) * 8;
    const float* ga = Ab + (long)aRow*lda + aCol;
    const float* gb = Bb + (long)bRow*ldb + bCol;

    uint32_t aSm[2], bSm[2];
    aSm[0] = (uint32_t)__cvta_generic_to_shared(&As[0][aRow][aCol]);
    aSm[1] = (uint32_t)__cvta_generic_to_shared(&As[1][aRow][aCol]);
    bSm[0] = (uint32_t)__cvta_generic_to_shared(&Bs[0][bRow][bCol]);
    bSm[1] = (uint32_t)__cvta_generic_to_shared(&Bs[1][bRow][bCol]);

    float acc[4][4][4];
    #pragma unroll
    for (int i = 0; i < 4; i++)
        #pragma unroll
        for (int j = 0; j < 4; j++)
            #pragma unroll
            for (int r = 0; r < 4; r++) acc[i][j][r] = 0.f;

    const int KT = K >> 4;
    cpa16(aSm[0],      ga);
    cpa16(aSm[0] + 16, ga + 4);
    cpa16(bSm[0],      gb);
    cpa16(bSm[0] + 16, gb + 4);
    asm volatile("cp.async.commit_group;");

    int buf = 0;
    for (int kt = 0; kt < KT; kt++) {
        if (kt + 1 < KT) {
            const float* gan = ga + (kt+1)*16;
            const float* gbn = gb + (long)(kt+1)*16*ldb;
            int nb = buf ^ 1;
            cpa16(aSm[nb],      gan);
            cpa16(aSm[nb] + 16, gan + 4);
            cpa16(bSm[nb],      gbn);
            cpa16(bSm[nb] + 16, gbn + 4);
            asm volatile("cp.async.commit_group;");
            asm volatile("cp.async.wait_group 1;");
        } else {
            asm volatile("cp.async.wait_group 0;");
        }
        __syncthreads();

        #pragma unroll
        for (int ks = 0; ks < 2; ks++) {
            uint32_t afr[4][4];
            #pragma unroll
            for (int mt = 0; mt < 4; mt++) {
                const float* ap = &As[buf][wm*64 + mt*16][ks*8 + tig];
                afr[mt][0] = f2u(ap[g*20]);
                afr[mt][1] = f2u(ap[(g+8)*20]);
                afr[mt][2] = f2u(ap[g*20 + 4]);
                afr[mt][3] = f2u(ap[(g+8)*20 + 4]);
            }
            uint32_t bfr[4][2];
            #pragma unroll
            for (int nt = 0; nt < 4; nt++) {
                const float* bp = &Bs[buf][ks*8 + tig][wn*32 + nt*8 + g];
                bfr[nt][0] = f2u(bp[0]);
                bfr[nt][1] = f2u(bp[4*136]);
            }
            #pragma unroll
            for (int mt = 0; mt < 4; mt++)
                #pragma unroll
                for (int nt = 0; nt < 4; nt++)
                    mma_tf32(acc[mt][nt], afr[mt][0], afr[mt][1], afr[mt][2], afr[mt][3],
                             bfr[nt][0], bfr[nt][1]);
        }
        __syncthreads();
        buf ^= 1;
    }

    #pragma unroll
    for (int nt = 0; nt < 4; nt++) {
        int col = wn*32 + nt*8 + 2*tig;
        float bx = bias[bn0 + col], by = bias[bn0 + col + 1];
        #pragma unroll
        for (int mt = 0; mt < 4; mt++) {
            int r0 = wm*64 + mt*16 + g;
            float c0 = acc[mt][nt][0] + bx, c1 = acc[mt][nt][1] + by;
            float c2 = acc[mt][nt][2] + bx, c3 = acc[mt][nt][3] + by;
            if (relu) { c0=fmaxf(c0,0.f); c1=fmaxf(c1,0.f); c2=fmaxf(c2,0.f); c3=fmaxf(c3,0.f); }
            if (roundOut) { c0=rtf32(c0); c1=rtf32(c1); c2=rtf32(c2); c3=rtf32(c3); }
            *reinterpret_cast<float2*>(Cb + (long)r0*ldc + col)     = make_float2(c0, c1);
            *reinterpret_cast<float2*>(Cb + (long)(r0+8)*ldc + col) = make_float2(c2, c3);
        }
    }
}

// ---------------- per-NS-position linear, direct (used for w1ns: N=4096) ----------------
__global__ __launch_bounds__(128) void ns_linear_kernel(
    const float* __restrict__ X, long xBatch, int xRow,
    const float* __restrict__ W, const float* __restrict__ bias,
    float* __restrict__ Y, long yBatch, int yRow,
    int K, int N, int relu)
{
    __shared__ float Xs[4][1024];
    int n = blockIdx.y;
    int t = threadIdx.x;
    int o = blockIdx.x * 128 + t;
    const float* Wn = W + (long)n*K*N + o;
    float a0=0.f, a1=0.f, a2=0.f, a3=0.f;
    for (int k0 = 0; k0 < K; k0 += 1024) {
        __syncthreads();
        for (int i = t; i < 1024; i += 128) {
            long xo = (long)n*xRow + k0 + i;
            Xs[0][i] = X[0*xBatch + xo];
            Xs[1][i] = X[1*xBatch + xo];
            Xs[2][i] = X[2*xBatch + xo];
            Xs[3][i] = X[3*xBatch + xo];
        }
        __syncthreads();
        const float* Wp = Wn + (long)k0*N;
        #pragma unroll 8
        for (int k = 0; k < 1024; k++) {
            float w = Wp[(long)k*N];
            a0 += w*Xs[0][k]; a1 += w*Xs[1][k]; a2 += w*Xs[2][k]; a3 += w*Xs[3][k];
        }
    }
    float bv = bias[(long)n*N + o];
    a0 += bv; a1 += bv; a2 += bv; a3 += bv;
    if (relu) { a0=fmaxf(a0,0.f); a1=fmaxf(a1,0.f); a2=fmaxf(a2,0.f); a3=fmaxf(a3,0.f); }
    long yo = (long)n*yRow + o;
    Y[0*yBatch+yo]=a0; Y[1*yBatch+yo]=a1; Y[2*yBatch+yo]=a2; Y[3*yBatch+yo]=a3;
}

// ---------------- per-NS-position linear, K-split partials (N=1024 cases) ----------------
// grid (N/128, NSN, KS); part[((z*BSZ+b)*NSN+n)*N+o]
__global__ __launch_bounds__(128) void ns_split_kernel(
    const float* __restrict__ X, long xBatch, int xRow,
    const float* __restrict__ W, float* __restrict__ part,
    int K, int N, int kchunk)
{
    __shared__ float Xs[4][512];
    int n = blockIdx.y, z = blockIdx.z;
    int t = threadIdx.x;
    int o = blockIdx.x * 128 + t;
    int k0 = z * kchunk;
    for (int i = t; i < kchunk; i += 128) {
        long xo = (long)n*xRow + k0 + i;
        Xs[0][i] = X[0*xBatch + xo];
        Xs[1][i] = X[1*xBatch + xo];
        Xs[2][i] = X[2*xBatch + xo];
        Xs[3][i] = X[3*xBatch + xo];
    }
    __syncthreads();
    const float* Wp = W + (long)n*K*N + (long)k0*N + o;
    float a0=0.f, a1=0.f, a2=0.f, a3=0.f;
    #pragma unroll 8
    for (int k = 0; k < kchunk; k++) {
        float w = Wp[(long)k*N];
        a0 += w*Xs[0][k]; a1 += w*Xs[1][k]; a2 += w*Xs[2][k]; a3 += w*Xs[3][k];
    }
    part[((long)(z*BSZ+0)*NSN + n)*N + o] = a0;
    part[((long)(z*BSZ+1)*NSN + n)*N + o] = a1;
    part[((long)(z*BSZ+2)*NSN + n)*N + o] = a2;
    part[((long)(z*BSZ+3)*NSN + n)*N + o] = a3;
}

// grid (N/256, NSN, BSZ)
__global__ __launch_bounds__(256) void ns_reduce_kernel(
    const float* __restrict__ part, const float* __restrict__ bias,
    float* __restrict__ Y, long yBatch, int yRow, int N, int KS, int relu)
{
    int o = blockIdx.x*256 + threadIdx.x;
    int n = blockIdx.y, b = blockIdx.z;
    float s = bias[(long)n*N + o];
    for (int z = 0; z < KS; z++)
        s += part[((long)(z*BSZ+b)*NSN + n)*N + o];
    if (relu) s = fmaxf(s, 0.f);
    Y[(long)b*yBatch + (long)n*yRow + o] = s;
}

// ---------------- RoPE in-place (row stride param for kv buffer) ----------------
__global__ void rope_kernel(float* __restrict__ buf, int rowsPerB, int pos0, int rstride, int total) {
    int idx = blockIdx.x*blockDim.x + threadIdx.x;
    if (idx >= total) return;
    int j  = idx & 31;
    int h  = (idx >> 5) & (NH-1);
    int rr = idx >> 9;
    int b  = rr / rowsPerB;
    int r  = rr - b*rowsPerB;
    double inv = pow(10000.0, -(double)j / 32.0);
    double ang = (double)(pos0 + r) * inv;
    double sd, cd;
    sincos(ang, &sd, &cd);
    float s = (float)sd, c = (float)cd;
    float* base = buf + ((long)b*rowsPerB + r)*(long)rstride + h*HD;
    float x1 = base[j], x2 = base[j+32];
    base[j]    = x1*c - x2*s;
    base[j+32] = x2*c + x1*s;
}

// ---------------- tensor-core flash attention (tf32) ----------------
// block: 64 q-rows x (32-key tiles streamed); grid (5, NH, BSZ); 256 threads / 8 warps
__global__ __launch_bounds__(256) void attn_mma_kernel(
    const float* __restrict__ q, const float* __restrict__ kv,
    float* __restrict__ attn, const int* __restrict__ seqlen)
{
    __shared__ float qs [64][68];
    __shared__ float ksm[32][68];
    __shared__ float vsm[32][72];
    __shared__ float ssm[64][36];
    __shared__ float corrs[64];
    __shared__ float lrow[64];

    int qt = blockIdx.x, h = blockIdx.y, b = blockIdx.z;
    int tid = threadIdx.x;
    int w = tid >> 5, lane = tid & 31;
    int g = lane >> 2, tig = lane & 3;
    int wm = w >> 2, wn = w & 3;          // wm: 2 row-halves of 32; wn: 4 key/dim columns
    int L = seqlen[b];
    int kmin = MAXS - L;

    // stage q tile (tf32-rounded)
    for (int i = tid; i < 64*16; i += 256) {
        int r = i >> 4, c4 = (i & 15) * 4;
        int qg = qt*64 + r;
        float4 val = make_float4(0.f,0.f,0.f,0.f);
        if (qg < QLEN)
            val = *reinterpret_cast<const float4*>(q + ((long)b*QLEN + qg)*DM + h*HD + c4);
        qs[r][c4]   = rtf32(val.x);
        qs[r][c4+1] = rtf32(val.y);
        qs[r][c4+2] = rtf32(val.z);
        qs[r][c4+3] = rtf32(val.w);
    }

    int srow = tid >> 2, ssub = tid & 3;  // softmax ownership: 4 threads per q-row
    float m = -1e30f, l = 0.f;

    float oacc[2][2][4];
    #pragma unroll
    for (int i = 0; i < 2; i++)
        #pragma unroll
        for (int j = 0; j < 2; j++)
            #pragma unroll
            for (int r = 0; r < 4; r++) oacc[i][j][r] = 0.f;

    int qgmax = min(QLEN-1, qt*64 + 63);
    int t0 = kmin >> 5;
    int t1 = (MAXS - OUTN + qgmax) >> 5;

    for (int kt = t0; kt <= t1; kt++) {
        int key0 = kt * 32;
        __syncthreads();
        for (int i = tid; i < 32*16; i += 256) {
            int r = i >> 4, c4 = (i & 15) * 4;
            int key = key0 + r;
            float4 kk = make_float4(0.f,0.f,0.f,0.f), vv = kk;
            if (key < TOTAL) {
                const float* base = kv + ((long)b*TOTAL + key)*(2*DM) + h*HD;
                kk = *reinterpret_cast<const float4*>(base + c4);
                vv = *reinterpret_cast<const float4*>(base + DM + c4);
            }
            ksm[r][c4]=rtf32(kk.x); ksm[r][c4+1]=rtf32(kk.y);
            ksm[r][c4+2]=rtf32(kk.z); ksm[r][c4+3]=rtf32(kk.w);
            vsm[r][c4]=rtf32(vv.x); vsm[r][c4+1]=rtf32(vv.y);
            vsm[r][c4+2]=rtf32(vv.z); vsm[r][c4+3]=rtf32(vv.w);
        }
        __syncthreads();

        // S = Q K^T : warp covers rows wm*32..+31, keys wn*8..+7
        float sa[2][4];
        #pragma unroll
        for (int mt = 0; mt < 2; mt++)
            #pragma unroll
            for (int r = 0; r < 4; r++) sa[mt][r] = 0.f;
        #pragma unroll
        for (int dk = 0; dk < 8; dk++) {
            uint32_t bf0 = f2u(ksm[wn*8 + g][dk*8 + tig]);
            uint32_t bf1 = f2u(ksm[wn*8 + g][dk*8 + tig + 4]);
            #pragma unroll
            for (int mt = 0; mt < 2; mt++) {
                int m0 = wm*32 + mt*16;
                mma_tf32(sa[mt],
                    f2u(qs[m0+g][dk*8+tig]),   f2u(qs[m0+g+8][dk*8+tig]),
                    f2u(qs[m0+g][dk*8+tig+4]), f2u(qs[m0+g+8][dk*8+tig+4]),
                    bf0, bf1);
            }
        }
        // write S with mask + scale
        #pragma unroll
        for (int mt = 0; mt < 2; mt++) {
            #pragma unroll
            for (int hh = 0; hh < 2; hh++) {
                int r = wm*32 + mt*16 + g + hh*8;
                int qg = qt*64 + r;
                int key = key0 + wn*8 + 2*tig;
                int kcap = MAXS - OUTN + qg;
                bool rowok = (qg < QLEN);
                float sA = sa[mt][hh*2+0], sB = sa[mt][hh*2+1];
                bool v0 = rowok && (key   < TOTAL) && (key   >= kmin) && (key   <= kcap);
                bool v1 = rowok && (key+1 < TOTAL) && (key+1 >= kmin) && (key+1 <= kcap);
                ssm[r][wn*8 + 2*tig]     = v0 ? sA*0.125f : -1e9f;
                ssm[r][wn*8 + 2*tig + 1] = v1 ? sB*0.125f : -1e9f;
            }
        }
        __syncthreads();

        // streaming softmax (row srow, keys ssub*8..+7)
        float sv[8];
        #pragma unroll
        for (int j = 0; j < 8; j++) sv[j] = ssm[srow][ssub*8 + j];
        float tmax = sv[0];
        #pragma unroll
        for (int j = 1; j < 8; j++) tmax = fmaxf(tmax, sv[j]);
        tmax = fmaxf(tmax, __shfl_xor_sync(0xffffffffu, tmax, 1));
        tmax = fmaxf(tmax, __shfl_xor_sync(0xffffffffu, tmax, 2));
        float corr = 1.f;
        if (tmax > -1e8f) {
            float m_new = fmaxf(m, tmax);
            corr = __expf(m - m_new);
            float ps = 0.f;
            #pragma unroll
            for (int j = 0; j < 8; j++) {
                float p = __expf(sv[j] - m_new);
                ps += p;
                ssm[srow][ssub*8 + j] = rtf32(p);
            }
            ps += __shfl_xor_sync(0xffffffffu, ps, 1);
            ps += __shfl_xor_sync(0xffffffffu, ps, 2);
            l = l*corr + ps;
            m = m_new;
        } else {
            #pragma unroll
            for (int j = 0; j < 8; j++) ssm[srow][ssub*8 + j] = 0.f;
        }
        if (ssub == 0) corrs[srow] = corr;
        __syncthreads();

        // rescale O, then O += P @ V
        #pragma unroll
        for (int mt = 0; mt < 2; mt++) {
            float c0 = corrs[wm*32 + mt*16 + g];
            float c1 = corrs[wm*32 + mt*16 + g + 8];
            #pragma unroll
            for (int nt = 0; nt < 2; nt++) {
                oacc[mt][nt][0] *= c0; oacc[mt][nt][1] *= c0;
                oacc[mt][nt][2] *= c1; oacc[mt][nt][3] *= c1;
            }
        }
        #pragma unroll
        for (int kd = 0; kd < 4; kd++) {
            uint32_t bf[2][2];
            #pragma unroll
            for (int nt = 0; nt < 2; nt++) {
                int n = wn*16 + nt*8 + g;
                bf[nt][0] = f2u(vsm[kd*8 + tig][n]);
                bf[nt][1] = f2u(vsm[kd*8 + tig + 4][n]);
            }
            #pragma unroll
            for (int mt = 0; mt < 2; mt++) {
                int m0 = wm*32 + mt*16;
                uint32_t a0 = f2u(ssm[m0+g][kd*8+tig]);
                uint32_t a1 = f2u(ssm[m0+g+8][kd*8+tig]);
                uint32_t a2 = f2u(ssm[m0+g][kd*8+tig+4]);
                uint32_t a3 = f2u(ssm[m0+g+8][kd*8+tig+4]);
                #pragma unroll
                for (int nt = 0; nt < 2; nt++)
                    mma_tf32(oacc[mt][nt], a0, a1, a2, a3, bf[nt][0], bf[nt][1]);
            }
        }
    }

    if (ssub == 0) lrow[srow] = l;
    __syncthreads();
    #pragma unroll
    for (int mt = 0; mt < 2; mt++) {
        #pragma unroll
        for (int hh = 0; hh < 2; hh++) {
            int r = wm*32 + mt*16 + g + hh*8;
            int qg = qt*64 + r;
            if (qg < QLEN) {
                float invl = 1.f / lrow[r];
                #pragma unroll
                for (int nt = 0; nt < 2; nt++) {
                    int col = wn*16 + nt*8 + 2*tig;
                    *reinterpret_cast<float2*>(attn + ((long)b*QLEN + qg)*DM + h*HD + col)
                        = make_float2(oacc[mt][nt][hh*2]*invl, oacc[mt][nt][hh*2+1]*invl);
                }
            }
        }
    }
}

// ---------------- final assembly ----------------
__global__ void assemble_kernel(float* __restrict__ out, const int* __restrict__ seqlen, int out_size) {
    int idx = blockIdx.x*blockDim.x + threadIdx.x;
    const int main_n = BSZ*QLEN*DM;
    if (idx < main_n) {
        int b = idx / (QLEN*DM);
        int rem = idx - b*(QLEN*DM);
        int r = rem / DM;
        int d = rem - r*DM;
        float f;
        if (r < OUTN) f = g_fs [((long)b*OUTN + r)*DM + d];
        else          f = g_fns[((long)b*NSN + (r - OUTN))*DM + d];
        out[idx] = f + g_h1[idx];
    }
    if (idx < BSZ && out_size >= main_n + BSZ) {
        int L = seqlen[idx];
        out[main_n + idx] = (float)(L < OUTN ? L : OUTN);
    }
}

extern "C" void kernel_launch(void* const* d_in, const int* in_sizes, int n_in,
                              void* d_out, int out_size) {
    (void)in_sizes; (void)n_in;
    const float* x    = (const float*)d_in[0];
    const int*   seq  = (const int*)  d_in[1];
    const float* wqkv = (const float*)d_in[2];
    const float* bqkv = (const float*)d_in[3];
    const float* wnsq = (const float*)d_in[4];
    const float* bnsq = (const float*)d_in[5];
    const float* wnsk = (const float*)d_in[6];
    const float* bnsk = (const float*)d_in[7];
    const float* wnsv = (const float*)d_in[8];
    const float* bnsv = (const float*)d_in[9];
    const float* n1w  = (const float*)d_in[10];
    const float* n2w  = (const float*)d_in[11];
    const float* fw1  = (const float*)d_in[12];
    const float* fb1  = (const float*)d_in[13];
    const float* fw2  = (const float*)d_in[14];
    const float* fb2  = (const float*)d_in[15];
    const float* w1ns = (const float*)d_in[16];
    const float* b1ns = (const float*)d_in[17];
    const float* w2ns = (const float*)d_in[18];
    const float* b2ns = (const float*)d_in[19];
    float* out = (float*)d_out;

    float *xn,*q,*kv,*attn,*hn,*ts,*tns,*fs,*fns,*part,*wq_r,*w1_r,*w2_r;
    cudaGetSymbolAddress((void**)&xn,   g_xn);
    cudaGetSymbolAddress((void**)&q,    g_q);
    cudaGetSymbolAddress((void**)&kv,   g_kv);
    cudaGetSymbolAddress((void**)&attn, g_attn);
    cudaGetSymbolAddress((void**)&hn,   g_hn);
    cudaGetSymbolAddress((void**)&ts,   g_ts);
    cudaGetSymbolAddress((void**)&tns,  g_tns);
    cudaGetSymbolAddress((void**)&fs,   g_fs);
    cudaGetSymbolAddress((void**)&fns,  g_fns);
    cudaGetSymbolAddress((void**)&part, g_part);
    cudaGetSymbolAddress((void**)&wq_r, g_wqkv);
    cudaGetSymbolAddress((void**)&w1_r, g_w1);
    cudaGetSymbolAddress((void**)&w2_r, g_w2);

    const long aB  = (long)TOTAL*DM;     // xn batch stride
    const long qB  = (long)QLEN*DM;      // q/h1/hn batch stride
    const long kvB = (long)TOTAL*2*DM;   // kv batch stride

    // 0) round shared GEMM weights to tf32
    round_tf32_kernel<<<(DM*3*DM/4 + 255)/256, 256>>>(wqkv, wq_r, DM*3*DM/4);
    round_tf32_kernel<<<(DM*FFND/4 + 255)/256, 256>>>(fw1, w1_r, DM*FFND/4);
    round_tf32_kernel<<<(FFND*DM/4 + 255)/256, 256>>>(fw2, w2_r, FFND*DM/4);

    // 1) xn = rmsnorm(x, norm1)
    rmsnorm_kernel<<<BSZ*TOTAL, 256>>>(x, n1w, xn);

    // 2) fused K+V projection (N=2048) and Q projection
    mma_gemm_kernel<<<dim3(2*DM/128, (BSZ*MAXS)/128), 256>>>(xn, DM, aB, MAXS,
        wq_r + DM, 3*DM, bqkv + DM, kv, 2*DM, kvB, DM, 0, 0);
    mma_gemm_kernel<<<dim3(DM/128, (BSZ*OUTN)/128), 256>>>(xn + (long)(MAXS-OUTN)*DM, DM, aB, OUTN,
        wq_r,      3*DM, bqkv,      q,  DM,  qB, DM, 0, 0);

    // 3) per-position NS projections (K-split, 8-way)
    ns_split_kernel<<<dim3(DM/128, NSN, 8), 128>>>(xn + (long)MAXS*DM, aB, DM, wnsq, part, DM, DM, DM/8);
    ns_reduce_kernel<<<dim3(DM/256, NSN, BSZ), 256>>>(part, bnsq, q + (long)OUTN*DM, qB, DM, DM, 8, 0);
    ns_split_kernel<<<dim3(DM/128, NSN, 8), 128>>>(xn + (long)MAXS*DM, aB, DM, wnsk, part, DM, DM, DM/8);
    ns_reduce_kernel<<<dim3(DM/256, NSN, BSZ), 256>>>(part, bnsk, kv + (long)MAXS*2*DM, kvB, 2*DM, DM, 8, 0);
    ns_split_kernel<<<dim3(DM/128, NSN, 8), 128>>>(xn + (long)MAXS*DM, aB, DM, wnsv, part, DM, DM, DM/8);
    ns_reduce_kernel<<<dim3(DM/256, NSN, BSZ), 256>>>(part, bnsv, kv + (long)MAXS*2*DM + DM, kvB, 2*DM, DM, 8, 0);

    // 4) RoPE (q: stride 1024; k inside kv: stride 2048)
    {
        int totq = BSZ*QLEN*NH*32;
        rope_kernel<<<(totq+255)/256, 256>>>(q, QLEN, TOTAL-QLEN, DM, totq);
        int totk = BSZ*TOTAL*NH*32;
        rope_kernel<<<(totk+255)/256, 256>>>(kv, TOTAL, 0, 2*DM, totk);
    }

    // 5) tensor-core attention
    attn_mma_kernel<<<dim3((QLEN+63)/64, NH, BSZ), 256>>>(q, kv, attn, seq);

    // 6) h1 = residual + attn ; hn = rmsnorm(h1)
    add_rmsnorm_kernel<<<BSZ*QLEN, 256>>>(x, n2w);

    // 7) shared FFN
    mma_gemm_kernel<<<dim3(FFND/128, (BSZ*OUTN)/128), 256>>>(hn, DM, qB, OUTN,
        w1_r, FFND, fb1, ts, FFND, (long)OUTN*FFND, DM, 1, 1);
    mma_gemm_kernel<<<dim3(DM/128, (BSZ*OUTN)/128), 256>>>(ts, FFND, (long)OUTN*FFND, OUTN,
        w2_r, DM, fb2, fs, DM, (long)OUTN*DM, FFND, 0, 0);

    // 8) NS FFN: w1 direct (N=4096), w2 via K-split
    ns_linear_kernel<<<dim3(FFND/128, NSN), 128>>>(hn + (long)OUTN*DM, qB, DM,
        w1ns, b1ns, tns, (long)NSN*FFND, FFND, DM, FFND, 1);
    ns_split_kernel<<<dim3(DM/128, NSN, 8), 128>>>(tns, (long)NSN*FFND, FFND, w2ns, part, FFND, DM, FFND/8);
    ns_reduce_kernel<<<dim3(DM/256, NSN, BSZ), 256>>>(part, b2ns, fns, (long)NSN*DM, DM, DM, 8, 0);

    // 9) assemble output
    assemble_kernel<<<(BSZ*QLEN*DM + 255)/256, 256>>>(out, seq, out_size);
}

// round 4
// speedup vs baseline: 2.1816x; 1.0643x over previous
#include <cuda_runtime.h>
#include <cstdint>

#define BSZ   4
#define TOTAL 2064
#define DM    1024
#define NSN   16
#define OUTN  256
#define QLEN  272
#define NH    16
#define HD    64
#define FFND  4096
#define MAXS  2048

// Scratch (static device globals; no allocation allowed)
__device__ float g_xn  [BSZ*TOTAL*DM];
__device__ float g_q   [BSZ*QLEN*DM];
__device__ float g_kv  [BSZ*TOTAL*2*DM];   // k = cols 0..1023, v = cols 1024..2047
__device__ float g_attn[BSZ*QLEN*DM];
__device__ float g_h1  [BSZ*QLEN*DM];
__device__ float g_hn  [BSZ*QLEN*DM];
__device__ float g_ts  [BSZ*OUTN*FFND];
__device__ float g_tns [BSZ*NSN*FFND];
__device__ float g_fs  [BSZ*OUTN*DM];
__device__ float g_fns [BSZ*NSN*DM];
__device__ float g_part[8*BSZ*NSN*DM];     // k-split partials
// TF32-rounded weights
__device__ float g_wqkv[DM*3*DM];
__device__ float g_w1  [DM*FFND];
__device__ float g_w2  [FFND*DM];

__device__ __forceinline__ float rtf32(float x) {
    uint32_t u;
    asm("cvt.rna.tf32.f32 %0, %1;" : "=r"(u) : "f"(x));
    return __uint_as_float(u);
}
__device__ __forceinline__ uint32_t f2u(float x) { return __float_as_uint(x); }

__device__ __forceinline__ void cpa16(uint32_t dst, const void* src) {
    asm volatile("cp.async.ca.shared.global [%0], [%1], 16;" :: "r"(dst), "l"(src));
}

__device__ __forceinline__ void mma_tf32(float* c,
        uint32_t a0, uint32_t a1, uint32_t a2, uint32_t a3,
        uint32_t b0, uint32_t b1) {
    asm volatile(
        "mma.sync.aligned.m16n8k8.row.col.f32.tf32.tf32.f32 "
        "{%0,%1,%2,%3}, {%4,%5,%6,%7}, {%8,%9}, {%0,%1,%2,%3};\n"
        : "+f"(c[0]), "+f"(c[1]), "+f"(c[2]), "+f"(c[3])
        : "r"(a0), "r"(a1), "r"(a2), "r"(a3), "r"(b0), "r"(b1));
}

// ---------------- weight rounding to tf32 ----------------
__global__ __launch_bounds__(256) void round_tf32_kernel(const float* __restrict__ in,
        float* __restrict__ out, int n4) {
    int i = blockIdx.x*blockDim.x + threadIdx.x;
    if (i >= n4) return;
    float4 v = reinterpret_cast<const float4*>(in)[i];
    v.x = rtf32(v.x); v.y = rtf32(v.y); v.z = rtf32(v.z); v.w = rtf32(v.w);
    reinterpret_cast<float4*>(out)[i] = v;
}

// ---------------- rmsnorm (output tf32-rounded) ----------------
__global__ __launch_bounds__(256) void rmsnorm_kernel(const float* __restrict__ in,
        const float* __restrict__ w, float* __restrict__ out) {
    long row = blockIdx.x;
    int t = threadIdx.x;
    float4 v = reinterpret_cast<const float4*>(in + row*DM)[t];
    float ss = v.x*v.x + v.y*v.y + v.z*v.z + v.w*v.w;
    __shared__ float red[8];
    for (int o = 16; o; o >>= 1) ss += __shfl_xor_sync(0xffffffffu, ss, o);
    if ((t & 31) == 0) red[t >> 5] = ss;
    __syncthreads();
    if (t < 32) {
        float s = (t < 8) ? red[t] : 0.f;
        for (int o = 4; o; o >>= 1) s += __shfl_xor_sync(0xffffffffu, s, o);
        if (t == 0) red[0] = s;
    }
    __syncthreads();
    float rs = rsqrtf(red[0] * (1.f/DM) + 1e-6f);
    float4 wv = reinterpret_cast<const float4*>(w)[t];
    float4 o4 = make_float4(rtf32(v.x*rs*wv.x), rtf32(v.y*rs*wv.y),
                            rtf32(v.z*rs*wv.z), rtf32(v.w*rs*wv.w));
    reinterpret_cast<float4*>(out + row*DM)[t] = o4;
}

// ---------------- h1 = x[:, -272:] + attn ; hn = rmsnorm(h1) ----------------
__global__ __launch_bounds__(256) void add_rmsnorm_kernel(const float* __restrict__ x,
        const float* __restrict__ w) {
    int row = blockIdx.x;
    int b = row / QLEN, r = row - b*QLEN;
    int t = threadIdx.x;
    float4 xv = reinterpret_cast<const float4*>(x + ((long)b*TOTAL + (TOTAL-QLEN) + r)*DM)[t];
    float4 av = reinterpret_cast<const float4*>(g_attn + (long)row*DM)[t];
    float4 hv = make_float4(xv.x+av.x, xv.y+av.y, xv.z+av.z, xv.w+av.w);
    reinterpret_cast<float4*>(g_h1 + (long)row*DM)[t] = hv;
    float ss = hv.x*hv.x + hv.y*hv.y + hv.z*hv.z + hv.w*hv.w;
    __shared__ float red[8];
    for (int o = 16; o; o >>= 1) ss += __shfl_xor_sync(0xffffffffu, ss, o);
    if ((t & 31) == 0) red[t >> 5] = ss;
    __syncthreads();
    if (t < 32) {
        float s = (t < 8) ? red[t] : 0.f;
        for (int o = 4; o; o >>= 1) s += __shfl_xor_sync(0xffffffffu, s, o);
        if (t == 0) red[0] = s;
    }
    __syncthreads();
    float rs = rsqrtf(red[0] * (1.f/DM) + 1e-6f);
    float4 wv = reinterpret_cast<const float4*>(w)[t];
    float4 o4 = make_float4(rtf32(hv.x*rs*wv.x), rtf32(hv.y*rs*wv.y),
                            rtf32(hv.z*rs*wv.z), rtf32(hv.w*rs*wv.w));
    reinterpret_cast<float4*>(g_hn + (long)row*DM)[t] = o4;
}

// ---------------- TF32 tensor-core GEMM, MTILEx128x16 tiles, 3-stage cp.async ----------------
// One __syncthreads per k-tile; issue stage kt+2 right after the barrier.
template<int MTILE>
__global__ __launch_bounds__(256, 2) void mma_gemm3_kernel(
    const float* __restrict__ A, int lda, long aBatch, int rpb,
    const float* __restrict__ Bw, int ldb,
    const float* __restrict__ bias,
    float* __restrict__ C, int ldc, long cBatch,
    int K, int relu, int roundOut)
{
    constexpr int S    = 3;
    constexpr int APAD = 20;
    constexpr int ASTG = MTILE*APAD;
    constexpr int BSTG = 16*136;
    constexpr int MT   = MTILE/32;
    extern __shared__ float sm[];
    float* AsBase = sm;
    float* BsBase = sm + S*ASTG;

    int t = threadIdx.x;
    int w = t >> 5, lane = t & 31;
    int g = lane >> 2, tig = lane & 3;
    int wm = w >> 2, wn = w & 3;

    int row0 = blockIdx.y * MTILE;
    int bn0  = blockIdx.x * 128;
    int batch = row0 / rpb;
    int rin   = row0 % rpb;
    const float* Ab = A + (long)batch*aBatch + (long)rin*lda;
    const float* Bb = Bw + bn0;
    float* Cb = C + (long)batch*cBatch + (long)rin*ldc + bn0;

    int aRow, aCol;
    if (MTILE == 128) { aRow = t >> 1; aCol = (t & 1) * 8; }
    else              { aRow = t >> 2; aCol = (t & 3) * 4; }
    int bRow = t >> 4, bCol = (t & 15) * 8;

    const float* gaB = Ab + (long)aRow*lda + aCol;
    const float* gbB = Bb + (long)bRow*ldb + bCol;
    uint32_t aSmB = (uint32_t)__cvta_generic_to_shared(AsBase) + (aRow*APAD + aCol)*4;
    uint32_t bSmB = (uint32_t)__cvta_generic_to_shared(BsBase) + (bRow*136 + bCol)*4;

    float acc[MT][4][4];
    #pragma unroll
    for (int i = 0; i < MT; i++)
        #pragma unroll
        for (int j = 0; j < 4; j++)
            #pragma unroll
            for (int r = 0; r < 4; r++) acc[i][j][r] = 0.f;

    const int KT = K >> 4;
    auto issue = [&](int kt) {
        int s = kt % S;
        const float* ga = gaB + kt*16;
        const float* gb = gbB + (long)kt*16*ldb;
        uint32_t aS = aSmB + s*ASTG*4;
        uint32_t bS = bSmB + s*BSTG*4;
        cpa16(aS, ga);
        if (MTILE == 128) cpa16(aS + 16, ga + 4);
        cpa16(bS, gb);
        cpa16(bS + 16, gb + 4);
        asm volatile("cp.async.commit_group;");
    };
    issue(0);
    issue(1);

    for (int kt = 0; kt < KT; kt++) {
        if (kt == KT - 1) asm volatile("cp.async.wait_group 0;");
        else              asm volatile("cp.async.wait_group 1;");
        __syncthreads();
        if (kt + 2 < KT) issue(kt + 2);

        const float* As = AsBase + (kt % S)*ASTG;
        const float* Bs = BsBase + (kt % S)*BSTG;
        #pragma unroll
        for (int ks = 0; ks < 2; ks++) {
            uint32_t afr[MT][4];
            #pragma unroll
            for (int mt = 0; mt < MT; mt++) {
                const float* ap = As + (wm*(MTILE/2) + mt*16)*APAD + ks*8 + tig;
                afr[mt][0] = f2u(ap[g*APAD]);
                afr[mt][1] = f2u(ap[(g+8)*APAD]);
                afr[mt][2] = f2u(ap[g*APAD + 4]);
                afr[mt][3] = f2u(ap[(g+8)*APAD + 4]);
            }
            uint32_t bfr[4][2];
            #pragma unroll
            for (int nt = 0; nt < 4; nt++) {
                const float* bp = Bs + (ks*8 + tig)*136 + wn*32 + nt*8 + g;
                bfr[nt][0] = f2u(bp[0]);
                bfr[nt][1] = f2u(bp[4*136]);
            }
            #pragma unroll
            for (int mt = 0; mt < MT; mt++)
                #pragma unroll
                for (int nt = 0; nt < 4; nt++)
                    mma_tf32(acc[mt][nt], afr[mt][0], afr[mt][1], afr[mt][2], afr[mt][3],
                             bfr[nt][0], bfr[nt][1]);
        }
    }

    #pragma unroll
    for (int nt = 0; nt < 4; nt++) {
        int col = wn*32 + nt*8 + 2*tig;
        float bx = bias[bn0 + col], by = bias[bn0 + col + 1];
        #pragma unroll
        for (int mt = 0; mt < MT; mt++) {
            int r0 = wm*(MTILE/2) + mt*16 + g;
            float c0 = acc[mt][nt][0] + bx, c1 = acc[mt][nt][1] + by;
            float c2 = acc[mt][nt][2] + bx, c3 = acc[mt][nt][3] + by;
            if (relu) { c0=fmaxf(c0,0.f); c1=fmaxf(c1,0.f); c2=fmaxf(c2,0.f); c3=fmaxf(c3,0.f); }
            if (roundOut) { c0=rtf32(c0); c1=rtf32(c1); c2=rtf32(c2); c3=rtf32(c3); }
            *reinterpret_cast<float2*>(Cb + (long)r0*ldc + col)     = make_float2(c0, c1);
            *reinterpret_cast<float2*>(Cb + (long)(r0+8)*ldc + col) = make_float2(c2, c3);
        }
    }
}

// ---------------- per-NS-position linear, direct (used for w1ns: N=4096) ----------------
__global__ __launch_bounds__(128) void ns_linear_kernel(
    const float* __restrict__ X, long xBatch, int xRow,
    const float* __restrict__ W, const float* __restrict__ bias,
    float* __restrict__ Y, long yBatch, int yRow,
    int K, int N, int relu)
{
    __shared__ float Xs[4][1024];
    int n = blockIdx.y;
    int t = threadIdx.x;
    int o = blockIdx.x * 128 + t;
    const float* Wn = W + (long)n*K*N + o;
    float a0=0.f, a1=0.f, a2=0.f, a3=0.f;
    for (int k0 = 0; k0 < K; k0 += 1024) {
        __syncthreads();
        for (int i = t; i < 1024; i += 128) {
            long xo = (long)n*xRow + k0 + i;
            Xs[0][i] = X[0*xBatch + xo];
            Xs[1][i] = X[1*xBatch + xo];
            Xs[2][i] = X[2*xBatch + xo];
            Xs[3][i] = X[3*xBatch + xo];
        }
        __syncthreads();
        const float* Wp = Wn + (long)k0*N;
        #pragma unroll 8
        for (int k = 0; k < 1024; k++) {
            float w = Wp[(long)k*N];
            a0 += w*Xs[0][k]; a1 += w*Xs[1][k]; a2 += w*Xs[2][k]; a3 += w*Xs[3][k];
        }
    }
    float bv = bias[(long)n*N + o];
    a0 += bv; a1 += bv; a2 += bv; a3 += bv;
    if (relu) { a0=fmaxf(a0,0.f); a1=fmaxf(a1,0.f); a2=fmaxf(a2,0.f); a3=fmaxf(a3,0.f); }
    long yo = (long)n*yRow + o;
    Y[0*yBatch+yo]=a0; Y[1*yBatch+yo]=a1; Y[2*yBatch+yo]=a2; Y[3*yBatch+yo]=a3;
}

// ---------------- per-NS-position linear, K-split partials (N=1024 cases) ----------------
__global__ __launch_bounds__(128) void ns_split_kernel(
    const float* __restrict__ X, long xBatch, int xRow,
    const float* __restrict__ W, float* __restrict__ part,
    int K, int N, int kchunk)
{
    __shared__ float Xs[4][512];
    int n = blockIdx.y, z = blockIdx.z;
    int t = threadIdx.x;
    int o = blockIdx.x * 128 + t;
    int k0 = z * kchunk;
    for (int i = t; i < kchunk; i += 128) {
        long xo = (long)n*xRow + k0 + i;
        Xs[0][i] = X[0*xBatch + xo];
        Xs[1][i] = X[1*xBatch + xo];
        Xs[2][i] = X[2*xBatch + xo];
        Xs[3][i] = X[3*xBatch + xo];
    }
    __syncthreads();
    const float* Wp = W + (long)n*K*N + (long)k0*N + o;
    float a0=0.f, a1=0.f, a2=0.f, a3=0.f;
    #pragma unroll 8
    for (int k = 0; k < kchunk; k++) {
        float w = Wp[(long)k*N];
        a0 += w*Xs[0][k]; a1 += w*Xs[1][k]; a2 += w*Xs[2][k]; a3 += w*Xs[3][k];
    }
    part[((long)(z*BSZ+0)*NSN + n)*N + o] = a0;
    part[((long)(z*BSZ+1)*NSN + n)*N + o] = a1;
    part[((long)(z*BSZ+2)*NSN + n)*N + o] = a2;
    part[((long)(z*BSZ+3)*NSN + n)*N + o] = a3;
}

__global__ __launch_bounds__(256) void ns_reduce_kernel(
    const float* __restrict__ part, const float* __restrict__ bias,
    float* __restrict__ Y, long yBatch, int yRow, int N, int KS, int relu)
{
    int o = blockIdx.x*256 + threadIdx.x;
    int n = blockIdx.y, b = blockIdx.z;
    float s = bias[(long)n*N + o];
    for (int z = 0; z < KS; z++)
        s += part[((long)(z*BSZ+b)*NSN + n)*N + o];
    if (relu) s = fmaxf(s, 0.f);
    Y[(long)b*yBatch + (long)n*yRow + o] = s;
}

// ---------------- RoPE in-place ----------------
__global__ void rope_kernel(float* __restrict__ buf, int rowsPerB, int pos0, int rstride, int total) {
    int idx = blockIdx.x*blockDim.x + threadIdx.x;
    if (idx >= total) return;
    int j  = idx & 31;
    int h  = (idx >> 5) & (NH-1);
    int rr = idx >> 9;
    int b  = rr / rowsPerB;
    int r  = rr - b*rowsPerB;
    double inv = pow(10000.0, -(double)j / 32.0);
    double ang = (double)(pos0 + r) * inv;
    double sd, cd;
    sincos(ang, &sd, &cd);
    float s = (float)sd, c = (float)cd;
    float* base = buf + ((long)b*rowsPerB + r)*(long)rstride + h*HD;
    float x1 = base[j], x2 = base[j+32];
    base[j]    = x1*c - x2*s;
    base[j+32] = x2*c + x1*s;
}

// ---------------- tensor-core flash attention (tf32) ----------------
__global__ __launch_bounds__(256) void attn_mma_kernel(
    const float* __restrict__ q, const float* __restrict__ kv,
    float* __restrict__ attn, const int* __restrict__ seqlen)
{
    __shared__ float qs [64][68];
    __shared__ float ksm[32][68];
    __shared__ float vsm[32][72];
    __shared__ float ssm[64][36];
    __shared__ float corrs[64];
    __shared__ float lrow[64];

    int qt = blockIdx.x, h = blockIdx.y, b = blockIdx.z;
    int tid = threadIdx.x;
    int w = tid >> 5, lane = tid & 31;
    int g = lane >> 2, tig = lane & 3;
    int wm = w >> 2, wn = w & 3;
    int L = seqlen[b];
    int kmin = MAXS - L;

    for (int i = tid; i < 64*16; i += 256) {
        int r = i >> 4, c4 = (i & 15) * 4;
        int qg = qt*64 + r;
        float4 val = make_float4(0.f,0.f,0.f,0.f);
        if (qg < QLEN)
            val = *reinterpret_cast<const float4*>(q + ((long)b*QLEN + qg)*DM + h*HD + c4);
        qs[r][c4]   = rtf32(val.x);
        qs[r][c4+1] = rtf32(val.y);
        qs[r][c4+2] = rtf32(val.z);
        qs[r][c4+3] = rtf32(val.w);
    }

    int srow = tid >> 2, ssub = tid & 3;
    float m = -1e30f, l = 0.f;

    float oacc[2][2][4];
    #pragma unroll
    for (int i = 0; i < 2; i++)
        #pragma unroll
        for (int j = 0; j < 2; j++)
            #pragma unroll
            for (int r = 0; r < 4; r++) oacc[i][j][r] = 0.f;

    int qgmax = min(QLEN-1, qt*64 + 63);
    int t0 = kmin >> 5;
    int t1 = (MAXS - OUTN + qgmax) >> 5;

    for (int kt = t0; kt <= t1; kt++) {
        int key0 = kt * 32;
        __syncthreads();
        for (int i = tid; i < 32*16; i += 256) {
            int r = i >> 4, c4 = (i & 15) * 4;
            int key = key0 + r;
            float4 kk = make_float4(0.f,0.f,0.f,0.f), vv = kk;
            if (key < TOTAL) {
                const float* base = kv + ((long)b*TOTAL + key)*(2*DM) + h*HD;
                kk = *reinterpret_cast<const float4*>(base + c4);
                vv = *reinterpret_cast<const float4*>(base + DM + c4);
            }
            ksm[r][c4]=rtf32(kk.x); ksm[r][c4+1]=rtf32(kk.y);
            ksm[r][c4+2]=rtf32(kk.z); ksm[r][c4+3]=rtf32(kk.w);
            vsm[r][c4]=rtf32(vv.x); vsm[r][c4+1]=rtf32(vv.y);
            vsm[r][c4+2]=rtf32(vv.z); vsm[r][c4+3]=rtf32(vv.w);
        }
        __syncthreads();

        float sa[2][4];
        #pragma unroll
        for (int mt = 0; mt < 2; mt++)
            #pragma unroll
            for (int r = 0; r < 4; r++) sa[mt][r] = 0.f;
        #pragma unroll
        for (int dk = 0; dk < 8; dk++) {
            uint32_t bf0 = f2u(ksm[wn*8 + g][dk*8 + tig]);
            uint32_t bf1 = f2u(ksm[wn*8 + g][dk*8 + tig + 4]);
            #pragma unroll
            for (int mt = 0; mt < 2; mt++) {
                int m0 = wm*32 + mt*16;
                mma_tf32(sa[mt],
                    f2u(qs[m0+g][dk*8+tig]),   f2u(qs[m0+g+8][dk*8+tig]),
                    f2u(qs[m0+g][dk*8+tig+4]), f2u(qs[m0+g+8][dk*8+tig+4]),
                    bf0, bf1);
            }
        }
        #pragma unroll
        for (int mt = 0; mt < 2; mt++) {
            #pragma unroll
            for (int hh = 0; hh < 2; hh++) {
                int r = wm*32 + mt*16 + g + hh*8;
                int qg = qt*64 + r;
                int key = key0 + wn*8 + 2*tig;
                int kcap = MAXS - OUTN + qg;
                bool rowok = (qg < QLEN);
                float sA = sa[mt][hh*2+0], sB = sa[mt][hh*2+1];
                bool v0 = rowok && (key   < TOTAL) && (key   >= kmin) && (key   <= kcap);
                bool v1 = rowok && (key+1 < TOTAL) && (key+1 >= kmin) && (key+1 <= kcap);
                ssm[r][wn*8 + 2*tig]     = v0 ? sA*0.125f : -1e9f;
                ssm[r][wn*8 + 2*tig + 1] = v1 ? sB*0.125f : -1e9f;
            }
        }
        __syncthreads();

        float sv[8];
        #pragma unroll
        for (int j = 0; j < 8; j++) sv[j] = ssm[srow][ssub*8 + j];
        float tmax = sv[0];
        #pragma unroll
        for (int j = 1; j < 8; j++) tmax = fmaxf(tmax, sv[j]);
        tmax = fmaxf(tmax, __shfl_xor_sync(0xffffffffu, tmax, 1));
        tmax = fmaxf(tmax, __shfl_xor_sync(0xffffffffu, tmax, 2));
        float corr = 1.f;
        if (tmax > -1e8f) {
            float m_new = fmaxf(m, tmax);
            corr = __expf(m - m_new);
            float ps = 0.f;
            #pragma unroll
            for (int j = 0; j < 8; j++) {
                float p = __expf(sv[j] - m_new);
                ps += p;
                ssm[srow][ssub*8 + j] = rtf32(p);
            }
            ps += __shfl_xor_sync(0xffffffffu, ps, 1);
            ps += __shfl_xor_sync(0xffffffffu, ps, 2);
            l = l*corr + ps;
            m = m_new;
        } else {
            #pragma unroll
            for (int j = 0; j < 8; j++) ssm[srow][ssub*8 + j] = 0.f;
        }
        if (ssub == 0) corrs[srow] = corr;
        __syncthreads();

        #pragma unroll
        for (int mt = 0; mt < 2; mt++) {
            float c0 = corrs[wm*32 + mt*16 + g];
            float c1 = corrs[wm*32 + mt*16 + g + 8];
            #pragma unroll
            for (int nt = 0; nt < 2; nt++) {
                oacc[mt][nt][0] *= c0; oacc[mt][nt][1] *= c0;
                oacc[mt][nt][2] *= c1; oacc[mt][nt][3] *= c1;
            }
        }
        #pragma unroll
        for (int kd = 0; kd < 4; kd++) {
            uint32_t bf[2][2];
            #pragma unroll
            for (int nt = 0; nt < 2; nt++) {
                int n = wn*16 + nt*8 + g;
                bf[nt][0] = f2u(vsm[kd*8 + tig][n]);
                bf[nt][1] = f2u(vsm[kd*8 + tig + 4][n]);
            }
            #pragma unroll
            for (int mt = 0; mt < 2; mt++) {
                int m0 = wm*32 + mt*16;
                uint32_t a0 = f2u(ssm[m0+g][kd*8+tig]);
                uint32_t a1 = f2u(ssm[m0+g+8][kd*8+tig]);
                uint32_t a2 = f2u(ssm[m0+g][kd*8+tig+4]);
                uint32_t a3 = f2u(ssm[m0+g+8][kd*8+tig+4]);
                #pragma unroll
                for (int nt = 0; nt < 2; nt++)
                    mma_tf32(oacc[mt][nt], a0, a1, a2, a3, bf[nt][0], bf[nt][1]);
            }
        }
    }

    if (ssub == 0) lrow[srow] = l;
    __syncthreads();
    #pragma unroll
    for (int mt = 0; mt < 2; mt++) {
        #pragma unroll
        for (int hh = 0; hh < 2; hh++) {
            int r = wm*32 + mt*16 + g + hh*8;
            int qg = qt*64 + r;
            if (qg < QLEN) {
                float invl = 1.f / lrow[r];
                #pragma unroll
                for (int nt = 0; nt < 2; nt++) {
                    int col = wn*16 + nt*8 + 2*tig;
                    *reinterpret_cast<float2*>(attn + ((long)b*QLEN + qg)*DM + h*HD + col)
                        = make_float2(oacc[mt][nt][hh*2]*invl, oacc[mt][nt][hh*2+1]*invl);
                }
            }
        }
    }
}

// ---------------- final assembly ----------------
__global__ void assemble_kernel(float* __restrict__ out, const int* __restrict__ seqlen, int out_size) {
    int idx = blockIdx.x*blockDim.x + threadIdx.x;
    const int main_n = BSZ*QLEN*DM;
    if (idx < main_n) {
        int b = idx / (QLEN*DM);
        int rem = idx - b*(QLEN*DM);
        int r = rem / DM;
        int d = rem - r*DM;
        float f;
        if (r < OUTN) f = g_fs [((long)b*OUTN + r)*DM + d];
        else          f = g_fns[((long)b*NSN + (r - OUTN))*DM + d];
        out[idx] = f + g_h1[idx];
    }
    if (idx < BSZ && out_size >= main_n + BSZ) {
        int L = seqlen[idx];
        out[main_n + idx] = (float)(L < OUTN ? L : OUTN);
    }
}

extern "C" void kernel_launch(void* const* d_in, const int* in_sizes, int n_in,
                              void* d_out, int out_size) {
    (void)in_sizes; (void)n_in;
    const float* x    = (const float*)d_in[0];
    const int*   seq  = (const int*)  d_in[1];
    const float* wqkv = (const float*)d_in[2];
    const float* bqkv = (const float*)d_in[3];
    const float* wnsq = (const float*)d_in[4];
    const float* bnsq = (const float*)d_in[5];
    const float* wnsk = (const float*)d_in[6];
    const float* bnsk = (const float*)d_in[7];
    const float* wnsv = (const float*)d_in[8];
    const float* bnsv = (const float*)d_in[9];
    const float* n1w  = (const float*)d_in[10];
    const float* n2w  = (const float*)d_in[11];
    const float* fw1  = (const float*)d_in[12];
    const float* fb1  = (const float*)d_in[13];
    const float* fw2  = (const float*)d_in[14];
    const float* fb2  = (const float*)d_in[15];
    const float* w1ns = (const float*)d_in[16];
    const float* b1ns = (const float*)d_in[17];
    const float* w2ns = (const float*)d_in[18];
    const float* b2ns = (const float*)d_in[19];
    float* out = (float*)d_out;

    float *xn,*q,*kv,*attn,*hn,*ts,*tns,*fs,*fns,*part,*wq_r,*w1_r,*w2_r;
    cudaGetSymbolAddress((void**)&xn,   g_xn);
    cudaGetSymbolAddress((void**)&q,    g_q);
    cudaGetSymbolAddress((void**)&kv,   g_kv);
    cudaGetSymbolAddress((void**)&attn, g_attn);
    cudaGetSymbolAddress((void**)&hn,   g_hn);
    cudaGetSymbolAddress((void**)&ts,   g_ts);
    cudaGetSymbolAddress((void**)&tns,  g_tns);
    cudaGetSymbolAddress((void**)&fs,   g_fs);
    cudaGetSymbolAddress((void**)&fns,  g_fns);
    cudaGetSymbolAddress((void**)&part, g_part);
    cudaGetSymbolAddress((void**)&wq_r, g_wqkv);
    cudaGetSymbolAddress((void**)&w1_r, g_w1);
    cudaGetSymbolAddress((void**)&w2_r, g_w2);

    const long aB  = (long)TOTAL*DM;
    const long qB  = (long)QLEN*DM;
    const long kvB = (long)TOTAL*2*DM;

    const int SMEM128 = (3*128*20 + 3*16*136) * 4;   // 56832 B
    const int SMEM64  = (3*64*20  + 3*16*136) * 4;   // 41472 B
    cudaFuncSetAttribute(mma_gemm3_kernel<128>, cudaFuncAttributeMaxDynamicSharedMemorySize, SMEM128);
    cudaFuncSetAttribute(mma_gemm3_kernel<64>,  cudaFuncAttributeMaxDynamicSharedMemorySize, SMEM64);

    // 0) round shared GEMM weights to tf32
    round_tf32_kernel<<<(DM*3*DM/4 + 255)/256, 256>>>(wqkv, wq_r, DM*3*DM/4);
    round_tf32_kernel<<<(DM*FFND/4 + 255)/256, 256>>>(fw1, w1_r, DM*FFND/4);
    round_tf32_kernel<<<(FFND*DM/4 + 255)/256, 256>>>(fw2, w2_r, FFND*DM/4);

    // 1) xn = rmsnorm(x, norm1)
    rmsnorm_kernel<<<BSZ*TOTAL, 256>>>(x, n1w, xn);

    // 2) fused K+V projection (N=2048) and Q projection
    mma_gemm3_kernel<128><<<dim3(2*DM/128, (BSZ*MAXS)/128), 256, SMEM128>>>(xn, DM, aB, MAXS,
        wq_r + DM, 3*DM, bqkv + DM, kv, 2*DM, kvB, DM, 0, 0);
    mma_gemm3_kernel<64><<<dim3(DM/128, (BSZ*OUTN)/64), 256, SMEM64>>>(xn + (long)(MAXS-OUTN)*DM, DM, aB, OUTN,
        wq_r,      3*DM, bqkv,      q,  DM,  qB, DM, 0, 0);

    // 3) per-position NS projections (K-split, 8-way)
    ns_split_kernel<<<dim3(DM/128, NSN, 8), 128>>>(xn + (long)MAXS*DM, aB, DM, wnsq, part, DM, DM, DM/8);
    ns_reduce_kernel<<<dim3(DM/256, NSN, BSZ), 256>>>(part, bnsq, q + (long)OUTN*DM, qB, DM, DM, 8, 0);
    ns_split_kernel<<<dim3(DM/128, NSN, 8), 128>>>(xn + (long)MAXS*DM, aB, DM, wnsk, part, DM, DM, DM/8);
    ns_reduce_kernel<<<dim3(DM/256, NSN, BSZ), 256>>>(part, bnsk, kv + (long)MAXS*2*DM, kvB, 2*DM, DM, 8, 0);
    ns_split_kernel<<<dim3(DM/128, NSN, 8), 128>>>(xn + (long)MAXS*DM, aB, DM, wnsv, part, DM, DM, DM/8);
    ns_reduce_kernel<<<dim3(DM/256, NSN, BSZ), 256>>>(part, bnsv, kv + (long)MAXS*2*DM + DM, kvB, 2*DM, DM, 8, 0);

    // 4) RoPE
    {
        int totq = BSZ*QLEN*NH*32;
        rope_kernel<<<(totq+255)/256, 256>>>(q, QLEN, TOTAL-QLEN, DM, totq);
        int totk = BSZ*TOTAL*NH*32;
        rope_kernel<<<(totk+255)/256, 256>>>(kv, TOTAL, 0, 2*DM, totk);
    }

    // 5) tensor-core attention
    attn_mma_kernel<<<dim3((QLEN+63)/64, NH, BSZ), 256>>>(q, kv, attn, seq);

    // 6) h1 = residual + attn ; hn = rmsnorm(h1)
    add_rmsnorm_kernel<<<BSZ*QLEN, 256>>>(x, n2w);

    // 7) shared FFN
    mma_gemm3_kernel<128><<<dim3(FFND/128, (BSZ*OUTN)/128), 256, SMEM128>>>(hn, DM, qB, OUTN,
        w1_r, FFND, fb1, ts, FFND, (long)OUTN*FFND, DM, 1, 1);
    mma_gemm3_kernel<64><<<dim3(DM/128, (BSZ*OUTN)/64), 256, SMEM64>>>(ts, FFND, (long)OUTN*FFND, OUTN,
        w2_r, DM, fb2, fs, DM, (long)OUTN*DM, FFND, 0, 0);

    // 8) NS FFN: w1 direct (N=4096), w2 via K-split
    ns_linear_kernel<<<dim3(FFND/128, NSN), 128>>>(hn + (long)OUTN*DM, qB, DM,
        w1ns, b1ns, tns, (long)NSN*FFND, FFND, DM, FFND, 1);
    ns_split_kernel<<<dim3(DM/128, NSN, 8), 128>>>(tns, (long)NSN*FFND, FFND, w2ns, part, FFND, DM, FFND/8);
    ns_reduce_kernel<<<dim3(DM/256, NSN, BSZ), 256>>>(part, b2ns, fns, (long)NSN*DM, DM, DM, 8, 0);

    // 9) assemble output
    assemble_kernel<<<(BSZ*QLEN*DM + 255)/256, 256>>>(out, seq, out_size);
}

// round 6
// speedup vs baseline: 2.2705x; 1.0407x over previous
#include <cuda_runtime.h>
#include <cstdint>

#define BSZ   4
#define TOTAL 2064
#define DM    1024
#define NSN   16
#define OUTN  256
#define QLEN  272
#define NH    16
#define HD    64
#define FFND  4096
#define MAXS  2048

// Scratch (static device globals; no allocation allowed)
__device__ float g_xn  [BSZ*TOTAL*DM];
__device__ float g_q   [BSZ*QLEN*DM];
__device__ float g_kv  [BSZ*TOTAL*2*DM];   // k = cols 0..1023, v = cols 1024..2047
__device__ float g_attn[BSZ*QLEN*DM];
__device__ float g_h1  [BSZ*QLEN*DM];
__device__ float g_hn  [BSZ*QLEN*DM];
__device__ float g_ts  [BSZ*OUTN*FFND];
__device__ float g_tns [BSZ*NSN*FFND];
__device__ float g_fs  [BSZ*OUTN*DM];
__device__ float g_fns [BSZ*NSN*DM];
__device__ float g_part[8*BSZ*NSN*DM];     // k-split partials
// TF32-rounded weights
__device__ float g_wqkv[DM*3*DM];
__device__ float g_w1  [DM*FFND];
__device__ float g_w2  [FFND*DM];

__device__ __forceinline__ float rtf32(float x) {
    uint32_t u;
    asm("cvt.rna.tf32.f32 %0, %1;" : "=r"(u) : "f"(x));
    return __uint_as_float(u);
}
__device__ __forceinline__ uint32_t f2u(float x) { return __float_as_uint(x); }

__device__ __forceinline__ void cpa16(uint32_t dst, const void* src) {
    asm volatile("cp.async.ca.shared.global [%0], [%1], 16;" :: "r"(dst), "l"(src));
}

__device__ __forceinline__ void mma_tf32(float* c,
        uint32_t a0, uint32_t a1, uint32_t a2, uint32_t a3,
        uint32_t b0, uint32_t b1) {
    asm volatile(
        "mma.sync.aligned.m16n8k8.row.col.f32.tf32.tf32.f32 "
        "{%0,%1,%2,%3}, {%4,%5,%6,%7}, {%8,%9}, {%0,%1,%2,%3};\n"
        : "+f"(c[0]), "+f"(c[1]), "+f"(c[2]), "+f"(c[3])
        : "r"(a0), "r"(a1), "r"(a2), "r"(a3), "r"(b0), "r"(b1));
}

// ---------------- weight rounding to tf32 ----------------
__global__ __launch_bounds__(256) void round_tf32_kernel(const float* __restrict__ in,
        float* __restrict__ out, int n4) {
    int i = blockIdx.x*blockDim.x + threadIdx.x;
    if (i >= n4) return;
    float4 v = reinterpret_cast<const float4*>(in)[i];
    v.x = rtf32(v.x); v.y = rtf32(v.y); v.z = rtf32(v.z); v.w = rtf32(v.w);
    reinterpret_cast<float4*>(out)[i] = v;
}

// ---------------- rmsnorm (output tf32-rounded) ----------------
__global__ __launch_bounds__(256) void rmsnorm_kernel(const float* __restrict__ in,
        const float* __restrict__ w, float* __restrict__ out) {
    long row = blockIdx.x;
    int t = threadIdx.x;
    float4 v = reinterpret_cast<const float4*>(in + row*DM)[t];
    float ss = v.x*v.x + v.y*v.y + v.z*v.z + v.w*v.w;
    __shared__ float red[8];
    for (int o = 16; o; o >>= 1) ss += __shfl_xor_sync(0xffffffffu, ss, o);
    if ((t & 31) == 0) red[t >> 5] = ss;
    __syncthreads();
    if (t < 32) {
        float s = (t < 8) ? red[t] : 0.f;
        for (int o = 4; o; o >>= 1) s += __shfl_xor_sync(0xffffffffu, s, o);
        if (t == 0) red[0] = s;
    }
    __syncthreads();
    float rs = rsqrtf(red[0] * (1.f/DM) + 1e-6f);
    float4 wv = reinterpret_cast<const float4*>(w)[t];
    float4 o4 = make_float4(rtf32(v.x*rs*wv.x), rtf32(v.y*rs*wv.y),
                            rtf32(v.z*rs*wv.z), rtf32(v.w*rs*wv.w));
    reinterpret_cast<float4*>(out + row*DM)[t] = o4;
}

// ---------------- h1 = x[:, -272:] + attn ; hn = rmsnorm(h1) ----------------
__global__ __launch_bounds__(256) void add_rmsnorm_kernel(const float* __restrict__ x,
        const float* __restrict__ w) {
    int row = blockIdx.x;
    int b = row / QLEN, r = row - b*QLEN;
    int t = threadIdx.x;
    float4 xv = reinterpret_cast<const float4*>(x + ((long)b*TOTAL + (TOTAL-QLEN) + r)*DM)[t];
    float4 av = reinterpret_cast<const float4*>(g_attn + (long)row*DM)[t];
    float4 hv = make_float4(xv.x+av.x, xv.y+av.y, xv.z+av.z, xv.w+av.w);
    reinterpret_cast<float4*>(g_h1 + (long)row*DM)[t] = hv;
    float ss = hv.x*hv.x + hv.y*hv.y + hv.z*hv.z + hv.w*hv.w;
    __shared__ float red[8];
    for (int o = 16; o; o >>= 1) ss += __shfl_xor_sync(0xffffffffu, ss, o);
    if ((t & 31) == 0) red[t >> 5] = ss;
    __syncthreads();
    if (t < 32) {
        float s = (t < 8) ? red[t] : 0.f;
        for (int o = 4; o; o >>= 1) s += __shfl_xor_sync(0xffffffffu, s, o);
        if (t == 0) red[0] = s;
    }
    __syncthreads();
    float rs = rsqrtf(red[0] * (1.f/DM) + 1e-6f);
    float4 wv = reinterpret_cast<const float4*>(w)[t];
    float4 o4 = make_float4(rtf32(hv.x*rs*wv.x), rtf32(hv.y*rs*wv.y),
                            rtf32(hv.z*rs*wv.z), rtf32(hv.w*rs*wv.w));
    reinterpret_cast<float4*>(g_hn + (long)row*DM)[t] = o4;
}

// ---------------- TF32 tensor-core GEMM, MTILEx128x32 tiles, 3-stage cp.async ----------------
// One __syncthreads per 32-deep k-tile; issue stage kt+2 right after the barrier.
template<int MTILE>
__global__ __launch_bounds__(256, 2) void mma_gemm32_kernel(
    const float* __restrict__ A, int lda, long aBatch, int rpb,
    const float* __restrict__ Bw, int ldb,
    const float* __restrict__ bias,
    float* __restrict__ C, int ldc, long cBatch,
    int K, int relu, int roundOut)
{
    constexpr int S    = 3;
    constexpr int APAD = 36;                // conflict-free: (36g+tig)%32 distinct
    constexpr int ASTG = MTILE*APAD;
    constexpr int BSTG = 32*136;
    constexpr int MT   = MTILE/32;
    extern __shared__ float sm[];
    float* AsBase = sm;
    float* BsBase = sm + S*ASTG;

    int t = threadIdx.x;
    int w = t >> 5, lane = t & 31;
    int g = lane >> 2, tig = lane & 3;
    int wm = w >> 2, wn = w & 3;

    int row0 = blockIdx.y * MTILE;
    int bn0  = blockIdx.x * 128;
    int batch = row0 / rpb;
    int rin   = row0 % rpb;
    const float* Ab = A + (long)batch*aBatch + (long)rin*lda;
    const float* Bb = Bw + bn0;
    float* Cb = C + (long)batch*cBatch + (long)rin*ldc + bn0;

    uint32_t aSm0 = (uint32_t)__cvta_generic_to_shared(AsBase);
    uint32_t bSm0 = (uint32_t)__cvta_generic_to_shared(BsBase);

    float acc[MT][4][4];
    #pragma unroll
    for (int i = 0; i < MT; i++)
        #pragma unroll
        for (int j = 0; j < 4; j++)
            #pragma unroll
            for (int r = 0; r < 4; r++) acc[i][j][r] = 0.f;

    const int KT = K >> 5;
    auto issue = [&](int kt) {
        int s = kt % S;
        const float* ga = Ab + kt*32;
        const float* gb = Bb + (long)kt*32*ldb;
        uint32_t aS = aSm0 + s*ASTG*4;
        uint32_t bS = bSm0 + s*BSTG*4;
        // A tile: MTILE x 32, each chunk = 4 floats
        #pragma unroll
        for (int it = 0; it < MTILE/32; it++) {
            int i = t + it*256;
            int row = i >> 3, seg = i & 7;
            cpa16(aS + (row*APAD + seg*4)*4, ga + (long)row*lda + seg*4);
        }
        // B tile: 32 x 128
        #pragma unroll
        for (int it = 0; it < 4; it++) {
            int i = t + it*256;
            int row = i >> 5, seg = i & 31;
            cpa16(bS + (row*136 + seg*4)*4, gb + (long)row*ldb + seg*4);
        }
        asm volatile("cp.async.commit_group;");
    };
    issue(0);
    issue(1);

    for (int kt = 0; kt < KT; kt++) {
        if (kt == KT - 1) asm volatile("cp.async.wait_group 0;");
        else              asm volatile("cp.async.wait_group 1;");
        __syncthreads();
        if (kt + 2 < KT) issue(kt + 2);

        const float* As = AsBase + (kt % S)*ASTG;
        const float* Bs = BsBase + (kt % S)*BSTG;
        #pragma unroll
        for (int ks = 0; ks < 4; ks++) {
            uint32_t afr[MT][4];
            #pragma unroll
            for (int mt = 0; mt < MT; mt++) {
                const float* ap = As + (wm*(MTILE/2) + mt*16)*APAD + ks*8 + tig;
                afr[mt][0] = f2u(ap[g*APAD]);
                afr[mt][1] = f2u(ap[(g+8)*APAD]);
                afr[mt][2] = f2u(ap[g*APAD + 4]);
                afr[mt][3] = f2u(ap[(g+8)*APAD + 4]);
            }
            uint32_t bfr[4][2];
            #pragma unroll
            for (int nt = 0; nt < 4; nt++) {
                const float* bp = Bs + (ks*8 + tig)*136 + wn*32 + nt*8 + g;
                bfr[nt][0] = f2u(bp[0]);
                bfr[nt][1] = f2u(bp[4*136]);
            }
            #pragma unroll
            for (int mt = 0; mt < MT; mt++)
                #pragma unroll
                for (int nt = 0; nt < 4; nt++)
                    mma_tf32(acc[mt][nt], afr[mt][0], afr[mt][1], afr[mt][2], afr[mt][3],
                             bfr[nt][0], bfr[nt][1]);
        }
    }

    #pragma unroll
    for (int nt = 0; nt < 4; nt++) {
        int col = wn*32 + nt*8 + 2*tig;
        float bx = bias[bn0 + col], by = bias[bn0 + col + 1];
        #pragma unroll
        for (int mt = 0; mt < MT; mt++) {
            int r0 = wm*(MTILE/2) + mt*16 + g;
            float c0 = acc[mt][nt][0] + bx, c1 = acc[mt][nt][1] + by;
            float c2 = acc[mt][nt][2] + bx, c3 = acc[mt][nt][3] + by;
            if (relu) { c0=fmaxf(c0,0.f); c1=fmaxf(c1,0.f); c2=fmaxf(c2,0.f); c3=fmaxf(c3,0.f); }
            if (roundOut) { c0=rtf32(c0); c1=rtf32(c1); c2=rtf32(c2); c3=rtf32(c3); }
            *reinterpret_cast<float2*>(Cb + (long)r0*ldc + col)     = make_float2(c0, c1);
            *reinterpret_cast<float2*>(Cb + (long)(r0+8)*ldc + col) = make_float2(c2, c3);
        }
    }
}

// ---------------- per-NS-position linear, direct (w1ns: N=4096) ----------------
__global__ __launch_bounds__(128) void ns_linear_kernel(
    const float* __restrict__ X, long xBatch, int xRow,
    const float* __restrict__ W, const float* __restrict__ bias,
    float* __restrict__ Y, long yBatch, int yRow,
    int K, int N, int relu)
{
    __shared__ float Xs[4][1024];
    int n = blockIdx.y;
    int t = threadIdx.x;
    int o = blockIdx.x * 128 + t;
    const float* Wn = W + (long)n*K*N + o;
    float a0=0.f, a1=0.f, a2=0.f, a3=0.f;
    for (int k0 = 0; k0 < K; k0 += 1024) {
        __syncthreads();
        for (int i = t; i < 1024; i += 128) {
            long xo = (long)n*xRow + k0 + i;
            Xs[0][i] = X[0*xBatch + xo];
            Xs[1][i] = X[1*xBatch + xo];
            Xs[2][i] = X[2*xBatch + xo];
            Xs[3][i] = X[3*xBatch + xo];
        }
        __syncthreads();
        const float* Wp = Wn + (long)k0*N;
        #pragma unroll 8
        for (int k = 0; k < 1024; k++) {
            float w = Wp[(long)k*N];
            a0 += w*Xs[0][k]; a1 += w*Xs[1][k]; a2 += w*Xs[2][k]; a3 += w*Xs[3][k];
        }
    }
    float bv = bias[(long)n*N + o];
    a0 += bv; a1 += bv; a2 += bv; a3 += bv;
    if (relu) { a0=fmaxf(a0,0.f); a1=fmaxf(a1,0.f); a2=fmaxf(a2,0.f); a3=fmaxf(a3,0.f); }
    long yo = (long)n*yRow + o;
    Y[0*yBatch+yo]=a0; Y[1*yBatch+yo]=a1; Y[2*yBatch+yo]=a2; Y[3*yBatch+yo]=a3;
}

// ---------------- per-NS-position linear, K-split partials ----------------
__global__ __launch_bounds__(128) void ns_split_kernel(
    const float* __restrict__ X, long xBatch, int xRow,
    const float* __restrict__ W, float* __restrict__ part,
    int K, int N, int kchunk)
{
    __shared__ float Xs[4][512];
    int n = blockIdx.y, z = blockIdx.z;
    int t = threadIdx.x;
    int o = blockIdx.x * 128 + t;
    int k0 = z * kchunk;
    for (int i = t; i < kchunk; i += 128) {
        long xo = (long)n*xRow + k0 + i;
        Xs[0][i] = X[0*xBatch + xo];
        Xs[1][i] = X[1*xBatch + xo];
        Xs[2][i] = X[2*xBatch + xo];
        Xs[3][i] = X[3*xBatch + xo];
    }
    __syncthreads();
    const float* Wp = W + (long)n*K*N + (long)k0*N + o;
    float a0=0.f, a1=0.f, a2=0.f, a3=0.f;
    #pragma unroll 8
    for (int k = 0; k < kchunk; k++) {
        float w = Wp[(long)k*N];
        a0 += w*Xs[0][k]; a1 += w*Xs[1][k]; a2 += w*Xs[2][k]; a3 += w*Xs[3][k];
    }
    part[((long)(z*BSZ+0)*NSN + n)*N + o] = a0;
    part[((long)(z*BSZ+1)*NSN + n)*N + o] = a1;
    part[((long)(z*BSZ+2)*NSN + n)*N + o] = a2;
    part[((long)(z*BSZ+3)*NSN + n)*N + o] = a3;
}

__global__ __launch_bounds__(256) void ns_reduce_kernel(
    const float* __restrict__ part, const float* __restrict__ bias,
    float* __restrict__ Y, long yBatch, int yRow, int N, int KS, int relu)
{
    int o = blockIdx.x*256 + threadIdx.x;
    int n = blockIdx.y, b = blockIdx.z;
    float s = bias[(long)n*N + o];
    for (int z = 0; z < KS; z++)
        s += part[((long)(z*BSZ+b)*NSN + n)*N + o];
    if (relu) s = fmaxf(s, 0.f);
    Y[(long)b*yBatch + (long)n*yRow + o] = s;
}

// ---------------- RoPE in-place ----------------
__global__ void rope_kernel(float* __restrict__ buf, int rowsPerB, int pos0, int rstride, int total) {
    int idx = blockIdx.x*blockDim.x + threadIdx.x;
    if (idx >= total) return;
    int j  = idx & 31;
    int h  = (idx >> 5) & (NH-1);
    int rr = idx >> 9;
    int b  = rr / rowsPerB;
    int r  = rr - b*rowsPerB;
    double inv = pow(10000.0, -(double)j / 32.0);
    double ang = (double)(pos0 + r) * inv;
    double sd, cd;
    sincos(ang, &sd, &cd);
    float s = (float)sd, c = (float)cd;
    float* base = buf + ((long)b*rowsPerB + r)*(long)rstride + h*HD;
    float x1 = base[j], x2 = base[j+32];
    base[j]    = x1*c - x2*s;
    base[j+32] = x2*c + x1*s;
}

// ---------------- tensor-core flash attention (tf32) ----------------
__global__ __launch_bounds__(256) void attn_mma_kernel(
    const float* __restrict__ q, const float* __restrict__ kv,
    float* __restrict__ attn, const int* __restrict__ seqlen)
{
    __shared__ float qs [64][68];
    __shared__ float ksm[32][68];
    __shared__ float vsm[32][72];
    __shared__ float ssm[64][36];
    __shared__ float corrs[64];
    __shared__ float lrow[64];

    int qt = blockIdx.x, h = blockIdx.y, b = blockIdx.z;
    int tid = threadIdx.x;
    int w = tid >> 5, lane = tid & 31;
    int g = lane >> 2, tig = lane & 3;
    int wm = w >> 2, wn = w & 3;
    int L = seqlen[b];
    int kmin = MAXS - L;

    for (int i = tid; i < 64*16; i += 256) {
        int r = i >> 4, c4 = (i & 15) * 4;
        int qg = qt*64 + r;
        float4 val = make_float4(0.f,0.f,0.f,0.f);
        if (qg < QLEN)
            val = *reinterpret_cast<const float4*>(q + ((long)b*QLEN + qg)*DM + h*HD + c4);
        qs[r][c4]   = rtf32(val.x);
        qs[r][c4+1] = rtf32(val.y);
        qs[r][c4+2] = rtf32(val.z);
        qs[r][c4+3] = rtf32(val.w);
    }

    int srow = tid >> 2, ssub = tid & 3;
    float m = -1e30f, l = 0.f;

    float oacc[2][2][4];
    #pragma unroll
    for (int i = 0; i < 2; i++)
        #pragma unroll
        for (int j = 0; j < 2; j++)
            #pragma unroll
            for (int r = 0; r < 4; r++) oacc[i][j][r] = 0.f;

    int qgmax = min(QLEN-1, qt*64 + 63);
    int t0 = kmin >> 5;
    int t1 = (MAXS - OUTN + qgmax) >> 5;

    for (int kt = t0; kt <= t1; kt++) {
        int key0 = kt * 32;
        __syncthreads();
        for (int i = tid; i < 32*16; i += 256) {
            int r = i >> 4, c4 = (i & 15) * 4;
            int key = key0 + r;
            float4 kk = make_float4(0.f,0.f,0.f,0.f), vv = kk;
            if (key < TOTAL) {
                const float* base = kv + ((long)b*TOTAL + key)*(2*DM) + h*HD;
                kk = *reinterpret_cast<const float4*>(base + c4);
                vv = *reinterpret_cast<const float4*>(base + DM + c4);
            }
            ksm[r][c4]=rtf32(kk.x); ksm[r][c4+1]=rtf32(kk.y);
            ksm[r][c4+2]=rtf32(kk.z); ksm[r][c4+3]=rtf32(kk.w);
            vsm[r][c4]=rtf32(vv.x); vsm[r][c4+1]=rtf32(vv.y);
            vsm[r][c4+2]=rtf32(vv.z); vsm[r][c4+3]=rtf32(vv.w);
        }
        __syncthreads();

        float sa[2][4];
        #pragma unroll
        for (int mt = 0; mt < 2; mt++)
            #pragma unroll
            for (int r = 0; r < 4; r++) sa[mt][r] = 0.f;
        #pragma unroll
        for (int dk = 0; dk < 8; dk++) {
            uint32_t bf0 = f2u(ksm[wn*8 + g][dk*8 + tig]);
            uint32_t bf1 = f2u(ksm[wn*8 + g][dk*8 + tig + 4]);
            #pragma unroll
            for (int mt = 0; mt < 2; mt++) {
                int m0 = wm*32 + mt*16;
                mma_tf32(sa[mt],
                    f2u(qs[m0+g][dk*8+tig]),   f2u(qs[m0+g+8][dk*8+tig]),
                    f2u(qs[m0+g][dk*8+tig+4]), f2u(qs[m0+g+8][dk*8+tig+4]),
                    bf0, bf1);
            }
        }
        #pragma unroll
        for (int mt = 0; mt < 2; mt++) {
            #pragma unroll
            for (int hh = 0; hh < 2; hh++) {
                int r = wm*32 + mt*16 + g + hh*8;
                int qg = qt*64 + r;
                int key = key0 + wn*8 + 2*tig;
                int kcap = MAXS - OUTN + qg;
                bool rowok = (qg < QLEN);
                float sA = sa[mt][hh*2+0], sB = sa[mt][hh*2+1];
                bool v0 = rowok && (key   < TOTAL) && (key   >= kmin) && (key   <= kcap);
                bool v1 = rowok && (key+1 < TOTAL) && (key+1 >= kmin) && (key+1 <= kcap);
                ssm[r][wn*8 + 2*tig]     = v0 ? sA*0.125f : -1e9f;
                ssm[r][wn*8 + 2*tig + 1] = v1 ? sB*0.125f : -1e9f;
            }
        }
        __syncthreads();

        float sv[8];
        #pragma unroll
        for (int j = 0; j < 8; j++) sv[j] = ssm[srow][ssub*8 + j];
        float tmax = sv[0];
        #pragma unroll
        for (int j = 1; j < 8; j++) tmax = fmaxf(tmax, sv[j]);
        tmax = fmaxf(tmax, __shfl_xor_sync(0xffffffffu, tmax, 1));
        tmax = fmaxf(tmax, __shfl_xor_sync(0xffffffffu, tmax, 2));
        float corr = 1.f;
        if (tmax > -1e8f) {
            float m_new = fmaxf(m, tmax);
            corr = __expf(m - m_new);
            float ps = 0.f;
            #pragma unroll
            for (int j = 0; j < 8; j++) {
                float p = __expf(sv[j] - m_new);
                ps += p;
                ssm[srow][ssub*8 + j] = rtf32(p);
            }
            ps += __shfl_xor_sync(0xffffffffu, ps, 1);
            ps += __shfl_xor_sync(0xffffffffu, ps, 2);
            l = l*corr + ps;
            m = m_new;
        } else {
            #pragma unroll
            for (int j = 0; j < 8; j++) ssm[srow][ssub*8 + j] = 0.f;
        }
        if (ssub == 0) corrs[srow] = corr;
        __syncthreads();

        #pragma unroll
        for (int mt = 0; mt < 2; mt++) {
            float c0 = corrs[wm*32 + mt*16 + g];
            float c1 = corrs[wm*32 + mt*16 + g + 8];
            #pragma unroll
            for (int nt = 0; nt < 2; nt++) {
                oacc[mt][nt][0] *= c0; oacc[mt][nt][1] *= c0;
                oacc[mt][nt][2] *= c1; oacc[mt][nt][3] *= c1;
            }
        }
        #pragma unroll
        for (int kd = 0; kd < 4; kd++) {
            uint32_t bf[2][2];
            #pragma unroll
            for (int nt = 0; nt < 2; nt++) {
                int n = wn*16 + nt*8 + g;
                bf[nt][0] = f2u(vsm[kd*8 + tig][n]);
                bf[nt][1] = f2u(vsm[kd*8 + tig + 4][n]);
            }
            #pragma unroll
            for (int mt = 0; mt < 2; mt++) {
                int m0 = wm*32 + mt*16;
                uint32_t a0 = f2u(ssm[m0+g][kd*8+tig]);
                uint32_t a1 = f2u(ssm[m0+g+8][kd*8+tig]);
                uint32_t a2 = f2u(ssm[m0+g][kd*8+tig+4]);
                uint32_t a3 = f2u(ssm[m0+g+8][kd*8+tig+4]);
                #pragma unroll
                for (int nt = 0; nt < 2; nt++)
                    mma_tf32(oacc[mt][nt], a0, a1, a2, a3, bf[nt][0], bf[nt][1]);
            }
        }
    }

    if (ssub == 0) lrow[srow] = l;
    __syncthreads();
    #pragma unroll
    for (int mt = 0; mt < 2; mt++) {
        #pragma unroll
        for (int hh = 0; hh < 2; hh++) {
            int r = wm*32 + mt*16 + g + hh*8;
            int qg = qt*64 + r;
            if (qg < QLEN) {
                float invl = 1.f / lrow[r];
                #pragma unroll
                for (int nt = 0; nt < 2; nt++) {
                    int col = wn*16 + nt*8 + 2*tig;
                    *reinterpret_cast<float2*>(attn + ((long)b*QLEN + qg)*DM + h*HD + col)
                        = make_float2(oacc[mt][nt][hh*2]*invl, oacc[mt][nt][hh*2+1]*invl);
                }
            }
        }
    }
}

// ---------------- final assembly ----------------
__global__ void assemble_kernel(float* __restrict__ out, const int* __restrict__ seqlen, int out_size) {
    int idx = blockIdx.x*blockDim.x + threadIdx.x;
    const int main_n = BSZ*QLEN*DM;
    if (idx < main_n) {
        int b = idx / (QLEN*DM);
        int rem = idx - b*(QLEN*DM);
        int r = rem / DM;
        int d = rem - r*DM;
        float f;
        if (r < OUTN) f = g_fs [((long)b*OUTN + r)*DM + d];
        else          f = g_fns[((long)b*NSN + (r - OUTN))*DM + d];
        out[idx] = f + g_h1[idx];
    }
    if (idx < BSZ && out_size >= main_n + BSZ) {
        int L = seqlen[idx];
        out[main_n + idx] = (float)(L < OUTN ? L : OUTN);
    }
}

extern "C" void kernel_launch(void* const* d_in, const int* in_sizes, int n_in,
                              void* d_out, int out_size) {
    (void)in_sizes; (void)n_in;
    const float* x    = (const float*)d_in[0];
    const int*   seq  = (const int*)  d_in[1];
    const float* wqkv = (const float*)d_in[2];
    const float* bqkv = (const float*)d_in[3];
    const float* wnsq = (const float*)d_in[4];
    const float* bnsq = (const float*)d_in[5];
    const float* wnsk = (const float*)d_in[6];
    const float* bnsk = (const float*)d_in[7];
    const float* wnsv = (const float*)d_in[8];
    const float* bnsv = (const float*)d_in[9];
    const float* n1w  = (const float*)d_in[10];
    const float* n2w  = (const float*)d_in[11];
    const float* fw1  = (const float*)d_in[12];
    const float* fb1  = (const float*)d_in[13];
    const float* fw2  = (const float*)d_in[14];
    const float* fb2  = (const float*)d_in[15];
    const float* w1ns = (const float*)d_in[16];
    const float* b1ns = (const float*)d_in[17];
    const float* w2ns = (const float*)d_in[18];
    const float* b2ns = (const float*)d_in[19];
    float* out = (float*)d_out;

    float *xn,*q,*kv,*attn,*hn,*ts,*tns,*fs,*fns,*part,*wq_r,*w1_r,*w2_r;
    cudaGetSymbolAddress((void**)&xn,   g_xn);
    cudaGetSymbolAddress((void**)&q,    g_q);
    cudaGetSymbolAddress((void**)&kv,   g_kv);
    cudaGetSymbolAddress((void**)&attn, g_attn);
    cudaGetSymbolAddress((void**)&hn,   g_hn);
    cudaGetSymbolAddress((void**)&ts,   g_ts);
    cudaGetSymbolAddress((void**)&tns,  g_tns);
    cudaGetSymbolAddress((void**)&fs,   g_fs);
    cudaGetSymbolAddress((void**)&fns,  g_fns);
    cudaGetSymbolAddress((void**)&part, g_part);
    cudaGetSymbolAddress((void**)&wq_r, g_wqkv);
    cudaGetSymbolAddress((void**)&w1_r, g_w1);
    cudaGetSymbolAddress((void**)&w2_r, g_w2);

    const long aB  = (long)TOTAL*DM;
    const long qB  = (long)QLEN*DM;
    const long kvB = (long)TOTAL*2*DM;

    const int SMEM128 = (3*128*36 + 3*32*136) * 4;   // 107520 B
    const int SMEM64  = (3*64*36  + 3*32*136) * 4;   //  79872 B
    cudaFuncSetAttribute(mma_gemm32_kernel<128>, cudaFuncAttributeMaxDynamicSharedMemorySize, SMEM128);
    cudaFuncSetAttribute(mma_gemm32_kernel<64>,  cudaFuncAttributeMaxDynamicSharedMemorySize, SMEM64);

    // 1) xn = rmsnorm(x, norm1)  [launch #1 — keeps ncu -s 5 aimed at KV GEMM]
    rmsnorm_kernel<<<BSZ*TOTAL, 256>>>(x, n1w, xn);

    // 0) round shared GEMM weights to tf32  [launches #2-#4]
    round_tf32_kernel<<<(DM*3*DM/4 + 255)/256, 256>>>(wqkv, wq_r, DM*3*DM/4);
    round_tf32_kernel<<<(DM*FFND/4 + 255)/256, 256>>>(fw1, w1_r, DM*FFND/4);
    round_tf32_kernel<<<(FFND*DM/4 + 255)/256, 256>>>(fw2, w2_r, FFND*DM/4);

    // 2) Q projection [#5], fused K+V projection [#6 — ncu capture target]
    mma_gemm32_kernel<64><<<dim3(DM/128, (BSZ*OUTN)/64), 256, SMEM64>>>(xn + (long)(MAXS-OUTN)*DM, DM, aB, OUTN,
        wq_r,      3*DM, bqkv,      q,  DM,  qB, DM, 0, 0);
    mma_gemm32_kernel<128><<<dim3(2*DM/128, (BSZ*MAXS)/128), 256, SMEM128>>>(xn, DM, aB, MAXS,
        wq_r + DM, 3*DM, bqkv + DM, kv, 2*DM, kvB, DM, 0, 0);

    // 3) per-position NS projections (K-split, 8-way)
    ns_split_kernel<<<dim3(DM/128, NSN, 8), 128>>>(xn + (long)MAXS*DM, aB, DM, wnsq, part, DM, DM, DM/8);
    ns_reduce_kernel<<<dim3(DM/256, NSN, BSZ), 256>>>(part, bnsq, q + (long)OUTN*DM, qB, DM, DM, 8, 0);
    ns_split_kernel<<<dim3(DM/128, NSN, 8), 128>>>(xn + (long)MAXS*DM, aB, DM, wnsk, part, DM, DM, DM/8);
    ns_reduce_kernel<<<dim3(DM/256, NSN, BSZ), 256>>>(part, bnsk, kv + (long)MAXS*2*DM, kvB, 2*DM, DM, 8, 0);
    ns_split_kernel<<<dim3(DM/128, NSN, 8), 128>>>(xn + (long)MAXS*DM, aB, DM, wnsv, part, DM, DM, DM/8);
    ns_reduce_kernel<<<dim3(DM/256, NSN, BSZ), 256>>>(part, bnsv, kv + (long)MAXS*2*DM + DM, kvB, 2*DM, DM, 8, 0);

    // 4) RoPE
    {
        int totq = BSZ*QLEN*NH*32;
        rope_kernel<<<(totq+255)/256, 256>>>(q, QLEN, TOTAL-QLEN, DM, totq);
        int totk = BSZ*TOTAL*NH*32;
        rope_kernel<<<(totk+255)/256, 256>>>(kv, TOTAL, 0, 2*DM, totk);
    }

    // 5) tensor-core attention
    attn_mma_kernel<<<dim3((QLEN+63)/64, NH, BSZ), 256>>>(q, kv, attn, seq);

    // 6) h1 = residual + attn ; hn = rmsnorm(h1)
    add_rmsnorm_kernel<<<BSZ*QLEN, 256>>>(x, n2w);

    // 7) shared FFN
    mma_gemm32_kernel<128><<<dim3(FFND/128, (BSZ*OUTN)/128), 256, SMEM128>>>(hn, DM, qB, OUTN,
        w1_r, FFND, fb1, ts, FFND, (long)OUTN*FFND, DM, 1, 1);
    mma_gemm32_kernel<64><<<dim3(DM/128, (BSZ*OUTN)/64), 256, SMEM64>>>(ts, FFND, (long)OUTN*FFND, OUTN,
        w2_r, DM, fb2, fs, DM, (long)OUTN*DM, FFND, 0, 0);

    // 8) NS FFN: w1 direct (N=4096), w2 via K-split
    ns_linear_kernel<<<dim3(FFND/128, NSN), 128>>>(hn + (long)OUTN*DM, qB, DM,
        w1ns, b1ns, tns, (long)NSN*FFND, FFND, DM, FFND, 1);
    ns_split_kernel<<<dim3(DM/128, NSN, 8), 128>>>(tns, (long)NSN*FFND, FFND, w2ns, part, FFND, DM, FFND/8);
    ns_reduce_kernel<<<dim3(DM/256, NSN, BSZ), 256>>>(part, b2ns, fns, (long)NSN*DM, DM, DM, 8, 0);

    // 9) assemble output
    assemble_kernel<<<(BSZ*QLEN*DM + 255)/256, 256>>>(out, seq, out_size);
}

// round 7
// speedup vs baseline: 2.2859x; 1.0068x over previous
#include <cuda_runtime.h>
#include <cstdint>

#define BSZ   4
#define TOTAL 2064
#define DM    1024
#define NSN   16
#define OUTN  256
#define QLEN  272
#define NH    16
#define HD    64
#define FFND  4096
#define MAXS  2048

// Scratch (static device globals; no allocation allowed)
__device__ float g_xn  [BSZ*TOTAL*DM];
__device__ float g_q   [BSZ*QLEN*DM];
__device__ float g_kv  [BSZ*TOTAL*2*DM];   // k = cols 0..1023, v = cols 1024..2047
__device__ float g_attn[BSZ*QLEN*DM];
__device__ float g_h1  [BSZ*QLEN*DM];
__device__ float g_hn  [BSZ*QLEN*DM];
__device__ float g_ts  [BSZ*OUTN*FFND];
__device__ float g_tns [BSZ*NSN*FFND];
__device__ float g_fs  [BSZ*OUTN*DM];
__device__ float g_fns [BSZ*NSN*DM];
__device__ float g_part[8*BSZ*NSN*DM];     // k-split partials
// TF32-rounded, TRANSPOSED weights ([N, K] row-major)
__device__ float g_wqkv[3*DM*DM];          // rows: 0..1023 Q, 1024..2047 K, 2048..3071 V
__device__ float g_w1  [FFND*DM];
__device__ float g_w2  [DM*FFND];

__device__ __forceinline__ float rtf32(float x) {
    uint32_t u;
    asm("cvt.rna.tf32.f32 %0, %1;" : "=r"(u) : "f"(x));
    return __uint_as_float(u);
}
__device__ __forceinline__ uint32_t f2u(float x) { return __float_as_uint(x); }

__device__ __forceinline__ void cpa16(uint32_t dst, const void* src) {
    asm volatile("cp.async.ca.shared.global [%0], [%1], 16;" :: "r"(dst), "l"(src));
}

__device__ __forceinline__ void mma_tf32(float* c,
        uint32_t a0, uint32_t a1, uint32_t a2, uint32_t a3,
        uint32_t b0, uint32_t b1) {
    asm volatile(
        "mma.sync.aligned.m16n8k8.row.col.f32.tf32.tf32.f32 "
        "{%0,%1,%2,%3}, {%4,%5,%6,%7}, {%8,%9}, {%0,%1,%2,%3};\n"
        : "+f"(c[0]), "+f"(c[1]), "+f"(c[2]), "+f"(c[3])
        : "r"(a0), "r"(a1), "r"(a2), "r"(a3), "r"(b0), "r"(b1));
}

__device__ __forceinline__ void ldsm4(uint32_t* r, uint32_t addr) {
    asm volatile("ldmatrix.sync.aligned.m8n8.x4.shared.b16 {%0,%1,%2,%3}, [%4];"
        : "=r"(r[0]), "=r"(r[1]), "=r"(r[2]), "=r"(r[3]) : "r"(addr));
}

// ---------------- transpose + tf32 round: out[c*R + r] = rtf32(in[r*C + c]) ----------------
__global__ __launch_bounds__(256) void transpose_tf32_kernel(const float* __restrict__ in,
        float* __restrict__ out, int R, int C) {
    __shared__ float tile[32][33];
    int c0 = blockIdx.x*32, r0 = blockIdx.y*32;
    int tx = threadIdx.x, ty = threadIdx.y;   // 32 x 8
    for (int i = ty; i < 32; i += 8)
        tile[i][tx] = in[(long)(r0+i)*C + c0 + tx];
    __syncthreads();
    for (int i = ty; i < 32; i += 8)
        out[(long)(c0+i)*R + r0 + tx] = rtf32(tile[tx][i]);
}

// ---------------- rmsnorm (output tf32-rounded) ----------------
__global__ __launch_bounds__(256) void rmsnorm_kernel(const float* __restrict__ in,
        const float* __restrict__ w, float* __restrict__ out) {
    long row = blockIdx.x;
    int t = threadIdx.x;
    float4 v = reinterpret_cast<const float4*>(in + row*DM)[t];
    float ss = v.x*v.x + v.y*v.y + v.z*v.z + v.w*v.w;
    __shared__ float red[8];
    for (int o = 16; o; o >>= 1) ss += __shfl_xor_sync(0xffffffffu, ss, o);
    if ((t & 31) == 0) red[t >> 5] = ss;
    __syncthreads();
    if (t < 32) {
        float s = (t < 8) ? red[t] : 0.f;
        for (int o = 4; o; o >>= 1) s += __shfl_xor_sync(0xffffffffu, s, o);
        if (t == 0) red[0] = s;
    }
    __syncthreads();
    float rs = rsqrtf(red[0] * (1.f/DM) + 1e-6f);
    float4 wv = reinterpret_cast<const float4*>(w)[t];
    float4 o4 = make_float4(rtf32(v.x*rs*wv.x), rtf32(v.y*rs*wv.y),
                            rtf32(v.z*rs*wv.z), rtf32(v.w*rs*wv.w));
    reinterpret_cast<float4*>(out + row*DM)[t] = o4;
}

// ---------------- h1 = x[:, -272:] + attn ; hn = rmsnorm(h1) ----------------
__global__ __launch_bounds__(256) void add_rmsnorm_kernel(const float* __restrict__ x,
        const float* __restrict__ w) {
    int row = blockIdx.x;
    int b = row / QLEN, r = row - b*QLEN;
    int t = threadIdx.x;
    float4 xv = reinterpret_cast<const float4*>(x + ((long)b*TOTAL + (TOTAL-QLEN) + r)*DM)[t];
    float4 av = reinterpret_cast<const float4*>(g_attn + (long)row*DM)[t];
    float4 hv = make_float4(xv.x+av.x, xv.y+av.y, xv.z+av.z, xv.w+av.w);
    reinterpret_cast<float4*>(g_h1 + (long)row*DM)[t] = hv;
    float ss = hv.x*hv.x + hv.y*hv.y + hv.z*hv.z + hv.w*hv.w;
    __shared__ float red[8];
    for (int o = 16; o; o >>= 1) ss += __shfl_xor_sync(0xffffffffu, ss, o);
    if ((t & 31) == 0) red[t >> 5] = ss;
    __syncthreads();
    if (t < 32) {
        float s = (t < 8) ? red[t] : 0.f;
        for (int o = 4; o; o >>= 1) s += __shfl_xor_sync(0xffffffffu, s, o);
        if (t == 0) red[0] = s;
    }
    __syncthreads();
    float rs = rsqrtf(red[0] * (1.f/DM) + 1e-6f);
    float4 wv = reinterpret_cast<const float4*>(w)[t];
    float4 o4 = make_float4(rtf32(hv.x*rs*wv.x), rtf32(hv.y*rs*wv.y),
                            rtf32(hv.z*rs*wv.z), rtf32(hv.w*rs*wv.w));
    reinterpret_cast<float4*>(g_hn + (long)row*DM)[t] = o4;
}

// ---------------- TF32 tensor-core GEMM, MTILEx128x32, 3-stage cp.async, LDSM frags ----------
// A [M,K] row-major; Bt [N,K] row-major (transposed weights). C = A * Bt^T + bias.
template<int MTILE>
__global__ __launch_bounds__(256, 2) void mma_gemmT_kernel(
    const float* __restrict__ A, int lda, long aBatch, int rpb,
    const float* __restrict__ Bt, int ldbt,
    const float* __restrict__ bias,
    float* __restrict__ C, int ldc, long cBatch,
    int K, int relu, int roundOut)
{
    constexpr int S    = 3;
    constexpr int PAD  = 36;                 // 9 x 16B units: conflict-free LDSM rows
    constexpr int ASTG = MTILE*PAD;
    constexpr int BSTG = 128*PAD;
    constexpr int MT   = MTILE/32;
    extern __shared__ float sm[];
    float* AsBase = sm;
    float* BsBase = sm + S*ASTG;

    int t = threadIdx.x;
    int w = t >> 5, lane = t & 31;
    int g = lane >> 2, tig = lane & 3;
    int wm = w >> 2, wn = w & 3;

    int row0 = blockIdx.y * MTILE;
    int bn0  = blockIdx.x * 128;
    int batch = row0 / rpb;
    int rin   = row0 % rpb;
    const float* Ab = A + (long)batch*aBatch + (long)rin*lda;
    const float* Bb = Bt + (long)bn0*ldbt;
    float* Cb = C + (long)batch*cBatch + (long)rin*ldc + bn0;

    uint32_t aSm0 = (uint32_t)__cvta_generic_to_shared(AsBase);
    uint32_t bSm0 = (uint32_t)__cvta_generic_to_shared(BsBase);

    float acc[MT][4][4];
    #pragma unroll
    for (int i = 0; i < MT; i++)
        #pragma unroll
        for (int j = 0; j < 4; j++)
            #pragma unroll
            for (int r = 0; r < 4; r++) acc[i][j][r] = 0.f;

    const int KT = K >> 5;
    auto issue = [&](int kt) {
        int s = kt % S;
        const float* ga = Ab + kt*32;
        const float* gb = Bb + kt*32;
        uint32_t aS = aSm0 + s*ASTG*4;
        uint32_t bS = bSm0 + s*BSTG*4;
        #pragma unroll
        for (int it = 0; it < MTILE/32; it++) {
            int i = t + it*256;
            int row = i >> 3, seg = i & 7;
            cpa16(aS + (row*PAD + seg*4)*4, ga + (long)row*lda + seg*4);
        }
        #pragma unroll
        for (int it = 0; it < 4; it++) {
            int i = t + it*256;
            int row = i >> 3, seg = i & 7;
            cpa16(bS + (row*PAD + seg*4)*4, gb + (long)row*ldbt + seg*4);
        }
        asm volatile("cp.async.commit_group;");
    };
    issue(0);
    issue(1);

    // LDSM lane-address components
    int aRowL = (lane & 7) + ((lane >> 3) & 1) * 8;   // row within 16-row tile
    int aColL = (lane >> 4) * 4;                      // +0 / +4 floats
    int bRowL = ((lane >> 4) & 1) * 8 + (lane & 7);   // lanes 0-15: nt-lo rows, 16-31: nt-hi
    int bColL = ((lane >> 3) & 1) * 4;                // lanes 8-15 / 24-31: +4 floats

    for (int kt = 0; kt < KT; kt++) {
        if (kt == KT - 1) asm volatile("cp.async.wait_group 0;");
        else              asm volatile("cp.async.wait_group 1;");
        __syncthreads();
        if (kt + 2 < KT) issue(kt + 2);

        int s = kt % S;
        uint32_t As = aSm0 + s*ASTG*4;
        uint32_t Bs = bSm0 + s*BSTG*4;
        #pragma unroll
        for (int ks = 0; ks < 4; ks++) {
            uint32_t afr[MT][4];
            #pragma unroll
            for (int mt = 0; mt < MT; mt++)
                ldsm4(afr[mt], As + ((wm*(MTILE/2) + mt*16 + aRowL)*PAD + ks*8 + aColL)*4);
            uint32_t bfr[4][2];
            #pragma unroll
            for (int p = 0; p < 2; p++) {
                uint32_t r4[4];
                ldsm4(r4, Bs + ((wn*32 + p*16 + bRowL)*PAD + ks*8 + bColL)*4);
                bfr[2*p][0]   = r4[0]; bfr[2*p][1]   = r4[1];
                bfr[2*p+1][0] = r4[2]; bfr[2*p+1][1] = r4[3];
            }
            #pragma unroll
            for (int mt = 0; mt < MT; mt++)
                #pragma unroll
                for (int nt = 0; nt < 4; nt++)
                    mma_tf32(acc[mt][nt], afr[mt][0], afr[mt][1], afr[mt][2], afr[mt][3],
                             bfr[nt][0], bfr[nt][1]);
        }
    }

    #pragma unroll
    for (int nt = 0; nt < 4; nt++) {
        int col = wn*32 + nt*8 + 2*tig;
        float bx = bias[bn0 + col], by = bias[bn0 + col + 1];
        #pragma unroll
        for (int mt = 0; mt < MT; mt++) {
            int r0 = wm*(MTILE/2) + mt*16 + g;
            float c0 = acc[mt][nt][0] + bx, c1 = acc[mt][nt][1] + by;
            float c2 = acc[mt][nt][2] + bx, c3 = acc[mt][nt][3] + by;
            if (relu) { c0=fmaxf(c0,0.f); c1=fmaxf(c1,0.f); c2=fmaxf(c2,0.f); c3=fmaxf(c3,0.f); }
            if (roundOut) { c0=rtf32(c0); c1=rtf32(c1); c2=rtf32(c2); c3=rtf32(c3); }
            *reinterpret_cast<float2*>(Cb + (long)r0*ldc + col)     = make_float2(c0, c1);
            *reinterpret_cast<float2*>(Cb + (long)(r0+8)*ldc + col) = make_float2(c2, c3);
        }
    }
}

// ---------------- per-NS-position linear, direct (w1ns: N=4096) ----------------
__global__ __launch_bounds__(128) void ns_linear_kernel(
    const float* __restrict__ X, long xBatch, int xRow,
    const float* __restrict__ W, const float* __restrict__ bias,
    float* __restrict__ Y, long yBatch, int yRow,
    int K, int N, int relu)
{
    __shared__ float Xs[4][1024];
    int n = blockIdx.y;
    int t = threadIdx.x;
    int o = blockIdx.x * 128 + t;
    const float* Wn = W + (long)n*K*N + o;
    float a0=0.f, a1=0.f, a2=0.f, a3=0.f;
    for (int k0 = 0; k0 < K; k0 += 1024) {
        __syncthreads();
        for (int i = t; i < 1024; i += 128) {
            long xo = (long)n*xRow + k0 + i;
            Xs[0][i] = X[0*xBatch + xo];
            Xs[1][i] = X[1*xBatch + xo];
            Xs[2][i] = X[2*xBatch + xo];
            Xs[3][i] = X[3*xBatch + xo];
        }
        __syncthreads();
        const float* Wp = Wn + (long)k0*N;
        #pragma unroll 8
        for (int k = 0; k < 1024; k++) {
            float w = Wp[(long)k*N];
            a0 += w*Xs[0][k]; a1 += w*Xs[1][k]; a2 += w*Xs[2][k]; a3 += w*Xs[3][k];
        }
    }
    float bv = bias[(long)n*N + o];
    a0 += bv; a1 += bv; a2 += bv; a3 += bv;
    if (relu) { a0=fmaxf(a0,0.f); a1=fmaxf(a1,0.f); a2=fmaxf(a2,0.f); a3=fmaxf(a3,0.f); }
    long yo = (long)n*yRow + o;
    Y[0*yBatch+yo]=a0; Y[1*yBatch+yo]=a1; Y[2*yBatch+yo]=a2; Y[3*yBatch+yo]=a3;
}

// ---------------- per-NS-position linear, K-split partials ----------------
__global__ __launch_bounds__(128) void ns_split_kernel(
    const float* __restrict__ X, long xBatch, int xRow,
    const float* __restrict__ W, float* __restrict__ part,
    int K, int N, int kchunk)
{
    __shared__ float Xs[4][512];
    int n = blockIdx.y, z = blockIdx.z;
    int t = threadIdx.x;
    int o = blockIdx.x * 128 + t;
    int k0 = z * kchunk;
    for (int i = t; i < kchunk; i += 128) {
        long xo = (long)n*xRow + k0 + i;
        Xs[0][i] = X[0*xBatch + xo];
        Xs[1][i] = X[1*xBatch + xo];
        Xs[2][i] = X[2*xBatch + xo];
        Xs[3][i] = X[3*xBatch + xo];
    }
    __syncthreads();
    const float* Wp = W + (long)n*K*N + (long)k0*N + o;
    float a0=0.f, a1=0.f, a2=0.f, a3=0.f;
    #pragma unroll 8
    for (int k = 0; k < kchunk; k++) {
        float w = Wp[(long)k*N];
        a0 += w*Xs[0][k]; a1 += w*Xs[1][k]; a2 += w*Xs[2][k]; a3 += w*Xs[3][k];
    }
    part[((long)(z*BSZ+0)*NSN + n)*N + o] = a0;
    part[((long)(z*BSZ+1)*NSN + n)*N + o] = a1;
    part[((long)(z*BSZ+2)*NSN + n)*N + o] = a2;
    part[((long)(z*BSZ+3)*NSN + n)*N + o] = a3;
}

__global__ __launch_bounds__(256) void ns_reduce_kernel(
    const float* __restrict__ part, const float* __restrict__ bias,
    float* __restrict__ Y, long yBatch, int yRow, int N, int KS, int relu)
{
    int o = blockIdx.x*256 + threadIdx.x;
    int n = blockIdx.y, b = blockIdx.z;
    float s = bias[(long)n*N + o];
    for (int z = 0; z < KS; z++)
        s += part[((long)(z*BSZ+b)*NSN + n)*N + o];
    if (relu) s = fmaxf(s, 0.f);
    Y[(long)b*yBatch + (long)n*yRow + o] = s;
}

// ---------------- RoPE in-place ----------------
__global__ void rope_kernel(float* __restrict__ buf, int rowsPerB, int pos0, int rstride, int total) {
    int idx = blockIdx.x*blockDim.x + threadIdx.x;
    if (idx >= total) return;
    int j  = idx & 31;
    int h  = (idx >> 5) & (NH-1);
    int rr = idx >> 9;
    int b  = rr / rowsPerB;
    int r  = rr - b*rowsPerB;
    double inv = pow(10000.0, -(double)j / 32.0);
    double ang = (double)(pos0 + r) * inv;
    double sd, cd;
    sincos(ang, &sd, &cd);
    float s = (float)sd, c = (float)cd;
    float* base = buf + ((long)b*rowsPerB + r)*(long)rstride + h*HD;
    float x1 = base[j], x2 = base[j+32];
    base[j]    = x1*c - x2*s;
    base[j+32] = x2*c + x1*s;
}

// ---------------- tensor-core flash attention (tf32) ----------------
__global__ __launch_bounds__(256) void attn_mma_kernel(
    const float* __restrict__ q, const float* __restrict__ kv,
    float* __restrict__ attn, const int* __restrict__ seqlen)
{
    __shared__ float qs [64][68];
    __shared__ float ksm[32][68];
    __shared__ float vsm[32][72];
    __shared__ float ssm[64][36];
    __shared__ float corrs[64];
    __shared__ float lrow[64];

    int qt = blockIdx.x, h = blockIdx.y, b = blockIdx.z;
    int tid = threadIdx.x;
    int w = tid >> 5, lane = tid & 31;
    int g = lane >> 2, tig = lane & 3;
    int wm = w >> 2, wn = w & 3;
    int L = seqlen[b];
    int kmin = MAXS - L;

    for (int i = tid; i < 64*16; i += 256) {
        int r = i >> 4, c4 = (i & 15) * 4;
        int qg = qt*64 + r;
        float4 val = make_float4(0.f,0.f,0.f,0.f);
        if (qg < QLEN)
            val = *reinterpret_cast<const float4*>(q + ((long)b*QLEN + qg)*DM + h*HD + c4);
        qs[r][c4]   = rtf32(val.x);
        qs[r][c4+1] = rtf32(val.y);
        qs[r][c4+2] = rtf32(val.z);
        qs[r][c4+3] = rtf32(val.w);
    }

    int srow = tid >> 2, ssub = tid & 3;
    float m = -1e30f, l = 0.f;

    float oacc[2][2][4];
    #pragma unroll
    for (int i = 0; i < 2; i++)
        #pragma unroll
        for (int j = 0; j < 2; j++)
            #pragma unroll
            for (int r = 0; r < 4; r++) oacc[i][j][r] = 0.f;

    int qgmax = min(QLEN-1, qt*64 + 63);
    int t0 = kmin >> 5;
    int t1 = (MAXS - OUTN + qgmax) >> 5;

    for (int kt = t0; kt <= t1; kt++) {
        int key0 = kt * 32;
        __syncthreads();
        for (int i = tid; i < 32*16; i += 256) {
            int r = i >> 4, c4 = (i & 15) * 4;
            int key = key0 + r;
            float4 kk = make_float4(0.f,0.f,0.f,0.f), vv = kk;
            if (key < TOTAL) {
                const float* base = kv + ((long)b*TOTAL + key)*(2*DM) + h*HD;
                kk = *reinterpret_cast<const float4*>(base + c4);
                vv = *reinterpret_cast<const float4*>(base + DM + c4);
            }
            ksm[r][c4]=rtf32(kk.x); ksm[r][c4+1]=rtf32(kk.y);
            ksm[r][c4+2]=rtf32(kk.z); ksm[r][c4+3]=rtf32(kk.w);
            vsm[r][c4]=rtf32(vv.x); vsm[r][c4+1]=rtf32(vv.y);
            vsm[r][c4+2]=rtf32(vv.z); vsm[r][c4+3]=rtf32(vv.w);
        }
        __syncthreads();

        float sa[2][4];
        #pragma unroll
        for (int mt = 0; mt < 2; mt++)
            #pragma unroll
            for (int r = 0; r < 4; r++) sa[mt][r] = 0.f;
        #pragma unroll
        for (int dk = 0; dk < 8; dk++) {
            uint32_t bf0 = f2u(ksm[wn*8 + g][dk*8 + tig]);
            uint32_t bf1 = f2u(ksm[wn*8 + g][dk*8 + tig + 4]);
            #pragma unroll
            for (int mt = 0; mt < 2; mt++) {
                int m0 = wm*32 + mt*16;
                mma_tf32(sa[mt],
                    f2u(qs[m0+g][dk*8+tig]),   f2u(qs[m0+g+8][dk*8+tig]),
                    f2u(qs[m0+g][dk*8+tig+4]), f2u(qs[m0+g+8][dk*8+tig+4]),
                    bf0, bf1);
            }
        }
        #pragma unroll
        for (int mt = 0; mt < 2; mt++) {
            #pragma unroll
            for (int hh = 0; hh < 2; hh++) {
                int r = wm*32 + mt*16 + g + hh*8;
                int qg = qt*64 + r;
                int key = key0 + wn*8 + 2*tig;
                int kcap = MAXS - OUTN + qg;
                bool rowok = (qg < QLEN);
                float sA = sa[mt][hh*2+0], sB = sa[mt][hh*2+1];
                bool v0 = rowok && (key   < TOTAL) && (key   >= kmin) && (key   <= kcap);
                bool v1 = rowok && (key+1 < TOTAL) && (key+1 >= kmin) && (key+1 <= kcap);
                ssm[r][wn*8 + 2*tig]     = v0 ? sA*0.125f : -1e9f;
                ssm[r][wn*8 + 2*tig + 1] = v1 ? sB*0.125f : -1e9f;
            }
        }
        __syncthreads();

        float sv[8];
        #pragma unroll
        for (int j = 0; j < 8; j++) sv[j] = ssm[srow][ssub*8 + j];
        float tmax = sv[0];
        #pragma unroll
        for (int j = 1; j < 8; j++) tmax = fmaxf(tmax, sv[j]);
        tmax = fmaxf(tmax, __shfl_xor_sync(0xffffffffu, tmax, 1));
        tmax = fmaxf(tmax, __shfl_xor_sync(0xffffffffu, tmax, 2));
        float corr = 1.f;
        if (tmax > -1e8f) {
            float m_new = fmaxf(m, tmax);
            corr = __expf(m - m_new);
            float ps = 0.f;
            #pragma unroll
            for (int j = 0; j < 8; j++) {
                float p = __expf(sv[j] - m_new);
                ps += p;
                ssm[srow][ssub*8 + j] = rtf32(p);
            }
            ps += __shfl_xor_sync(0xffffffffu, ps, 1);
            ps += __shfl_xor_sync(0xffffffffu, ps, 2);
            l = l*corr + ps;
            m = m_new;
        } else {
            #pragma unroll
            for (int j = 0; j < 8; j++) ssm[srow][ssub*8 + j] = 0.f;
        }
        if (ssub == 0) corrs[srow] = corr;
        __syncthreads();

        #pragma unroll
        for (int mt = 0; mt < 2; mt++) {
            float c0 = corrs[wm*32 + mt*16 + g];
            float c1 = corrs[wm*32 + mt*16 + g + 8];
            #pragma unroll
            for (int nt = 0; nt < 2; nt++) {
                oacc[mt][nt][0] *= c0; oacc[mt][nt][1] *= c0;
                oacc[mt][nt][2] *= c1; oacc[mt][nt][3] *= c1;
            }
        }
        #pragma unroll
        for (int kd = 0; kd < 4; kd++) {
            uint32_t bf[2][2];
            #pragma unroll
            for (int nt = 0; nt < 2; nt++) {
                int n = wn*16 + nt*8 + g;
                bf[nt][0] = f2u(vsm[kd*8 + tig][n]);
                bf[nt][1] = f2u(vsm[kd*8 + tig + 4][n]);
            }
            #pragma unroll
            for (int mt = 0; mt < 2; mt++) {
                int m0 = wm*32 + mt*16;
                uint32_t a0 = f2u(ssm[m0+g][kd*8+tig]);
                uint32_t a1 = f2u(ssm[m0+g+8][kd*8+tig]);
                uint32_t a2 = f2u(ssm[m0+g][kd*8+tig+4]);
                uint32_t a3 = f2u(ssm[m0+g+8][kd*8+tig+4]);
                #pragma unroll
                for (int nt = 0; nt < 2; nt++)
                    mma_tf32(oacc[mt][nt], a0, a1, a2, a3, bf[nt][0], bf[nt][1]);
            }
        }
    }

    if (ssub == 0) lrow[srow] = l;
    __syncthreads();
    #pragma unroll
    for (int mt = 0; mt < 2; mt++) {
        #pragma unroll
        for (int hh = 0; hh < 2; hh++) {
            int r = wm*32 + mt*16 + g + hh*8;
            int qg = qt*64 + r;
            if (qg < QLEN) {
                float invl = 1.f / lrow[r];
                #pragma unroll
                for (int nt = 0; nt < 2; nt++) {
                    int col = wn*16 + nt*8 + 2*tig;
                    *reinterpret_cast<float2*>(attn + ((long)b*QLEN + qg)*DM + h*HD + col)
                        = make_float2(oacc[mt][nt][hh*2]*invl, oacc[mt][nt][hh*2+1]*invl);
                }
            }
        }
    }
}

// ---------------- final assembly ----------------
__global__ void assemble_kernel(float* __restrict__ out, const int* __restrict__ seqlen, int out_size) {
    int idx = blockIdx.x*blockDim.x + threadIdx.x;
    const int main_n = BSZ*QLEN*DM;
    if (idx < main_n) {
        int b = idx / (QLEN*DM);
        int rem = idx - b*(QLEN*DM);
        int r = rem / DM;
        int d = rem - r*DM;
        float f;
        if (r < OUTN) f = g_fs [((long)b*OUTN + r)*DM + d];
        else          f = g_fns[((long)b*NSN + (r - OUTN))*DM + d];
        out[idx] = f + g_h1[idx];
    }
    if (idx < BSZ && out_size >= main_n + BSZ) {
        int L = seqlen[idx];
        out[main_n + idx] = (float)(L < OUTN ? L : OUTN);
    }
}

extern "C" void kernel_launch(void* const* d_in, const int* in_sizes, int n_in,
                              void* d_out, int out_size) {
    (void)in_sizes; (void)n_in;
    const float* x    = (const float*)d_in[0];
    const int*   seq  = (const int*)  d_in[1];
    const float* wqkv = (const float*)d_in[2];
    const float* bqkv = (const float*)d_in[3];
    const float* wnsq = (const float*)d_in[4];
    const float* bnsq = (const float*)d_in[5];
    const float* wnsk = (const float*)d_in[6];
    const float* bnsk = (const float*)d_in[7];
    const float* wnsv = (const float*)d_in[8];
    const float* bnsv = (const float*)d_in[9];
    const float* n1w  = (const float*)d_in[10];
    const float* n2w  = (const float*)d_in[11];
    const float* fw1  = (const float*)d_in[12];
    const float* fb1  = (const float*)d_in[13];
    const float* fw2  = (const float*)d_in[14];
    const float* fb2  = (const float*)d_in[15];
    const float* w1ns = (const float*)d_in[16];
    const float* b1ns = (const float*)d_in[17];
    const float* w2ns = (const float*)d_in[18];
    const float* b2ns = (const float*)d_in[19];
    float* out = (float*)d_out;

    float *xn,*q,*kv,*attn,*hn,*ts,*tns,*fs,*fns,*part,*wq_t,*w1t,*w2t;
    cudaGetSymbolAddress((void**)&xn,   g_xn);
    cudaGetSymbolAddress((void**)&q,    g_q);
    cudaGetSymbolAddress((void**)&kv,   g_kv);
    cudaGetSymbolAddress((void**)&attn, g_attn);
    cudaGetSymbolAddress((void**)&hn,   g_hn);
    cudaGetSymbolAddress((void**)&ts,   g_ts);
    cudaGetSymbolAddress((void**)&tns,  g_tns);
    cudaGetSymbolAddress((void**)&fs,   g_fs);
    cudaGetSymbolAddress((void**)&fns,  g_fns);
    cudaGetSymbolAddress((void**)&part, g_part);
    cudaGetSymbolAddress((void**)&wq_t, g_wqkv);
    cudaGetSymbolAddress((void**)&w1t,  g_w1);
    cudaGetSymbolAddress((void**)&w2t,  g_w2);

    const long aB  = (long)TOTAL*DM;
    const long qB  = (long)QLEN*DM;
    const long kvB = (long)TOTAL*2*DM;

    const int SMEM128 = (3*128*36 + 3*128*36) * 4;   // 110592 B
    const int SMEM64  = (3*64*36  + 3*128*36) * 4;   //  82944 B
    cudaFuncSetAttribute(mma_gemmT_kernel<128>, cudaFuncAttributeMaxDynamicSharedMemorySize, SMEM128);
    cudaFuncSetAttribute(mma_gemmT_kernel<64>,  cudaFuncAttributeMaxDynamicSharedMemorySize, SMEM64);

    // #1 transpose+round qkv weights ; #2 rmsnorm ; #3 transpose w1 ; #4 KV GEMM (ncu target)
    transpose_tf32_kernel<<<dim3(3*DM/32, DM/32), dim3(32,8)>>>(wqkv, wq_t, DM, 3*DM);
    rmsnorm_kernel<<<BSZ*TOTAL, 256>>>(x, n1w, xn);
    transpose_tf32_kernel<<<dim3(FFND/32, DM/32), dim3(32,8)>>>(fw1, w1t, DM, FFND);
    mma_gemmT_kernel<128><<<dim3(2*DM/128, (BSZ*MAXS)/128), 256, SMEM128>>>(xn, DM, aB, MAXS,
        wq_t + (long)DM*DM, DM, bqkv + DM, kv, 2*DM, kvB, DM, 0, 0);

    // remaining prep + Q projection
    transpose_tf32_kernel<<<dim3(DM/32, FFND/32), dim3(32,8)>>>(fw2, w2t, FFND, DM);
    mma_gemmT_kernel<64><<<dim3(DM/128, (BSZ*OUTN)/64), 256, SMEM64>>>(xn + (long)(MAXS-OUTN)*DM, DM, aB, OUTN,
        wq_t, DM, bqkv, q, DM, qB, DM, 0, 0);

    // per-position NS projections (K-split, 8-way)
    ns_split_kernel<<<dim3(DM/128, NSN, 8), 128>>>(xn + (long)MAXS*DM, aB, DM, wnsq, part, DM, DM, DM/8);
    ns_reduce_kernel<<<dim3(DM/256, NSN, BSZ), 256>>>(part, bnsq, q + (long)OUTN*DM, qB, DM, DM, 8, 0);
    ns_split_kernel<<<dim3(DM/128, NSN, 8), 128>>>(xn + (long)MAXS*DM, aB, DM, wnsk, part, DM, DM, DM/8);
    ns_reduce_kernel<<<dim3(DM/256, NSN, BSZ), 256>>>(part, bnsk, kv + (long)MAXS*2*DM, kvB, 2*DM, DM, 8, 0);
    ns_split_kernel<<<dim3(DM/128, NSN, 8), 128>>>(xn + (long)MAXS*DM, aB, DM, wnsv, part, DM, DM, DM/8);
    ns_reduce_kernel<<<dim3(DM/256, NSN, BSZ), 256>>>(part, bnsv, kv + (long)MAXS*2*DM + DM, kvB, 2*DM, DM, 8, 0);

    // RoPE
    {
        int totq = BSZ*QLEN*NH*32;
        rope_kernel<<<(totq+255)/256, 256>>>(q, QLEN, TOTAL-QLEN, DM, totq);
        int totk = BSZ*TOTAL*NH*32;
        rope_kernel<<<(totk+255)/256, 256>>>(kv, TOTAL, 0, 2*DM, totk);
    }

    // attention
    attn_mma_kernel<<<dim3((QLEN+63)/64, NH, BSZ), 256>>>(q, kv, attn, seq);

    // h1 = residual + attn ; hn = rmsnorm(h1)
    add_rmsnorm_kernel<<<BSZ*QLEN, 256>>>(x, n2w);

    // shared FFN
    mma_gemmT_kernel<128><<<dim3(FFND/128, (BSZ*OUTN)/128), 256, SMEM128>>>(hn, DM, qB, OUTN,
        w1t, DM, fb1, ts, FFND, (long)OUTN*FFND, DM, 1, 1);
    mma_gemmT_kernel<64><<<dim3(DM/128, (BSZ*OUTN)/64), 256, SMEM64>>>(ts, FFND, (long)OUTN*FFND, OUTN,
        w2t, FFND, fb2, fs, DM, (long)OUTN*DM, FFND, 0, 0);

    // NS FFN: w1 direct (N=4096), w2 via K-split
    ns_linear_kernel<<<dim3(FFND/128, NSN), 128>>>(hn + (long)OUTN*DM, qB, DM,
        w1ns, b1ns, tns, (long)NSN*FFND, FFND, DM, FFND, 1);
    ns_split_kernel<<<dim3(DM/128, NSN, 8), 128>>>(tns, (long)NSN*FFND, FFND, w2ns, part, FFND, DM, FFND/8);
    ns_reduce_kernel<<<dim3(DM/256, NSN, BSZ), 256>>>(part, b2ns, fns, (long)NSN*DM, DM, DM, 8, 0);

    // assemble output
    assemble_kernel<<<(BSZ*QLEN*DM + 255)/256, 256>>>(out, seq, out_size);
}

// round 8
// speedup vs baseline: 4.7869x; 2.0941x over previous
#include <cuda_runtime.h>
#include <cstdint>

#define BSZ   4
#define TOTAL 2064
#define DM    1024
#define NSN   16
#define OUTN  256
#define QLEN  272
#define NH    16
#define HD    64
#define FFND  4096
#define MAXS  2048

// Scratch (static device globals; no allocation allowed)
__device__ float g_xn  [BSZ*TOTAL*DM];
__device__ float g_q   [BSZ*QLEN*DM];
__device__ float g_kv  [BSZ*TOTAL*2*DM];   // k = cols 0..1023, v = cols 1024..2047
__device__ float g_attn[BSZ*QLEN*DM];
__device__ float g_h1  [BSZ*QLEN*DM];
__device__ float g_hn  [BSZ*QLEN*DM];
__device__ float g_ts  [BSZ*OUTN*FFND];
__device__ float g_tns [BSZ*NSN*FFND];
__device__ float g_fs  [BSZ*OUTN*DM];
__device__ float g_fns [BSZ*NSN*DM];
__device__ float g_part[2*1024*1024];      // k-split partials (max KS*BSZ*NSN*N = 1M floats)
// TF32-rounded, TRANSPOSED weights ([N, K] row-major)
__device__ float g_wqkv[3*DM*DM];          // rows: 0..1023 Q, 1024..2047 K, 2048..3071 V
__device__ float g_w1  [FFND*DM];
__device__ float g_w2  [DM*FFND];

__device__ __forceinline__ float rtf32(float x) {
    uint32_t u;
    asm("cvt.rna.tf32.f32 %0, %1;" : "=r"(u) : "f"(x));
    return __uint_as_float(u);
}
__device__ __forceinline__ uint32_t f2u(float x) { return __float_as_uint(x); }

__device__ __forceinline__ void cpa16(uint32_t dst, const void* src) {
    asm volatile("cp.async.ca.shared.global [%0], [%1], 16;" :: "r"(dst), "l"(src));
}

__device__ __forceinline__ void mma_tf32(float* c,
        uint32_t a0, uint32_t a1, uint32_t a2, uint32_t a3,
        uint32_t b0, uint32_t b1) {
    asm volatile(
        "mma.sync.aligned.m16n8k8.row.col.f32.tf32.tf32.f32 "
        "{%0,%1,%2,%3}, {%4,%5,%6,%7}, {%8,%9}, {%0,%1,%2,%3};\n"
        : "+f"(c[0]), "+f"(c[1]), "+f"(c[2]), "+f"(c[3])
        : "r"(a0), "r"(a1), "r"(a2), "r"(a3), "r"(b0), "r"(b1));
}

__device__ __forceinline__ void ldsm4(uint32_t* r, uint32_t addr) {
    asm volatile("ldmatrix.sync.aligned.m8n8.x4.shared.b16 {%0,%1,%2,%3}, [%4];"
        : "=r"(r[0]), "=r"(r[1]), "=r"(r[2]), "=r"(r[3]) : "r"(addr));
}

// ---------------- transpose + tf32 round: out[c*R + r] = rtf32(in[r*C + c]) ----------------
__global__ __launch_bounds__(256) void transpose_tf32_kernel(const float* __restrict__ in,
        float* __restrict__ out, int R, int C) {
    __shared__ float tile[32][33];
    int c0 = blockIdx.x*32, r0 = blockIdx.y*32;
    int tx = threadIdx.x, ty = threadIdx.y;   // 32 x 8
    for (int i = ty; i < 32; i += 8)
        tile[i][tx] = in[(long)(r0+i)*C + c0 + tx];
    __syncthreads();
    for (int i = ty; i < 32; i += 8)
        out[(long)(c0+i)*R + r0 + tx] = rtf32(tile[tx][i]);
}

// ---------------- rmsnorm (output tf32-rounded) ----------------
__global__ __launch_bounds__(256) void rmsnorm_kernel(const float* __restrict__ in,
        const float* __restrict__ w, float* __restrict__ out) {
    long row = blockIdx.x;
    int t = threadIdx.x;
    float4 v = reinterpret_cast<const float4*>(in + row*DM)[t];
    float ss = v.x*v.x + v.y*v.y + v.z*v.z + v.w*v.w;
    __shared__ float red[8];
    for (int o = 16; o; o >>= 1) ss += __shfl_xor_sync(0xffffffffu, ss, o);
    if ((t & 31) == 0) red[t >> 5] = ss;
    __syncthreads();
    if (t < 32) {
        float s = (t < 8) ? red[t] : 0.f;
        for (int o = 4; o; o >>= 1) s += __shfl_xor_sync(0xffffffffu, s, o);
        if (t == 0) red[0] = s;
    }
    __syncthreads();
    float rs = rsqrtf(red[0] * (1.f/DM) + 1e-6f);
    float4 wv = reinterpret_cast<const float4*>(w)[t];
    float4 o4 = make_float4(rtf32(v.x*rs*wv.x), rtf32(v.y*rs*wv.y),
                            rtf32(v.z*rs*wv.z), rtf32(v.w*rs*wv.w));
    reinterpret_cast<float4*>(out + row*DM)[t] = o4;
}

// ---------------- h1 = x[:, -272:] + attn ; hn = rmsnorm(h1) ----------------
__global__ __launch_bounds__(256) void add_rmsnorm_kernel(const float* __restrict__ x,
        const float* __restrict__ w) {
    int row = blockIdx.x;
    int b = row / QLEN, r = row - b*QLEN;
    int t = threadIdx.x;
    float4 xv = reinterpret_cast<const float4*>(x + ((long)b*TOTAL + (TOTAL-QLEN) + r)*DM)[t];
    float4 av = reinterpret_cast<const float4*>(g_attn + (long)row*DM)[t];
    float4 hv = make_float4(xv.x+av.x, xv.y+av.y, xv.z+av.z, xv.w+av.w);
    reinterpret_cast<float4*>(g_h1 + (long)row*DM)[t] = hv;
    float ss = hv.x*hv.x + hv.y*hv.y + hv.z*hv.z + hv.w*hv.w;
    __shared__ float red[8];
    for (int o = 16; o; o >>= 1) ss += __shfl_xor_sync(0xffffffffu, ss, o);
    if ((t & 31) == 0) red[t >> 5] = ss;
    __syncthreads();
    if (t < 32) {
        float s = (t < 8) ? red[t] : 0.f;
        for (int o = 4; o; o >>= 1) s += __shfl_xor_sync(0xffffffffu, s, o);
        if (t == 0) red[0] = s;
    }
    __syncthreads();
    float rs = rsqrtf(red[0] * (1.f/DM) + 1e-6f);
    float4 wv = reinterpret_cast<const float4*>(w)[t];
    float4 o4 = make_float4(rtf32(hv.x*rs*wv.x), rtf32(hv.y*rs*wv.y),
                            rtf32(hv.z*rs*wv.z), rtf32(hv.w*rs*wv.w));
    reinterpret_cast<float4*>(g_hn + (long)row*DM)[t] = o4;
}

// ---------------- TF32 tensor-core GEMM, MTILEx128x32, 3-stage cp.async, LDSM frags ----------
// A [M,K] row-major; Bt [N,K] row-major (transposed weights). C = A * Bt^T + bias.
template<int MTILE>
__global__ __launch_bounds__(256, 2) void mma_gemmT_kernel(
    const float* __restrict__ A, int lda, long aBatch, int rpb,
    const float* __restrict__ Bt, int ldbt,
    const float* __restrict__ bias,
    float* __restrict__ C, int ldc, long cBatch,
    int K, int relu, int roundOut)
{
    constexpr int S    = 3;
    constexpr int PAD  = 36;                 // 9 x 16B units: conflict-free LDSM rows
    constexpr int ASTG = MTILE*PAD;
    constexpr int BSTG = 128*PAD;
    constexpr int MT   = MTILE/32;
    extern __shared__ float sm[];
    float* AsBase = sm;
    float* BsBase = sm + S*ASTG;

    int t = threadIdx.x;
    int w = t >> 5, lane = t & 31;
    int g = lane >> 2, tig = lane & 3;
    int wm = w >> 2, wn = w & 3;

    int row0 = blockIdx.y * MTILE;
    int bn0  = blockIdx.x * 128;
    int batch = row0 / rpb;
    int rin   = row0 % rpb;
    const float* Ab = A + (long)batch*aBatch + (long)rin*lda;
    const float* Bb = Bt + (long)bn0*ldbt;
    float* Cb = C + (long)batch*cBatch + (long)rin*ldc + bn0;

    uint32_t aSm0 = (uint32_t)__cvta_generic_to_shared(AsBase);
    uint32_t bSm0 = (uint32_t)__cvta_generic_to_shared(BsBase);

    float acc[MT][4][4];
    #pragma unroll
    for (int i = 0; i < MT; i++)
        #pragma unroll
        for (int j = 0; j < 4; j++)
            #pragma unroll
            for (int r = 0; r < 4; r++) acc[i][j][r] = 0.f;

    const int KT = K >> 5;
    auto issue = [&](int kt) {
        int s = kt % S;
        const float* ga = Ab + kt*32;
        const float* gb = Bb + kt*32;
        uint32_t aS = aSm0 + s*ASTG*4;
        uint32_t bS = bSm0 + s*BSTG*4;
        #pragma unroll
        for (int it = 0; it < MTILE/32; it++) {
            int i = t + it*256;
            int row = i >> 3, seg = i & 7;
            cpa16(aS + (row*PAD + seg*4)*4, ga + (long)row*lda + seg*4);
        }
        #pragma unroll
        for (int it = 0; it < 4; it++) {
            int i = t + it*256;
            int row = i >> 3, seg = i & 7;
            cpa16(bS + (row*PAD + seg*4)*4, gb + (long)row*ldbt + seg*4);
        }
        asm volatile("cp.async.commit_group;");
    };
    issue(0);
    issue(1);

    int aRowL = (lane & 7) + ((lane >> 3) & 1) * 8;
    int aColL = (lane >> 4) * 4;
    int bRowL = ((lane >> 4) & 1) * 8 + (lane & 7);
    int bColL = ((lane >> 3) & 1) * 4;

    for (int kt = 0; kt < KT; kt++) {
        if (kt == KT - 1) asm volatile("cp.async.wait_group 0;");
        else              asm volatile("cp.async.wait_group 1;");
        __syncthreads();
        if (kt + 2 < KT) issue(kt + 2);

        int s = kt % S;
        uint32_t As = aSm0 + s*ASTG*4;
        uint32_t Bs = bSm0 + s*BSTG*4;
        #pragma unroll
        for (int ks = 0; ks < 4; ks++) {
            uint32_t afr[MT][4];
            #pragma unroll
            for (int mt = 0; mt < MT; mt++)
                ldsm4(afr[mt], As + ((wm*(MTILE/2) + mt*16 + aRowL)*PAD + ks*8 + aColL)*4);
            uint32_t bfr[4][2];
            #pragma unroll
            for (int p = 0; p < 2; p++) {
                uint32_t r4[4];
                ldsm4(r4, Bs + ((wn*32 + p*16 + bRowL)*PAD + ks*8 + bColL)*4);
                bfr[2*p][0]   = r4[0]; bfr[2*p][1]   = r4[1];
                bfr[2*p+1][0] = r4[2]; bfr[2*p+1][1] = r4[3];
            }
            #pragma unroll
            for (int mt = 0; mt < MT; mt++)
                #pragma unroll
                for (int nt = 0; nt < 4; nt++)
                    mma_tf32(acc[mt][nt], afr[mt][0], afr[mt][1], afr[mt][2], afr[mt][3],
                             bfr[nt][0], bfr[nt][1]);
        }
    }

    #pragma unroll
    for (int nt = 0; nt < 4; nt++) {
        int col = wn*32 + nt*8 + 2*tig;
        float bx = bias[bn0 + col], by = bias[bn0 + col + 1];
        #pragma unroll
        for (int mt = 0; mt < MT; mt++) {
            int r0 = wm*(MTILE/2) + mt*16 + g;
            float c0 = acc[mt][nt][0] + bx, c1 = acc[mt][nt][1] + by;
            float c2 = acc[mt][nt][2] + bx, c3 = acc[mt][nt][3] + by;
            if (relu) { c0=fmaxf(c0,0.f); c1=fmaxf(c1,0.f); c2=fmaxf(c2,0.f); c3=fmaxf(c3,0.f); }
            if (roundOut) { c0=rtf32(c0); c1=rtf32(c1); c2=rtf32(c2); c3=rtf32(c3); }
            *reinterpret_cast<float2*>(Cb + (long)r0*ldc + col)     = make_float2(c0, c1);
            *reinterpret_cast<float2*>(Cb + (long)(r0+8)*ldc + col) = make_float2(c2, c3);
        }
    }
}

// ---------------- per-NS-position linear: vectorized K-split partials ----------------
// grid (N/512, NSN, KS); each thread: 4 consecutive outputs (float4 W loads), 4 batches.
__global__ __launch_bounds__(128) void ns_split4_kernel(
    const float* __restrict__ X, long xBatch, int xRow,
    const float* __restrict__ W, float* __restrict__ part,
    int K, int N, int kchunk)
{
    __shared__ float Xs[4][512];
    int n = blockIdx.y, z = blockIdx.z;
    int t = threadIdx.x;
    int o4 = (blockIdx.x*128 + t)*4;
    int k0 = z*kchunk;
    for (int i = t; i < kchunk; i += 128) {
        long xo = (long)n*xRow + k0 + i;
        Xs[0][i] = X[0*xBatch + xo];
        Xs[1][i] = X[1*xBatch + xo];
        Xs[2][i] = X[2*xBatch + xo];
        Xs[3][i] = X[3*xBatch + xo];
    }
    __syncthreads();
    const float* Wp = W + (long)n*K*N + (long)k0*N + o4;
    float acc[4][4];
    #pragma unroll
    for (int b = 0; b < 4; b++)
        #pragma unroll
        for (int j = 0; j < 4; j++) acc[b][j] = 0.f;
    #pragma unroll 8
    for (int k = 0; k < kchunk; k++) {
        float4 wv = *reinterpret_cast<const float4*>(Wp + (long)k*N);
        #pragma unroll
        for (int b = 0; b < 4; b++) {
            float xv = Xs[b][k];
            acc[b][0] += xv*wv.x; acc[b][1] += xv*wv.y;
            acc[b][2] += xv*wv.z; acc[b][3] += xv*wv.w;
        }
    }
    #pragma unroll
    for (int b = 0; b < 4; b++)
        *reinterpret_cast<float4*>(&part[((long)(z*BSZ+b)*NSN + n)*N + o4]) =
            make_float4(acc[b][0], acc[b][1], acc[b][2], acc[b][3]);
}

// grid (N/256, NSN, BSZ)
__global__ __launch_bounds__(256) void ns_reduce_kernel(
    const float* __restrict__ part, const float* __restrict__ bias,
    float* __restrict__ Y, long yBatch, int yRow, int N, int KS, int relu)
{
    int o = blockIdx.x*256 + threadIdx.x;
    int n = blockIdx.y, b = blockIdx.z;
    float s = bias[(long)n*N + o];
    for (int z = 0; z < KS; z++)
        s += part[((long)(z*BSZ+b)*NSN + n)*N + o];
    if (relu) s = fmaxf(s, 0.f);
    Y[(long)b*yBatch + (long)n*yRow + o] = s;
}

// ---------------- RoPE in-place (fp32 path; double only for product + range reduction) ------
__global__ void rope_kernel(float* __restrict__ buf, int rowsPerB, int pos0, int rstride, int total) {
    int idx = blockIdx.x*blockDim.x + threadIdx.x;
    if (idx >= total) return;
    int j  = idx & 31;
    int h  = (idx >> 5) & (NH-1);
    int rr = idx >> 9;
    int b  = rr / rowsPerB;
    int r  = rr - b*rowsPerB;
    // inv = 10000^(-j/32) in fp32 (reference computes inv/angles in float32)
    float inv = exp2f(-(float)j * 0.41524101186092029f);   // log2(10000)/32
    double ang = (double)(pos0 + r) * (double)inv;
    const double TWO_PI = 6.2831853071795864769;
    double red = ang - TWO_PI * rint(ang * (1.0/6.2831853071795864769));
    float rf = (float)red;                                  // |rf| <= pi
    float s, c;
    sincosf(rf, &s, &c);
    float* base = buf + ((long)b*rowsPerB + r)*(long)rstride + h*HD;
    float x1 = base[j], x2 = base[j+32];
    base[j]    = x1*c - x2*s;
    base[j+32] = x2*c + x1*s;
}

// ---------------- tensor-core flash attention (tf32) ----------------
__global__ __launch_bounds__(256) void attn_mma_kernel(
    const float* __restrict__ q, const float* __restrict__ kv,
    float* __restrict__ attn, const int* __restrict__ seqlen)
{
    __shared__ float qs [64][68];
    __shared__ float ksm[32][68];
    __shared__ float vsm[32][72];
    __shared__ float ssm[64][36];
    __shared__ float corrs[64];
    __shared__ float lrow[64];

    int qt = blockIdx.x, h = blockIdx.y, b = blockIdx.z;
    int tid = threadIdx.x;
    int w = tid >> 5, lane = tid & 31;
    int g = lane >> 2, tig = lane & 3;
    int wm = w >> 2, wn = w & 3;
    int L = seqlen[b];
    int kmin = MAXS - L;

    for (int i = tid; i < 64*16; i += 256) {
        int r = i >> 4, c4 = (i & 15) * 4;
        int qg = qt*64 + r;
        float4 val = make_float4(0.f,0.f,0.f,0.f);
        if (qg < QLEN)
            val = *reinterpret_cast<const float4*>(q + ((long)b*QLEN + qg)*DM + h*HD + c4);
        qs[r][c4]   = rtf32(val.x);
        qs[r][c4+1] = rtf32(val.y);
        qs[r][c4+2] = rtf32(val.z);
        qs[r][c4+3] = rtf32(val.w);
    }

    int srow = tid >> 2, ssub = tid & 3;
    float m = -1e30f, l = 0.f;

    float oacc[2][2][4];
    #pragma unroll
    for (int i = 0; i < 2; i++)
        #pragma unroll
        for (int j = 0; j < 2; j++)
            #pragma unroll
            for (int r = 0; r < 4; r++) oacc[i][j][r] = 0.f;

    int qgmax = min(QLEN-1, qt*64 + 63);
    int t0 = kmin >> 5;
    int t1 = (MAXS - OUTN + qgmax) >> 5;

    for (int kt = t0; kt <= t1; kt++) {
        int key0 = kt * 32;
        __syncthreads();
        for (int i = tid; i < 32*16; i += 256) {
            int r = i >> 4, c4 = (i & 15) * 4;
            int key = key0 + r;
            float4 kk = make_float4(0.f,0.f,0.f,0.f), vv = kk;
            if (key < TOTAL) {
                const float* base = kv + ((long)b*TOTAL + key)*(2*DM) + h*HD;
                kk = *reinterpret_cast<const float4*>(base + c4);
                vv = *reinterpret_cast<const float4*>(base + DM + c4);
            }
            ksm[r][c4]=rtf32(kk.x); ksm[r][c4+1]=rtf32(kk.y);
            ksm[r][c4+2]=rtf32(kk.z); ksm[r][c4+3]=rtf32(kk.w);
            vsm[r][c4]=rtf32(vv.x); vsm[r][c4+1]=rtf32(vv.y);
            vsm[r][c4+2]=rtf32(vv.z); vsm[r][c4+3]=rtf32(vv.w);
        }
        __syncthreads();

        float sa[2][4];
        #pragma unroll
        for (int mt = 0; mt < 2; mt++)
            #pragma unroll
            for (int r = 0; r < 4; r++) sa[mt][r] = 0.f;
        #pragma unroll
        for (int dk = 0; dk < 8; dk++) {
            uint32_t bf0 = f2u(ksm[wn*8 + g][dk*8 + tig]);
            uint32_t bf1 = f2u(ksm[wn*8 + g][dk*8 + tig + 4]);
            #pragma unroll
            for (int mt = 0; mt < 2; mt++) {
                int m0 = wm*32 + mt*16;
                mma_tf32(sa[mt],
                    f2u(qs[m0+g][dk*8+tig]),   f2u(qs[m0+g+8][dk*8+tig]),
                    f2u(qs[m0+g][dk*8+tig+4]), f2u(qs[m0+g+8][dk*8+tig+4]),
                    bf0, bf1);
            }
        }
        #pragma unroll
        for (int mt = 0; mt < 2; mt++) {
            #pragma unroll
            for (int hh = 0; hh < 2; hh++) {
                int r = wm*32 + mt*16 + g + hh*8;
                int qg = qt*64 + r;
                int key = key0 + wn*8 + 2*tig;
                int kcap = MAXS - OUTN + qg;
                bool rowok = (qg < QLEN);
                float sA = sa[mt][hh*2+0], sB = sa[mt][hh*2+1];
                bool v0 = rowok && (key   < TOTAL) && (key   >= kmin) && (key   <= kcap);
                bool v1 = rowok && (key+1 < TOTAL) && (key+1 >= kmin) && (key+1 <= kcap);
                ssm[r][wn*8 + 2*tig]     = v0 ? sA*0.125f : -1e9f;
                ssm[r][wn*8 + 2*tig + 1] = v1 ? sB*0.125f : -1e9f;
            }
        }
        __syncthreads();

        float sv[8];
        #pragma unroll
        for (int j = 0; j < 8; j++) sv[j] = ssm[srow][ssub*8 + j];
        float tmax = sv[0];
        #pragma unroll
        for (int j = 1; j < 8; j++) tmax = fmaxf(tmax, sv[j]);
        tmax = fmaxf(tmax, __shfl_xor_sync(0xffffffffu, tmax, 1));
        tmax = fmaxf(tmax, __shfl_xor_sync(0xffffffffu, tmax, 2));
        float corr = 1.f;
        if (tmax > -1e8f) {
            float m_new = fmaxf(m, tmax);
            corr = __expf(m - m_new);
            float ps = 0.f;
            #pragma unroll
            for (int j = 0; j < 8; j++) {
                float p = __expf(sv[j] - m_new);
                ps += p;
                ssm[srow][ssub*8 + j] = rtf32(p);
            }
            ps += __shfl_xor_sync(0xffffffffu, ps, 1);
            ps += __shfl_xor_sync(0xffffffffu, ps, 2);
            l = l*corr + ps;
            m = m_new;
        } else {
            #pragma unroll
            for (int j = 0; j < 8; j++) ssm[srow][ssub*8 + j] = 0.f;
        }
        if (ssub == 0) corrs[srow] = corr;
        __syncthreads();

        #pragma unroll
        for (int mt = 0; mt < 2; mt++) {
            float c0 = corrs[wm*32 + mt*16 + g];
            float c1 = corrs[wm*32 + mt*16 + g + 8];
            #pragma unroll
            for (int nt = 0; nt < 2; nt++) {
                oacc[mt][nt][0] *= c0; oacc[mt][nt][1] *= c0;
                oacc[mt][nt][2] *= c1; oacc[mt][nt][3] *= c1;
            }
        }
        #pragma unroll
        for (int kd = 0; kd < 4; kd++) {
            uint32_t bf[2][2];
            #pragma unroll
            for (int nt = 0; nt < 2; nt++) {
                int n = wn*16 + nt*8 + g;
                bf[nt][0] = f2u(vsm[kd*8 + tig][n]);
                bf[nt][1] = f2u(vsm[kd*8 + tig + 4][n]);
            }
            #pragma unroll
            for (int mt = 0; mt < 2; mt++) {
                int m0 = wm*32 + mt*16;
                uint32_t a0 = f2u(ssm[m0+g][kd*8+tig]);
                uint32_t a1 = f2u(ssm[m0+g+8][kd*8+tig]);
                uint32_t a2 = f2u(ssm[m0+g][kd*8+tig+4]);
                uint32_t a3 = f2u(ssm[m0+g+8][kd*8+tig+4]);
                #pragma unroll
                for (int nt = 0; nt < 2; nt++)
                    mma_tf32(oacc[mt][nt], a0, a1, a2, a3, bf[nt][0], bf[nt][1]);
            }
        }
    }

    if (ssub == 0) lrow[srow] = l;
    __syncthreads();
    #pragma unroll
    for (int mt = 0; mt < 2; mt++) {
        #pragma unroll
        for (int hh = 0; hh < 2; hh++) {
            int r = wm*32 + mt*16 + g + hh*8;
            int qg = qt*64 + r;
            if (qg < QLEN) {
                float invl = 1.f / lrow[r];
                #pragma unroll
                for (int nt = 0; nt < 2; nt++) {
                    int col = wn*16 + nt*8 + 2*tig;
                    *reinterpret_cast<float2*>(attn + ((long)b*QLEN + qg)*DM + h*HD + col)
                        = make_float2(oacc[mt][nt][hh*2]*invl, oacc[mt][nt][hh*2+1]*invl);
                }
            }
        }
    }
}

// ---------------- final assembly ----------------
__global__ void assemble_kernel(float* __restrict__ out, const int* __restrict__ seqlen, int out_size) {
    int idx = blockIdx.x*blockDim.x + threadIdx.x;
    const int main_n = BSZ*QLEN*DM;
    if (idx < main_n) {
        int b = idx / (QLEN*DM);
        int rem = idx - b*(QLEN*DM);
        int r = rem / DM;
        int d = rem - r*DM;
        float f;
        if (r < OUTN) f = g_fs [((long)b*OUTN + r)*DM + d];
        else          f = g_fns[((long)b*NSN + (r - OUTN))*DM + d];
        out[idx] = f + g_h1[idx];
    }
    if (idx < BSZ && out_size >= main_n + BSZ) {
        int L = seqlen[idx];
        out[main_n + idx] = (float)(L < OUTN ? L : OUTN);
    }
}

extern "C" void kernel_launch(void* const* d_in, const int* in_sizes, int n_in,
                              void* d_out, int out_size) {
    (void)in_sizes; (void)n_in;
    const float* x    = (const float*)d_in[0];
    const int*   seq  = (const int*)  d_in[1];
    const float* wqkv = (const float*)d_in[2];
    const float* bqkv = (const float*)d_in[3];
    const float* wnsq = (const float*)d_in[4];
    const float* bnsq = (const float*)d_in[5];
    const float* wnsk = (const float*)d_in[6];
    const float* bnsk = (const float*)d_in[7];
    const float* wnsv = (const float*)d_in[8];
    const float* bnsv = (const float*)d_in[9];
    const float* n1w  = (const float*)d_in[10];
    const float* n2w  = (const float*)d_in[11];
    const float* fw1  = (const float*)d_in[12];
    const float* fb1  = (const float*)d_in[13];
    const float* fw2  = (const float*)d_in[14];
    const float* fb2  = (const float*)d_in[15];
    const float* w1ns = (const float*)d_in[16];
    const float* b1ns = (const float*)d_in[17];
    const float* w2ns = (const float*)d_in[18];
    const float* b2ns = (const float*)d_in[19];
    float* out = (float*)d_out;

    float *xn,*q,*kv,*attn,*hn,*ts,*tns,*fs,*fns,*part,*wq_t,*w1t,*w2t;
    cudaGetSymbolAddress((void**)&xn,   g_xn);
    cudaGetSymbolAddress((void**)&q,    g_q);
    cudaGetSymbolAddress((void**)&kv,   g_kv);
    cudaGetSymbolAddress((void**)&attn, g_attn);
    cudaGetSymbolAddress((void**)&hn,   g_hn);
    cudaGetSymbolAddress((void**)&ts,   g_ts);
    cudaGetSymbolAddress((void**)&tns,  g_tns);
    cudaGetSymbolAddress((void**)&fs,   g_fs);
    cudaGetSymbolAddress((void**)&fns,  g_fns);
    cudaGetSymbolAddress((void**)&part, g_part);
    cudaGetSymbolAddress((void**)&wq_t, g_wqkv);
    cudaGetSymbolAddress((void**)&w1t,  g_w1);
    cudaGetSymbolAddress((void**)&w2t,  g_w2);

    const long aB  = (long)TOTAL*DM;
    const long qB  = (long)QLEN*DM;
    const long kvB = (long)TOTAL*2*DM;

    const int SMEM128 = (3*128*36 + 3*128*36) * 4;   // 110592 B
    const int SMEM64  = (3*64*36  + 3*128*36) * 4;   //  82944 B
    cudaFuncSetAttribute(mma_gemmT_kernel<128>, cudaFuncAttributeMaxDynamicSharedMemorySize, SMEM128);
    cudaFuncSetAttribute(mma_gemmT_kernel<64>,  cudaFuncAttributeMaxDynamicSharedMemorySize, SMEM64);

    // #1 transpose wqkv ; #2 rmsnorm ; #3 transpose w1 ; #4 ns_split4 v (ncu target)
    transpose_tf32_kernel<<<dim3(3*DM/32, DM/32), dim3(32,8)>>>(wqkv, wq_t, DM, 3*DM);
    rmsnorm_kernel<<<BSZ*TOTAL, 256>>>(x, n1w, xn);
    transpose_tf32_kernel<<<dim3(FFND/32, DM/32), dim3(32,8)>>>(fw1, w1t, DM, FFND);
    ns_split4_kernel<<<dim3(DM/512, NSN, 16), 128>>>(xn + (long)MAXS*DM, aB, DM, wnsv, part, DM, DM, DM/16);
    ns_reduce_kernel<<<dim3(DM/256, NSN, BSZ), 256>>>(part, bnsv, kv + (long)MAXS*2*DM + DM, kvB, 2*DM, DM, 16, 0);

    // shared projections
    mma_gemmT_kernel<128><<<dim3(2*DM/128, (BSZ*MAXS)/128), 256, SMEM128>>>(xn, DM, aB, MAXS,
        wq_t + (long)DM*DM, DM, bqkv + DM, kv, 2*DM, kvB, DM, 0, 0);
    mma_gemmT_kernel<64><<<dim3(DM/128, (BSZ*OUTN)/64), 256, SMEM64>>>(xn + (long)(MAXS-OUTN)*DM, DM, aB, OUTN,
        wq_t, DM, bqkv, q, DM, qB, DM, 0, 0);

    // remaining NS projections (q, k)
    ns_split4_kernel<<<dim3(DM/512, NSN, 16), 128>>>(xn + (long)MAXS*DM, aB, DM, wnsq, part, DM, DM, DM/16);
    ns_reduce_kernel<<<dim3(DM/256, NSN, BSZ), 256>>>(part, bnsq, q + (long)OUTN*DM, qB, DM, DM, 16, 0);
    ns_split4_kernel<<<dim3(DM/512, NSN, 16), 128>>>(xn + (long)MAXS*DM, aB, DM, wnsk, part, DM, DM, DM/16);
    ns_reduce_kernel<<<dim3(DM/256, NSN, BSZ), 256>>>(part, bnsk, kv + (long)MAXS*2*DM, kvB, 2*DM, DM, 16, 0);

    // transpose w2 (independent prep)
    transpose_tf32_kernel<<<dim3(DM/32, FFND/32), dim3(32,8)>>>(fw2, w2t, FFND, DM);

    // RoPE (fp32 path)
    {
        int totq = BSZ*QLEN*NH*32;
        rope_kernel<<<(totq+255)/256, 256>>>(q, QLEN, TOTAL-QLEN, DM, totq);
        int totk = BSZ*TOTAL*NH*32;
        rope_kernel<<<(totk+255)/256, 256>>>(kv, TOTAL, 0, 2*DM, totk);
    }

    // attention
    attn_mma_kernel<<<dim3((QLEN+63)/64, NH, BSZ), 256>>>(q, kv, attn, seq);

    // h1 = residual + attn ; hn = rmsnorm(h1)
    add_rmsnorm_kernel<<<BSZ*QLEN, 256>>>(x, n2w);

    // shared FFN
    mma_gemmT_kernel<128><<<dim3(FFND/128, (BSZ*OUTN)/128), 256, SMEM128>>>(hn, DM, qB, OUTN,
        w1t, DM, fb1, ts, FFND, (long)OUTN*FFND, DM, 1, 1);
    mma_gemmT_kernel<64><<<dim3(DM/128, (BSZ*OUTN)/64), 256, SMEM64>>>(ts, FFND, (long)OUTN*FFND, OUTN,
        w2t, FFND, fb2, fs, DM, (long)OUTN*DM, FFND, 0, 0);

    // NS FFN: w1 (N=4096, KS=4) and w2 (K=4096, KS=16)
    ns_split4_kernel<<<dim3(FFND/512, NSN, 4), 128>>>(hn + (long)OUTN*DM, qB, DM, w1ns, part, DM, FFND, DM/4);
    ns_reduce_kernel<<<dim3(FFND/256, NSN, BSZ), 256>>>(part, b1ns, tns, (long)NSN*FFND, FFND, FFND, 4, 1);
    ns_split4_kernel<<<dim3(DM/512, NSN, 16), 128>>>(tns, (long)NSN*FFND, FFND, w2ns, part, FFND, DM, FFND/16);
    ns_reduce_kernel<<<dim3(DM/256, NSN, BSZ), 256>>>(part, b2ns, fns, (long)NSN*DM, DM, DM, 16, 0);

    // assemble output
    assemble_kernel<<<(BSZ*QLEN*DM + 255)/256, 256>>>(out, seq, out_size);
}

// round 9
// speedup vs baseline: 5.5012x; 1.1492x over previous
#include <cuda_runtime.h>
#include <cstdint>

#define BSZ   4
#define TOTAL 2064
#define DM    1024
#define NSN   16
#define OUTN  256
#define QLEN  272
#define NH    16
#define HD    64
#define FFND  4096
#define MAXS  2048

// Scratch (static device globals; no allocation allowed)
__device__ float g_xn  [BSZ*TOTAL*DM];
__device__ float g_q   [BSZ*QLEN*DM];
__device__ float g_kv  [BSZ*TOTAL*2*DM];   // k = cols 0..1023, v = cols 1024..2047
__device__ float g_attn[BSZ*QLEN*DM];
__device__ float g_h1  [BSZ*QLEN*DM];
__device__ float g_hn  [BSZ*QLEN*DM];
__device__ float g_ts  [BSZ*OUTN*FFND];
__device__ float g_tns [BSZ*NSN*FFND];
__device__ float g_fs  [BSZ*OUTN*DM];
__device__ float g_fns [BSZ*NSN*DM];
__device__ float g_part[4*1024*1024];      // k-split partials (max KS*BSZ*NSN*N floats)
// TF32-rounded, TRANSPOSED weights ([N, K] row-major)
__device__ float g_wqkv[3*DM*DM];          // rows: 0..1023 Q, 1024..2047 K, 2048..3071 V
__device__ float g_w1  [FFND*DM];
__device__ float g_w2  [DM*FFND];

__device__ __forceinline__ float rtf32(float x) {
    uint32_t u;
    asm("cvt.rna.tf32.f32 %0, %1;" : "=r"(u) : "f"(x));
    return __uint_as_float(u);
}
__device__ __forceinline__ uint32_t f2u(float x) { return __float_as_uint(x); }

__device__ __forceinline__ void cpa16(uint32_t dst, const void* src) {
    asm volatile("cp.async.ca.shared.global [%0], [%1], 16;" :: "r"(dst), "l"(src));
}

__device__ __forceinline__ void mma_tf32(float* c,
        uint32_t a0, uint32_t a1, uint32_t a2, uint32_t a3,
        uint32_t b0, uint32_t b1) {
    asm volatile(
        "mma.sync.aligned.m16n8k8.row.col.f32.tf32.tf32.f32 "
        "{%0,%1,%2,%3}, {%4,%5,%6,%7}, {%8,%9}, {%0,%1,%2,%3};\n"
        : "+f"(c[0]), "+f"(c[1]), "+f"(c[2]), "+f"(c[3])
        : "r"(a0), "r"(a1), "r"(a2), "r"(a3), "r"(b0), "r"(b1));
}

__device__ __forceinline__ void ldsm4(uint32_t* r, uint32_t addr) {
    asm volatile("ldmatrix.sync.aligned.m8n8.x4.shared.b16 {%0,%1,%2,%3}, [%4];"
        : "=r"(r[0]), "=r"(r[1]), "=r"(r[2]), "=r"(r[3]) : "r"(addr));
}

// ---------------- transpose + tf32 round: out[c*R + r] = rtf32(in[r*C + c]) ----------------
__global__ __launch_bounds__(256) void transpose_tf32_kernel(const float* __restrict__ in,
        float* __restrict__ out, int R, int C) {
    __shared__ float tile[32][33];
    int c0 = blockIdx.x*32, r0 = blockIdx.y*32;
    int tx = threadIdx.x, ty = threadIdx.y;   // 32 x 8
    for (int i = ty; i < 32; i += 8)
        tile[i][tx] = in[(long)(r0+i)*C + c0 + tx];
    __syncthreads();
    for (int i = ty; i < 32; i += 8)
        out[(long)(c0+i)*R + r0 + tx] = rtf32(tile[tx][i]);
}

// ---------------- rmsnorm (output tf32-rounded) ----------------
__global__ __launch_bounds__(256) void rmsnorm_kernel(const float* __restrict__ in,
        const float* __restrict__ w, float* __restrict__ out) {
    long row = blockIdx.x;
    int t = threadIdx.x;
    float4 v = reinterpret_cast<const float4*>(in + row*DM)[t];
    float ss = v.x*v.x + v.y*v.y + v.z*v.z + v.w*v.w;
    __shared__ float red[8];
    for (int o = 16; o; o >>= 1) ss += __shfl_xor_sync(0xffffffffu, ss, o);
    if ((t & 31) == 0) red[t >> 5] = ss;
    __syncthreads();
    if (t < 32) {
        float s = (t < 8) ? red[t] : 0.f;
        for (int o = 4; o; o >>= 1) s += __shfl_xor_sync(0xffffffffu, s, o);
        if (t == 0) red[0] = s;
    }
    __syncthreads();
    float rs = rsqrtf(red[0] * (1.f/DM) + 1e-6f);
    float4 wv = reinterpret_cast<const float4*>(w)[t];
    float4 o4 = make_float4(rtf32(v.x*rs*wv.x), rtf32(v.y*rs*wv.y),
                            rtf32(v.z*rs*wv.z), rtf32(v.w*rs*wv.w));
    reinterpret_cast<float4*>(out + row*DM)[t] = o4;
}

// ---------------- h1 = x[:, -272:] + attn ; hn = rmsnorm(h1) ----------------
__global__ __launch_bounds__(256) void add_rmsnorm_kernel(const float* __restrict__ x,
        const float* __restrict__ w) {
    int row = blockIdx.x;
    int b = row / QLEN, r = row - b*QLEN;
    int t = threadIdx.x;
    float4 xv = reinterpret_cast<const float4*>(x + ((long)b*TOTAL + (TOTAL-QLEN) + r)*DM)[t];
    float4 av = reinterpret_cast<const float4*>(g_attn + (long)row*DM)[t];
    float4 hv = make_float4(xv.x+av.x, xv.y+av.y, xv.z+av.z, xv.w+av.w);
    reinterpret_cast<float4*>(g_h1 + (long)row*DM)[t] = hv;
    float ss = hv.x*hv.x + hv.y*hv.y + hv.z*hv.z + hv.w*hv.w;
    __shared__ float red[8];
    for (int o = 16; o; o >>= 1) ss += __shfl_xor_sync(0xffffffffu, ss, o);
    if ((t & 31) == 0) red[t >> 5] = ss;
    __syncthreads();
    if (t < 32) {
        float s = (t < 8) ? red[t] : 0.f;
        for (int o = 4; o; o >>= 1) s += __shfl_xor_sync(0xffffffffu, s, o);
        if (t == 0) red[0] = s;
    }
    __syncthreads();
    float rs = rsqrtf(red[0] * (1.f/DM) + 1e-6f);
    float4 wv = reinterpret_cast<const float4*>(w)[t];
    float4 o4 = make_float4(rtf32(hv.x*rs*wv.x), rtf32(hv.y*rs*wv.y),
                            rtf32(hv.z*rs*wv.z), rtf32(hv.w*rs*wv.w));
    reinterpret_cast<float4*>(g_hn + (long)row*DM)[t] = o4;
}

// ---------------- TF32 tensor-core GEMM, MTILEx128x32, 3-stage cp.async, LDSM frags ----------
// A [M,K] row-major; Bt [N,K] row-major (transposed weights). C = A * Bt^T + bias.
// kvSkip: skip whole tiles whose rows are all < MAXS - seqlen[batch] (dead KV rows).
template<int MTILE>
__global__ __launch_bounds__(256, 2) void mma_gemmT_kernel(
    const float* __restrict__ A, int lda, long aBatch, int rpb,
    const float* __restrict__ Bt, int ldbt,
    const float* __restrict__ bias,
    float* __restrict__ C, int ldc, long cBatch,
    int K, int relu, int roundOut,
    const int* __restrict__ seqlen, int kvSkip)
{
    constexpr int S    = 3;
    constexpr int PAD  = 36;                 // 9 x 16B units: conflict-free LDSM rows
    constexpr int ASTG = MTILE*PAD;
    constexpr int BSTG = 128*PAD;
    constexpr int MT   = MTILE/32;
    extern __shared__ float sm[];
    float* AsBase = sm;
    float* BsBase = sm + S*ASTG;

    int t = threadIdx.x;
    int w = t >> 5, lane = t & 31;
    int g = lane >> 2, tig = lane & 3;
    int wm = w >> 2, wn = w & 3;

    int row0 = blockIdx.y * MTILE;
    int bn0  = blockIdx.x * 128;
    int batch = row0 / rpb;
    int rin   = row0 % rpb;
    if (kvSkip) {
        int kmin = MAXS - seqlen[batch];
        if (rin + MTILE - 1 < kmin) return;   // whole tile is dead KV rows
    }
    const float* Ab = A + (long)batch*aBatch + (long)rin*lda;
    const float* Bb = Bt + (long)bn0*ldbt;
    float* Cb = C + (long)batch*cBatch + (long)rin*ldc + bn0;

    uint32_t aSm0 = (uint32_t)__cvta_generic_to_shared(AsBase);
    uint32_t bSm0 = (uint32_t)__cvta_generic_to_shared(BsBase);

    float acc[MT][4][4];
    #pragma unroll
    for (int i = 0; i < MT; i++)
        #pragma unroll
        for (int j = 0; j < 4; j++)
            #pragma unroll
            for (int r = 0; r < 4; r++) acc[i][j][r] = 0.f;

    const int KT = K >> 5;
    auto issue = [&](int kt) {
        int s = kt % S;
        const float* ga = Ab + kt*32;
        const float* gb = Bb + kt*32;
        uint32_t aS = aSm0 + s*ASTG*4;
        uint32_t bS = bSm0 + s*BSTG*4;
        #pragma unroll
        for (int it = 0; it < MTILE/32; it++) {
            int i = t + it*256;
            int row = i >> 3, seg = i & 7;
            cpa16(aS + (row*PAD + seg*4)*4, ga + (long)row*lda + seg*4);
        }
        #pragma unroll
        for (int it = 0; it < 4; it++) {
            int i = t + it*256;
            int row = i >> 3, seg = i & 7;
            cpa16(bS + (row*PAD + seg*4)*4, gb + (long)row*ldbt + seg*4);
        }
        asm volatile("cp.async.commit_group;");
    };
    issue(0);
    issue(1);

    int aRowL = (lane & 7) + ((lane >> 3) & 1) * 8;
    int aColL = (lane >> 4) * 4;
    int bRowL = ((lane >> 4) & 1) * 8 + (lane & 7);
    int bColL = ((lane >> 3) & 1) * 4;

    for (int kt = 0; kt < KT; kt++) {
        if (kt == KT - 1) asm volatile("cp.async.wait_group 0;");
        else              asm volatile("cp.async.wait_group 1;");
        __syncthreads();
        if (kt + 2 < KT) issue(kt + 2);

        int s = kt % S;
        uint32_t As = aSm0 + s*ASTG*4;
        uint32_t Bs = bSm0 + s*BSTG*4;
        #pragma unroll
        for (int ks = 0; ks < 4; ks++) {
            uint32_t afr[MT][4];
            #pragma unroll
            for (int mt = 0; mt < MT; mt++)
                ldsm4(afr[mt], As + ((wm*(MTILE/2) + mt*16 + aRowL)*PAD + ks*8 + aColL)*4);
            uint32_t bfr[4][2];
            #pragma unroll
            for (int p = 0; p < 2; p++) {
                uint32_t r4[4];
                ldsm4(r4, Bs + ((wn*32 + p*16 + bRowL)*PAD + ks*8 + bColL)*4);
                bfr[2*p][0]   = r4[0]; bfr[2*p][1]   = r4[1];
                bfr[2*p+1][0] = r4[2]; bfr[2*p+1][1] = r4[3];
            }
            #pragma unroll
            for (int mt = 0; mt < MT; mt++)
                #pragma unroll
                for (int nt = 0; nt < 4; nt++)
                    mma_tf32(acc[mt][nt], afr[mt][0], afr[mt][1], afr[mt][2], afr[mt][3],
                             bfr[nt][0], bfr[nt][1]);
        }
    }

    #pragma unroll
    for (int nt = 0; nt < 4; nt++) {
        int col = wn*32 + nt*8 + 2*tig;
        float bx = bias[bn0 + col], by = bias[bn0 + col + 1];
        #pragma unroll
        for (int mt = 0; mt < MT; mt++) {
            int r0 = wm*(MTILE/2) + mt*16 + g;
            float c0 = acc[mt][nt][0] + bx, c1 = acc[mt][nt][1] + by;
            float c2 = acc[mt][nt][2] + bx, c3 = acc[mt][nt][3] + by;
            if (relu) { c0=fmaxf(c0,0.f); c1=fmaxf(c1,0.f); c2=fmaxf(c2,0.f); c3=fmaxf(c3,0.f); }
            if (roundOut) { c0=rtf32(c0); c1=rtf32(c1); c2=rtf32(c2); c3=rtf32(c3); }
            *reinterpret_cast<float2*>(Cb + (long)r0*ldc + col)     = make_float2(c0, c1);
            *reinterpret_cast<float2*>(Cb + (long)(r0+8)*ldc + col) = make_float2(c2, c3);
        }
    }
}

// ---------------- per-NS-position linear: vectorized K-split partials ----------------
// grid (N/512, NSN, KS); each thread: 4 consecutive outputs (float4 W loads), 4 batches.
__global__ __launch_bounds__(128) void ns_split4_kernel(
    const float* __restrict__ X, long xBatch, int xRow,
    const float* __restrict__ W, float* __restrict__ part,
    int K, int N, int kchunk)
{
    __shared__ float Xs[4][512];
    int n = blockIdx.y, z = blockIdx.z;
    int t = threadIdx.x;
    int o4 = (blockIdx.x*128 + t)*4;
    int k0 = z*kchunk;
    for (int i = t; i < kchunk; i += 128) {
        long xo = (long)n*xRow + k0 + i;
        Xs[0][i] = X[0*xBatch + xo];
        Xs[1][i] = X[1*xBatch + xo];
        Xs[2][i] = X[2*xBatch + xo];
        Xs[3][i] = X[3*xBatch + xo];
    }
    __syncthreads();
    const float* Wp = W + (long)n*K*N + (long)k0*N + o4;
    float acc[4][4];
    #pragma unroll
    for (int b = 0; b < 4; b++)
        #pragma unroll
        for (int j = 0; j < 4; j++) acc[b][j] = 0.f;
    #pragma unroll 8
    for (int k = 0; k < kchunk; k++) {
        float4 wv = *reinterpret_cast<const float4*>(Wp + (long)k*N);
        #pragma unroll
        for (int b = 0; b < 4; b++) {
            float xv = Xs[b][k];
            acc[b][0] += xv*wv.x; acc[b][1] += xv*wv.y;
            acc[b][2] += xv*wv.z; acc[b][3] += xv*wv.w;
        }
    }
    #pragma unroll
    for (int b = 0; b < 4; b++)
        *reinterpret_cast<float4*>(&part[((long)(z*BSZ+b)*NSN + n)*N + o4]) =
            make_float4(acc[b][0], acc[b][1], acc[b][2], acc[b][3]);
}

// grid (N/256, NSN, BSZ)
__global__ __launch_bounds__(256) void ns_reduce_kernel(
    const float* __restrict__ part, const float* __restrict__ bias,
    float* __restrict__ Y, long yBatch, int yRow, int N, int KS, int relu)
{
    int o = blockIdx.x*256 + threadIdx.x;
    int n = blockIdx.y, b = blockIdx.z;
    float s = bias[(long)n*N + o];
    for (int z = 0; z < KS; z++)
        s += part[((long)(z*BSZ+b)*NSN + n)*N + o];
    if (relu) s = fmaxf(s, 0.f);
    Y[(long)b*yBatch + (long)n*yRow + o] = s;
}

// ---------------- RoPE in-place (fp32 path; double only for product + range reduction) ------
__global__ void rope_kernel(float* __restrict__ buf, int rowsPerB, int pos0, int rstride, int total) {
    int idx = blockIdx.x*blockDim.x + threadIdx.x;
    if (idx >= total) return;
    int j  = idx & 31;
    int h  = (idx >> 5) & (NH-1);
    int rr = idx >> 9;
    int b  = rr / rowsPerB;
    int r  = rr - b*rowsPerB;
    float inv = exp2f(-(float)j * 0.41524101186092029f);   // log2(10000)/32
    double ang = (double)(pos0 + r) * (double)inv;
    const double TWO_PI = 6.2831853071795864769;
    double red = ang - TWO_PI * rint(ang * (1.0/6.2831853071795864769));
    float rf = (float)red;
    float s, c;
    sincosf(rf, &s, &c);
    float* base = buf + ((long)b*rowsPerB + r)*(long)rstride + h*HD;
    float x1 = base[j], x2 = base[j+32];
    base[j]    = x1*c - x2*s;
    base[j+32] = x2*c + x1*s;
}

// ---------------- tensor-core flash attention (tf32) ----------------
__global__ __launch_bounds__(256) void attn_mma_kernel(
    const float* __restrict__ q, const float* __restrict__ kv,
    float* __restrict__ attn, const int* __restrict__ seqlen)
{
    __shared__ float qs [64][68];
    __shared__ float ksm[32][68];
    __shared__ float vsm[32][72];
    __shared__ float ssm[64][36];
    __shared__ float corrs[64];
    __shared__ float lrow[64];

    int qt = blockIdx.x, h = blockIdx.y, b = blockIdx.z;
    int tid = threadIdx.x;
    int w = tid >> 5, lane = tid & 31;
    int g = lane >> 2, tig = lane & 3;
    int wm = w >> 2, wn = w & 3;
    int L = seqlen[b];
    int kmin = MAXS - L;

    for (int i = tid; i < 64*16; i += 256) {
        int r = i >> 4, c4 = (i & 15) * 4;
        int qg = qt*64 + r;
        float4 val = make_float4(0.f,0.f,0.f,0.f);
        if (qg < QLEN)
            val = *reinterpret_cast<const float4*>(q + ((long)b*QLEN + qg)*DM + h*HD + c4);
        qs[r][c4]   = rtf32(val.x);
        qs[r][c4+1] = rtf32(val.y);
        qs[r][c4+2] = rtf32(val.z);
        qs[r][c4+3] = rtf32(val.w);
    }

    int srow = tid >> 2, ssub = tid & 3;
    float m = -1e30f, l = 0.f;

    float oacc[2][2][4];
    #pragma unroll
    for (int i = 0; i < 2; i++)
        #pragma unroll
        for (int j = 0; j < 2; j++)
            #pragma unroll
            for (int r = 0; r < 4; r++) oacc[i][j][r] = 0.f;

    int qgmax = min(QLEN-1, qt*64 + 63);
    int t0 = kmin >> 5;
    int t1 = (MAXS - OUTN + qgmax) >> 5;

    for (int kt = t0; kt <= t1; kt++) {
        int key0 = kt * 32;
        __syncthreads();
        for (int i = tid; i < 32*16; i += 256) {
            int r = i >> 4, c4 = (i & 15) * 4;
            int key = key0 + r;
            float4 kk = make_float4(0.f,0.f,0.f,0.f), vv = kk;
            if (key < TOTAL) {
                const float* base = kv + ((long)b*TOTAL + key)*(2*DM) + h*HD;
                kk = *reinterpret_cast<const float4*>(base + c4);
                vv = *reinterpret_cast<const float4*>(base + DM + c4);
            }
            ksm[r][c4]=rtf32(kk.x); ksm[r][c4+1]=rtf32(kk.y);
            ksm[r][c4+2]=rtf32(kk.z); ksm[r][c4+3]=rtf32(kk.w);
            vsm[r][c4]=rtf32(vv.x); vsm[r][c4+1]=rtf32(vv.y);
            vsm[r][c4+2]=rtf32(vv.z); vsm[r][c4+3]=rtf32(vv.w);
        }
        __syncthreads();

        float sa[2][4];
        #pragma unroll
        for (int mt = 0; mt < 2; mt++)
            #pragma unroll
            for (int r = 0; r < 4; r++) sa[mt][r] = 0.f;
        #pragma unroll
        for (int dk = 0; dk < 8; dk++) {
            uint32_t bf0 = f2u(ksm[wn*8 + g][dk*8 + tig]);
            uint32_t bf1 = f2u(ksm[wn*8 + g][dk*8 + tig + 4]);
            #pragma unroll
            for (int mt = 0; mt < 2; mt++) {
                int m0 = wm*32 + mt*16;
                mma_tf32(sa[mt],
                    f2u(qs[m0+g][dk*8+tig]),   f2u(qs[m0+g+8][dk*8+tig]),
                    f2u(qs[m0+g][dk*8+tig+4]), f2u(qs[m0+g+8][dk*8+tig+4]),
                    bf0, bf1);
            }
        }
        #pragma unroll
        for (int mt = 0; mt < 2; mt++) {
            #pragma unroll
            for (int hh = 0; hh < 2; hh++) {
                int r = wm*32 + mt*16 + g + hh*8;
                int qg = qt*64 + r;
                int key = key0 + wn*8 + 2*tig;
                int kcap = MAXS - OUTN + qg;
                bool rowok = (qg < QLEN);
                float sA = sa[mt][hh*2+0], sB = sa[mt][hh*2+1];
                bool v0 = rowok && (key   < TOTAL) && (key   >= kmin) && (key   <= kcap);
                bool v1 = rowok && (key+1 < TOTAL) && (key+1 >= kmin) && (key+1 <= kcap);
                ssm[r][wn*8 + 2*tig]     = v0 ? sA*0.125f : -1e9f;
                ssm[r][wn*8 + 2*tig + 1] = v1 ? sB*0.125f : -1e9f;
            }
        }
        __syncthreads();

        float sv[8];
        #pragma unroll
        for (int j = 0; j < 8; j++) sv[j] = ssm[srow][ssub*8 + j];
        float tmax = sv[0];
        #pragma unroll
        for (int j = 1; j < 8; j++) tmax = fmaxf(tmax, sv[j]);
        tmax = fmaxf(tmax, __shfl_xor_sync(0xffffffffu, tmax, 1));
        tmax = fmaxf(tmax, __shfl_xor_sync(0xffffffffu, tmax, 2));
        float corr = 1.f;
        if (tmax > -1e8f) {
            float m_new = fmaxf(m, tmax);
            corr = __expf(m - m_new);
            float ps = 0.f;
            #pragma unroll
            for (int j = 0; j < 8; j++) {
                float p = __expf(sv[j] - m_new);
                ps += p;
                ssm[srow][ssub*8 + j] = rtf32(p);
            }
            ps += __shfl_xor_sync(0xffffffffu, ps, 1);
            ps += __shfl_xor_sync(0xffffffffu, ps, 2);
            l = l*corr + ps;
            m = m_new;
        } else {
            #pragma unroll
            for (int j = 0; j < 8; j++) ssm[srow][ssub*8 + j] = 0.f;
        }
        if (ssub == 0) corrs[srow] = corr;
        __syncthreads();

        #pragma unroll
        for (int mt = 0; mt < 2; mt++) {
            float c0 = corrs[wm*32 + mt*16 + g];
            float c1 = corrs[wm*32 + mt*16 + g + 8];
            #pragma unroll
            for (int nt = 0; nt < 2; nt++) {
                oacc[mt][nt][0] *= c0; oacc[mt][nt][1] *= c0;
                oacc[mt][nt][2] *= c1; oacc[mt][nt][3] *= c1;
            }
        }
        #pragma unroll
        for (int kd = 0; kd < 4; kd++) {
            uint32_t bf[2][2];
            #pragma unroll
            for (int nt = 0; nt < 2; nt++) {
                int n = wn*16 + nt*8 + g;
                bf[nt][0] = f2u(vsm[kd*8 + tig][n]);
                bf[nt][1] = f2u(vsm[kd*8 + tig + 4][n]);
            }
            #pragma unroll
            for (int mt = 0; mt < 2; mt++) {
                int m0 = wm*32 + mt*16;
                uint32_t a0 = f2u(ssm[m0+g][kd*8+tig]);
                uint32_t a1 = f2u(ssm[m0+g+8][kd*8+tig]);
                uint32_t a2 = f2u(ssm[m0+g][kd*8+tig+4]);
                uint32_t a3 = f2u(ssm[m0+g+8][kd*8+tig+4]);
                #pragma unroll
                for (int nt = 0; nt < 2; nt++)
                    mma_tf32(oacc[mt][nt], a0, a1, a2, a3, bf[nt][0], bf[nt][1]);
            }
        }
    }

    if (ssub == 0) lrow[srow] = l;
    __syncthreads();
    #pragma unroll
    for (int mt = 0; mt < 2; mt++) {
        #pragma unroll
        for (int hh = 0; hh < 2; hh++) {
            int r = wm*32 + mt*16 + g + hh*8;
            int qg = qt*64 + r;
            if (qg < QLEN) {
                float invl = 1.f / lrow[r];
                #pragma unroll
                for (int nt = 0; nt < 2; nt++) {
                    int col = wn*16 + nt*8 + 2*tig;
                    *reinterpret_cast<float2*>(attn + ((long)b*QLEN + qg)*DM + h*HD + col)
                        = make_float2(oacc[mt][nt][hh*2]*invl, oacc[mt][nt][hh*2+1]*invl);
                }
            }
        }
    }
}

// ---------------- final assembly ----------------
__global__ void assemble_kernel(float* __restrict__ out, const int* __restrict__ seqlen, int out_size) {
    int idx = blockIdx.x*blockDim.x + threadIdx.x;
    const int main_n = BSZ*QLEN*DM;
    if (idx < main_n) {
        int b = idx / (QLEN*DM);
        int rem = idx - b*(QLEN*DM);
        int r = rem / DM;
        int d = rem - r*DM;
        float f;
        if (r < OUTN) f = g_fs [((long)b*OUTN + r)*DM + d];
        else          f = g_fns[((long)b*NSN + (r - OUTN))*DM + d];
        out[idx] = f + g_h1[idx];
    }
    if (idx < BSZ && out_size >= main_n + BSZ) {
        int L = seqlen[idx];
        out[main_n + idx] = (float)(L < OUTN ? L : OUTN);
    }
}

extern "C" void kernel_launch(void* const* d_in, const int* in_sizes, int n_in,
                              void* d_out, int out_size) {
    (void)in_sizes; (void)n_in;
    const float* x    = (const float*)d_in[0];
    const int*   seq  = (const int*)  d_in[1];
    const float* wqkv = (const float*)d_in[2];
    const float* bqkv = (const float*)d_in[3];
    const float* wnsq = (const float*)d_in[4];
    const float* bnsq = (const float*)d_in[5];
    const float* wnsk = (const float*)d_in[6];
    const float* bnsk = (const float*)d_in[7];
    const float* wnsv = (const float*)d_in[8];
    const float* bnsv = (const float*)d_in[9];
    const float* n1w  = (const float*)d_in[10];
    const float* n2w  = (const float*)d_in[11];
    const float* fw1  = (const float*)d_in[12];
    const float* fb1  = (const float*)d_in[13];
    const float* fw2  = (const float*)d_in[14];
    const float* fb2  = (const float*)d_in[15];
    const float* w1ns = (const float*)d_in[16];
    const float* b1ns = (const float*)d_in[17];
    const float* w2ns = (const float*)d_in[18];
    const float* b2ns = (const float*)d_in[19];
    float* out = (float*)d_out;

    float *xn,*q,*kv,*attn,*hn,*ts,*tns,*fs,*fns,*part,*wq_t,*w1t,*w2t;
    cudaGetSymbolAddress((void**)&xn,   g_xn);
    cudaGetSymbolAddress((void**)&q,    g_q);
    cudaGetSymbolAddress((void**)&kv,   g_kv);
    cudaGetSymbolAddress((void**)&attn, g_attn);
    cudaGetSymbolAddress((void**)&hn,   g_hn);
    cudaGetSymbolAddress((void**)&ts,   g_ts);
    cudaGetSymbolAddress((void**)&tns,  g_tns);
    cudaGetSymbolAddress((void**)&fs,   g_fs);
    cudaGetSymbolAddress((void**)&fns,  g_fns);
    cudaGetSymbolAddress((void**)&part, g_part);
    cudaGetSymbolAddress((void**)&wq_t, g_wqkv);
    cudaGetSymbolAddress((void**)&w1t,  g_w1);
    cudaGetSymbolAddress((void**)&w2t,  g_w2);

    const long aB  = (long)TOTAL*DM;
    const long qB  = (long)QLEN*DM;
    const long kvB = (long)TOTAL*2*DM;

    const int SMEM128 = (3*128*36 + 3*128*36) * 4;   // 110592 B
    const int SMEM64  = (3*64*36  + 3*128*36) * 4;   //  82944 B
    cudaFuncSetAttribute(mma_gemmT_kernel<128>, cudaFuncAttributeMaxDynamicSharedMemorySize, SMEM128);
    cudaFuncSetAttribute(mma_gemmT_kernel<64>,  cudaFuncAttributeMaxDynamicSharedMemorySize, SMEM64);

    // #1 transpose wqkv ; #2 rmsnorm ; #3 transpose w1 ; #4 KV GEMM (ncu target, with skip)
    transpose_tf32_kernel<<<dim3(3*DM/32, DM/32), dim3(32,8)>>>(wqkv, wq_t, DM, 3*DM);
    rmsnorm_kernel<<<BSZ*TOTAL, 256>>>(x, n1w, xn);
    transpose_tf32_kernel<<<dim3(FFND/32, DM/32), dim3(32,8)>>>(fw1, w1t, DM, FFND);
    mma_gemmT_kernel<128><<<dim3(2*DM/128, (BSZ*MAXS)/128), 256, SMEM128>>>(xn, DM, aB, MAXS,
        wq_t + (long)DM*DM, DM, bqkv + DM, kv, 2*DM, kvB, DM, 0, 0, seq, 1);

    // Q projection
    mma_gemmT_kernel<64><<<dim3(DM/128, (BSZ*OUTN)/64), 256, SMEM64>>>(xn + (long)(MAXS-OUTN)*DM, DM, aB, OUTN,
        wq_t, DM, bqkv, q, DM, qB, DM, 0, 0, seq, 0);

    // NS projections (KS=32, kchunk=32)
    ns_split4_kernel<<<dim3(DM/512, NSN, 32), 128>>>(xn + (long)MAXS*DM, aB, DM, wnsv, part, DM, DM, DM/32);
    ns_reduce_kernel<<<dim3(DM/256, NSN, BSZ), 256>>>(part, bnsv, kv + (long)MAXS*2*DM + DM, kvB, 2*DM, DM, 32, 0);
    ns_split4_kernel<<<dim3(DM/512, NSN, 32), 128>>>(xn + (long)MAXS*DM, aB, DM, wnsq, part, DM, DM, DM/32);
    ns_reduce_kernel<<<dim3(DM/256, NSN, BSZ), 256>>>(part, bnsq, q + (long)OUTN*DM, qB, DM, DM, 32, 0);
    ns_split4_kernel<<<dim3(DM/512, NSN, 32), 128>>>(xn + (long)MAXS*DM, aB, DM, wnsk, part, DM, DM, DM/32);
    ns_reduce_kernel<<<dim3(DM/256, NSN, BSZ), 256>>>(part, bnsk, kv + (long)MAXS*2*DM, kvB, 2*DM, DM, 32, 0);

    // transpose w2 (independent prep)
    transpose_tf32_kernel<<<dim3(DM/32, FFND/32), dim3(32,8)>>>(fw2, w2t, FFND, DM);

    // RoPE (fp32 path)
    {
        int totq = BSZ*QLEN*NH*32;
        rope_kernel<<<(totq+255)/256, 256>>>(q, QLEN, TOTAL-QLEN, DM, totq);
        int totk = BSZ*TOTAL*NH*32;
        rope_kernel<<<(totk+255)/256, 256>>>(kv, TOTAL, 0, 2*DM, totk);
    }

    // attention
    attn_mma_kernel<<<dim3((QLEN+63)/64, NH, BSZ), 256>>>(q, kv, attn, seq);

    // h1 = residual + attn ; hn = rmsnorm(h1)
    add_rmsnorm_kernel<<<BSZ*QLEN, 256>>>(x, n2w);

    // shared FFN
    mma_gemmT_kernel<128><<<dim3(FFND/128, (BSZ*OUTN)/128), 256, SMEM128>>>(hn, DM, qB, OUTN,
        w1t, DM, fb1, ts, FFND, (long)OUTN*FFND, DM, 1, 1, seq, 0);
    mma_gemmT_kernel<64><<<dim3(DM/128, (BSZ*OUTN)/64), 256, SMEM64>>>(ts, FFND, (long)OUTN*FFND, OUTN,
        w2t, FFND, fb2, fs, DM, (long)OUTN*DM, FFND, 0, 0, seq, 0);

    // NS FFN: w1 (N=4096, KS=16, kchunk=64) and w2 (K=4096, KS=32, kchunk=128)
    ns_split4_kernel<<<dim3(FFND/512, NSN, 16), 128>>>(hn + (long)OUTN*DM, qB, DM, w1ns, part, DM, FFND, DM/16);
    ns_reduce_kernel<<<dim3(FFND/256, NSN, BSZ), 256>>>(part, b1ns, tns, (long)NSN*FFND, FFND, FFND, 16, 1);
    ns_split4_kernel<<<dim3(DM/512, NSN, 32), 128>>>(tns, (long)NSN*FFND, FFND, w2ns, part, FFND, DM, FFND/32);
    ns_reduce_kernel<<<dim3(DM/256, NSN, BSZ), 256>>>(part, b2ns, fns, (long)NSN*DM, DM, DM, 32, 0);

    // assemble output
    assemble_kernel<<<(BSZ*QLEN*DM + 255)/256, 256>>>(out, seq, out_size);
}

// round 10
// speedup vs baseline: 5.7003x; 1.0362x over previous
#include <cuda_runtime.h>
#include <cstdint>

#define BSZ   4
#define TOTAL 2064
#define DM    1024
#define NSN   16
#define OUTN  256
#define QLEN  272
#define NH    16
#define HD    64
#define FFND  4096
#define MAXS  2048

// Scratch (static device globals; no allocation allowed)
__device__ float g_xn  [BSZ*TOTAL*DM];
__device__ float g_q   [BSZ*QLEN*DM];
__device__ float g_kv  [BSZ*TOTAL*2*DM];   // k = cols 0..1023, v = cols 1024..2047
__device__ float g_attn[BSZ*QLEN*DM];
__device__ float g_h1  [BSZ*QLEN*DM];
__device__ float g_hn  [BSZ*QLEN*DM];
__device__ float g_ts  [BSZ*OUTN*FFND];
__device__ float g_tns [BSZ*NSN*FFND];
__device__ float g_fs  [BSZ*OUTN*DM];
__device__ float g_fns [BSZ*NSN*DM];
__device__ float g_part[4*1024*1024];      // k-split partials
// TF32-rounded, TRANSPOSED weights ([N, K] row-major)
__device__ float g_wqkv[3*DM*DM];
__device__ float g_w1  [FFND*DM];
__device__ float g_w2  [DM*FFND];

__device__ __forceinline__ float rtf32(float x) {
    uint32_t u;
    asm("cvt.rna.tf32.f32 %0, %1;" : "=r"(u) : "f"(x));
    return __uint_as_float(u);
}
__device__ __forceinline__ uint32_t f2u(float x) { return __float_as_uint(x); }

__device__ __forceinline__ void cpa16(uint32_t dst, const void* src) {
    asm volatile("cp.async.ca.shared.global [%0], [%1], 16;" :: "r"(dst), "l"(src));
}

__device__ __forceinline__ void mma_tf32(float* c,
        uint32_t a0, uint32_t a1, uint32_t a2, uint32_t a3,
        uint32_t b0, uint32_t b1) {
    asm volatile(
        "mma.sync.aligned.m16n8k8.row.col.f32.tf32.tf32.f32 "
        "{%0,%1,%2,%3}, {%4,%5,%6,%7}, {%8,%9}, {%0,%1,%2,%3};\n"
        : "+f"(c[0]), "+f"(c[1]), "+f"(c[2]), "+f"(c[3])
        : "r"(a0), "r"(a1), "r"(a2), "r"(a3), "r"(b0), "r"(b1));
}

__device__ __forceinline__ void ldsm4(uint32_t* r, uint32_t addr) {
    asm volatile("ldmatrix.sync.aligned.m8n8.x4.shared.b16 {%0,%1,%2,%3}, [%4];"
        : "=r"(r[0]), "=r"(r[1]), "=r"(r[2]), "=r"(r[3]) : "r"(addr));
}

// ---------------- transpose + tf32 round ----------------
__global__ __launch_bounds__(256) void transpose_tf32_kernel(const float* __restrict__ in,
        float* __restrict__ out, int R, int C) {
    __shared__ float tile[32][33];
    int c0 = blockIdx.x*32, r0 = blockIdx.y*32;
    int tx = threadIdx.x, ty = threadIdx.y;
    for (int i = ty; i < 32; i += 8)
        tile[i][tx] = in[(long)(r0+i)*C + c0 + tx];
    __syncthreads();
    for (int i = ty; i < 32; i += 8)
        out[(long)(c0+i)*R + r0 + tx] = rtf32(tile[tx][i]);
}

// ---------------- rmsnorm (output tf32-rounded) ----------------
__global__ __launch_bounds__(256) void rmsnorm_kernel(const float* __restrict__ in,
        const float* __restrict__ w, float* __restrict__ out) {
    long row = blockIdx.x;
    int t = threadIdx.x;
    float4 v = reinterpret_cast<const float4*>(in + row*DM)[t];
    float ss = v.x*v.x + v.y*v.y + v.z*v.z + v.w*v.w;
    __shared__ float red[8];
    for (int o = 16; o; o >>= 1) ss += __shfl_xor_sync(0xffffffffu, ss, o);
    if ((t & 31) == 0) red[t >> 5] = ss;
    __syncthreads();
    if (t < 32) {
        float s = (t < 8) ? red[t] : 0.f;
        for (int o = 4; o; o >>= 1) s += __shfl_xor_sync(0xffffffffu, s, o);
        if (t == 0) red[0] = s;
    }
    __syncthreads();
    float rs = rsqrtf(red[0] * (1.f/DM) + 1e-6f);
    float4 wv = reinterpret_cast<const float4*>(w)[t];
    float4 o4 = make_float4(rtf32(v.x*rs*wv.x), rtf32(v.y*rs*wv.y),
                            rtf32(v.z*rs*wv.z), rtf32(v.w*rs*wv.w));
    reinterpret_cast<float4*>(out + row*DM)[t] = o4;
}

// ---------------- h1 = x[:, -272:] + attn ; hn = rmsnorm(h1) ----------------
__global__ __launch_bounds__(256) void add_rmsnorm_kernel(const float* __restrict__ x,
        const float* __restrict__ w) {
    int row = blockIdx.x;
    int b = row / QLEN, r = row - b*QLEN;
    int t = threadIdx.x;
    float4 xv = reinterpret_cast<const float4*>(x + ((long)b*TOTAL + (TOTAL-QLEN) + r)*DM)[t];
    float4 av = reinterpret_cast<const float4*>(g_attn + (long)row*DM)[t];
    float4 hv = make_float4(xv.x+av.x, xv.y+av.y, xv.z+av.z, xv.w+av.w);
    reinterpret_cast<float4*>(g_h1 + (long)row*DM)[t] = hv;
    float ss = hv.x*hv.x + hv.y*hv.y + hv.z*hv.z + hv.w*hv.w;
    __shared__ float red[8];
    for (int o = 16; o; o >>= 1) ss += __shfl_xor_sync(0xffffffffu, ss, o);
    if ((t & 31) == 0) red[t >> 5] = ss;
    __syncthreads();
    if (t < 32) {
        float s = (t < 8) ? red[t] : 0.f;
        for (int o = 4; o; o >>= 1) s += __shfl_xor_sync(0xffffffffu, s, o);
        if (t == 0) red[0] = s;
    }
    __syncthreads();
    float rs = rsqrtf(red[0] * (1.f/DM) + 1e-6f);
    float4 wv = reinterpret_cast<const float4*>(w)[t];
    float4 o4 = make_float4(rtf32(hv.x*rs*wv.x), rtf32(hv.y*rs*wv.y),
                            rtf32(hv.z*rs*wv.z), rtf32(hv.w*rs*wv.w));
    reinterpret_cast<float4*>(g_hn + (long)row*DM)[t] = o4;
}

// ---------------- TF32 tensor-core GEMM, MTILEx128x32, 3-stage cp.async, LDSM frags ----------
template<int MTILE>
__global__ __launch_bounds__(256, 2) void mma_gemmT_kernel(
    const float* __restrict__ A, int lda, long aBatch, int rpb,
    const float* __restrict__ Bt, int ldbt,
    const float* __restrict__ bias,
    float* __restrict__ C, int ldc, long cBatch,
    int K, int relu, int roundOut,
    const int* __restrict__ seqlen, int kvSkip)
{
    constexpr int S    = 3;
    constexpr int PAD  = 36;
    constexpr int ASTG = MTILE*PAD;
    constexpr int BSTG = 128*PAD;
    constexpr int MT   = MTILE/32;
    extern __shared__ float sm[];
    float* AsBase = sm;
    float* BsBase = sm + S*ASTG;

    int t = threadIdx.x;
    int w = t >> 5, lane = t & 31;
    int g = lane >> 2, tig = lane & 3;
    int wm = w >> 2, wn = w & 3;

    int row0 = blockIdx.y * MTILE;
    int bn0  = blockIdx.x * 128;
    int batch = row0 / rpb;
    int rin   = row0 % rpb;
    if (kvSkip) {
        int kmin = MAXS - seqlen[batch];
        if (rin + MTILE - 1 < kmin) return;
    }
    const float* Ab = A + (long)batch*aBatch + (long)rin*lda;
    const float* Bb = Bt + (long)bn0*ldbt;
    float* Cb = C + (long)batch*cBatch + (long)rin*ldc + bn0;

    uint32_t aSm0 = (uint32_t)__cvta_generic_to_shared(AsBase);
    uint32_t bSm0 = (uint32_t)__cvta_generic_to_shared(BsBase);

    float acc[MT][4][4];
    #pragma unroll
    for (int i = 0; i < MT; i++)
        #pragma unroll
        for (int j = 0; j < 4; j++)
            #pragma unroll
            for (int r = 0; r < 4; r++) acc[i][j][r] = 0.f;

    const int KT = K >> 5;
    auto issue = [&](int kt) {
        int s = kt % S;
        const float* ga = Ab + kt*32;
        const float* gb = Bb + kt*32;
        uint32_t aS = aSm0 + s*ASTG*4;
        uint32_t bS = bSm0 + s*BSTG*4;
        #pragma unroll
        for (int it = 0; it < MTILE/32; it++) {
            int i = t + it*256;
            int row = i >> 3, seg = i & 7;
            cpa16(aS + (row*PAD + seg*4)*4, ga + (long)row*lda + seg*4);
        }
        #pragma unroll
        for (int it = 0; it < 4; it++) {
            int i = t + it*256;
            int row = i >> 3, seg = i & 7;
            cpa16(bS + (row*PAD + seg*4)*4, gb + (long)row*ldbt + seg*4);
        }
        asm volatile("cp.async.commit_group;");
    };
    issue(0);
    issue(1);

    int aRowL = (lane & 7) + ((lane >> 3) & 1) * 8;
    int aColL = (lane >> 4) * 4;
    int bRowL = ((lane >> 4) & 1) * 8 + (lane & 7);
    int bColL = ((lane >> 3) & 1) * 4;

    for (int kt = 0; kt < KT; kt++) {
        if (kt == KT - 1) asm volatile("cp.async.wait_group 0;");
        else              asm volatile("cp.async.wait_group 1;");
        __syncthreads();
        if (kt + 2 < KT) issue(kt + 2);

        int s = kt % S;
        uint32_t As = aSm0 + s*ASTG*4;
        uint32_t Bs = bSm0 + s*BSTG*4;
        #pragma unroll
        for (int ks = 0; ks < 4; ks++) {
            uint32_t afr[MT][4];
            #pragma unroll
            for (int mt = 0; mt < MT; mt++)
                ldsm4(afr[mt], As + ((wm*(MTILE/2) + mt*16 + aRowL)*PAD + ks*8 + aColL)*4);
            uint32_t bfr[4][2];
            #pragma unroll
            for (int p = 0; p < 2; p++) {
                uint32_t r4[4];
                ldsm4(r4, Bs + ((wn*32 + p*16 + bRowL)*PAD + ks*8 + bColL)*4);
                bfr[2*p][0]   = r4[0]; bfr[2*p][1]   = r4[1];
                bfr[2*p+1][0] = r4[2]; bfr[2*p+1][1] = r4[3];
            }
            #pragma unroll
            for (int mt = 0; mt < MT; mt++)
                #pragma unroll
                for (int nt = 0; nt < 4; nt++)
                    mma_tf32(acc[mt][nt], afr[mt][0], afr[mt][1], afr[mt][2], afr[mt][3],
                             bfr[nt][0], bfr[nt][1]);
        }
    }

    #pragma unroll
    for (int nt = 0; nt < 4; nt++) {
        int col = wn*32 + nt*8 + 2*tig;
        float bx = bias[bn0 + col], by = bias[bn0 + col + 1];
        #pragma unroll
        for (int mt = 0; mt < MT; mt++) {
            int r0 = wm*(MTILE/2) + mt*16 + g;
            float c0 = acc[mt][nt][0] + bx, c1 = acc[mt][nt][1] + by;
            float c2 = acc[mt][nt][2] + bx, c3 = acc[mt][nt][3] + by;
            if (relu) { c0=fmaxf(c0,0.f); c1=fmaxf(c1,0.f); c2=fmaxf(c2,0.f); c3=fmaxf(c3,0.f); }
            if (roundOut) { c0=rtf32(c0); c1=rtf32(c1); c2=rtf32(c2); c3=rtf32(c3); }
            *reinterpret_cast<float2*>(Cb + (long)r0*ldc + col)     = make_float2(c0, c1);
            *reinterpret_cast<float2*>(Cb + (long)(r0+8)*ldc + col) = make_float2(c2, c3);
        }
    }
}

// ---------------- per-NS-position linear: vectorized K-split partials ----------------
__global__ __launch_bounds__(128) void ns_split4_kernel(
    const float* __restrict__ X, long xBatch, int xRow,
    const float* __restrict__ W, float* __restrict__ part,
    int K, int N, int kchunk)
{
    __shared__ float Xs[4][512];
    int n = blockIdx.y, z = blockIdx.z;
    int t = threadIdx.x;
    int o4 = (blockIdx.x*128 + t)*4;
    int k0 = z*kchunk;
    for (int i = t; i < kchunk; i += 128) {
        long xo = (long)n*xRow + k0 + i;
        Xs[0][i] = X[0*xBatch + xo];
        Xs[1][i] = X[1*xBatch + xo];
        Xs[2][i] = X[2*xBatch + xo];
        Xs[3][i] = X[3*xBatch + xo];
    }
    __syncthreads();
    const float* Wp = W + (long)n*K*N + (long)k0*N + o4;
    float acc[4][4];
    #pragma unroll
    for (int b = 0; b < 4; b++)
        #pragma unroll
        for (int j = 0; j < 4; j++) acc[b][j] = 0.f;
    #pragma unroll 8
    for (int k = 0; k < kchunk; k++) {
        float4 wv = *reinterpret_cast<const float4*>(Wp + (long)k*N);
        #pragma unroll
        for (int b = 0; b < 4; b++) {
            float xv = Xs[b][k];
            acc[b][0] += xv*wv.x; acc[b][1] += xv*wv.y;
            acc[b][2] += xv*wv.z; acc[b][3] += xv*wv.w;
        }
    }
    #pragma unroll
    for (int b = 0; b < 4; b++)
        *reinterpret_cast<float4*>(&part[((long)(z*BSZ+b)*NSN + n)*N + o4]) =
            make_float4(acc[b][0], acc[b][1], acc[b][2], acc[b][3]);
}

__global__ __launch_bounds__(256) void ns_reduce_kernel(
    const float* __restrict__ part, const float* __restrict__ bias,
    float* __restrict__ Y, long yBatch, int yRow, int N, int KS, int relu)
{
    int o = blockIdx.x*256 + threadIdx.x;
    int n = blockIdx.y, b = blockIdx.z;
    float s = bias[(long)n*N + o];
    for (int z = 0; z < KS; z++)
        s += part[((long)(z*BSZ+b)*NSN + n)*N + o];
    if (relu) s = fmaxf(s, 0.f);
    Y[(long)b*yBatch + (long)n*yRow + o] = s;
}

// ---------------- RoPE in-place (fp32 path) ----------------
__global__ void rope_kernel(float* __restrict__ buf, int rowsPerB, int pos0, int rstride, int total) {
    int idx = blockIdx.x*blockDim.x + threadIdx.x;
    if (idx >= total) return;
    int j  = idx & 31;
    int h  = (idx >> 5) & (NH-1);
    int rr = idx >> 9;
    int b  = rr / rowsPerB;
    int r  = rr - b*rowsPerB;
    float inv = exp2f(-(float)j * 0.41524101186092029f);
    double ang = (double)(pos0 + r) * (double)inv;
    const double TWO_PI = 6.2831853071795864769;
    double red = ang - TWO_PI * rint(ang * (1.0/6.2831853071795864769));
    float rf = (float)red;
    float s, c;
    sincosf(rf, &s, &c);
    float* base = buf + ((long)b*rowsPerB + r)*(long)rstride + h*HD;
    float x1 = base[j], x2 = base[j+32];
    base[j]    = x1*c - x2*s;
    base[j+32] = x2*c + x1*s;
}

// ---------------- tensor-core flash attention (tf32) ----------------
__global__ __launch_bounds__(256) void attn_mma_kernel(
    const float* __restrict__ q, const float* __restrict__ kv,
    float* __restrict__ attn, const int* __restrict__ seqlen)
{
    __shared__ float qs [64][68];
    __shared__ float ksm[32][68];
    __shared__ float vsm[32][72];
    __shared__ float ssm[64][36];
    __shared__ float corrs[64];
    __shared__ float lrow[64];

    int qt = blockIdx.x, h = blockIdx.y, b = blockIdx.z;
    int tid = threadIdx.x;
    int w = tid >> 5, lane = tid & 31;
    int g = lane >> 2, tig = lane & 3;
    int wm = w >> 2, wn = w & 3;
    int L = seqlen[b];
    int kmin = MAXS - L;

    for (int i = tid; i < 64*16; i += 256) {
        int r = i >> 4, c4 = (i & 15) * 4;
        int qg = qt*64 + r;
        float4 val = make_float4(0.f,0.f,0.f,0.f);
        if (qg < QLEN)
            val = *reinterpret_cast<const float4*>(q + ((long)b*QLEN + qg)*DM + h*HD + c4);
        qs[r][c4]   = rtf32(val.x);
        qs[r][c4+1] = rtf32(val.y);
        qs[r][c4+2] = rtf32(val.z);
        qs[r][c4+3] = rtf32(val.w);
    }

    int srow = tid >> 2, ssub = tid & 3;
    float m = -1e30f, l = 0.f;

    float oacc[2][2][4];
    #pragma unroll
    for (int i = 0; i < 2; i++)
        #pragma unroll
        for (int j = 0; j < 2; j++)
            #pragma unroll
            for (int r = 0; r < 4; r++) oacc[i][j][r] = 0.f;

    int qgmax = min(QLEN-1, qt*64 + 63);
    int t0 = kmin >> 5;
    int t1 = (MAXS - OUTN + qgmax) >> 5;

    for (int kt = t0; kt <= t1; kt++) {
        int key0 = kt * 32;
        __syncthreads();
        for (int i = tid; i < 32*16; i += 256) {
            int r = i >> 4, c4 = (i & 15) * 4;
            int key = key0 + r;
            float4 kk = make_float4(0.f,0.f,0.f,0.f), vv = kk;
            if (key < TOTAL) {
                const float* base = kv + ((long)b*TOTAL + key)*(2*DM) + h*HD;
                kk = *reinterpret_cast<const float4*>(base + c4);
                vv = *reinterpret_cast<const float4*>(base + DM + c4);
            }
            ksm[r][c4]=rtf32(kk.x); ksm[r][c4+1]=rtf32(kk.y);
            ksm[r][c4+2]=rtf32(kk.z); ksm[r][c4+3]=rtf32(kk.w);
            vsm[r][c4]=rtf32(vv.x); vsm[r][c4+1]=rtf32(vv.y);
            vsm[r][c4+2]=rtf32(vv.z); vsm[r][c4+3]=rtf32(vv.w);
        }
        __syncthreads();

        float sa[2][4];
        #pragma unroll
        for (int mt = 0; mt < 2; mt++)
            #pragma unroll
            for (int r = 0; r < 4; r++) sa[mt][r] = 0.f;
        #pragma unroll
        for (int dk = 0; dk < 8; dk++) {
            uint32_t bf0 = f2u(ksm[wn*8 + g][dk*8 + tig]);
            uint32_t bf1 = f2u(ksm[wn*8 + g][dk*8 + tig + 4]);
            #pragma unroll
            for (int mt = 0; mt < 2; mt++) {
                int m0 = wm*32 + mt*16;
                mma_tf32(sa[mt],
                    f2u(qs[m0+g][dk*8+tig]),   f2u(qs[m0+g+8][dk*8+tig]),
                    f2u(qs[m0+g][dk*8+tig+4]), f2u(qs[m0+g+8][dk*8+tig+4]),
                    bf0, bf1);
            }
        }
        #pragma unroll
        for (int mt = 0; mt < 2; mt++) {
            #pragma unroll
            for (int hh = 0; hh < 2; hh++) {
                int r = wm*32 + mt*16 + g + hh*8;
                int qg = qt*64 + r;
                int key = key0 + wn*8 + 2*tig;
                int kcap = MAXS - OUTN + qg;
                bool rowok = (qg < QLEN);
                float sA = sa[mt][hh*2+0], sB = sa[mt][hh*2+1];
                bool v0 = rowok && (key   < TOTAL) && (key   >= kmin) && (key   <= kcap);
                bool v1 = rowok && (key+1 < TOTAL) && (key+1 >= kmin) && (key+1 <= kcap);
                ssm[r][wn*8 + 2*tig]     = v0 ? sA*0.125f : -1e9f;
                ssm[r][wn*8 + 2*tig + 1] = v1 ? sB*0.125f : -1e9f;
            }
        }
        __syncthreads();

        float sv[8];
        #pragma unroll
        for (int j = 0; j < 8; j++) sv[j] = ssm[srow][ssub*8 + j];
        float tmax = sv[0];
        #pragma unroll
        for (int j = 1; j < 8; j++) tmax = fmaxf(tmax, sv[j]);
        tmax = fmaxf(tmax, __shfl_xor_sync(0xffffffffu, tmax, 1));
        tmax = fmaxf(tmax, __shfl_xor_sync(0xffffffffu, tmax, 2));
        float corr = 1.f;
        if (tmax > -1e8f) {
            float m_new = fmaxf(m, tmax);
            corr = __expf(m - m_new);
            float ps = 0.f;
            #pragma unroll
            for (int j = 0; j < 8; j++) {
                float p = __expf(sv[j] - m_new);
                ps += p;
                ssm[srow][ssub*8 + j] = rtf32(p);
            }
            ps += __shfl_xor_sync(0xffffffffu, ps, 1);
            ps += __shfl_xor_sync(0xffffffffu, ps, 2);
            l = l*corr + ps;
            m = m_new;
        } else {
            #pragma unroll
            for (int j = 0; j < 8; j++) ssm[srow][ssub*8 + j] = 0.f;
        }
        if (ssub == 0) corrs[srow] = corr;
        __syncthreads();

        #pragma unroll
        for (int mt = 0; mt < 2; mt++) {
            float c0 = corrs[wm*32 + mt*16 + g];
            float c1 = corrs[wm*32 + mt*16 + g + 8];
            #pragma unroll
            for (int nt = 0; nt < 2; nt++) {
                oacc[mt][nt][0] *= c0; oacc[mt][nt][1] *= c0;
                oacc[mt][nt][2] *= c1; oacc[mt][nt][3] *= c1;
            }
        }
        #pragma unroll
        for (int kd = 0; kd < 4; kd++) {
            uint32_t bf[2][2];
            #pragma unroll
            for (int nt = 0; nt < 2; nt++) {
                int n = wn*16 + nt*8 + g;
                bf[nt][0] = f2u(vsm[kd*8 + tig][n]);
                bf[nt][1] = f2u(vsm[kd*8 + tig + 4][n]);
            }
            #pragma unroll
            for (int mt = 0; mt < 2; mt++) {
                int m0 = wm*32 + mt*16;
                uint32_t a0 = f2u(ssm[m0+g][kd*8+tig]);
                uint32_t a1 = f2u(ssm[m0+g+8][kd*8+tig]);
                uint32_t a2 = f2u(ssm[m0+g][kd*8+tig+4]);
                uint32_t a3 = f2u(ssm[m0+g+8][kd*8+tig+4]);
                #pragma unroll
                for (int nt = 0; nt < 2; nt++)
                    mma_tf32(oacc[mt][nt], a0, a1, a2, a3, bf[nt][0], bf[nt][1]);
            }
        }
    }

    if (ssub == 0) lrow[srow] = l;
    __syncthreads();
    #pragma unroll
    for (int mt = 0; mt < 2; mt++) {
        #pragma unroll
        for (int hh = 0; hh < 2; hh++) {
            int r = wm*32 + mt*16 + g + hh*8;
            int qg = qt*64 + r;
            if (qg < QLEN) {
                float invl = 1.f / lrow[r];
                #pragma unroll
                for (int nt = 0; nt < 2; nt++) {
                    int col = wn*16 + nt*8 + 2*tig;
                    *reinterpret_cast<float2*>(attn + ((long)b*QLEN + qg)*DM + h*HD + col)
                        = make_float2(oacc[mt][nt][hh*2]*invl, oacc[mt][nt][hh*2+1]*invl);
                }
            }
        }
    }
}

// ---------------- final assembly ----------------
__global__ void assemble_kernel(float* __restrict__ out, const int* __restrict__ seqlen, int out_size) {
    int idx = blockIdx.x*blockDim.x + threadIdx.x;
    const int main_n = BSZ*QLEN*DM;
    if (idx < main_n) {
        int b = idx / (QLEN*DM);
        int rem = idx - b*(QLEN*DM);
        int r = rem / DM;
        int d = rem - r*DM;
        float f;
        if (r < OUTN) f = g_fs [((long)b*OUTN + r)*DM + d];
        else          f = g_fns[((long)b*NSN + (r - OUTN))*DM + d];
        out[idx] = f + g_h1[idx];
    }
    if (idx < BSZ && out_size >= main_n + BSZ) {
        int L = seqlen[idx];
        out[main_n + idx] = (float)(L < OUTN ? L : OUTN);
    }
}

extern "C" void kernel_launch(void* const* d_in, const int* in_sizes, int n_in,
                              void* d_out, int out_size) {
    (void)in_sizes; (void)n_in;
    const float* x    = (const float*)d_in[0];
    const int*   seq  = (const int*)  d_in[1];
    const float* wqkv = (const float*)d_in[2];
    const float* bqkv = (const float*)d_in[3];
    const float* wnsq = (const float*)d_in[4];
    const float* bnsq = (const float*)d_in[5];
    const float* wnsk = (const float*)d_in[6];
    const float* bnsk = (const float*)d_in[7];
    const float* wnsv = (const float*)d_in[8];
    const float* bnsv = (const float*)d_in[9];
    const float* n1w  = (const float*)d_in[10];
    const float* n2w  = (const float*)d_in[11];
    const float* fw1  = (const float*)d_in[12];
    const float* fb1  = (const float*)d_in[13];
    const float* fw2  = (const float*)d_in[14];
    const float* fb2  = (const float*)d_in[15];
    const float* w1ns = (const float*)d_in[16];
    const float* b1ns = (const float*)d_in[17];
    const float* w2ns = (const float*)d_in[18];
    const float* b2ns = (const float*)d_in[19];
    float* out = (float*)d_out;

    float *xn,*q,*kv,*attn,*hn,*ts,*tns,*fs,*fns,*part,*wq_t,*w1t,*w2t;
    cudaGetSymbolAddress((void**)&xn,   g_xn);
    cudaGetSymbolAddress((void**)&q,    g_q);
    cudaGetSymbolAddress((void**)&kv,   g_kv);
    cudaGetSymbolAddress((void**)&attn, g_attn);
    cudaGetSymbolAddress((void**)&hn,   g_hn);
    cudaGetSymbolAddress((void**)&ts,   g_ts);
    cudaGetSymbolAddress((void**)&tns,  g_tns);
    cudaGetSymbolAddress((void**)&fs,   g_fs);
    cudaGetSymbolAddress((void**)&fns,  g_fns);
    cudaGetSymbolAddress((void**)&part, g_part);
    cudaGetSymbolAddress((void**)&wq_t, g_wqkv);
    cudaGetSymbolAddress((void**)&w1t,  g_w1);
    cudaGetSymbolAddress((void**)&w2t,  g_w2);
    float* part2 = part + 2*1024*1024;   // second half for concurrent phase-1 user

    const long aB  = (long)TOTAL*DM;
    const long qB  = (long)QLEN*DM;
    const long kvB = (long)TOTAL*2*DM;

    const int SMEM128 = (3*128*36 + 3*128*36) * 4;
    const int SMEM64  = (3*64*36  + 3*128*36) * 4;
    cudaFuncSetAttribute(mma_gemmT_kernel<128>, cudaFuncAttributeMaxDynamicSharedMemorySize, SMEM128);
    cudaFuncSetAttribute(mma_gemmT_kernel<64>,  cudaFuncAttributeMaxDynamicSharedMemorySize, SMEM64);

    // One-time resource init (resource creation only; launched work is identical every call).
    static cudaStream_t s1 = nullptr, s2 = nullptr, s3 = nullptr;
    static cudaEvent_t  e0, e1, e2, e3, e4, e5;
    if (s1 == nullptr) {
        cudaStreamCreateWithFlags(&s1, cudaStreamNonBlocking);
        cudaStreamCreateWithFlags(&s2, cudaStreamNonBlocking);
        cudaStreamCreateWithFlags(&s3, cudaStreamNonBlocking);
        cudaEventCreateWithFlags(&e0, cudaEventDisableTiming);
        cudaEventCreateWithFlags(&e1, cudaEventDisableTiming);
        cudaEventCreateWithFlags(&e2, cudaEventDisableTiming);
        cudaEventCreateWithFlags(&e3, cudaEventDisableTiming);
        cudaEventCreateWithFlags(&e4, cudaEventDisableTiming);
        cudaEventCreateWithFlags(&e5, cudaEventDisableTiming);
    }
    cudaStream_t s0 = 0;   // legacy default stream (capture origin)

    // ---- Phase 1 ----
    // s0: weight transpose (qkv) + rmsnorm, then fork
    transpose_tf32_kernel<<<dim3(3*DM/32, DM/32), dim3(32,8), 0, s0>>>(wqkv, wq_t, DM, 3*DM);
    rmsnorm_kernel<<<BSZ*TOTAL, 256, 0, s0>>>(x, n1w, xn);
    cudaEventRecord(e0, s0);

    // s2: FFN weight transposes (independent of e0; forked via e0 for capture ordering)
    cudaStreamWaitEvent(s2, e0, 0);
    transpose_tf32_kernel<<<dim3(FFND/32, DM/32), dim3(32,8), 0, s2>>>(fw1, w1t, DM, FFND);
    transpose_tf32_kernel<<<dim3(DM/32, FFND/32), dim3(32,8), 0, s2>>>(fw2, w2t, FFND, DM);
    cudaEventRecord(e2, s2);

    // s1: Q projection -> ns_q (uses part2) -> rope_q
    cudaStreamWaitEvent(s1, e0, 0);
    mma_gemmT_kernel<64><<<dim3(DM/128, (BSZ*OUTN)/64), 256, SMEM64, s1>>>(
        xn + (long)(MAXS-OUTN)*DM, DM, aB, OUTN, wq_t, DM, bqkv, q, DM, qB, DM, 0, 0, seq, 0);
    ns_split4_kernel<<<dim3(DM/512, NSN, 32), 128, 0, s1>>>(xn + (long)MAXS*DM, aB, DM, wnsq, part2, DM, DM, DM/32);
    ns_reduce_kernel<<<dim3(DM/256, NSN, BSZ), 256, 0, s1>>>(part2, bnsq, q + (long)OUTN*DM, qB, DM, DM, 32, 0);
    {
        int totq = BSZ*QLEN*NH*32;
        rope_kernel<<<(totq+255)/256, 256, 0, s1>>>(q, QLEN, TOTAL-QLEN, DM, totq);
    }
    cudaEventRecord(e1, s1);

    // s3: ns_v then ns_k (serialized; use part[0..2M))
    cudaStreamWaitEvent(s3, e0, 0);
    ns_split4_kernel<<<dim3(DM/512, NSN, 32), 128, 0, s3>>>(xn + (long)MAXS*DM, aB, DM, wnsv, part, DM, DM, DM/32);
    ns_reduce_kernel<<<dim3(DM/256, NSN, BSZ), 256, 0, s3>>>(part, bnsv, kv + (long)MAXS*2*DM + DM, kvB, 2*DM, DM, 32, 0);
    ns_split4_kernel<<<dim3(DM/512, NSN, 32), 128, 0, s3>>>(xn + (long)MAXS*DM, aB, DM, wnsk, part, DM, DM, DM/32);
    ns_reduce_kernel<<<dim3(DM/256, NSN, BSZ), 256, 0, s3>>>(part, bnsk, kv + (long)MAXS*2*DM, kvB, 2*DM, DM, 32, 0);
    cudaEventRecord(e3, s3);

    // s0: KV projection (overlaps s1/s2/s3), then rope_k after ns_k/ns_v land
    mma_gemmT_kernel<128><<<dim3(2*DM/128, (BSZ*MAXS)/128), 256, SMEM128, s0>>>(xn, DM, aB, MAXS,
        wq_t + (long)DM*DM, DM, bqkv + DM, kv, 2*DM, kvB, DM, 0, 0, seq, 1);
    cudaStreamWaitEvent(s0, e3, 0);
    {
        int totk = BSZ*TOTAL*NH*32;
        rope_kernel<<<(totk+255)/256, 256, 0, s0>>>(kv, TOTAL, 0, 2*DM, totk);
    }

    // attention (needs roped q from s1)
    cudaStreamWaitEvent(s0, e1, 0);
    attn_mma_kernel<<<dim3((QLEN+63)/64, NH, BSZ), 256, 0, s0>>>(q, kv, attn, seq);

    // h1 = residual + attn ; hn = rmsnorm(h1)
    add_rmsnorm_kernel<<<BSZ*QLEN, 256, 0, s0>>>(x, n2w);
    cudaEventRecord(e4, s0);

    // ---- Phase 2 ----
    // s1: NS FFN (w1 KS=16 uses full part [4M]; then w2 KS=32 uses part [2M]) — serialized on s1
    cudaStreamWaitEvent(s1, e4, 0);
    ns_split4_kernel<<<dim3(FFND/512, NSN, 16), 128, 0, s1>>>(hn + (long)OUTN*DM, qB, DM, w1ns, part, DM, FFND, DM/16);
    ns_reduce_kernel<<<dim3(FFND/256, NSN, BSZ), 256, 0, s1>>>(part, b1ns, tns, (long)NSN*FFND, FFND, FFND, 16, 1);
    ns_split4_kernel<<<dim3(DM/512, NSN, 32), 128, 0, s1>>>(tns, (long)NSN*FFND, FFND, w2ns, part, FFND, DM, FFND/32);
    ns_reduce_kernel<<<dim3(DM/256, NSN, BSZ), 256, 0, s1>>>(part, b2ns, fns, (long)NSN*DM, DM, DM, 32, 0);
    cudaEventRecord(e5, s1);

    // s0: shared FFN (needs transposed weights from s2)
    cudaStreamWaitEvent(s0, e2, 0);
    mma_gemmT_kernel<128><<<dim3(FFND/128, (BSZ*OUTN)/128), 256, SMEM128, s0>>>(hn, DM, qB, OUTN,
        w1t, DM, fb1, ts, FFND, (long)OUTN*FFND, DM, 1, 1, seq, 0);
    mma_gemmT_kernel<64><<<dim3(DM/128, (BSZ*OUTN)/64), 256, SMEM64, s0>>>(ts, FFND, (long)OUTN*FFND, OUTN,
        w2t, FFND, fb2, fs, DM, (long)OUTN*DM, FFND, 0, 0, seq, 0);

    // join + assemble
    cudaStreamWaitEvent(s0, e5, 0);
    assemble_kernel<<<(BSZ*QLEN*DM + 255)/256, 256, 0, s0>>>(out, seq, out_size);
}

// round 11
// speedup vs baseline: 5.9663x; 1.0467x over previous
#include <cuda_runtime.h>
#include <cstdint>

#define BSZ   4
#define TOTAL 2064
#define DM    1024
#define NSN   16
#define OUTN  256
#define QLEN  272
#define NH    16
#define HD    64
#define FFND  4096
#define MAXS  2048

// Scratch (static device globals; no allocation allowed)
__device__ float g_xn  [BSZ*TOTAL*DM];
__device__ float g_q   [BSZ*QLEN*DM];
__device__ float g_kv  [BSZ*TOTAL*2*DM];   // k = cols 0..1023, v = cols 1024..2047
__device__ float g_attn[BSZ*QLEN*DM];
__device__ float g_h1  [BSZ*QLEN*DM];
__device__ float g_hn  [BSZ*QLEN*DM];
__device__ float g_ts  [BSZ*OUTN*FFND];
__device__ float g_tns [BSZ*NSN*FFND];
__device__ float g_fs  [BSZ*OUTN*DM];
__device__ float g_fns [BSZ*NSN*DM];
__device__ float g_part[4*1024*1024];      // k-split partials
// TF32-rounded, TRANSPOSED weights ([N, K] row-major)
__device__ float g_wqkv[3*DM*DM];
__device__ float g_w1  [FFND*DM];
__device__ float g_w2  [DM*FFND];

__device__ __forceinline__ float rtf32(float x) {
    uint32_t u;
    asm("cvt.rna.tf32.f32 %0, %1;" : "=r"(u) : "f"(x));
    return __uint_as_float(u);
}
__device__ __forceinline__ uint32_t f2u(float x) { return __float_as_uint(x); }

__device__ __forceinline__ void cpa16(uint32_t dst, const void* src) {
    asm volatile("cp.async.ca.shared.global [%0], [%1], 16;" :: "r"(dst), "l"(src));
}

__device__ __forceinline__ void mma_tf32(float* c,
        uint32_t a0, uint32_t a1, uint32_t a2, uint32_t a3,
        uint32_t b0, uint32_t b1) {
    asm volatile(
        "mma.sync.aligned.m16n8k8.row.col.f32.tf32.tf32.f32 "
        "{%0,%1,%2,%3}, {%4,%5,%6,%7}, {%8,%9}, {%0,%1,%2,%3};\n"
        : "+f"(c[0]), "+f"(c[1]), "+f"(c[2]), "+f"(c[3])
        : "r"(a0), "r"(a1), "r"(a2), "r"(a3), "r"(b0), "r"(b1));
}

__device__ __forceinline__ void ldsm4(uint32_t* r, uint32_t addr) {
    asm volatile("ldmatrix.sync.aligned.m8n8.x4.shared.b16 {%0,%1,%2,%3}, [%4];"
        : "=r"(r[0]), "=r"(r[1]), "=r"(r[2]), "=r"(r[3]) : "r"(addr));
}

// ---------------- transpose + tf32 round ----------------
__global__ __launch_bounds__(256) void transpose_tf32_kernel(const float* __restrict__ in,
        float* __restrict__ out, int R, int C) {
    __shared__ float tile[32][33];
    int c0 = blockIdx.x*32, r0 = blockIdx.y*32;
    int tx = threadIdx.x, ty = threadIdx.y;
    for (int i = ty; i < 32; i += 8)
        tile[i][tx] = in[(long)(r0+i)*C + c0 + tx];
    __syncthreads();
    for (int i = ty; i < 32; i += 8)
        out[(long)(c0+i)*R + r0 + tx] = rtf32(tile[tx][i]);
}

// ---------------- rmsnorm (output tf32-rounded) ----------------
__global__ __launch_bounds__(256) void rmsnorm_kernel(const float* __restrict__ in,
        const float* __restrict__ w, float* __restrict__ out) {
    long row = blockIdx.x;
    int t = threadIdx.x;
    float4 v = reinterpret_cast<const float4*>(in + row*DM)[t];
    float ss = v.x*v.x + v.y*v.y + v.z*v.z + v.w*v.w;
    __shared__ float red[8];
    for (int o = 16; o; o >>= 1) ss += __shfl_xor_sync(0xffffffffu, ss, o);
    if ((t & 31) == 0) red[t >> 5] = ss;
    __syncthreads();
    if (t < 32) {
        float s = (t < 8) ? red[t] : 0.f;
        for (int o = 4; o; o >>= 1) s += __shfl_xor_sync(0xffffffffu, s, o);
        if (t == 0) red[0] = s;
    }
    __syncthreads();
    float rs = rsqrtf(red[0] * (1.f/DM) + 1e-6f);
    float4 wv = reinterpret_cast<const float4*>(w)[t];
    float4 o4 = make_float4(rtf32(v.x*rs*wv.x), rtf32(v.y*rs*wv.y),
                            rtf32(v.z*rs*wv.z), rtf32(v.w*rs*wv.w));
    reinterpret_cast<float4*>(out + row*DM)[t] = o4;
}

// ---------------- h1 = x[:, -272:] + attn ; hn = rmsnorm(h1) ----------------
__global__ __launch_bounds__(256) void add_rmsnorm_kernel(const float* __restrict__ x,
        const float* __restrict__ w) {
    int row = blockIdx.x;
    int b = row / QLEN, r = row - b*QLEN;
    int t = threadIdx.x;
    float4 xv = reinterpret_cast<const float4*>(x + ((long)b*TOTAL + (TOTAL-QLEN) + r)*DM)[t];
    float4 av = reinterpret_cast<const float4*>(g_attn + (long)row*DM)[t];
    float4 hv = make_float4(xv.x+av.x, xv.y+av.y, xv.z+av.z, xv.w+av.w);
    reinterpret_cast<float4*>(g_h1 + (long)row*DM)[t] = hv;
    float ss = hv.x*hv.x + hv.y*hv.y + hv.z*hv.z + hv.w*hv.w;
    __shared__ float red[8];
    for (int o = 16; o; o >>= 1) ss += __shfl_xor_sync(0xffffffffu, ss, o);
    if ((t & 31) == 0) red[t >> 5] = ss;
    __syncthreads();
    if (t < 32) {
        float s = (t < 8) ? red[t] : 0.f;
        for (int o = 4; o; o >>= 1) s += __shfl_xor_sync(0xffffffffu, s, o);
        if (t == 0) red[0] = s;
    }
    __syncthreads();
    float rs = rsqrtf(red[0] * (1.f/DM) + 1e-6f);
    float4 wv = reinterpret_cast<const float4*>(w)[t];
    float4 o4 = make_float4(rtf32(hv.x*rs*wv.x), rtf32(hv.y*rs*wv.y),
                            rtf32(hv.z*rs*wv.z), rtf32(hv.w*rs*wv.w));
    reinterpret_cast<float4*>(g_hn + (long)row*DM)[t] = o4;
}

// ---------------- TF32 tensor-core GEMM, MTILEx128x32, 3-stage cp.async, LDSM frags ----------
template<int MTILE>
__global__ __launch_bounds__(256, 2) void mma_gemmT_kernel(
    const float* __restrict__ A, int lda, long aBatch, int rpb,
    const float* __restrict__ Bt, int ldbt,
    const float* __restrict__ bias,
    float* __restrict__ C, int ldc, long cBatch,
    int K, int relu, int roundOut,
    const int* __restrict__ seqlen, int kvSkip)
{
    constexpr int S    = 3;
    constexpr int PAD  = 36;
    constexpr int ASTG = MTILE*PAD;
    constexpr int BSTG = 128*PAD;
    constexpr int MT   = MTILE/32;
    extern __shared__ float sm[];
    float* AsBase = sm;
    float* BsBase = sm + S*ASTG;

    int t = threadIdx.x;
    int w = t >> 5, lane = t & 31;
    int g = lane >> 2, tig = lane & 3;
    int wm = w >> 2, wn = w & 3;

    int row0 = blockIdx.y * MTILE;
    int bn0  = blockIdx.x * 128;
    int batch = row0 / rpb;
    int rin   = row0 % rpb;
    if (kvSkip) {
        int kmin = MAXS - seqlen[batch];
        if (rin + MTILE - 1 < kmin) return;
    }
    const float* Ab = A + (long)batch*aBatch + (long)rin*lda;
    const float* Bb = Bt + (long)bn0*ldbt;
    float* Cb = C + (long)batch*cBatch + (long)rin*ldc + bn0;

    uint32_t aSm0 = (uint32_t)__cvta_generic_to_shared(AsBase);
    uint32_t bSm0 = (uint32_t)__cvta_generic_to_shared(BsBase);

    float acc[MT][4][4];
    #pragma unroll
    for (int i = 0; i < MT; i++)
        #pragma unroll
        for (int j = 0; j < 4; j++)
            #pragma unroll
            for (int r = 0; r < 4; r++) acc[i][j][r] = 0.f;

    const int KT = K >> 5;
    auto issue = [&](int kt) {
        int s = kt % S;
        const float* ga = Ab + kt*32;
        const float* gb = Bb + kt*32;
        uint32_t aS = aSm0 + s*ASTG*4;
        uint32_t bS = bSm0 + s*BSTG*4;
        #pragma unroll
        for (int it = 0; it < MTILE/32; it++) {
            int i = t + it*256;
            int row = i >> 3, seg = i & 7;
            cpa16(aS + (row*PAD + seg*4)*4, ga + (long)row*lda + seg*4);
        }
        #pragma unroll
        for (int it = 0; it < 4; it++) {
            int i = t + it*256;
            int row = i >> 3, seg = i & 7;
            cpa16(bS + (row*PAD + seg*4)*4, gb + (long)row*ldbt + seg*4);
        }
        asm volatile("cp.async.commit_group;");
    };
    issue(0);
    issue(1);

    int aRowL = (lane & 7) + ((lane >> 3) & 1) * 8;
    int aColL = (lane >> 4) * 4;
    int bRowL = ((lane >> 4) & 1) * 8 + (lane & 7);
    int bColL = ((lane >> 3) & 1) * 4;

    for (int kt = 0; kt < KT; kt++) {
        if (kt == KT - 1) asm volatile("cp.async.wait_group 0;");
        else              asm volatile("cp.async.wait_group 1;");
        __syncthreads();
        if (kt + 2 < KT) issue(kt + 2);

        int s = kt % S;
        uint32_t As = aSm0 + s*ASTG*4;
        uint32_t Bs = bSm0 + s*BSTG*4;
        #pragma unroll
        for (int ks = 0; ks < 4; ks++) {
            uint32_t afr[MT][4];
            #pragma unroll
            for (int mt = 0; mt < MT; mt++)
                ldsm4(afr[mt], As + ((wm*(MTILE/2) + mt*16 + aRowL)*PAD + ks*8 + aColL)*4);
            uint32_t bfr[4][2];
            #pragma unroll
            for (int p = 0; p < 2; p++) {
                uint32_t r4[4];
                ldsm4(r4, Bs + ((wn*32 + p*16 + bRowL)*PAD + ks*8 + bColL)*4);
                bfr[2*p][0]   = r4[0]; bfr[2*p][1]   = r4[1];
                bfr[2*p+1][0] = r4[2]; bfr[2*p+1][1] = r4[3];
            }
            #pragma unroll
            for (int mt = 0; mt < MT; mt++)
                #pragma unroll
                for (int nt = 0; nt < 4; nt++)
                    mma_tf32(acc[mt][nt], afr[mt][0], afr[mt][1], afr[mt][2], afr[mt][3],
                             bfr[nt][0], bfr[nt][1]);
        }
    }

    #pragma unroll
    for (int nt = 0; nt < 4; nt++) {
        int col = wn*32 + nt*8 + 2*tig;
        float bx = bias[bn0 + col], by = bias[bn0 + col + 1];
        #pragma unroll
        for (int mt = 0; mt < MT; mt++) {
            int r0 = wm*(MTILE/2) + mt*16 + g;
            float c0 = acc[mt][nt][0] + bx, c1 = acc[mt][nt][1] + by;
            float c2 = acc[mt][nt][2] + bx, c3 = acc[mt][nt][3] + by;
            if (relu) { c0=fmaxf(c0,0.f); c1=fmaxf(c1,0.f); c2=fmaxf(c2,0.f); c3=fmaxf(c3,0.f); }
            if (roundOut) { c0=rtf32(c0); c1=rtf32(c1); c2=rtf32(c2); c3=rtf32(c3); }
            *reinterpret_cast<float2*>(Cb + (long)r0*ldc + col)     = make_float2(c0, c1);
            *reinterpret_cast<float2*>(Cb + (long)(r0+8)*ldc + col) = make_float2(c2, c3);
        }
    }
}

// ---------------- per-NS-position linear: vectorized K-split partials ----------------
__global__ __launch_bounds__(128) void ns_split4_kernel(
    const float* __restrict__ X, long xBatch, int xRow,
    const float* __restrict__ W, float* __restrict__ part,
    int K, int N, int kchunk)
{
    __shared__ float Xs[4][512];
    int n = blockIdx.y, z = blockIdx.z;
    int t = threadIdx.x;
    int o4 = (blockIdx.x*128 + t)*4;
    int k0 = z*kchunk;
    for (int i = t; i < kchunk; i += 128) {
        long xo = (long)n*xRow + k0 + i;
        Xs[0][i] = X[0*xBatch + xo];
        Xs[1][i] = X[1*xBatch + xo];
        Xs[2][i] = X[2*xBatch + xo];
        Xs[3][i] = X[3*xBatch + xo];
    }
    __syncthreads();
    const float* Wp = W + (long)n*K*N + (long)k0*N + o4;
    float acc[4][4];
    #pragma unroll
    for (int b = 0; b < 4; b++)
        #pragma unroll
        for (int j = 0; j < 4; j++) acc[b][j] = 0.f;
    #pragma unroll 8
    for (int k = 0; k < kchunk; k++) {
        float4 wv = *reinterpret_cast<const float4*>(Wp + (long)k*N);
        #pragma unroll
        for (int b = 0; b < 4; b++) {
            float xv = Xs[b][k];
            acc[b][0] += xv*wv.x; acc[b][1] += xv*wv.y;
            acc[b][2] += xv*wv.z; acc[b][3] += xv*wv.w;
        }
    }
    #pragma unroll
    for (int b = 0; b < 4; b++)
        *reinterpret_cast<float4*>(&part[((long)(z*BSZ+b)*NSN + n)*N + o4]) =
            make_float4(acc[b][0], acc[b][1], acc[b][2], acc[b][3]);
}

__global__ __launch_bounds__(256) void ns_reduce_kernel(
    const float* __restrict__ part, const float* __restrict__ bias,
    float* __restrict__ Y, long yBatch, int yRow, int N, int KS, int relu, int roundOut)
{
    int o = blockIdx.x*256 + threadIdx.x;
    int n = blockIdx.y, b = blockIdx.z;
    float s = bias[(long)n*N + o];
    for (int z = 0; z < KS; z++)
        s += part[((long)(z*BSZ+b)*NSN + n)*N + o];
    if (relu) s = fmaxf(s, 0.f);
    if (roundOut) s = rtf32(s);
    Y[(long)b*yBatch + (long)n*yRow + o] = s;
}

// ---------------- RoPE in-place (fp32 path, rounded output) ----------------
__global__ void rope_kernel(float* __restrict__ buf, int rowsPerB, int pos0, int rstride, int total) {
    int idx = blockIdx.x*blockDim.x + threadIdx.x;
    if (idx >= total) return;
    int j  = idx & 31;
    int h  = (idx >> 5) & (NH-1);
    int rr = idx >> 9;
    int b  = rr / rowsPerB;
    int r  = rr - b*rowsPerB;
    float inv = exp2f(-(float)j * 0.41524101186092029f);
    double ang = (double)(pos0 + r) * (double)inv;
    const double TWO_PI = 6.2831853071795864769;
    double red = ang - TWO_PI * rint(ang * (1.0/6.2831853071795864769));
    float rf = (float)red;
    float s, c;
    sincosf(rf, &s, &c);
    float* base = buf + ((long)b*rowsPerB + r)*(long)rstride + h*HD;
    float x1 = base[j], x2 = base[j+32];
    base[j]    = rtf32(x1*c - x2*s);
    base[j+32] = rtf32(x2*c + x1*s);
}

// ---------------- tensor-core flash attention (tf32), 2-stage cp.async KV prefetch -------
// Inputs q/kv are pre-rounded to tf32 values.
__global__ __launch_bounds__(256) void attn_mma_kernel(
    const float* __restrict__ q, const float* __restrict__ kv,
    float* __restrict__ attn, const int* __restrict__ seqlen)
{
    __shared__ float qs [64][68];
    __shared__ float ksm[2][32][68];
    __shared__ float vsm[2][32][72];
    __shared__ float ssm[64][36];
    __shared__ float corrs[64];
    __shared__ float lrow[64];

    int qt = blockIdx.x, h = blockIdx.y, b = blockIdx.z;
    int tid = threadIdx.x;
    int w = tid >> 5, lane = tid & 31;
    int g = lane >> 2, tig = lane & 3;
    int wm = w >> 2, wn = w & 3;
    int L = seqlen[b];
    int kmin = MAXS - L;

    for (int i = tid; i < 64*16; i += 256) {
        int r = i >> 4, c4 = (i & 15) * 4;
        int qg = qt*64 + r;
        float4 val = make_float4(0.f,0.f,0.f,0.f);
        if (qg < QLEN)
            val = *reinterpret_cast<const float4*>(q + ((long)b*QLEN + qg)*DM + h*HD + c4);
        *reinterpret_cast<float4*>(&qs[r][c4]) = val;
    }

    int srow = tid >> 2, ssub = tid & 3;
    float m = -1e30f, l = 0.f;

    float oacc[2][2][4];
    #pragma unroll
    for (int i = 0; i < 2; i++)
        #pragma unroll
        for (int j = 0; j < 2; j++)
            #pragma unroll
            for (int r = 0; r < 4; r++) oacc[i][j][r] = 0.f;

    int qgmax = min(QLEN-1, qt*64 + 63);
    int t0 = kmin >> 5;
    int t1 = (MAXS - OUTN + qgmax) >> 5;

    uint32_t ksmA0 = (uint32_t)__cvta_generic_to_shared(&ksm[0][0][0]);
    uint32_t vsmA0 = (uint32_t)__cvta_generic_to_shared(&vsm[0][0][0]);

    // cp.async loader: tile kt into buffer kt&1. 1024 16B chunks / 256 threads = 4 each.
    auto loadTile = [&](int kt) {
        int buf = kt & 1;
        int key0 = kt * 32;
        #pragma unroll
        for (int it = 0; it < 2; it++) {
            int i = tid + it*256;             // 0..511 : k then v split by half
            int r = (i >> 4) & 31;            // row 0..31
            int c4 = (i & 15) * 4;
            int key = key0 + r;
            long off = ((long)b*TOTAL + min(key, TOTAL-1))*(2*DM) + h*HD + c4;
            // k chunk
            cpa16(ksmA0 + (buf*32*68 + r*68 + c4)*4, kv + off);
            // v chunk
            cpa16(vsmA0 + (buf*32*72 + r*72 + c4)*4, kv + off + DM);
        }
        asm volatile("cp.async.commit_group;");
    };
    loadTile(t0);
    asm volatile("cp.async.commit_group;");   // keep group count consistent (empty group)

    for (int kt = t0; kt <= t1; kt++) {
        int key0 = kt * 32;
        int buf = kt & 1;
        asm volatile("cp.async.wait_group 1;");
        __syncthreads();
        if (kt + 1 <= t1) loadTile(kt + 1);
        else              asm volatile("cp.async.commit_group;");

        float sa[2][4];
        #pragma unroll
        for (int mt = 0; mt < 2; mt++)
            #pragma unroll
            for (int r = 0; r < 4; r++) sa[mt][r] = 0.f;
        #pragma unroll
        for (int dk = 0; dk < 8; dk++) {
            uint32_t bf0 = f2u(ksm[buf][wn*8 + g][dk*8 + tig]);
            uint32_t bf1 = f2u(ksm[buf][wn*8 + g][dk*8 + tig + 4]);
            #pragma unroll
            for (int mt = 0; mt < 2; mt++) {
                int m0 = wm*32 + mt*16;
                mma_tf32(sa[mt],
                    f2u(qs[m0+g][dk*8+tig]),   f2u(qs[m0+g+8][dk*8+tig]),
                    f2u(qs[m0+g][dk*8+tig+4]), f2u(qs[m0+g+8][dk*8+tig+4]),
                    bf0, bf1);
            }
        }
        #pragma unroll
        for (int mt = 0; mt < 2; mt++) {
            #pragma unroll
            for (int hh = 0; hh < 2; hh++) {
                int r = wm*32 + mt*16 + g + hh*8;
                int qg = qt*64 + r;
                int key = key0 + wn*8 + 2*tig;
                int kcap = MAXS - OUTN + qg;
                bool rowok = (qg < QLEN);
                float sA = sa[mt][hh*2+0], sB = sa[mt][hh*2+1];
                bool v0 = rowok && (key   < TOTAL) && (key   >= kmin) && (key   <= kcap);
                bool v1 = rowok && (key+1 < TOTAL) && (key+1 >= kmin) && (key+1 <= kcap);
                ssm[r][wn*8 + 2*tig]     = v0 ? sA*0.125f : -1e9f;
                ssm[r][wn*8 + 2*tig + 1] = v1 ? sB*0.125f : -1e9f;
            }
        }
        __syncthreads();

        float sv[8];
        #pragma unroll
        for (int j = 0; j < 8; j++) sv[j] = ssm[srow][ssub*8 + j];
        float tmax = sv[0];
        #pragma unroll
        for (int j = 1; j < 8; j++) tmax = fmaxf(tmax, sv[j]);
        tmax = fmaxf(tmax, __shfl_xor_sync(0xffffffffu, tmax, 1));
        tmax = fmaxf(tmax, __shfl_xor_sync(0xffffffffu, tmax, 2));
        float corr = 1.f;
        if (tmax > -1e8f) {
            float m_new = fmaxf(m, tmax);
            corr = __expf(m - m_new);
            float ps = 0.f;
            #pragma unroll
            for (int j = 0; j < 8; j++) {
                float p = __expf(sv[j] - m_new);
                ps += p;
                ssm[srow][ssub*8 + j] = rtf32(p);
            }
            ps += __shfl_xor_sync(0xffffffffu, ps, 1);
            ps += __shfl_xor_sync(0xffffffffu, ps, 2);
            l = l*corr + ps;
            m = m_new;
        } else {
            #pragma unroll
            for (int j = 0; j < 8; j++) ssm[srow][ssub*8 + j] = 0.f;
        }
        if (ssub == 0) corrs[srow] = corr;
        __syncthreads();

        #pragma unroll
        for (int mt = 0; mt < 2; mt++) {
            float c0 = corrs[wm*32 + mt*16 + g];
            float c1 = corrs[wm*32 + mt*16 + g + 8];
            #pragma unroll
            for (int nt = 0; nt < 2; nt++) {
                oacc[mt][nt][0] *= c0; oacc[mt][nt][1] *= c0;
                oacc[mt][nt][2] *= c1; oacc[mt][nt][3] *= c1;
            }
        }
        #pragma unroll
        for (int kd = 0; kd < 4; kd++) {
            uint32_t bf[2][2];
            #pragma unroll
            for (int nt = 0; nt < 2; nt++) {
                int n = wn*16 + nt*8 + g;
                bf[nt][0] = f2u(vsm[buf][kd*8 + tig][n]);
                bf[nt][1] = f2u(vsm[buf][kd*8 + tig + 4][n]);
            }
            #pragma unroll
            for (int mt = 0; mt < 2; mt++) {
                int m0 = wm*32 + mt*16;
                uint32_t a0 = f2u(ssm[m0+g][kd*8+tig]);
                uint32_t a1 = f2u(ssm[m0+g+8][kd*8+tig]);
                uint32_t a2 = f2u(ssm[m0+g][kd*8+tig+4]);
                uint32_t a3 = f2u(ssm[m0+g+8][kd*8+tig+4]);
                #pragma unroll
                for (int nt = 0; nt < 2; nt++)
                    mma_tf32(oacc[mt][nt], a0, a1, a2, a3, bf[nt][0], bf[nt][1]);
            }
        }
        __syncthreads();   // protect ssm reuse + buffer handoff next iteration
    }

    if (ssub == 0) lrow[srow] = l;
    __syncthreads();
    #pragma unroll
    for (int mt = 0; mt < 2; mt++) {
        #pragma unroll
        for (int hh = 0; hh < 2; hh++) {
            int r = wm*32 + mt*16 + g + hh*8;
            int qg = qt*64 + r;
            if (qg < QLEN) {
                float invl = 1.f / lrow[r];
                #pragma unroll
                for (int nt = 0; nt < 2; nt++) {
                    int col = wn*16 + nt*8 + 2*tig;
                    *reinterpret_cast<float2*>(attn + ((long)b*QLEN + qg)*DM + h*HD + col)
                        = make_float2(oacc[mt][nt][hh*2]*invl, oacc[mt][nt][hh*2+1]*invl);
                }
            }
        }
    }
}

// ---------------- final assembly ----------------
__global__ void assemble_kernel(float* __restrict__ out, const int* __restrict__ seqlen, int out_size) {
    int idx = blockIdx.x*blockDim.x + threadIdx.x;
    const int main_n = BSZ*QLEN*DM;
    if (idx < main_n) {
        int b = idx / (QLEN*DM);
        int rem = idx - b*(QLEN*DM);
        int r = rem / DM;
        int d = rem - r*DM;
        float f;
        if (r < OUTN) f = g_fs [((long)b*OUTN + r)*DM + d];
        else          f = g_fns[((long)b*NSN + (r - OUTN))*DM + d];
        out[idx] = f + g_h1[idx];
    }
    if (idx < BSZ && out_size >= main_n + BSZ) {
        int L = seqlen[idx];
        out[main_n + idx] = (float)(L < OUTN ? L : OUTN);
    }
}

extern "C" void kernel_launch(void* const* d_in, const int* in_sizes, int n_in,
                              void* d_out, int out_size) {
    (void)in_sizes; (void)n_in;
    const float* x    = (const float*)d_in[0];
    const int*   seq  = (const int*)  d_in[1];
    const float* wqkv = (const float*)d_in[2];
    const float* bqkv = (const float*)d_in[3];
    const float* wnsq = (const float*)d_in[4];
    const float* bnsq = (const float*)d_in[5];
    const float* wnsk = (const float*)d_in[6];
    const float* bnsk = (const float*)d_in[7];
    const float* wnsv = (const float*)d_in[8];
    const float* bnsv = (const float*)d_in[9];
    const float* n1w  = (const float*)d_in[10];
    const float* n2w  = (const float*)d_in[11];
    const float* fw1  = (const float*)d_in[12];
    const float* fb1  = (const float*)d_in[13];
    const float* fw2  = (const float*)d_in[14];
    const float* fb2  = (const float*)d_in[15];
    const float* w1ns = (const float*)d_in[16];
    const float* b1ns = (const float*)d_in[17];
    const float* w2ns = (const float*)d_in[18];
    const float* b2ns = (const float*)d_in[19];
    float* out = (float*)d_out;

    float *xn,*q,*kv,*attn,*hn,*ts,*tns,*fs,*fns,*part,*wq_t,*w1t,*w2t;
    cudaGetSymbolAddress((void**)&xn,   g_xn);
    cudaGetSymbolAddress((void**)&q,    g_q);
    cudaGetSymbolAddress((void**)&kv,   g_kv);
    cudaGetSymbolAddress((void**)&attn, g_attn);
    cudaGetSymbolAddress((void**)&hn,   g_hn);
    cudaGetSymbolAddress((void**)&ts,   g_ts);
    cudaGetSymbolAddress((void**)&tns,  g_tns);
    cudaGetSymbolAddress((void**)&fs,   g_fs);
    cudaGetSymbolAddress((void**)&fns,  g_fns);
    cudaGetSymbolAddress((void**)&part, g_part);
    cudaGetSymbolAddress((void**)&wq_t, g_wqkv);
    cudaGetSymbolAddress((void**)&w1t,  g_w1);
    cudaGetSymbolAddress((void**)&w2t,  g_w2);
    float* part2 = part + 2*1024*1024;

    const long aB  = (long)TOTAL*DM;
    const long qB  = (long)QLEN*DM;
    const long kvB = (long)TOTAL*2*DM;

    const int SMEM128 = (3*128*36 + 3*128*36) * 4;
    const int SMEM64  = (3*64*36  + 3*128*36) * 4;
    cudaFuncSetAttribute(mma_gemmT_kernel<128>, cudaFuncAttributeMaxDynamicSharedMemorySize, SMEM128);
    cudaFuncSetAttribute(mma_gemmT_kernel<64>,  cudaFuncAttributeMaxDynamicSharedMemorySize, SMEM64);

    static cudaStream_t s1 = nullptr, s2 = nullptr, s3 = nullptr;
    static cudaEvent_t  e0, e1, e2, e3, e4, e5;
    if (s1 == nullptr) {
        cudaStreamCreateWithFlags(&s1, cudaStreamNonBlocking);
        cudaStreamCreateWithFlags(&s2, cudaStreamNonBlocking);
        cudaStreamCreateWithFlags(&s3, cudaStreamNonBlocking);
        cudaEventCreateWithFlags(&e0, cudaEventDisableTiming);
        cudaEventCreateWithFlags(&e1, cudaEventDisableTiming);
        cudaEventCreateWithFlags(&e2, cudaEventDisableTiming);
        cudaEventCreateWithFlags(&e3, cudaEventDisableTiming);
        cudaEventCreateWithFlags(&e4, cudaEventDisableTiming);
        cudaEventCreateWithFlags(&e5, cudaEventDisableTiming);
    }
    cudaStream_t s0 = 0;

    // ---- Phase 1 ----
    transpose_tf32_kernel<<<dim3(3*DM/32, DM/32), dim3(32,8), 0, s0>>>(wqkv, wq_t, DM, 3*DM);
    rmsnorm_kernel<<<BSZ*TOTAL, 256, 0, s0>>>(x, n1w, xn);
    cudaEventRecord(e0, s0);

    cudaStreamWaitEvent(s2, e0, 0);
    transpose_tf32_kernel<<<dim3(FFND/32, DM/32), dim3(32,8), 0, s2>>>(fw1, w1t, DM, FFND);
    transpose_tf32_kernel<<<dim3(DM/32, FFND/32), dim3(32,8), 0, s2>>>(fw2, w2t, FFND, DM);
    cudaEventRecord(e2, s2);

    // s1: Q projection (rounded) -> ns_q (rounded) -> rope_q
    cudaStreamWaitEvent(s1, e0, 0);
    mma_gemmT_kernel<64><<<dim3(DM/128, (BSZ*OUTN)/64), 256, SMEM64, s1>>>(
        xn + (long)(MAXS-OUTN)*DM, DM, aB, OUTN, wq_t, DM, bqkv, q, DM, qB, DM, 0, 1, seq, 0);
    ns_split4_kernel<<<dim3(DM/512, NSN, 32), 128, 0, s1>>>(xn + (long)MAXS*DM, aB, DM, wnsq, part2, DM, DM, DM/32);
    ns_reduce_kernel<<<dim3(DM/256, NSN, BSZ), 256, 0, s1>>>(part2, bnsq, q + (long)OUTN*DM, qB, DM, DM, 32, 0, 1);
    {
        int totq = BSZ*QLEN*NH*32;
        rope_kernel<<<(totq+255)/256, 256, 0, s1>>>(q, QLEN, TOTAL-QLEN, DM, totq);
    }
    cudaEventRecord(e1, s1);

    // s3: ns_v then ns_k (rounded outputs)
    cudaStreamWaitEvent(s3, e0, 0);
    ns_split4_kernel<<<dim3(DM/512, NSN, 32), 128, 0, s3>>>(xn + (long)MAXS*DM, aB, DM, wnsv, part, DM, DM, DM/32);
    ns_reduce_kernel<<<dim3(DM/256, NSN, BSZ), 256, 0, s3>>>(part, bnsv, kv + (long)MAXS*2*DM + DM, kvB, 2*DM, DM, 32, 0, 1);
    ns_split4_kernel<<<dim3(DM/512, NSN, 32), 128, 0, s3>>>(xn + (long)MAXS*DM, aB, DM, wnsk, part, DM, DM, DM/32);
    ns_reduce_kernel<<<dim3(DM/256, NSN, BSZ), 256, 0, s3>>>(part, bnsk, kv + (long)MAXS*2*DM, kvB, 2*DM, DM, 32, 0, 1);
    cudaEventRecord(e3, s3);

    // s0: KV projection (rounded output), then rope_k
    mma_gemmT_kernel<128><<<dim3(2*DM/128, (BSZ*MAXS)/128), 256, SMEM128, s0>>>(xn, DM, aB, MAXS,
        wq_t + (long)DM*DM, DM, bqkv + DM, kv, 2*DM, kvB, DM, 0, 1, seq, 1);
    cudaStreamWaitEvent(s0, e3, 0);
    {
        int totk = BSZ*TOTAL*NH*32;
        rope_kernel<<<(totk+255)/256, 256, 0, s0>>>(kv, TOTAL, 0, 2*DM, totk);
    }

    cudaStreamWaitEvent(s0, e1, 0);
    attn_mma_kernel<<<dim3((QLEN+63)/64, NH, BSZ), 256, 0, s0>>>(q, kv, attn, seq);

    add_rmsnorm_kernel<<<BSZ*QLEN, 256, 0, s0>>>(x, n2w);
    cudaEventRecord(e4, s0);

    // ---- Phase 2 ----
    cudaStreamWaitEvent(s1, e4, 0);
    ns_split4_kernel<<<dim3(FFND/512, NSN, 16), 128, 0, s1>>>(hn + (long)OUTN*DM, qB, DM, w1ns, part, DM, FFND, DM/16);
    ns_reduce_kernel<<<dim3(FFND/256, NSN, BSZ), 256, 0, s1>>>(part, b1ns, tns, (long)NSN*FFND, FFND, FFND, 16, 1, 0);
    ns_split4_kernel<<<dim3(DM/512, NSN, 32), 128, 0, s1>>>(tns, (long)NSN*FFND, FFND, w2ns, part, FFND, DM, FFND/32);
    ns_reduce_kernel<<<dim3(DM/256, NSN, BSZ), 256, 0, s1>>>(part, b2ns, fns, (long)NSN*DM, DM, DM, 32, 0, 0);
    cudaEventRecord(e5, s1);

    cudaStreamWaitEvent(s0, e2, 0);
    mma_gemmT_kernel<128><<<dim3(FFND/128, (BSZ*OUTN)/128), 256, SMEM128, s0>>>(hn, DM, qB, OUTN,
        w1t, DM, fb1, ts, FFND, (long)OUTN*FFND, DM, 1, 1, seq, 0);
    mma_gemmT_kernel<64><<<dim3(DM/128, (BSZ*OUTN)/64), 256, SMEM64, s0>>>(ts, FFND, (long)OUTN*FFND, OUTN,
        w2t, FFND, fb2, fs, DM, (long)OUTN*DM, FFND, 0, 0, seq, 0);

    cudaStreamWaitEvent(s0, e5, 0);
    assemble_kernel<<<(BSZ*QLEN*DM + 255)/256, 256, 0, s0>>>(out, seq, out_size);
}

// round 12
// speedup vs baseline: 7.6506x; 1.2823x over previous
#include <cuda_runtime.h>
#include <cuda_bf16.h>
#include <cstdint>

#define BSZ   4
#define TOTAL 2064
#define DM    1024
#define NSN   16
#define OUTN  256
#define QLEN  272
#define NH    16
#define HD    64
#define FFND  4096
#define MAXS  2048

// Scratch (static device globals; no allocation allowed)
__device__ float g_xn  [BSZ*TOTAL*DM];
__device__ float g_q   [BSZ*QLEN*DM];
__device__ float g_kv  [BSZ*TOTAL*2*DM];
__device__ float g_attn[BSZ*QLEN*DM];
__device__ float g_h1  [BSZ*QLEN*DM];
__device__ float g_hn  [BSZ*QLEN*DM];
__device__ float g_tns [BSZ*NSN*FFND];
__device__ float g_fs  [BSZ*OUTN*DM];
__device__ float g_fns [BSZ*NSN*DM];
__device__ float g_part[4*1024*1024];
// bf16 activations + transposed bf16 weights ([N,K] row-major)
__device__ __nv_bfloat16 g_xnb [BSZ*TOTAL*DM];
__device__ __nv_bfloat16 g_hnb [BSZ*QLEN*DM];
__device__ __nv_bfloat16 g_tsb [BSZ*OUTN*FFND];
__device__ __nv_bfloat16 g_wqkvb[3*DM*DM];
__device__ __nv_bfloat16 g_w1b  [FFND*DM];
__device__ __nv_bfloat16 g_w2b  [DM*FFND];

__device__ __forceinline__ float rtf32(float x) {
    uint32_t u;
    asm("cvt.rna.tf32.f32 %0, %1;" : "=r"(u) : "f"(x));
    return __uint_as_float(u);
}
__device__ __forceinline__ uint32_t f2u(float x) { return __float_as_uint(x); }

__device__ __forceinline__ void cpa16(uint32_t dst, const void* src) {
    asm volatile("cp.async.ca.shared.global [%0], [%1], 16;" :: "r"(dst), "l"(src));
}

__device__ __forceinline__ void mma_tf32(float* c,
        uint32_t a0, uint32_t a1, uint32_t a2, uint32_t a3,
        uint32_t b0, uint32_t b1) {
    asm volatile(
        "mma.sync.aligned.m16n8k8.row.col.f32.tf32.tf32.f32 "
        "{%0,%1,%2,%3}, {%4,%5,%6,%7}, {%8,%9}, {%0,%1,%2,%3};\n"
        : "+f"(c[0]), "+f"(c[1]), "+f"(c[2]), "+f"(c[3])
        : "r"(a0), "r"(a1), "r"(a2), "r"(a3), "r"(b0), "r"(b1));
}
__device__ __forceinline__ void mma_bf16(float* c,
        uint32_t a0, uint32_t a1, uint32_t a2, uint32_t a3,
        uint32_t b0, uint32_t b1) {
    asm volatile(
        "mma.sync.aligned.m16n8k16.row.col.f32.bf16.bf16.f32 "
        "{%0,%1,%2,%3}, {%4,%5,%6,%7}, {%8,%9}, {%0,%1,%2,%3};\n"
        : "+f"(c[0]), "+f"(c[1]), "+f"(c[2]), "+f"(c[3])
        : "r"(a0), "r"(a1), "r"(a2), "r"(a3), "r"(b0), "r"(b1));
}

__device__ __forceinline__ void ldsm4(uint32_t* r, uint32_t addr) {
    asm volatile("ldmatrix.sync.aligned.m8n8.x4.shared.b16 {%0,%1,%2,%3}, [%4];"
        : "=r"(r[0]), "=r"(r[1]), "=r"(r[2]), "=r"(r[3]) : "r"(addr));
}

// ---------------- transpose + bf16 convert: out[c*R + r] = bf16(in[r*C + c]) ----------------
__global__ __launch_bounds__(256) void transpose_bf16_kernel(const float* __restrict__ in,
        __nv_bfloat16* __restrict__ out, int R, int C) {
    __shared__ float tile[32][33];
    int c0 = blockIdx.x*32, r0 = blockIdx.y*32;
    int tx = threadIdx.x, ty = threadIdx.y;
    for (int i = ty; i < 32; i += 8)
        tile[i][tx] = in[(long)(r0+i)*C + c0 + tx];
    __syncthreads();
    for (int i = ty; i < 32; i += 8)
        out[(long)(c0+i)*R + r0 + tx] = __float2bfloat16_rn(tile[tx][i]);
}

// ---------------- rmsnorm: fp32 out (tf32-rounded, for NS) + bf16 out (for GEMMs) ----------
__global__ __launch_bounds__(256) void rmsnorm_kernel(const float* __restrict__ in,
        const float* __restrict__ w, float* __restrict__ outf,
        __nv_bfloat16* __restrict__ outb) {
    long row = blockIdx.x;
    int t = threadIdx.x;
    float4 v = reinterpret_cast<const float4*>(in + row*DM)[t];
    float ss = v.x*v.x + v.y*v.y + v.z*v.z + v.w*v.w;
    __shared__ float red[8];
    for (int o = 16; o; o >>= 1) ss += __shfl_xor_sync(0xffffffffu, ss, o);
    if ((t & 31) == 0) red[t >> 5] = ss;
    __syncthreads();
    if (t < 32) {
        float s = (t < 8) ? red[t] : 0.f;
        for (int o = 4; o; o >>= 1) s += __shfl_xor_sync(0xffffffffu, s, o);
        if (t == 0) red[0] = s;
    }
    __syncthreads();
    float rs = rsqrtf(red[0] * (1.f/DM) + 1e-6f);
    float4 wv = reinterpret_cast<const float4*>(w)[t];
    float p0 = v.x*rs*wv.x, p1 = v.y*rs*wv.y, p2 = v.z*rs*wv.z, p3 = v.w*rs*wv.w;
    reinterpret_cast<float4*>(outf + row*DM)[t] =
        make_float4(rtf32(p0), rtf32(p1), rtf32(p2), rtf32(p3));
    __nv_bfloat162 b01, b23;
    b01.x = __float2bfloat16_rn(p0); b01.y = __float2bfloat16_rn(p1);
    b23.x = __float2bfloat16_rn(p2); b23.y = __float2bfloat16_rn(p3);
    reinterpret_cast<__nv_bfloat162*>(outb + row*DM)[t*2]   = b01;
    reinterpret_cast<__nv_bfloat162*>(outb + row*DM)[t*2+1] = b23;
}

// ---------------- h1 = x + attn ; hn (fp32 + bf16) ----------------
__global__ __launch_bounds__(256) void add_rmsnorm_kernel(const float* __restrict__ x,
        const float* __restrict__ w) {
    int row = blockIdx.x;
    int b = row / QLEN, r = row - b*QLEN;
    int t = threadIdx.x;
    float4 xv = reinterpret_cast<const float4*>(x + ((long)b*TOTAL + (TOTAL-QLEN) + r)*DM)[t];
    float4 av = reinterpret_cast<const float4*>(g_attn + (long)row*DM)[t];
    float4 hv = make_float4(xv.x+av.x, xv.y+av.y, xv.z+av.z, xv.w+av.w);
    reinterpret_cast<float4*>(g_h1 + (long)row*DM)[t] = hv;
    float ss = hv.x*hv.x + hv.y*hv.y + hv.z*hv.z + hv.w*hv.w;
    __shared__ float red[8];
    for (int o = 16; o; o >>= 1) ss += __shfl_xor_sync(0xffffffffu, ss, o);
    if ((t & 31) == 0) red[t >> 5] = ss;
    __syncthreads();
    if (t < 32) {
        float s = (t < 8) ? red[t] : 0.f;
        for (int o = 4; o; o >>= 1) s += __shfl_xor_sync(0xffffffffu, s, o);
        if (t == 0) red[0] = s;
    }
    __syncthreads();
    float rs = rsqrtf(red[0] * (1.f/DM) + 1e-6f);
    float4 wv = reinterpret_cast<const float4*>(w)[t];
    float p0 = hv.x*rs*wv.x, p1 = hv.y*rs*wv.y, p2 = hv.z*rs*wv.z, p3 = hv.w*rs*wv.w;
    reinterpret_cast<float4*>(g_hn + (long)row*DM)[t] =
        make_float4(rtf32(p0), rtf32(p1), rtf32(p2), rtf32(p3));
    __nv_bfloat162 b01, b23;
    b01.x = __float2bfloat16_rn(p0); b01.y = __float2bfloat16_rn(p1);
    b23.x = __float2bfloat16_rn(p2); b23.y = __float2bfloat16_rn(p3);
    reinterpret_cast<__nv_bfloat162*>(g_hnb + (long)row*DM)[t*2]   = b01;
    reinterpret_cast<__nv_bfloat162*>(g_hnb + (long)row*DM)[t*2+1] = b23;
}

// ---------------- BF16 tensor-core GEMM, MTILEx128x32, 3-stage cp.async, LDSM frags --------
// A [M,K] bf16 row-major; Bt [N,K] bf16 row-major. C = A*Bt^T + bias (fp32 accum).
template<int MTILE>
__global__ __launch_bounds__(256, 2) void mma_gemmB_kernel(
    const __nv_bfloat16* __restrict__ A, int lda, long aBatch, int rpb,
    const __nv_bfloat16* __restrict__ Bt, int ldbt,
    const float* __restrict__ bias,
    void* __restrict__ Cv, int ldc, long cBatch,
    int K, int relu, int roundOut, int outBf16,
    const int* __restrict__ seqlen, int kvSkip)
{
    constexpr int S    = 3;
    constexpr int PAD  = 40;                 // bf16 elements; 80B row = 5x16B units (odd)
    constexpr int ASTG = MTILE*PAD;          // elements
    constexpr int BSTG = 128*PAD;
    constexpr int MT   = MTILE/32;
    extern __shared__ __nv_bfloat16 smb[];
    __nv_bfloat16* AsBase = smb;
    __nv_bfloat16* BsBase = smb + S*ASTG;

    int t = threadIdx.x;
    int w = t >> 5, lane = t & 31;
    int g = lane >> 2, tig = lane & 3;
    int wm = w >> 2, wn = w & 3;

    int row0 = blockIdx.y * MTILE;
    int bn0  = blockIdx.x * 128;
    int batch = row0 / rpb;
    int rin   = row0 % rpb;
    if (kvSkip) {
        int kmin = MAXS - seqlen[batch];
        if (rin + MTILE - 1 < kmin) return;
    }
    const __nv_bfloat16* Ab = A + (long)batch*aBatch + (long)rin*lda;
    const __nv_bfloat16* Bb = Bt + (long)bn0*ldbt;

    uint32_t aSm0 = (uint32_t)__cvta_generic_to_shared(AsBase);
    uint32_t bSm0 = (uint32_t)__cvta_generic_to_shared(BsBase);

    float acc[MT][4][4];
    #pragma unroll
    for (int i = 0; i < MT; i++)
        #pragma unroll
        for (int j = 0; j < 4; j++)
            #pragma unroll
            for (int r = 0; r < 4; r++) acc[i][j][r] = 0.f;

    const int KT = K >> 5;
    auto issue = [&](int kt) {
        int s = kt % S;
        const __nv_bfloat16* ga = Ab + kt*32;
        const __nv_bfloat16* gb = Bb + kt*32;
        uint32_t aS = aSm0 + s*ASTG*2;
        uint32_t bS = bSm0 + s*BSTG*2;
        #pragma unroll
        for (int it = 0; it < MTILE/64; it++) {
            int i = t + it*256;
            int row = i >> 2, seg = i & 3;              // 4 chunks of 8 bf16 per row
            cpa16(aS + (row*PAD + seg*8)*2, ga + (long)row*lda + seg*8);
        }
        #pragma unroll
        for (int it = 0; it < 2; it++) {
            int i = t + it*256;
            int row = i >> 2, seg = i & 3;
            cpa16(bS + (row*PAD + seg*8)*2, gb + (long)row*ldbt + seg*8);
        }
        asm volatile("cp.async.commit_group;");
    };
    issue(0);
    issue(1);

    int aRow  = lane & 15;
    int aColH = (lane >> 4) * 8;
    int bRowO = ((lane >> 4) & 1)*8 + (lane & 7);
    int bColH = ((lane >> 3) & 1)*8;

    for (int kt = 0; kt < KT; kt++) {
        if (kt == KT - 1) asm volatile("cp.async.wait_group 0;");
        else              asm volatile("cp.async.wait_group 1;");
        __syncthreads();
        if (kt + 2 < KT) issue(kt + 2);

        int s = kt % S;
        uint32_t As = aSm0 + s*ASTG*2;
        uint32_t Bs = bSm0 + s*BSTG*2;
        #pragma unroll
        for (int ks = 0; ks < 2; ks++) {
            uint32_t afr[MT][4];
            #pragma unroll
            for (int mt = 0; mt < MT; mt++)
                ldsm4(afr[mt], As + ((wm*(MTILE/2) + mt*16 + aRow)*PAD + ks*16 + aColH)*2);
            uint32_t bfr[4][2];
            #pragma unroll
            for (int p = 0; p < 2; p++) {
                uint32_t r4[4];
                ldsm4(r4, Bs + ((wn*32 + p*16 + bRowO)*PAD + ks*16 + bColH)*2);
                bfr[2*p][0]   = r4[0]; bfr[2*p][1]   = r4[1];
                bfr[2*p+1][0] = r4[2]; bfr[2*p+1][1] = r4[3];
            }
            #pragma unroll
            for (int mt = 0; mt < MT; mt++)
                #pragma unroll
                for (int nt = 0; nt < 4; nt++)
                    mma_bf16(acc[mt][nt], afr[mt][0], afr[mt][1], afr[mt][2], afr[mt][3],
                             bfr[nt][0], bfr[nt][1]);
        }
    }

    float* Cf = (float*)Cv;
    __nv_bfloat16* Cb = (__nv_bfloat16*)Cv;
    #pragma unroll
    for (int nt = 0; nt < 4; nt++) {
        int col = wn*32 + nt*8 + 2*tig;
        float bx = bias[bn0 + col], by = bias[bn0 + col + 1];
        #pragma unroll
        for (int mt = 0; mt < MT; mt++) {
            int r0 = wm*(MTILE/2) + mt*16 + g;
            long base0 = (long)batch*cBatch + (long)(rin + r0)*ldc + bn0 + col;
            long base1 = base0 + (long)8*ldc;
            float c0 = acc[mt][nt][0] + bx, c1 = acc[mt][nt][1] + by;
            float c2 = acc[mt][nt][2] + bx, c3 = acc[mt][nt][3] + by;
            if (relu) { c0=fmaxf(c0,0.f); c1=fmaxf(c1,0.f); c2=fmaxf(c2,0.f); c3=fmaxf(c3,0.f); }
            if (outBf16) {
                __nv_bfloat162 v0, v1;
                v0.x = __float2bfloat16_rn(c0); v0.y = __float2bfloat16_rn(c1);
                v1.x = __float2bfloat16_rn(c2); v1.y = __float2bfloat16_rn(c3);
                *reinterpret_cast<__nv_bfloat162*>(Cb + base0) = v0;
                *reinterpret_cast<__nv_bfloat162*>(Cb + base1) = v1;
            } else {
                if (roundOut) { c0=rtf32(c0); c1=rtf32(c1); c2=rtf32(c2); c3=rtf32(c3); }
                *reinterpret_cast<float2*>(Cf + base0) = make_float2(c0, c1);
                *reinterpret_cast<float2*>(Cf + base1) = make_float2(c2, c3);
            }
        }
    }
}

// ---------------- per-NS-position linear: vectorized K-split partials ----------------
__global__ __launch_bounds__(128) void ns_split4_kernel(
    const float* __restrict__ X, long xBatch, int xRow,
    const float* __restrict__ W, float* __restrict__ part,
    int K, int N, int kchunk)
{
    __shared__ float Xs[4][512];
    int n = blockIdx.y, z = blockIdx.z;
    int t = threadIdx.x;
    int o4 = (blockIdx.x*128 + t)*4;
    int k0 = z*kchunk;
    for (int i = t; i < kchunk; i += 128) {
        long xo = (long)n*xRow + k0 + i;
        Xs[0][i] = X[0*xBatch + xo];
        Xs[1][i] = X[1*xBatch + xo];
        Xs[2][i] = X[2*xBatch + xo];
        Xs[3][i] = X[3*xBatch + xo];
    }
    __syncthreads();
    const float* Wp = W + (long)n*K*N + (long)k0*N + o4;
    float acc[4][4];
    #pragma unroll
    for (int b = 0; b < 4; b++)
        #pragma unroll
        for (int j = 0; j < 4; j++) acc[b][j] = 0.f;
    #pragma unroll 8
    for (int k = 0; k < kchunk; k++) {
        float4 wv = *reinterpret_cast<const float4*>(Wp + (long)k*N);
        #pragma unroll
        for (int b = 0; b < 4; b++) {
            float xv = Xs[b][k];
            acc[b][0] += xv*wv.x; acc[b][1] += xv*wv.y;
            acc[b][2] += xv*wv.z; acc[b][3] += xv*wv.w;
        }
    }
    #pragma unroll
    for (int b = 0; b < 4; b++)
        *reinterpret_cast<float4*>(&part[((long)(z*BSZ+b)*NSN + n)*N + o4]) =
            make_float4(acc[b][0], acc[b][1], acc[b][2], acc[b][3]);
}

__global__ __launch_bounds__(256) void ns_reduce_kernel(
    const float* __restrict__ part, const float* __restrict__ bias,
    float* __restrict__ Y, long yBatch, int yRow, int N, int KS, int relu, int roundOut)
{
    int o = blockIdx.x*256 + threadIdx.x;
    int n = blockIdx.y, b = blockIdx.z;
    float s = bias[(long)n*N + o];
    for (int z = 0; z < KS; z++)
        s += part[((long)(z*BSZ+b)*NSN + n)*N + o];
    if (relu) s = fmaxf(s, 0.f);
    if (roundOut) s = rtf32(s);
    Y[(long)b*yBatch + (long)n*yRow + o] = s;
}

// ---------------- RoPE in-place (fp32 path, rounded output) ----------------
__global__ void rope_kernel(float* __restrict__ buf, int rowsPerB, int pos0, int rstride, int total) {
    int idx = blockIdx.x*blockDim.x + threadIdx.x;
    if (idx >= total) return;
    int j  = idx & 31;
    int h  = (idx >> 5) & (NH-1);
    int rr = idx >> 9;
    int b  = rr / rowsPerB;
    int r  = rr - b*rowsPerB;
    float inv = exp2f(-(float)j * 0.41524101186092029f);
    double ang = (double)(pos0 + r) * (double)inv;
    const double TWO_PI = 6.2831853071795864769;
    double red = ang - TWO_PI * rint(ang * (1.0/6.2831853071795864769));
    float rf = (float)red;
    float s, c;
    sincosf(rf, &s, &c);
    float* base = buf + ((long)b*rowsPerB + r)*(long)rstride + h*HD;
    float x1 = base[j], x2 = base[j+32];
    base[j]    = rtf32(x1*c - x2*s);
    base[j+32] = rtf32(x2*c + x1*s);
}

// ---------------- tensor-core flash attention (tf32), 2-stage cp.async KV prefetch -------
__global__ __launch_bounds__(256) void attn_mma_kernel(
    const float* __restrict__ q, const float* __restrict__ kv,
    float* __restrict__ attn, const int* __restrict__ seqlen)
{
    __shared__ float qs [64][68];
    __shared__ float ksm[2][32][68];
    __shared__ float vsm[2][32][72];
    __shared__ float ssm[64][36];
    __shared__ float corrs[64];
    __shared__ float lrow[64];

    int qt = blockIdx.x, h = blockIdx.y, b = blockIdx.z;
    int tid = threadIdx.x;
    int w = tid >> 5, lane = tid & 31;
    int g = lane >> 2, tig = lane & 3;
    int wm = w >> 2, wn = w & 3;
    int L = seqlen[b];
    int kmin = MAXS - L;

    for (int i = tid; i < 64*16; i += 256) {
        int r = i >> 4, c4 = (i & 15) * 4;
        int qg = qt*64 + r;
        float4 val = make_float4(0.f,0.f,0.f,0.f);
        if (qg < QLEN)
            val = *reinterpret_cast<const float4*>(q + ((long)b*QLEN + qg)*DM + h*HD + c4);
        *reinterpret_cast<float4*>(&qs[r][c4]) = val;
    }

    int srow = tid >> 2, ssub = tid & 3;
    float m = -1e30f, l = 0.f;

    float oacc[2][2][4];
    #pragma unroll
    for (int i = 0; i < 2; i++)
        #pragma unroll
        for (int j = 0; j < 2; j++)
            #pragma unroll
            for (int r = 0; r < 4; r++) oacc[i][j][r] = 0.f;

    int qgmax = min(QLEN-1, qt*64 + 63);
    int t0 = kmin >> 5;
    int t1 = (MAXS - OUTN + qgmax) >> 5;

    uint32_t ksmA0 = (uint32_t)__cvta_generic_to_shared(&ksm[0][0][0]);
    uint32_t vsmA0 = (uint32_t)__cvta_generic_to_shared(&vsm[0][0][0]);

    auto loadTile = [&](int kt) {
        int buf = kt & 1;
        int key0 = kt * 32;
        #pragma unroll
        for (int it = 0; it < 2; it++) {
            int i = tid + it*256;
            int r = (i >> 4) & 31;
            int c4 = (i & 15) * 4;
            int key = key0 + r;
            long off = ((long)b*TOTAL + min(key, TOTAL-1))*(2*DM) + h*HD + c4;
            cpa16(ksmA0 + (buf*32*68 + r*68 + c4)*4, kv + off);
            cpa16(vsmA0 + (buf*32*72 + r*72 + c4)*4, kv + off + DM);
        }
        asm volatile("cp.async.commit_group;");
    };
    loadTile(t0);
    asm volatile("cp.async.commit_group;");

    for (int kt = t0; kt <= t1; kt++) {
        int key0 = kt * 32;
        int buf = kt & 1;
        asm volatile("cp.async.wait_group 1;");
        __syncthreads();
        if (kt + 1 <= t1) loadTile(kt + 1);
        else              asm volatile("cp.async.commit_group;");

        float sa[2][4];
        #pragma unroll
        for (int mt = 0; mt < 2; mt++)
            #pragma unroll
            for (int r = 0; r < 4; r++) sa[mt][r] = 0.f;
        #pragma unroll
        for (int dk = 0; dk < 8; dk++) {
            uint32_t bf0 = f2u(ksm[buf][wn*8 + g][dk*8 + tig]);
            uint32_t bf1 = f2u(ksm[buf][wn*8 + g][dk*8 + tig + 4]);
            #pragma unroll
            for (int mt = 0; mt < 2; mt++) {
                int m0 = wm*32 + mt*16;
                mma_tf32(sa[mt],
                    f2u(qs[m0+g][dk*8+tig]),   f2u(qs[m0+g+8][dk*8+tig]),
                    f2u(qs[m0+g][dk*8+tig+4]), f2u(qs[m0+g+8][dk*8+tig+4]),
                    bf0, bf1);
            }
        }
        #pragma unroll
        for (int mt = 0; mt < 2; mt++) {
            #pragma unroll
            for (int hh = 0; hh < 2; hh++) {
                int r = wm*32 + mt*16 + g + hh*8;
                int qg = qt*64 + r;
                int key = key0 + wn*8 + 2*tig;
                int kcap = MAXS - OUTN + qg;
                bool rowok = (qg < QLEN);
                float sA = sa[mt][hh*2+0], sB = sa[mt][hh*2+1];
                bool v0 = rowok && (key   < TOTAL) && (key   >= kmin) && (key   <= kcap);
                bool v1 = rowok && (key+1 < TOTAL) && (key+1 >= kmin) && (key+1 <= kcap);
                ssm[r][wn*8 + 2*tig]     = v0 ? sA*0.125f : -1e9f;
                ssm[r][wn*8 + 2*tig + 1] = v1 ? sB*0.125f : -1e9f;
            }
        }
        __syncthreads();

        float sv[8];
        #pragma unroll
        for (int j = 0; j < 8; j++) sv[j] = ssm[srow][ssub*8 + j];
        float tmax = sv[0];
        #pragma unroll
        for (int j = 1; j < 8; j++) tmax = fmaxf(tmax, sv[j]);
        tmax = fmaxf(tmax, __shfl_xor_sync(0xffffffffu, tmax, 1));
        tmax = fmaxf(tmax, __shfl_xor_sync(0xffffffffu, tmax, 2));
        float corr = 1.f;
        if (tmax > -1e8f) {
            float m_new = fmaxf(m, tmax);
            corr = __expf(m - m_new);
            float ps = 0.f;
            #pragma unroll
            for (int j = 0; j < 8; j++) {
                float p = __expf(sv[j] - m_new);
                ps += p;
                ssm[srow][ssub*8 + j] = rtf32(p);
            }
            ps += __shfl_xor_sync(0xffffffffu, ps, 1);
            ps += __shfl_xor_sync(0xffffffffu, ps, 2);
            l = l*corr + ps;
            m = m_new;
        } else {
            #pragma unroll
            for (int j = 0; j < 8; j++) ssm[srow][ssub*8 + j] = 0.f;
        }
        if (ssub == 0) corrs[srow] = corr;
        __syncthreads();

        #pragma unroll
        for (int mt = 0; mt < 2; mt++) {
            float c0 = corrs[wm*32 + mt*16 + g];
            float c1 = corrs[wm*32 + mt*16 + g + 8];
            #pragma unroll
            for (int nt = 0; nt < 2; nt++) {
                oacc[mt][nt][0] *= c0; oacc[mt][nt][1] *= c0;
                oacc[mt][nt][2] *= c1; oacc[mt][nt][3] *= c1;
            }
        }
        #pragma unroll
        for (int kd = 0; kd < 4; kd++) {
            uint32_t bf[2][2];
            #pragma unroll
            for (int nt = 0; nt < 2; nt++) {
                int n = wn*16 + nt*8 + g;
                bf[nt][0] = f2u(vsm[buf][kd*8 + tig][n]);
                bf[nt][1] = f2u(vsm[buf][kd*8 + tig + 4][n]);
            }
            #pragma unroll
            for (int mt = 0; mt < 2; mt++) {
                int m0 = wm*32 + mt*16;
                uint32_t a0 = f2u(ssm[m0+g][kd*8+tig]);
                uint32_t a1 = f2u(ssm[m0+g+8][kd*8+tig]);
                uint32_t a2 = f2u(ssm[m0+g][kd*8+tig+4]);
                uint32_t a3 = f2u(ssm[m0+g+8][kd*8+tig+4]);
                #pragma unroll
                for (int nt = 0; nt < 2; nt++)
                    mma_tf32(oacc[mt][nt], a0, a1, a2, a3, bf[nt][0], bf[nt][1]);
            }
        }
        __syncthreads();
    }

    if (ssub == 0) lrow[srow] = l;
    __syncthreads();
    #pragma unroll
    for (int mt = 0; mt < 2; mt++) {
        #pragma unroll
        for (int hh = 0; hh < 2; hh++) {
            int r = wm*32 + mt*16 + g + hh*8;
            int qg = qt*64 + r;
            if (qg < QLEN) {
                float invl = 1.f / lrow[r];
                #pragma unroll
                for (int nt = 0; nt < 2; nt++) {
                    int col = wn*16 + nt*8 + 2*tig;
                    *reinterpret_cast<float2*>(attn + ((long)b*QLEN + qg)*DM + h*HD + col)
                        = make_float2(oacc[mt][nt][hh*2]*invl, oacc[mt][nt][hh*2+1]*invl);
                }
            }
        }
    }
}

// ---------------- final assembly ----------------
__global__ void assemble_kernel(float* __restrict__ out, const int* __restrict__ seqlen, int out_size) {
    int idx = blockIdx.x*blockDim.x + threadIdx.x;
    const int main_n = BSZ*QLEN*DM;
    if (idx < main_n) {
        int b = idx / (QLEN*DM);
        int rem = idx - b*(QLEN*DM);
        int r = rem / DM;
        int d = rem - r*DM;
        float f;
        if (r < OUTN) f = g_fs [((long)b*OUTN + r)*DM + d];
        else          f = g_fns[((long)b*NSN + (r - OUTN))*DM + d];
        out[idx] = f + g_h1[idx];
    }
    if (idx < BSZ && out_size >= main_n + BSZ) {
        int L = seqlen[idx];
        out[main_n + idx] = (float)(L < OUTN ? L : OUTN);
    }
}

extern "C" void kernel_launch(void* const* d_in, const int* in_sizes, int n_in,
                              void* d_out, int out_size) {
    (void)in_sizes; (void)n_in;
    const float* x    = (const float*)d_in[0];
    const int*   seq  = (const int*)  d_in[1];
    const float* wqkv = (const float*)d_in[2];
    const float* bqkv = (const float*)d_in[3];
    const float* wnsq = (const float*)d_in[4];
    const float* bnsq = (const float*)d_in[5];
    const float* wnsk = (const float*)d_in[6];
    const float* bnsk = (const float*)d_in[7];
    const float* wnsv = (const float*)d_in[8];
    const float* bnsv = (const float*)d_in[9];
    const float* n1w  = (const float*)d_in[10];
    const float* n2w  = (const float*)d_in[11];
    const float* fw1  = (const float*)d_in[12];
    const float* fb1  = (const float*)d_in[13];
    const float* fw2  = (const float*)d_in[14];
    const float* fb2  = (const float*)d_in[15];
    const float* w1ns = (const float*)d_in[16];
    const float* b1ns = (const float*)d_in[17];
    const float* w2ns = (const float*)d_in[18];
    const float* b2ns = (const float*)d_in[19];
    float* out = (float*)d_out;

    float *xn,*q,*kv,*attn,*hn,*tns,*fs,*fns,*part;
    __nv_bfloat16 *xnb,*hnb,*tsb,*wqb,*w1b,*w2b;
    cudaGetSymbolAddress((void**)&xn,   g_xn);
    cudaGetSymbolAddress((void**)&q,    g_q);
    cudaGetSymbolAddress((void**)&kv,   g_kv);
    cudaGetSymbolAddress((void**)&attn, g_attn);
    cudaGetSymbolAddress((void**)&hn,   g_hn);
    cudaGetSymbolAddress((void**)&tns,  g_tns);
    cudaGetSymbolAddress((void**)&fs,   g_fs);
    cudaGetSymbolAddress((void**)&fns,  g_fns);
    cudaGetSymbolAddress((void**)&part, g_part);
    cudaGetSymbolAddress((void**)&xnb,  g_xnb);
    cudaGetSymbolAddress((void**)&hnb,  g_hnb);
    cudaGetSymbolAddress((void**)&tsb,  g_tsb);
    cudaGetSymbolAddress((void**)&wqb,  g_wqkvb);
    cudaGetSymbolAddress((void**)&w1b,  g_w1b);
    cudaGetSymbolAddress((void**)&w2b,  g_w2b);
    float* part2 = part + 2*1024*1024;

    const long aB  = (long)TOTAL*DM;
    const long qB  = (long)QLEN*DM;
    const long kvB = (long)TOTAL*2*DM;

    const int SMEMB128 = (3*128*40 + 3*128*40) * 2;   // 61440 B
    const int SMEMB64  = (3*64*40  + 3*128*40) * 2;   // 46080 B
    cudaFuncSetAttribute(mma_gemmB_kernel<128>, cudaFuncAttributeMaxDynamicSharedMemorySize, SMEMB128);
    cudaFuncSetAttribute(mma_gemmB_kernel<64>,  cudaFuncAttributeMaxDynamicSharedMemorySize, SMEMB64);

    static cudaStream_t s1 = nullptr, s2 = nullptr, s3 = nullptr;
    static cudaEvent_t  e0, e1, e2, e3, e4, e5;
    if (s1 == nullptr) {
        cudaStreamCreateWithFlags(&s1, cudaStreamNonBlocking);
        cudaStreamCreateWithFlags(&s2, cudaStreamNonBlocking);
        cudaStreamCreateWithFlags(&s3, cudaStreamNonBlocking);
        cudaEventCreateWithFlags(&e0, cudaEventDisableTiming);
        cudaEventCreateWithFlags(&e1, cudaEventDisableTiming);
        cudaEventCreateWithFlags(&e2, cudaEventDisableTiming);
        cudaEventCreateWithFlags(&e3, cudaEventDisableTiming);
        cudaEventCreateWithFlags(&e4, cudaEventDisableTiming);
        cudaEventCreateWithFlags(&e5, cudaEventDisableTiming);
    }
    cudaStream_t s0 = 0;

    // ---- Phase 1 ----
    transpose_bf16_kernel<<<dim3(3*DM/32, DM/32), dim3(32,8), 0, s0>>>(wqkv, wqb, DM, 3*DM);
    rmsnorm_kernel<<<BSZ*TOTAL, 256, 0, s0>>>(x, n1w, xn, xnb);
    cudaEventRecord(e0, s0);

    cudaStreamWaitEvent(s2, e0, 0);
    transpose_bf16_kernel<<<dim3(FFND/32, DM/32), dim3(32,8), 0, s2>>>(fw1, w1b, DM, FFND);
    transpose_bf16_kernel<<<dim3(DM/32, FFND/32), dim3(32,8), 0, s2>>>(fw2, w2b, FFND, DM);
    cudaEventRecord(e2, s2);

    // s1: Q projection (bf16 GEMM, rtf32 out) -> ns_q -> rope_q
    cudaStreamWaitEvent(s1, e0, 0);
    mma_gemmB_kernel<64><<<dim3(DM/128, (BSZ*OUTN)/64), 256, SMEMB64, s1>>>(
        xnb + (long)(MAXS-OUTN)*DM, DM, aB, OUTN, wqb, DM, bqkv, q, DM, qB, DM, 0, 1, 0, seq, 0);
    ns_split4_kernel<<<dim3(DM/512, NSN, 32), 128, 0, s1>>>(xn + (long)MAXS*DM, aB, DM, wnsq, part2, DM, DM, DM/32);
    ns_reduce_kernel<<<dim3(DM/256, NSN, BSZ), 256, 0, s1>>>(part2, bnsq, q + (long)OUTN*DM, qB, DM, DM, 32, 0, 1);
    {
        int totq = BSZ*QLEN*NH*32;
        rope_kernel<<<(totq+255)/256, 256, 0, s1>>>(q, QLEN, TOTAL-QLEN, DM, totq);
    }
    cudaEventRecord(e1, s1);

    // s3: ns_v then ns_k
    cudaStreamWaitEvent(s3, e0, 0);
    ns_split4_kernel<<<dim3(DM/512, NSN, 32), 128, 0, s3>>>(xn + (long)MAXS*DM, aB, DM, wnsv, part, DM, DM, DM/32);
    ns_reduce_kernel<<<dim3(DM/256, NSN, BSZ), 256, 0, s3>>>(part, bnsv, kv + (long)MAXS*2*DM + DM, kvB, 2*DM, DM, 32, 0, 1);
    ns_split4_kernel<<<dim3(DM/512, NSN, 32), 128, 0, s3>>>(xn + (long)MAXS*DM, aB, DM, wnsk, part, DM, DM, DM/32);
    ns_reduce_kernel<<<dim3(DM/256, NSN, BSZ), 256, 0, s3>>>(part, bnsk, kv + (long)MAXS*2*DM, kvB, 2*DM, DM, 32, 0, 1);
    cudaEventRecord(e3, s3);

    // s0: KV projection (bf16, skip, rtf32 out), then rope_k
    mma_gemmB_kernel<128><<<dim3(2*DM/128, (BSZ*MAXS)/128), 256, SMEMB128, s0>>>(xnb, DM, aB, MAXS,
        wqb + (long)DM*DM, DM, bqkv + DM, kv, 2*DM, kvB, DM, 0, 1, 0, seq, 1);
    cudaStreamWaitEvent(s0, e3, 0);
    {
        int totk = BSZ*TOTAL*NH*32;
        rope_kernel<<<(totk+255)/256, 256, 0, s0>>>(kv, TOTAL, 0, 2*DM, totk);
    }

    cudaStreamWaitEvent(s0, e1, 0);
    attn_mma_kernel<<<dim3((QLEN+63)/64, NH, BSZ), 256, 0, s0>>>(q, kv, attn, seq);

    add_rmsnorm_kernel<<<BSZ*QLEN, 256, 0, s0>>>(x, n2w);
    cudaEventRecord(e4, s0);

    // ---- Phase 2 ----
    cudaStreamWaitEvent(s1, e4, 0);
    ns_split4_kernel<<<dim3(FFND/512, NSN, 16), 128, 0, s1>>>(hn + (long)OUTN*DM, qB, DM, w1ns, part, DM, FFND, DM/16);
    ns_reduce_kernel<<<dim3(FFND/256, NSN, BSZ), 256, 0, s1>>>(part, b1ns, tns, (long)NSN*FFND, FFND, FFND, 16, 1, 0);
    ns_split4_kernel<<<dim3(DM/512, NSN, 32), 128, 0, s1>>>(tns, (long)NSN*FFND, FFND, w2ns, part, FFND, DM, FFND/32);
    ns_reduce_kernel<<<dim3(DM/256, NSN, BSZ), 256, 0, s1>>>(part, b2ns, fns, (long)NSN*DM, DM, DM, 32, 0, 0);
    cudaEventRecord(e5, s1);

    // s0: shared FFN (bf16 GEMMs; FFN1 emits bf16 activations)
    cudaStreamWaitEvent(s0, e2, 0);
    mma_gemmB_kernel<128><<<dim3(FFND/128, (BSZ*OUTN)/128), 256, SMEMB128, s0>>>(hnb, DM, qB, OUTN,
        w1b, DM, fb1, tsb, FFND, (long)OUTN*FFND, DM, 1, 0, 1, seq, 0);
    mma_gemmB_kernel<64><<<dim3(DM/128, (BSZ*OUTN)/64), 256, SMEMB64, s0>>>(tsb, FFND, (long)OUTN*FFND, OUTN,
        w2b, FFND, fb2, fs, DM, (long)OUTN*DM, FFND, 0, 0, 0, seq, 0);

    cudaStreamWaitEvent(s0, e5, 0);
    assemble_kernel<<<(BSZ*QLEN*DM + 255)/256, 256, 0, s0>>>(out, seq, out_size);
}

// round 13
// speedup vs baseline: 7.7986x; 1.0193x over previous
#include <cuda_runtime.h>
#include <cuda_bf16.h>
#include <cstdint>

#define BSZ   4
#define TOTAL 2064
#define DM    1024
#define NSN   16
#define OUTN  256
#define QLEN  272
#define NH    16
#define HD    64
#define FFND  4096
#define MAXS  2048

// Scratch (static device globals; no allocation allowed)
__device__ float g_xn  [BSZ*TOTAL*DM];
__device__ float g_q   [BSZ*QLEN*DM];
__device__ float g_kv  [BSZ*TOTAL*2*DM];
__device__ float g_attn[BSZ*QLEN*DM];
__device__ float g_h1  [BSZ*QLEN*DM];
__device__ float g_hn  [BSZ*QLEN*DM];
__device__ float g_tns [BSZ*NSN*FFND];
__device__ float g_fs  [BSZ*OUTN*DM];
__device__ float g_fns [BSZ*NSN*DM];
__device__ float g_part[4*1024*1024];
// bf16 activations + transposed bf16 weights ([N,K] row-major)
__device__ __nv_bfloat16 g_xnb [BSZ*TOTAL*DM];
__device__ __nv_bfloat16 g_hnb [BSZ*QLEN*DM];
__device__ __nv_bfloat16 g_tsb [BSZ*OUTN*FFND];
__device__ __nv_bfloat16 g_wqkvb[3*DM*DM];
__device__ __nv_bfloat16 g_w1b  [FFND*DM];
__device__ __nv_bfloat16 g_w2b  [DM*FFND];

__device__ __forceinline__ float rtf32(float x) {
    uint32_t u;
    asm("cvt.rna.tf32.f32 %0, %1;" : "=r"(u) : "f"(x));
    return __uint_as_float(u);
}
__device__ __forceinline__ uint32_t f2u(float x) { return __float_as_uint(x); }

__device__ __forceinline__ void cpa16(uint32_t dst, const void* src) {
    asm volatile("cp.async.ca.shared.global [%0], [%1], 16;" :: "r"(dst), "l"(src));
}

__device__ __forceinline__ void mma_tf32(float* c,
        uint32_t a0, uint32_t a1, uint32_t a2, uint32_t a3,
        uint32_t b0, uint32_t b1) {
    asm volatile(
        "mma.sync.aligned.m16n8k8.row.col.f32.tf32.tf32.f32 "
        "{%0,%1,%2,%3}, {%4,%5,%6,%7}, {%8,%9}, {%0,%1,%2,%3};\n"
        : "+f"(c[0]), "+f"(c[1]), "+f"(c[2]), "+f"(c[3])
        : "r"(a0), "r"(a1), "r"(a2), "r"(a3), "r"(b0), "r"(b1));
}
__device__ __forceinline__ void mma_bf16(float* c,
        uint32_t a0, uint32_t a1, uint32_t a2, uint32_t a3,
        uint32_t b0, uint32_t b1) {
    asm volatile(
        "mma.sync.aligned.m16n8k16.row.col.f32.bf16.bf16.f32 "
        "{%0,%1,%2,%3}, {%4,%5,%6,%7}, {%8,%9}, {%0,%1,%2,%3};\n"
        : "+f"(c[0]), "+f"(c[1]), "+f"(c[2]), "+f"(c[3])
        : "r"(a0), "r"(a1), "r"(a2), "r"(a3), "r"(b0), "r"(b1));
}

__device__ __forceinline__ void ldsm4(uint32_t* r, uint32_t addr) {
    asm volatile("ldmatrix.sync.aligned.m8n8.x4.shared.b16 {%0,%1,%2,%3}, [%4];"
        : "=r"(r[0]), "=r"(r[1]), "=r"(r[2]), "=r"(r[3]) : "r"(addr));
}

// ---------------- transpose + bf16 convert ----------------
__global__ __launch_bounds__(256) void transpose_bf16_kernel(const float* __restrict__ in,
        __nv_bfloat16* __restrict__ out, int R, int C) {
    __shared__ float tile[32][33];
    int c0 = blockIdx.x*32, r0 = blockIdx.y*32;
    int tx = threadIdx.x, ty = threadIdx.y;
    for (int i = ty; i < 32; i += 8)
        tile[i][tx] = in[(long)(r0+i)*C + c0 + tx];
    __syncthreads();
    for (int i = ty; i < 32; i += 8)
        out[(long)(c0+i)*R + r0 + tx] = __float2bfloat16_rn(tile[tx][i]);
}

// ---------------- rmsnorm: fp32 (tf32-rounded) + bf16 outputs ----------------
__global__ __launch_bounds__(256) void rmsnorm_kernel(const float* __restrict__ in,
        const float* __restrict__ w, float* __restrict__ outf,
        __nv_bfloat16* __restrict__ outb) {
    long row = blockIdx.x;
    int t = threadIdx.x;
    float4 v = reinterpret_cast<const float4*>(in + row*DM)[t];
    float ss = v.x*v.x + v.y*v.y + v.z*v.z + v.w*v.w;
    __shared__ float red[8];
    for (int o = 16; o; o >>= 1) ss += __shfl_xor_sync(0xffffffffu, ss, o);
    if ((t & 31) == 0) red[t >> 5] = ss;
    __syncthreads();
    if (t < 32) {
        float s = (t < 8) ? red[t] : 0.f;
        for (int o = 4; o; o >>= 1) s += __shfl_xor_sync(0xffffffffu, s, o);
        if (t == 0) red[0] = s;
    }
    __syncthreads();
    float rs = rsqrtf(red[0] * (1.f/DM) + 1e-6f);
    float4 wv = reinterpret_cast<const float4*>(w)[t];
    float p0 = v.x*rs*wv.x, p1 = v.y*rs*wv.y, p2 = v.z*rs*wv.z, p3 = v.w*rs*wv.w;
    reinterpret_cast<float4*>(outf + row*DM)[t] =
        make_float4(rtf32(p0), rtf32(p1), rtf32(p2), rtf32(p3));
    __nv_bfloat162 b01, b23;
    b01.x = __float2bfloat16_rn(p0); b01.y = __float2bfloat16_rn(p1);
    b23.x = __float2bfloat16_rn(p2); b23.y = __float2bfloat16_rn(p3);
    reinterpret_cast<__nv_bfloat162*>(outb + row*DM)[t*2]   = b01;
    reinterpret_cast<__nv_bfloat162*>(outb + row*DM)[t*2+1] = b23;
}

// ---------------- h1 = x + attn ; hn (fp32 + bf16) ----------------
__global__ __launch_bounds__(256) void add_rmsnorm_kernel(const float* __restrict__ x,
        const float* __restrict__ w) {
    int row = blockIdx.x;
    int b = row / QLEN, r = row - b*QLEN;
    int t = threadIdx.x;
    float4 xv = reinterpret_cast<const float4*>(x + ((long)b*TOTAL + (TOTAL-QLEN) + r)*DM)[t];
    float4 av = reinterpret_cast<const float4*>(g_attn + (long)row*DM)[t];
    float4 hv = make_float4(xv.x+av.x, xv.y+av.y, xv.z+av.z, xv.w+av.w);
    reinterpret_cast<float4*>(g_h1 + (long)row*DM)[t] = hv;
    float ss = hv.x*hv.x + hv.y*hv.y + hv.z*hv.z + hv.w*hv.w;
    __shared__ float red[8];
    for (int o = 16; o; o >>= 1) ss += __shfl_xor_sync(0xffffffffu, ss, o);
    if ((t & 31) == 0) red[t >> 5] = ss;
    __syncthreads();
    if (t < 32) {
        float s = (t < 8) ? red[t] : 0.f;
        for (int o = 4; o; o >>= 1) s += __shfl_xor_sync(0xffffffffu, s, o);
        if (t == 0) red[0] = s;
    }
    __syncthreads();
    float rs = rsqrtf(red[0] * (1.f/DM) + 1e-6f);
    float4 wv = reinterpret_cast<const float4*>(w)[t];
    float p0 = hv.x*rs*wv.x, p1 = hv.y*rs*wv.y, p2 = hv.z*rs*wv.z, p3 = hv.w*rs*wv.w;
    reinterpret_cast<float4*>(g_hn + (long)row*DM)[t] =
        make_float4(rtf32(p0), rtf32(p1), rtf32(p2), rtf32(p3));
    __nv_bfloat162 b01, b23;
    b01.x = __float2bfloat16_rn(p0); b01.y = __float2bfloat16_rn(p1);
    b23.x = __float2bfloat16_rn(p2); b23.y = __float2bfloat16_rn(p3);
    reinterpret_cast<__nv_bfloat162*>(g_hnb + (long)row*DM)[t*2]   = b01;
    reinterpret_cast<__nv_bfloat162*>(g_hnb + (long)row*DM)[t*2+1] = b23;
}

// ---------------- BF16 tensor-core GEMM ----------------
template<int MTILE>
__global__ __launch_bounds__(256, 2) void mma_gemmB_kernel(
    const __nv_bfloat16* __restrict__ A, int lda, long aBatch, int rpb,
    const __nv_bfloat16* __restrict__ Bt, int ldbt,
    const float* __restrict__ bias,
    void* __restrict__ Cv, int ldc, long cBatch,
    int K, int relu, int roundOut, int outBf16,
    const int* __restrict__ seqlen, int kvSkip)
{
    constexpr int S    = 3;
    constexpr int PAD  = 40;
    constexpr int ASTG = MTILE*PAD;
    constexpr int BSTG = 128*PAD;
    constexpr int MT   = MTILE/32;
    extern __shared__ __nv_bfloat16 smb[];
    __nv_bfloat16* AsBase = smb;
    __nv_bfloat16* BsBase = smb + S*ASTG;

    int t = threadIdx.x;
    int w = t >> 5, lane = t & 31;
    int g = lane >> 2, tig = lane & 3;
    int wm = w >> 2, wn = w & 3;

    int row0 = blockIdx.y * MTILE;
    int bn0  = blockIdx.x * 128;
    int batch = row0 / rpb;
    int rin   = row0 % rpb;
    if (kvSkip) {
        int kmin = MAXS - seqlen[batch];
        if (rin + MTILE - 1 < kmin) return;
    }
    const __nv_bfloat16* Ab = A + (long)batch*aBatch + (long)rin*lda;
    const __nv_bfloat16* Bb = Bt + (long)bn0*ldbt;

    uint32_t aSm0 = (uint32_t)__cvta_generic_to_shared(AsBase);
    uint32_t bSm0 = (uint32_t)__cvta_generic_to_shared(BsBase);

    float acc[MT][4][4];
    #pragma unroll
    for (int i = 0; i < MT; i++)
        #pragma unroll
        for (int j = 0; j < 4; j++)
            #pragma unroll
            for (int r = 0; r < 4; r++) acc[i][j][r] = 0.f;

    const int KT = K >> 5;
    auto issue = [&](int kt) {
        int s = kt % S;
        const __nv_bfloat16* ga = Ab + kt*32;
        const __nv_bfloat16* gb = Bb + kt*32;
        uint32_t aS = aSm0 + s*ASTG*2;
        uint32_t bS = bSm0 + s*BSTG*2;
        #pragma unroll
        for (int it = 0; it < MTILE/64; it++) {
            int i = t + it*256;
            int row = i >> 2, seg = i & 3;
            cpa16(aS + (row*PAD + seg*8)*2, ga + (long)row*lda + seg*8);
        }
        #pragma unroll
        for (int it = 0; it < 2; it++) {
            int i = t + it*256;
            int row = i >> 2, seg = i & 3;
            cpa16(bS + (row*PAD + seg*8)*2, gb + (long)row*ldbt + seg*8);
        }
        asm volatile("cp.async.commit_group;");
    };
    issue(0);
    issue(1);

    int aRow  = lane & 15;
    int aColH = (lane >> 4) * 8;
    int bRowO = ((lane >> 4) & 1)*8 + (lane & 7);
    int bColH = ((lane >> 3) & 1)*8;

    for (int kt = 0; kt < KT; kt++) {
        if (kt == KT - 1) asm volatile("cp.async.wait_group 0;");
        else              asm volatile("cp.async.wait_group 1;");
        __syncthreads();
        if (kt + 2 < KT) issue(kt + 2);

        int s = kt % S;
        uint32_t As = aSm0 + s*ASTG*2;
        uint32_t Bs = bSm0 + s*BSTG*2;
        #pragma unroll
        for (int ks = 0; ks < 2; ks++) {
            uint32_t afr[MT][4];
            #pragma unroll
            for (int mt = 0; mt < MT; mt++)
                ldsm4(afr[mt], As + ((wm*(MTILE/2) + mt*16 + aRow)*PAD + ks*16 + aColH)*2);
            uint32_t bfr[4][2];
            #pragma unroll
            for (int p = 0; p < 2; p++) {
                uint32_t r4[4];
                ldsm4(r4, Bs + ((wn*32 + p*16 + bRowO)*PAD + ks*16 + bColH)*2);
                bfr[2*p][0]   = r4[0]; bfr[2*p][1]   = r4[1];
                bfr[2*p+1][0] = r4[2]; bfr[2*p+1][1] = r4[3];
            }
            #pragma unroll
            for (int mt = 0; mt < MT; mt++)
                #pragma unroll
                for (int nt = 0; nt < 4; nt++)
                    mma_bf16(acc[mt][nt], afr[mt][0], afr[mt][1], afr[mt][2], afr[mt][3],
                             bfr[nt][0], bfr[nt][1]);
        }
    }

    float* Cf = (float*)Cv;
    __nv_bfloat16* Cb = (__nv_bfloat16*)Cv;
    #pragma unroll
    for (int nt = 0; nt < 4; nt++) {
        int col = wn*32 + nt*8 + 2*tig;
        float bx = bias[bn0 + col], by = bias[bn0 + col + 1];
        #pragma unroll
        for (int mt = 0; mt < MT; mt++) {
            int r0 = wm*(MTILE/2) + mt*16 + g;
            long base0 = (long)batch*cBatch + (long)(rin + r0)*ldc + bn0 + col;
            long base1 = base0 + (long)8*ldc;
            float c0 = acc[mt][nt][0] + bx, c1 = acc[mt][nt][1] + by;
            float c2 = acc[mt][nt][2] + bx, c3 = acc[mt][nt][3] + by;
            if (relu) { c0=fmaxf(c0,0.f); c1=fmaxf(c1,0.f); c2=fmaxf(c2,0.f); c3=fmaxf(c3,0.f); }
            if (outBf16) {
                __nv_bfloat162 v0, v1;
                v0.x = __float2bfloat16_rn(c0); v0.y = __float2bfloat16_rn(c1);
                v1.x = __float2bfloat16_rn(c2); v1.y = __float2bfloat16_rn(c3);
                *reinterpret_cast<__nv_bfloat162*>(Cb + base0) = v0;
                *reinterpret_cast<__nv_bfloat162*>(Cb + base1) = v1;
            } else {
                if (roundOut) { c0=rtf32(c0); c1=rtf32(c1); c2=rtf32(c2); c3=rtf32(c3); }
                *reinterpret_cast<float2*>(Cf + base0) = make_float2(c0, c1);
                *reinterpret_cast<float2*>(Cf + base1) = make_float2(c2, c3);
            }
        }
    }
}

// ---------------- per-NS-position linear: vectorized K-split partials ----------------
__global__ __launch_bounds__(128) void ns_split4_kernel(
    const float* __restrict__ X, long xBatch, int xRow,
    const float* __restrict__ W, float* __restrict__ part,
    int K, int N, int kchunk)
{
    __shared__ float Xs[4][512];
    int n = blockIdx.y, z = blockIdx.z;
    int t = threadIdx.x;
    int o4 = (blockIdx.x*128 + t)*4;
    int k0 = z*kchunk;
    for (int i = t; i < kchunk; i += 128) {
        long xo = (long)n*xRow + k0 + i;
        Xs[0][i] = X[0*xBatch + xo];
        Xs[1][i] = X[1*xBatch + xo];
        Xs[2][i] = X[2*xBatch + xo];
        Xs[3][i] = X[3*xBatch + xo];
    }
    __syncthreads();
    const float* Wp = W + (long)n*K*N + (long)k0*N + o4;
    float acc[4][4];
    #pragma unroll
    for (int b = 0; b < 4; b++)
        #pragma unroll
        for (int j = 0; j < 4; j++) acc[b][j] = 0.f;
    #pragma unroll 8
    for (int k = 0; k < kchunk; k++) {
        float4 wv = *reinterpret_cast<const float4*>(Wp + (long)k*N);
        #pragma unroll
        for (int b = 0; b < 4; b++) {
            float xv = Xs[b][k];
            acc[b][0] += xv*wv.x; acc[b][1] += xv*wv.y;
            acc[b][2] += xv*wv.z; acc[b][3] += xv*wv.w;
        }
    }
    #pragma unroll
    for (int b = 0; b < 4; b++)
        *reinterpret_cast<float4*>(&part[((long)(z*BSZ+b)*NSN + n)*N + o4]) =
            make_float4(acc[b][0], acc[b][1], acc[b][2], acc[b][3]);
}

__global__ __launch_bounds__(256) void ns_reduce_kernel(
    const float* __restrict__ part, const float* __restrict__ bias,
    float* __restrict__ Y, long yBatch, int yRow, int N, int KS, int relu, int roundOut)
{
    int o = blockIdx.x*256 + threadIdx.x;
    int n = blockIdx.y, b = blockIdx.z;
    float s = bias[(long)n*N + o];
    for (int z = 0; z < KS; z++)
        s += part[((long)(z*BSZ+b)*NSN + n)*N + o];
    if (relu) s = fmaxf(s, 0.f);
    if (roundOut) s = rtf32(s);
    Y[(long)b*yBatch + (long)n*yRow + o] = s;
}

// ---------------- RoPE in-place (fp32 path, rounded output) ----------------
__global__ void rope_kernel(float* __restrict__ buf, int rowsPerB, int pos0, int rstride, int total) {
    int idx = blockIdx.x*blockDim.x + threadIdx.x;
    if (idx >= total) return;
    int j  = idx & 31;
    int h  = (idx >> 5) & (NH-1);
    int rr = idx >> 9;
    int b  = rr / rowsPerB;
    int r  = rr - b*rowsPerB;
    float inv = exp2f(-(float)j * 0.41524101186092029f);
    double ang = (double)(pos0 + r) * (double)inv;
    const double TWO_PI = 6.2831853071795864769;
    double red = ang - TWO_PI * rint(ang * (1.0/6.2831853071795864769));
    float rf = (float)red;
    float s, c;
    sincosf(rf, &s, &c);
    float* base = buf + ((long)b*rowsPerB + r)*(long)rstride + h*HD;
    float x1 = base[j], x2 = base[j+32];
    base[j]    = rtf32(x1*c - x2*s);
    base[j+32] = rtf32(x2*c + x1*s);
}

// ---------------- tf32 flash attention, 64-key tiles, 2-stage cp.async, dyn smem ----------
// Layout (floats): qs 64x68 | ksm 2x64x68 | vsm 2x64x72 | ssm 64x68 | corrs 64 | lrow 64
#define ATT_QS(r,c)      dsm[(r)*68 + (c)]
#define ATT_KS(bf,r,c)   dsm[4352 + (bf)*4352 + (r)*68 + (c)]
#define ATT_VS(bf,r,c)   dsm[13056 + (bf)*4608 + (r)*72 + (c)]
#define ATT_SS(r,c)      dsm[22272 + (r)*68 + (c)]
#define ATT_SMEM_FLOATS  (26752 + 128)

__global__ __launch_bounds__(256) void attn_mma_kernel(
    const float* __restrict__ q, const float* __restrict__ kv,
    float* __restrict__ attn, const int* __restrict__ seqlen)
{
    extern __shared__ float dsm[];
    float* corrs = dsm + 26752;
    float* lrow  = corrs + 64;

    int qt = blockIdx.x, h = blockIdx.y, b = blockIdx.z;
    int tid = threadIdx.x;
    int w = tid >> 5, lane = tid & 31;
    int g = lane >> 2, tig = lane & 3;
    int wm = w >> 2, wn = w & 3;
    int L = seqlen[b];
    int kmin = MAXS - L;

    for (int i = tid; i < 64*16; i += 256) {
        int r = i >> 4, c4 = (i & 15) * 4;
        int qg = qt*64 + r;
        float4 val = make_float4(0.f,0.f,0.f,0.f);
        if (qg < QLEN)
            val = *reinterpret_cast<const float4*>(q + ((long)b*QLEN + qg)*DM + h*HD + c4);
        *reinterpret_cast<float4*>(&ATT_QS(r, c4)) = val;
    }

    int srow = tid >> 2, ssub = tid & 3;
    float m = -1e30f, l = 0.f;

    float oacc[2][2][4];
    #pragma unroll
    for (int i = 0; i < 2; i++)
        #pragma unroll
        for (int j = 0; j < 2; j++)
            #pragma unroll
            for (int r = 0; r < 4; r++) oacc[i][j][r] = 0.f;

    int qgmax = min(QLEN-1, qt*64 + 63);
    int t0 = kmin >> 6;
    int t1 = (MAXS - OUTN + qgmax) >> 6;

    uint32_t smBase = (uint32_t)__cvta_generic_to_shared(dsm);

    auto loadTile = [&](int kt) {
        int buf = kt & 1;
        int key0 = kt * 64;
        #pragma unroll
        for (int it = 0; it < 4; it++) {
            int i = tid + it*256;                 // 0..1023
            int r = i >> 4;                       // 0..63
            int c4 = (i & 15) * 4;
            int key = key0 + r;
            long off = ((long)b*TOTAL + min(key, TOTAL-1))*(2*DM) + h*HD + c4;
            cpa16(smBase + (4352 + buf*4352 + r*68 + c4)*4, kv + off);
            cpa16(smBase + (13056 + buf*4608 + r*72 + c4)*4, kv + off + DM);
        }
        asm volatile("cp.async.commit_group;");
    };
    loadTile(t0);
    asm volatile("cp.async.commit_group;");

    for (int kt = t0; kt <= t1; kt++) {
        int key0 = kt * 64;
        int buf = kt & 1;
        asm volatile("cp.async.wait_group 1;");
        __syncthreads();
        if (kt + 1 <= t1) loadTile(kt + 1);
        else              asm volatile("cp.async.commit_group;");

        // S = Q K^T : warp covers rows wm*32..+31 (2x16), keys wn*16..+15 (2x8)
        float sa[2][2][4];
        #pragma unroll
        for (int mt = 0; mt < 2; mt++)
            #pragma unroll
            for (int kn = 0; kn < 2; kn++)
                #pragma unroll
                for (int r = 0; r < 4; r++) sa[mt][kn][r] = 0.f;
        #pragma unroll
        for (int dk = 0; dk < 8; dk++) {
            #pragma unroll
            for (int kn = 0; kn < 2; kn++) {
                uint32_t bf0 = f2u(ATT_KS(buf, wn*16 + kn*8 + g, dk*8 + tig));
                uint32_t bf1 = f2u(ATT_KS(buf, wn*16 + kn*8 + g, dk*8 + tig + 4));
                #pragma unroll
                for (int mt = 0; mt < 2; mt++) {
                    int m0 = wm*32 + mt*16;
                    mma_tf32(sa[mt][kn],
                        f2u(ATT_QS(m0+g,   dk*8+tig)),   f2u(ATT_QS(m0+g+8, dk*8+tig)),
                        f2u(ATT_QS(m0+g,   dk*8+tig+4)), f2u(ATT_QS(m0+g+8, dk*8+tig+4)),
                        bf0, bf1);
                }
            }
        }
        #pragma unroll
        for (int mt = 0; mt < 2; mt++) {
            #pragma unroll
            for (int kn = 0; kn < 2; kn++) {
                #pragma unroll
                for (int hh = 0; hh < 2; hh++) {
                    int r = wm*32 + mt*16 + g + hh*8;
                    int qg = qt*64 + r;
                    int col = wn*16 + kn*8 + 2*tig;
                    int key = key0 + col;
                    int kcap = MAXS - OUTN + qg;
                    bool rowok = (qg < QLEN);
                    float sA = sa[mt][kn][hh*2+0], sB = sa[mt][kn][hh*2+1];
                    bool v0 = rowok && (key   < TOTAL) && (key   >= kmin) && (key   <= kcap);
                    bool v1 = rowok && (key+1 < TOTAL) && (key+1 >= kmin) && (key+1 <= kcap);
                    ATT_SS(r, col)     = v0 ? sA*0.125f : -1e9f;
                    ATT_SS(r, col + 1) = v1 ? sB*0.125f : -1e9f;
                }
            }
        }
        __syncthreads();

        // streaming softmax: row srow, keys ssub*16..+15
        float sv[16];
        #pragma unroll
        for (int j = 0; j < 16; j++) sv[j] = ATT_SS(srow, ssub*16 + j);
        float tmax = sv[0];
        #pragma unroll
        for (int j = 1; j < 16; j++) tmax = fmaxf(tmax, sv[j]);
        tmax = fmaxf(tmax, __shfl_xor_sync(0xffffffffu, tmax, 1));
        tmax = fmaxf(tmax, __shfl_xor_sync(0xffffffffu, tmax, 2));
        float corr = 1.f;
        if (tmax > -1e8f) {
            float m_new = fmaxf(m, tmax);
            corr = __expf(m - m_new);
            float ps = 0.f;
            #pragma unroll
            for (int j = 0; j < 16; j++) {
                float p = __expf(sv[j] - m_new);
                ps += p;
                ATT_SS(srow, ssub*16 + j) = rtf32(p);
            }
            ps += __shfl_xor_sync(0xffffffffu, ps, 1);
            ps += __shfl_xor_sync(0xffffffffu, ps, 2);
            l = l*corr + ps;
            m = m_new;
        } else {
            #pragma unroll
            for (int j = 0; j < 16; j++) ATT_SS(srow, ssub*16 + j) = 0.f;
        }
        if (ssub == 0) corrs[srow] = corr;
        __syncthreads();

        #pragma unroll
        for (int mt = 0; mt < 2; mt++) {
            float c0 = corrs[wm*32 + mt*16 + g];
            float c1 = corrs[wm*32 + mt*16 + g + 8];
            #pragma unroll
            for (int nt = 0; nt < 2; nt++) {
                oacc[mt][nt][0] *= c0; oacc[mt][nt][1] *= c0;
                oacc[mt][nt][2] *= c1; oacc[mt][nt][3] *= c1;
            }
        }
        #pragma unroll
        for (int kd = 0; kd < 8; kd++) {
            uint32_t bf[2][2];
            #pragma unroll
            for (int nt = 0; nt < 2; nt++) {
                int n = wn*16 + nt*8 + g;
                bf[nt][0] = f2u(ATT_VS(buf, kd*8 + tig,     n));
                bf[nt][1] = f2u(ATT_VS(buf, kd*8 + tig + 4, n));
            }
            #pragma unroll
            for (int mt = 0; mt < 2; mt++) {
                int m0 = wm*32 + mt*16;
                uint32_t a0 = f2u(ATT_SS(m0+g,   kd*8+tig));
                uint32_t a1 = f2u(ATT_SS(m0+g+8, kd*8+tig));
                uint32_t a2 = f2u(ATT_SS(m0+g,   kd*8+tig+4));
                uint32_t a3 = f2u(ATT_SS(m0+g+8, kd*8+tig+4));
                #pragma unroll
                for (int nt = 0; nt < 2; nt++)
                    mma_tf32(oacc[mt][nt], a0, a1, a2, a3, bf[nt][0], bf[nt][1]);
            }
        }
        __syncthreads();
    }

    if (ssub == 0) lrow[srow] = l;
    __syncthreads();
    #pragma unroll
    for (int mt = 0; mt < 2; mt++) {
        #pragma unroll
        for (int hh = 0; hh < 2; hh++) {
            int r = wm*32 + mt*16 + g + hh*8;
            int qg = qt*64 + r;
            if (qg < QLEN) {
                float invl = 1.f / lrow[r];
                #pragma unroll
                for (int nt = 0; nt < 2; nt++) {
                    int col = wn*16 + nt*8 + 2*tig;
                    *reinterpret_cast<float2*>(attn + ((long)b*QLEN + qg)*DM + h*HD + col)
                        = make_float2(oacc[mt][nt][hh*2]*invl, oacc[mt][nt][hh*2+1]*invl);
                }
            }
        }
    }
}

// ---------------- final assembly ----------------
__global__ void assemble_kernel(float* __restrict__ out, const int* __restrict__ seqlen, int out_size) {
    int idx = blockIdx.x*blockDim.x + threadIdx.x;
    const int main_n = BSZ*QLEN*DM;
    if (idx < main_n) {
        int b = idx / (QLEN*DM);
        int rem = idx - b*(QLEN*DM);
        int r = rem / DM;
        int d = rem - r*DM;
        float f;
        if (r < OUTN) f = g_fs [((long)b*OUTN + r)*DM + d];
        else          f = g_fns[((long)b*NSN + (r - OUTN))*DM + d];
        out[idx] = f + g_h1[idx];
    }
    if (idx < BSZ && out_size >= main_n + BSZ) {
        int L = seqlen[idx];
        out[main_n + idx] = (float)(L < OUTN ? L : OUTN);
    }
}

extern "C" void kernel_launch(void* const* d_in, const int* in_sizes, int n_in,
                              void* d_out, int out_size) {
    (void)in_sizes; (void)n_in;
    const float* x    = (const float*)d_in[0];
    const int*   seq  = (const int*)  d_in[1];
    const float* wqkv = (const float*)d_in[2];
    const float* bqkv = (const float*)d_in[3];
    const float* wnsq = (const float*)d_in[4];
    const float* bnsq = (const float*)d_in[5];
    const float* wnsk = (const float*)d_in[6];
    const float* bnsk = (const float*)d_in[7];
    const float* wnsv = (const float*)d_in[8];
    const float* bnsv = (const float*)d_in[9];
    const float* n1w  = (const float*)d_in[10];
    const float* n2w  = (const float*)d_in[11];
    const float* fw1  = (const float*)d_in[12];
    const float* fb1  = (const float*)d_in[13];
    const float* fw2  = (const float*)d_in[14];
    const float* fb2  = (const float*)d_in[15];
    const float* w1ns = (const float*)d_in[16];
    const float* b1ns = (const float*)d_in[17];
    const float* w2ns = (const float*)d_in[18];
    const float* b2ns = (const float*)d_in[19];
    float* out = (float*)d_out;

    float *xn,*q,*kv,*attn,*hn,*tns,*fs,*fns,*part;
    __nv_bfloat16 *xnb,*hnb,*tsb,*wqb,*w1b,*w2b;
    cudaGetSymbolAddress((void**)&xn,   g_xn);
    cudaGetSymbolAddress((void**)&q,    g_q);
    cudaGetSymbolAddress((void**)&kv,   g_kv);
    cudaGetSymbolAddress((void**)&attn, g_attn);
    cudaGetSymbolAddress((void**)&hn,   g_hn);
    cudaGetSymbolAddress((void**)&tns,  g_tns);
    cudaGetSymbolAddress((void**)&fs,   g_fs);
    cudaGetSymbolAddress((void**)&fns,  g_fns);
    cudaGetSymbolAddress((void**)&part, g_part);
    cudaGetSymbolAddress((void**)&xnb,  g_xnb);
    cudaGetSymbolAddress((void**)&hnb,  g_hnb);
    cudaGetSymbolAddress((void**)&tsb,  g_tsb);
    cudaGetSymbolAddress((void**)&wqb,  g_wqkvb);
    cudaGetSymbolAddress((void**)&w1b,  g_w1b);
    cudaGetSymbolAddress((void**)&w2b,  g_w2b);
    float* part2 = part + 2*1024*1024;

    const long aB  = (long)TOTAL*DM;
    const long qB  = (long)QLEN*DM;
    const long kvB = (long)TOTAL*2*DM;

    const int SMEMB128 = (3*128*40 + 3*128*40) * 2;
    const int SMEMB64  = (3*64*40  + 3*128*40) * 2;
    const int ATTSMEM  = ATT_SMEM_FLOATS * 4;
    cudaFuncSetAttribute(mma_gemmB_kernel<128>, cudaFuncAttributeMaxDynamicSharedMemorySize, SMEMB128);
    cudaFuncSetAttribute(mma_gemmB_kernel<64>,  cudaFuncAttributeMaxDynamicSharedMemorySize, SMEMB64);
    cudaFuncSetAttribute(attn_mma_kernel, cudaFuncAttributeMaxDynamicSharedMemorySize, ATTSMEM);

    static cudaStream_t s1 = nullptr, s2 = nullptr, s3 = nullptr;
    static cudaEvent_t  eB, e0, e1, e2, e2a, e3, e4, e5;
    if (s1 == nullptr) {
        cudaStreamCreateWithFlags(&s1, cudaStreamNonBlocking);
        cudaStreamCreateWithFlags(&s2, cudaStreamNonBlocking);
        cudaStreamCreateWithFlags(&s3, cudaStreamNonBlocking);
        cudaEventCreateWithFlags(&eB,  cudaEventDisableTiming);
        cudaEventCreateWithFlags(&e0,  cudaEventDisableTiming);
        cudaEventCreateWithFlags(&e1,  cudaEventDisableTiming);
        cudaEventCreateWithFlags(&e2,  cudaEventDisableTiming);
        cudaEventCreateWithFlags(&e2a, cudaEventDisableTiming);
        cudaEventCreateWithFlags(&e3,  cudaEventDisableTiming);
        cudaEventCreateWithFlags(&e4,  cudaEventDisableTiming);
        cudaEventCreateWithFlags(&e5,  cudaEventDisableTiming);
    }
    cudaStream_t s0 = 0;

    // ---- Phase 1 : head runs rmsnorm (s0) || weight transposes (s2) ----
    cudaEventRecord(eB, s0);
    cudaStreamWaitEvent(s2, eB, 0);
    transpose_bf16_kernel<<<dim3(3*DM/32, DM/32), dim3(32,8), 0, s2>>>(wqkv, wqb, DM, 3*DM);
    cudaEventRecord(e2a, s2);
    transpose_bf16_kernel<<<dim3(FFND/32, DM/32), dim3(32,8), 0, s2>>>(fw1, w1b, DM, FFND);
    transpose_bf16_kernel<<<dim3(DM/32, FFND/32), dim3(32,8), 0, s2>>>(fw2, w2b, FFND, DM);
    cudaEventRecord(e2, s2);

    rmsnorm_kernel<<<BSZ*TOTAL, 256, 0, s0>>>(x, n1w, xn, xnb);
    cudaEventRecord(e0, s0);

    // s1: Q projection -> ns_q -> rope_q
    cudaStreamWaitEvent(s1, e0, 0);
    cudaStreamWaitEvent(s1, e2a, 0);
    mma_gemmB_kernel<64><<<dim3(DM/128, (BSZ*OUTN)/64), 256, SMEMB64, s1>>>(
        xnb + (long)(MAXS-OUTN)*DM, DM, aB, OUTN, wqb, DM, bqkv, q, DM, qB, DM, 0, 1, 0, seq, 0);
    ns_split4_kernel<<<dim3(DM/512, NSN, 32), 128, 0, s1>>>(xn + (long)MAXS*DM, aB, DM, wnsq, part2, DM, DM, DM/32);
    ns_reduce_kernel<<<dim3(DM/256, NSN, BSZ), 256, 0, s1>>>(part2, bnsq, q + (long)OUTN*DM, qB, DM, DM, 32, 0, 1);
    {
        int totq = BSZ*QLEN*NH*32;
        rope_kernel<<<(totq+255)/256, 256, 0, s1>>>(q, QLEN, TOTAL-QLEN, DM, totq);
    }
    cudaEventRecord(e1, s1);

    // s3: ns_v then ns_k
    cudaStreamWaitEvent(s3, e0, 0);
    ns_split4_kernel<<<dim3(DM/512, NSN, 32), 128, 0, s3>>>(xn + (long)MAXS*DM, aB, DM, wnsv, part, DM, DM, DM/32);
    ns_reduce_kernel<<<dim3(DM/256, NSN, BSZ), 256, 0, s3>>>(part, bnsv, kv + (long)MAXS*2*DM + DM, kvB, 2*DM, DM, 32, 0, 1);
    ns_split4_kernel<<<dim3(DM/512, NSN, 32), 128, 0, s3>>>(xn + (long)MAXS*DM, aB, DM, wnsk, part, DM, DM, DM/32);
    ns_reduce_kernel<<<dim3(DM/256, NSN, BSZ), 256, 0, s3>>>(part, bnsk, kv + (long)MAXS*2*DM, kvB, 2*DM, DM, 32, 0, 1);
    cudaEventRecord(e3, s3);

    // s0: KV projection, then rope_k
    cudaStreamWaitEvent(s0, e2a, 0);
    mma_gemmB_kernel<128><<<dim3(2*DM/128, (BSZ*MAXS)/128), 256, SMEMB128, s0>>>(xnb, DM, aB, MAXS,
        wqb + (long)DM*DM, DM, bqkv + DM, kv, 2*DM, kvB, DM, 0, 1, 0, seq, 1);
    cudaStreamWaitEvent(s0, e3, 0);
    {
        int totk = BSZ*TOTAL*NH*32;
        rope_kernel<<<(totk+255)/256, 256, 0, s0>>>(kv, TOTAL, 0, 2*DM, totk);
    }

    cudaStreamWaitEvent(s0, e1, 0);
    attn_mma_kernel<<<dim3((QLEN+63)/64, NH, BSZ), 256, ATTSMEM, s0>>>(q, kv, attn, seq);

    add_rmsnorm_kernel<<<BSZ*QLEN, 256, 0, s0>>>(x, n2w);
    cudaEventRecord(e4, s0);

    // ---- Phase 2 ----
    cudaStreamWaitEvent(s1, e4, 0);
    ns_split4_kernel<<<dim3(FFND/512, NSN, 16), 128, 0, s1>>>(hn + (long)OUTN*DM, qB, DM, w1ns, part, DM, FFND, DM/16);
    ns_reduce_kernel<<<dim3(FFND/256, NSN, BSZ), 256, 0, s1>>>(part, b1ns, tns, (long)NSN*FFND, FFND, FFND, 16, 1, 0);
    ns_split4_kernel<<<dim3(DM/512, NSN, 32), 128, 0, s1>>>(tns, (long)NSN*FFND, FFND, w2ns, part, FFND, DM, FFND/32);
    ns_reduce_kernel<<<dim3(DM/256, NSN, BSZ), 256, 0, s1>>>(part, b2ns, fns, (long)NSN*DM, DM, DM, 32, 0, 0);
    cudaEventRecord(e5, s1);

    cudaStreamWaitEvent(s0, e2, 0);
    mma_gemmB_kernel<128><<<dim3(FFND/128, (BSZ*OUTN)/128), 256, SMEMB128, s0>>>(hnb, DM, qB, OUTN,
        w1b, DM, fb1, tsb, FFND, (long)OUTN*FFND, DM, 1, 0, 1, seq, 0);
    mma_gemmB_kernel<64><<<dim3(DM/128, (BSZ*OUTN)/64), 256, SMEMB64, s0>>>(tsb, FFND, (long)OUTN*FFND, OUTN,
        w2b, FFND, fb2, fs, DM, (long)OUTN*DM, FFND, 0, 0, 0, seq, 0);

    cudaStreamWaitEvent(s0, e5, 0);
    assemble_kernel<<<(BSZ*QLEN*DM + 255)/256, 256, 0, s0>>>(out, seq, out_size);
}

// round 14
// speedup vs baseline: 8.0771x; 1.0357x over previous
#include <cuda_runtime.h>
#include <cuda_bf16.h>
#include <cstdint>

#define BSZ   4
#define TOTAL 2064
#define DM    1024
#define NSN   16
#define OUTN  256
#define QLEN  272
#define NH    16
#define HD    64
#define FFND  4096
#define MAXS  2048

// Scratch (static device globals; no allocation allowed)
__device__ float g_xn  [BSZ*TOTAL*DM];
__device__ float g_q   [BSZ*QLEN*DM];
__device__ float g_kv  [BSZ*TOTAL*2*DM];
__device__ float g_attn[BSZ*QLEN*DM];
__device__ float g_h1  [BSZ*QLEN*DM];
__device__ float g_hn  [BSZ*QLEN*DM];
__device__ float g_tns [BSZ*NSN*FFND];
__device__ float g_fns [BSZ*NSN*DM];
__device__ float g_part[4*1024*1024];
// bf16 activations + transposed bf16 weights ([N,K] row-major)
__device__ __nv_bfloat16 g_xnb [BSZ*TOTAL*DM];
__device__ __nv_bfloat16 g_hnb [BSZ*QLEN*DM];
__device__ __nv_bfloat16 g_tsb [BSZ*OUTN*FFND];
__device__ __nv_bfloat16 g_wqkvb[3*DM*DM];
__device__ __nv_bfloat16 g_w1b  [FFND*DM];
__device__ __nv_bfloat16 g_w2b  [DM*FFND];

__device__ __forceinline__ float rtf32(float x) {
    uint32_t u;
    asm("cvt.rna.tf32.f32 %0, %1;" : "=r"(u) : "f"(x));
    return __uint_as_float(u);
}
__device__ __forceinline__ uint32_t f2u(float x) { return __float_as_uint(x); }

__device__ __forceinline__ void cpa16(uint32_t dst, const void* src) {
    asm volatile("cp.async.ca.shared.global [%0], [%1], 16;" :: "r"(dst), "l"(src));
}

__device__ __forceinline__ void mma_tf32(float* c,
        uint32_t a0, uint32_t a1, uint32_t a2, uint32_t a3,
        uint32_t b0, uint32_t b1) {
    asm volatile(
        "mma.sync.aligned.m16n8k8.row.col.f32.tf32.tf32.f32 "
        "{%0,%1,%2,%3}, {%4,%5,%6,%7}, {%8,%9}, {%0,%1,%2,%3};\n"
        : "+f"(c[0]), "+f"(c[1]), "+f"(c[2]), "+f"(c[3])
        : "r"(a0), "r"(a1), "r"(a2), "r"(a3), "r"(b0), "r"(b1));
}
__device__ __forceinline__ void mma_bf16(float* c,
        uint32_t a0, uint32_t a1, uint32_t a2, uint32_t a3,
        uint32_t b0, uint32_t b1) {
    asm volatile(
        "mma.sync.aligned.m16n8k16.row.col.f32.bf16.bf16.f32 "
        "{%0,%1,%2,%3}, {%4,%5,%6,%7}, {%8,%9}, {%0,%1,%2,%3};\n"
        : "+f"(c[0]), "+f"(c[1]), "+f"(c[2]), "+f"(c[3])
        : "r"(a0), "r"(a1), "r"(a2), "r"(a3), "r"(b0), "r"(b1));
}

__device__ __forceinline__ void ldsm4(uint32_t* r, uint32_t addr) {
    asm volatile("ldmatrix.sync.aligned.m8n8.x4.shared.b16 {%0,%1,%2,%3}, [%4];"
        : "=r"(r[0]), "=r"(r[1]), "=r"(r[2]), "=r"(r[3]) : "r"(addr));
}

// ---------------- transpose + bf16 convert ----------------
__global__ __launch_bounds__(256) void transpose_bf16_kernel(const float* __restrict__ in,
        __nv_bfloat16* __restrict__ out, int R, int C) {
    __shared__ float tile[32][33];
    int c0 = blockIdx.x*32, r0 = blockIdx.y*32;
    int tx = threadIdx.x, ty = threadIdx.y;
    for (int i = ty; i < 32; i += 8)
        tile[i][tx] = in[(long)(r0+i)*C + c0 + tx];
    __syncthreads();
    for (int i = ty; i < 32; i += 8)
        out[(long)(c0+i)*R + r0 + tx] = __float2bfloat16_rn(tile[tx][i]);
}

// ---------------- rmsnorm: fp32 (tf32-rounded) + bf16 outputs ----------------
__global__ __launch_bounds__(256) void rmsnorm_kernel(const float* __restrict__ in,
        const float* __restrict__ w, float* __restrict__ outf,
        __nv_bfloat16* __restrict__ outb) {
    long row = blockIdx.x;
    int t = threadIdx.x;
    float4 v = reinterpret_cast<const float4*>(in + row*DM)[t];
    float ss = v.x*v.x + v.y*v.y + v.z*v.z + v.w*v.w;
    __shared__ float red[8];
    for (int o = 16; o; o >>= 1) ss += __shfl_xor_sync(0xffffffffu, ss, o);
    if ((t & 31) == 0) red[t >> 5] = ss;
    __syncthreads();
    if (t < 32) {
        float s = (t < 8) ? red[t] : 0.f;
        for (int o = 4; o; o >>= 1) s += __shfl_xor_sync(0xffffffffu, s, o);
        if (t == 0) red[0] = s;
    }
    __syncthreads();
    float rs = rsqrtf(red[0] * (1.f/DM) + 1e-6f);
    float4 wv = reinterpret_cast<const float4*>(w)[t];
    float p0 = v.x*rs*wv.x, p1 = v.y*rs*wv.y, p2 = v.z*rs*wv.z, p3 = v.w*rs*wv.w;
    reinterpret_cast<float4*>(outf + row*DM)[t] =
        make_float4(rtf32(p0), rtf32(p1), rtf32(p2), rtf32(p3));
    __nv_bfloat162 b01, b23;
    b01.x = __float2bfloat16_rn(p0); b01.y = __float2bfloat16_rn(p1);
    b23.x = __float2bfloat16_rn(p2); b23.y = __float2bfloat16_rn(p3);
    reinterpret_cast<__nv_bfloat162*>(outb + row*DM)[t*2]   = b01;
    reinterpret_cast<__nv_bfloat162*>(outb + row*DM)[t*2+1] = b23;
}

// ---------------- h1 = x + attn ; hn (fp32 + bf16) ----------------
__global__ __launch_bounds__(256) void add_rmsnorm_kernel(const float* __restrict__ x,
        const float* __restrict__ w) {
    int row = blockIdx.x;
    int b = row / QLEN, r = row - b*QLEN;
    int t = threadIdx.x;
    float4 xv = reinterpret_cast<const float4*>(x + ((long)b*TOTAL + (TOTAL-QLEN) + r)*DM)[t];
    float4 av = reinterpret_cast<const float4*>(g_attn + (long)row*DM)[t];
    float4 hv = make_float4(xv.x+av.x, xv.y+av.y, xv.z+av.z, xv.w+av.w);
    reinterpret_cast<float4*>(g_h1 + (long)row*DM)[t] = hv;
    float ss = hv.x*hv.x + hv.y*hv.y + hv.z*hv.z + hv.w*hv.w;
    __shared__ float red[8];
    for (int o = 16; o; o >>= 1) ss += __shfl_xor_sync(0xffffffffu, ss, o);
    if ((t & 31) == 0) red[t >> 5] = ss;
    __syncthreads();
    if (t < 32) {
        float s = (t < 8) ? red[t] : 0.f;
        for (int o = 4; o; o >>= 1) s += __shfl_xor_sync(0xffffffffu, s, o);
        if (t == 0) red[0] = s;
    }
    __syncthreads();
    float rs = rsqrtf(red[0] * (1.f/DM) + 1e-6f);
    float4 wv = reinterpret_cast<const float4*>(w)[t];
    float p0 = hv.x*rs*wv.x, p1 = hv.y*rs*wv.y, p2 = hv.z*rs*wv.z, p3 = hv.w*rs*wv.w;
    reinterpret_cast<float4*>(g_hn + (long)row*DM)[t] =
        make_float4(rtf32(p0), rtf32(p1), rtf32(p2), rtf32(p3));
    __nv_bfloat162 b01, b23;
    b01.x = __float2bfloat16_rn(p0); b01.y = __float2bfloat16_rn(p1);
    b23.x = __float2bfloat16_rn(p2); b23.y = __float2bfloat16_rn(p3);
    reinterpret_cast<__nv_bfloat162*>(g_hnb + (long)row*DM)[t*2]   = b01;
    reinterpret_cast<__nv_bfloat162*>(g_hnb + (long)row*DM)[t*2+1] = b23;
}

// ---------------- BF16 tensor-core GEMM (optional fused residual add) ----------------
template<int MTILE>
__global__ __launch_bounds__(256, 2) void mma_gemmB_kernel(
    const __nv_bfloat16* __restrict__ A, int lda, long aBatch, int rpb,
    const __nv_bfloat16* __restrict__ Bt, int ldbt,
    const float* __restrict__ bias,
    void* __restrict__ Cv, int ldc, long cBatch,
    int K, int relu, int roundOut, int outBf16,
    const int* __restrict__ seqlen, int kvSkip,
    const float* __restrict__ res)          // if non-null: C = gemm+bias+res (same indexing)
{
    constexpr int S    = 3;
    constexpr int PAD  = 40;
    constexpr int ASTG = MTILE*PAD;
    constexpr int BSTG = 128*PAD;
    constexpr int MT   = MTILE/32;
    extern __shared__ __nv_bfloat16 smb[];
    __nv_bfloat16* AsBase = smb;
    __nv_bfloat16* BsBase = smb + S*ASTG;

    int t = threadIdx.x;
    int w = t >> 5, lane = t & 31;
    int g = lane >> 2, tig = lane & 3;
    int wm = w >> 2, wn = w & 3;

    int row0 = blockIdx.y * MTILE;
    int bn0  = blockIdx.x * 128;
    int batch = row0 / rpb;
    int rin   = row0 % rpb;
    if (kvSkip) {
        int kmin = MAXS - seqlen[batch];
        if (rin + MTILE - 1 < kmin) return;
    }
    const __nv_bfloat16* Ab = A + (long)batch*aBatch + (long)rin*lda;
    const __nv_bfloat16* Bb = Bt + (long)bn0*ldbt;

    uint32_t aSm0 = (uint32_t)__cvta_generic_to_shared(AsBase);
    uint32_t bSm0 = (uint32_t)__cvta_generic_to_shared(BsBase);

    float acc[MT][4][4];
    #pragma unroll
    for (int i = 0; i < MT; i++)
        #pragma unroll
        for (int j = 0; j < 4; j++)
            #pragma unroll
            for (int r = 0; r < 4; r++) acc[i][j][r] = 0.f;

    const int KT = K >> 5;
    auto issue = [&](int kt) {
        int s = kt % S;
        const __nv_bfloat16* ga = Ab + kt*32;
        const __nv_bfloat16* gb = Bb + kt*32;
        uint32_t aS = aSm0 + s*ASTG*2;
        uint32_t bS = bSm0 + s*BSTG*2;
        #pragma unroll
        for (int it = 0; it < MTILE/64; it++) {
            int i = t + it*256;
            int row = i >> 2, seg = i & 3;
            cpa16(aS + (row*PAD + seg*8)*2, ga + (long)row*lda + seg*8);
        }
        #pragma unroll
        for (int it = 0; it < 2; it++) {
            int i = t + it*256;
            int row = i >> 2, seg = i & 3;
            cpa16(bS + (row*PAD + seg*8)*2, gb + (long)row*ldbt + seg*8);
        }
        asm volatile("cp.async.commit_group;");
    };
    issue(0);
    issue(1);

    int aRow  = lane & 15;
    int aColH = (lane >> 4) * 8;
    int bRowO = ((lane >> 4) & 1)*8 + (lane & 7);
    int bColH = ((lane >> 3) & 1)*8;

    for (int kt = 0; kt < KT; kt++) {
        if (kt == KT - 1) asm volatile("cp.async.wait_group 0;");
        else              asm volatile("cp.async.wait_group 1;");
        __syncthreads();
        if (kt + 2 < KT) issue(kt + 2);

        int s = kt % S;
        uint32_t As = aSm0 + s*ASTG*2;
        uint32_t Bs = bSm0 + s*BSTG*2;
        #pragma unroll
        for (int ks = 0; ks < 2; ks++) {
            uint32_t afr[MT][4];
            #pragma unroll
            for (int mt = 0; mt < MT; mt++)
                ldsm4(afr[mt], As + ((wm*(MTILE/2) + mt*16 + aRow)*PAD + ks*16 + aColH)*2);
            uint32_t bfr[4][2];
            #pragma unroll
            for (int p = 0; p < 2; p++) {
                uint32_t r4[4];
                ldsm4(r4, Bs + ((wn*32 + p*16 + bRowO)*PAD + ks*16 + bColH)*2);
                bfr[2*p][0]   = r4[0]; bfr[2*p][1]   = r4[1];
                bfr[2*p+1][0] = r4[2]; bfr[2*p+1][1] = r4[3];
            }
            #pragma unroll
            for (int mt = 0; mt < MT; mt++)
                #pragma unroll
                for (int nt = 0; nt < 4; nt++)
                    mma_bf16(acc[mt][nt], afr[mt][0], afr[mt][1], afr[mt][2], afr[mt][3],
                             bfr[nt][0], bfr[nt][1]);
        }
    }

    float* Cf = (float*)Cv;
    __nv_bfloat16* Cb = (__nv_bfloat16*)Cv;
    #pragma unroll
    for (int nt = 0; nt < 4; nt++) {
        int col = wn*32 + nt*8 + 2*tig;
        float bx = bias[bn0 + col], by = bias[bn0 + col + 1];
        #pragma unroll
        for (int mt = 0; mt < MT; mt++) {
            int r0 = wm*(MTILE/2) + mt*16 + g;
            long base0 = (long)batch*cBatch + (long)(rin + r0)*ldc + bn0 + col;
            long base1 = base0 + (long)8*ldc;
            float c0 = acc[mt][nt][0] + bx, c1 = acc[mt][nt][1] + by;
            float c2 = acc[mt][nt][2] + bx, c3 = acc[mt][nt][3] + by;
            if (relu) { c0=fmaxf(c0,0.f); c1=fmaxf(c1,0.f); c2=fmaxf(c2,0.f); c3=fmaxf(c3,0.f); }
            if (res) {
                float2 r0v = *reinterpret_cast<const float2*>(res + base0);
                float2 r1v = *reinterpret_cast<const float2*>(res + base1);
                c0 += r0v.x; c1 += r0v.y; c2 += r1v.x; c3 += r1v.y;
            }
            if (outBf16) {
                __nv_bfloat162 v0, v1;
                v0.x = __float2bfloat16_rn(c0); v0.y = __float2bfloat16_rn(c1);
                v1.x = __float2bfloat16_rn(c2); v1.y = __float2bfloat16_rn(c3);
                *reinterpret_cast<__nv_bfloat162*>(Cb + base0) = v0;
                *reinterpret_cast<__nv_bfloat162*>(Cb + base1) = v1;
            } else {
                if (roundOut) { c0=rtf32(c0); c1=rtf32(c1); c2=rtf32(c2); c3=rtf32(c3); }
                *reinterpret_cast<float2*>(Cf + base0) = make_float2(c0, c1);
                *reinterpret_cast<float2*>(Cf + base1) = make_float2(c2, c3);
            }
        }
    }
}

// ---------------- per-NS-position linear: vectorized K-split partials ----------------
__global__ __launch_bounds__(128) void ns_split4_kernel(
    const float* __restrict__ X, long xBatch, int xRow,
    const float* __restrict__ W, float* __restrict__ part,
    int K, int N, int kchunk)
{
    __shared__ float Xs[4][512];
    int n = blockIdx.y, z = blockIdx.z;
    int t = threadIdx.x;
    int o4 = (blockIdx.x*128 + t)*4;
    int k0 = z*kchunk;
    for (int i = t; i < kchunk; i += 128) {
        long xo = (long)n*xRow + k0 + i;
        Xs[0][i] = X[0*xBatch + xo];
        Xs[1][i] = X[1*xBatch + xo];
        Xs[2][i] = X[2*xBatch + xo];
        Xs[3][i] = X[3*xBatch + xo];
    }
    __syncthreads();
    const float* Wp = W + (long)n*K*N + (long)k0*N + o4;
    float acc[4][4];
    #pragma unroll
    for (int b = 0; b < 4; b++)
        #pragma unroll
        for (int j = 0; j < 4; j++) acc[b][j] = 0.f;
    #pragma unroll 8
    for (int k = 0; k < kchunk; k++) {
        float4 wv = *reinterpret_cast<const float4*>(Wp + (long)k*N);
        #pragma unroll
        for (int b = 0; b < 4; b++) {
            float xv = Xs[b][k];
            acc[b][0] += xv*wv.x; acc[b][1] += xv*wv.y;
            acc[b][2] += xv*wv.z; acc[b][3] += xv*wv.w;
        }
    }
    #pragma unroll
    for (int b = 0; b < 4; b++)
        *reinterpret_cast<float4*>(&part[((long)(z*BSZ+b)*NSN + n)*N + o4]) =
            make_float4(acc[b][0], acc[b][1], acc[b][2], acc[b][3]);
}

__global__ __launch_bounds__(256) void ns_reduce_kernel(
    const float* __restrict__ part, const float* __restrict__ bias,
    float* __restrict__ Y, long yBatch, int yRow, int N, int KS, int relu, int roundOut,
    const float* __restrict__ res)
{
    int o = blockIdx.x*256 + threadIdx.x;
    int n = blockIdx.y, b = blockIdx.z;
    float s = bias[(long)n*N + o];
    for (int z = 0; z < KS; z++)
        s += part[((long)(z*BSZ+b)*NSN + n)*N + o];
    if (relu) s = fmaxf(s, 0.f);
    if (roundOut) s = rtf32(s);
    long idx = (long)b*yBatch + (long)n*yRow + o;
    if (res) s += res[idx];
    Y[idx] = s;
}

// ---------------- RoPE in-place (fp32 path, rounded output) ----------------
__global__ void rope_kernel(float* __restrict__ buf, int rowsPerB, int pos0, int rstride, int total) {
    int idx = blockIdx.x*blockDim.x + threadIdx.x;
    if (idx >= total) return;
    int j  = idx & 31;
    int h  = (idx >> 5) & (NH-1);
    int rr = idx >> 9;
    int b  = rr / rowsPerB;
    int r  = rr - b*rowsPerB;
    float inv = exp2f(-(float)j * 0.41524101186092029f);
    double ang = (double)(pos0 + r) * (double)inv;
    const double TWO_PI = 6.2831853071795864769;
    double red = ang - TWO_PI * rint(ang * (1.0/6.2831853071795864769));
    float rf = (float)red;
    float s, c;
    sincosf(rf, &s, &c);
    float* base = buf + ((long)b*rowsPerB + r)*(long)rstride + h*HD;
    float x1 = base[j], x2 = base[j+32];
    base[j]    = rtf32(x1*c - x2*s);
    base[j+32] = rtf32(x2*c + x1*s);
}

// ---------------- tf32 flash attention, 64-key tiles, Q frags hoisted ----------
#define ATT_QS(r,c)      dsm[(r)*68 + (c)]
#define ATT_KS(bf,r,c)   dsm[4352 + (bf)*4352 + (r)*68 + (c)]
#define ATT_VS(bf,r,c)   dsm[13056 + (bf)*4608 + (r)*72 + (c)]
#define ATT_SS(r,c)      dsm[22272 + (r)*68 + (c)]
#define ATT_SMEM_FLOATS  (26752 + 128)

__global__ __launch_bounds__(256, 2) void attn_mma_kernel(
    const float* __restrict__ q, const float* __restrict__ kv,
    float* __restrict__ attn, const int* __restrict__ seqlen)
{
    extern __shared__ float dsm[];
    float* corrs = dsm + 26752;
    float* lrow  = corrs + 64;

    int qt = blockIdx.x, h = blockIdx.y, b = blockIdx.z;
    int tid = threadIdx.x;
    int w = tid >> 5, lane = tid & 31;
    int g = lane >> 2, tig = lane & 3;
    int wm = w >> 2, wn = w & 3;
    int L = seqlen[b];
    int kmin = MAXS - L;

    for (int i = tid; i < 64*16; i += 256) {
        int r = i >> 4, c4 = (i & 15) * 4;
        int qg = qt*64 + r;
        float4 val = make_float4(0.f,0.f,0.f,0.f);
        if (qg < QLEN)
            val = *reinterpret_cast<const float4*>(q + ((long)b*QLEN + qg)*DM + h*HD + c4);
        *reinterpret_cast<float4*>(&ATT_QS(r, c4)) = val;
    }

    int srow = tid >> 2, ssub = tid & 3;
    float m = -1e30f, l = 0.f;

    float oacc[2][2][4];
    #pragma unroll
    for (int i = 0; i < 2; i++)
        #pragma unroll
        for (int j = 0; j < 2; j++)
            #pragma unroll
            for (int r = 0; r < 4; r++) oacc[i][j][r] = 0.f;

    int qgmax = min(QLEN-1, qt*64 + 63);
    int t0 = kmin >> 6;
    int t1 = (MAXS - OUTN + qgmax) >> 6;

    uint32_t smBase = (uint32_t)__cvta_generic_to_shared(dsm);

    auto loadTile = [&](int kt) {
        int buf = kt & 1;
        int key0 = kt * 64;
        #pragma unroll
        for (int it = 0; it < 4; it++) {
            int i = tid + it*256;
            int r = i >> 4;
            int c4 = (i & 15) * 4;
            int key = key0 + r;
            long off = ((long)b*TOTAL + min(key, TOTAL-1))*(2*DM) + h*HD + c4;
            cpa16(smBase + (4352 + buf*4352 + r*68 + c4)*4, kv + off);
            cpa16(smBase + (13056 + buf*4608 + r*72 + c4)*4, kv + off + DM);
        }
        asm volatile("cp.async.commit_group;");
    };
    loadTile(t0);
    asm volatile("cp.async.commit_group;");

    // hoist Q fragments (constant over key tiles)
    __syncthreads();
    uint32_t qfr[8][2][4];
    #pragma unroll
    for (int dk = 0; dk < 8; dk++)
        #pragma unroll
        for (int mt = 0; mt < 2; mt++) {
            int m0 = wm*32 + mt*16;
            qfr[dk][mt][0] = f2u(ATT_QS(m0+g,   dk*8+tig));
            qfr[dk][mt][1] = f2u(ATT_QS(m0+g+8, dk*8+tig));
            qfr[dk][mt][2] = f2u(ATT_QS(m0+g,   dk*8+tig+4));
            qfr[dk][mt][3] = f2u(ATT_QS(m0+g+8, dk*8+tig+4));
        }

    for (int kt = t0; kt <= t1; kt++) {
        int key0 = kt * 64;
        int buf = kt & 1;
        asm volatile("cp.async.wait_group 1;");
        __syncthreads();
        if (kt + 1 <= t1) loadTile(kt + 1);
        else              asm volatile("cp.async.commit_group;");

        float sa[2][2][4];
        #pragma unroll
        for (int mt = 0; mt < 2; mt++)
            #pragma unroll
            for (int kn = 0; kn < 2; kn++)
                #pragma unroll
                for (int r = 0; r < 4; r++) sa[mt][kn][r] = 0.f;
        #pragma unroll
        for (int dk = 0; dk < 8; dk++) {
            #pragma unroll
            for (int kn = 0; kn < 2; kn++) {
                uint32_t bf0 = f2u(ATT_KS(buf, wn*16 + kn*8 + g, dk*8 + tig));
                uint32_t bf1 = f2u(ATT_KS(buf, wn*16 + kn*8 + g, dk*8 + tig + 4));
                #pragma unroll
                for (int mt = 0; mt < 2; mt++)
                    mma_tf32(sa[mt][kn], qfr[dk][mt][0], qfr[dk][mt][1],
                             qfr[dk][mt][2], qfr[dk][mt][3], bf0, bf1);
            }
        }
        #pragma unroll
        for (int mt = 0; mt < 2; mt++) {
            #pragma unroll
            for (int kn = 0; kn < 2; kn++) {
                #pragma unroll
                for (int hh = 0; hh < 2; hh++) {
                    int r = wm*32 + mt*16 + g + hh*8;
                    int qg = qt*64 + r;
                    int col = wn*16 + kn*8 + 2*tig;
                    int key = key0 + col;
                    int kcap = MAXS - OUTN + qg;
                    bool rowok = (qg < QLEN);
                    float sA = sa[mt][kn][hh*2+0], sB = sa[mt][kn][hh*2+1];
                    bool v0 = rowok && (key   < TOTAL) && (key   >= kmin) && (key   <= kcap);
                    bool v1 = rowok && (key+1 < TOTAL) && (key+1 >= kmin) && (key+1 <= kcap);
                    ATT_SS(r, col)     = v0 ? sA*0.125f : -1e9f;
                    ATT_SS(r, col + 1) = v1 ? sB*0.125f : -1e9f;
                }
            }
        }
        __syncthreads();

        float sv[16];
        #pragma unroll
        for (int j = 0; j < 16; j++) sv[j] = ATT_SS(srow, ssub*16 + j);
        float tmax = sv[0];
        #pragma unroll
        for (int j = 1; j < 16; j++) tmax = fmaxf(tmax, sv[j]);
        tmax = fmaxf(tmax, __shfl_xor_sync(0xffffffffu, tmax, 1));
        tmax = fmaxf(tmax, __shfl_xor_sync(0xffffffffu, tmax, 2));
        float corr = 1.f;
        if (tmax > -1e8f) {
            float m_new = fmaxf(m, tmax);
            corr = __expf(m - m_new);
            float ps = 0.f;
            #pragma unroll
            for (int j = 0; j < 16; j++) {
                float p = __expf(sv[j] - m_new);
                ps += p;
                ATT_SS(srow, ssub*16 + j) = rtf32(p);
            }
            ps += __shfl_xor_sync(0xffffffffu, ps, 1);
            ps += __shfl_xor_sync(0xffffffffu, ps, 2);
            l = l*corr + ps;
            m = m_new;
        } else {
            #pragma unroll
            for (int j = 0; j < 16; j++) ATT_SS(srow, ssub*16 + j) = 0.f;
        }
        if (ssub == 0) corrs[srow] = corr;
        __syncthreads();

        #pragma unroll
        for (int mt = 0; mt < 2; mt++) {
            float c0 = corrs[wm*32 + mt*16 + g];
            float c1 = corrs[wm*32 + mt*16 + g + 8];
            #pragma unroll
            for (int nt = 0; nt < 2; nt++) {
                oacc[mt][nt][0] *= c0; oacc[mt][nt][1] *= c0;
                oacc[mt][nt][2] *= c1; oacc[mt][nt][3] *= c1;
            }
        }
        #pragma unroll
        for (int kd = 0; kd < 8; kd++) {
            uint32_t bf[2][2];
            #pragma unroll
            for (int nt = 0; nt < 2; nt++) {
                int n = wn*16 + nt*8 + g;
                bf[nt][0] = f2u(ATT_VS(buf, kd*8 + tig,     n));
                bf[nt][1] = f2u(ATT_VS(buf, kd*8 + tig + 4, n));
            }
            #pragma unroll
            for (int mt = 0; mt < 2; mt++) {
                int m0 = wm*32 + mt*16;
                uint32_t a0 = f2u(ATT_SS(m0+g,   kd*8+tig));
                uint32_t a1 = f2u(ATT_SS(m0+g+8, kd*8+tig));
                uint32_t a2 = f2u(ATT_SS(m0+g,   kd*8+tig+4));
                uint32_t a3 = f2u(ATT_SS(m0+g+8, kd*8+tig+4));
                #pragma unroll
                for (int nt = 0; nt < 2; nt++)
                    mma_tf32(oacc[mt][nt], a0, a1, a2, a3, bf[nt][0], bf[nt][1]);
            }
        }
        __syncthreads();
    }

    if (ssub == 0) lrow[srow] = l;
    __syncthreads();
    #pragma unroll
    for (int mt = 0; mt < 2; mt++) {
        #pragma unroll
        for (int hh = 0; hh < 2; hh++) {
            int r = wm*32 + mt*16 + g + hh*8;
            int qg = qt*64 + r;
            if (qg < QLEN) {
                float invl = 1.f / lrow[r];
                #pragma unroll
                for (int nt = 0; nt < 2; nt++) {
                    int col = wn*16 + nt*8 + 2*tig;
                    *reinterpret_cast<float2*>(attn + ((long)b*QLEN + qg)*DM + h*HD + col)
                        = make_float2(oacc[mt][nt][hh*2]*invl, oacc[mt][nt][hh*2+1]*invl);
                }
            }
        }
    }
}

// ---------------- tail: optional seqlen extras ----------------
__global__ void tail_kernel(float* __restrict__ out, const int* __restrict__ seqlen, int out_size) {
    int b = threadIdx.x;
    const int main_n = BSZ*QLEN*DM;
    if (b < BSZ && out_size >= main_n + BSZ) {
        int L = seqlen[b];
        out[main_n + b] = (float)(L < OUTN ? L : OUTN);
    }
}

extern "C" void kernel_launch(void* const* d_in, const int* in_sizes, int n_in,
                              void* d_out, int out_size) {
    (void)in_sizes; (void)n_in;
    const float* x    = (const float*)d_in[0];
    const int*   seq  = (const int*)  d_in[1];
    const float* wqkv = (const float*)d_in[2];
    const float* bqkv = (const float*)d_in[3];
    const float* wnsq = (const float*)d_in[4];
    const float* bnsq = (const float*)d_in[5];
    const float* wnsk = (const float*)d_in[6];
    const float* bnsk = (const float*)d_in[7];
    const float* wnsv = (const float*)d_in[8];
    const float* bnsv = (const float*)d_in[9];
    const float* n1w  = (const float*)d_in[10];
    const float* n2w  = (const float*)d_in[11];
    const float* fw1  = (const float*)d_in[12];
    const float* fb1  = (const float*)d_in[13];
    const float* fw2  = (const float*)d_in[14];
    const float* fb2  = (const float*)d_in[15];
    const float* w1ns = (const float*)d_in[16];
    const float* b1ns = (const float*)d_in[17];
    const float* w2ns = (const float*)d_in[18];
    const float* b2ns = (const float*)d_in[19];
    float* out = (float*)d_out;

    float *xn,*q,*kv,*attn,*h1,*hn,*tns,*fns,*part;
    __nv_bfloat16 *xnb,*hnb,*tsb,*wqb,*w1b,*w2b;
    cudaGetSymbolAddress((void**)&xn,   g_xn);
    cudaGetSymbolAddress((void**)&q,    g_q);
    cudaGetSymbolAddress((void**)&kv,   g_kv);
    cudaGetSymbolAddress((void**)&attn, g_attn);
    cudaGetSymbolAddress((void**)&h1,   g_h1);
    cudaGetSymbolAddress((void**)&hn,   g_hn);
    cudaGetSymbolAddress((void**)&tns,  g_tns);
    cudaGetSymbolAddress((void**)&fns,  g_fns);
    cudaGetSymbolAddress((void**)&part, g_part);
    cudaGetSymbolAddress((void**)&xnb,  g_xnb);
    cudaGetSymbolAddress((void**)&hnb,  g_hnb);
    cudaGetSymbolAddress((void**)&tsb,  g_tsb);
    cudaGetSymbolAddress((void**)&wqb,  g_wqkvb);
    cudaGetSymbolAddress((void**)&w1b,  g_w1b);
    cudaGetSymbolAddress((void**)&w2b,  g_w2b);
    float* part2 = part + 2*1024*1024;

    const long aB  = (long)TOTAL*DM;
    const long qB  = (long)QLEN*DM;
    const long kvB = (long)TOTAL*2*DM;

    const int SMEMB128 = (3*128*40 + 3*128*40) * 2;
    const int SMEMB64  = (3*64*40  + 3*128*40) * 2;
    const int ATTSMEM  = ATT_SMEM_FLOATS * 4;
    cudaFuncSetAttribute(mma_gemmB_kernel<128>, cudaFuncAttributeMaxDynamicSharedMemorySize, SMEMB128);
    cudaFuncSetAttribute(mma_gemmB_kernel<64>,  cudaFuncAttributeMaxDynamicSharedMemorySize, SMEMB64);
    cudaFuncSetAttribute(attn_mma_kernel, cudaFuncAttributeMaxDynamicSharedMemorySize, ATTSMEM);

    static cudaStream_t s1 = nullptr, s2 = nullptr, s3 = nullptr;
    static cudaEvent_t  eB, e0, e1, e2, e2a, e3, e4, e5;
    if (s1 == nullptr) {
        cudaStreamCreateWithFlags(&s1, cudaStreamNonBlocking);
        cudaStreamCreateWithFlags(&s2, cudaStreamNonBlocking);
        cudaStreamCreateWithFlags(&s3, cudaStreamNonBlocking);
        cudaEventCreateWithFlags(&eB,  cudaEventDisableTiming);
        cudaEventCreateWithFlags(&e0,  cudaEventDisableTiming);
        cudaEventCreateWithFlags(&e1,  cudaEventDisableTiming);
        cudaEventCreateWithFlags(&e2,  cudaEventDisableTiming);
        cudaEventCreateWithFlags(&e2a, cudaEventDisableTiming);
        cudaEventCreateWithFlags(&e3,  cudaEventDisableTiming);
        cudaEventCreateWithFlags(&e4,  cudaEventDisableTiming);
        cudaEventCreateWithFlags(&e5,  cudaEventDisableTiming);
    }
    cudaStream_t s0 = 0;

    // ---- Phase 1 : rmsnorm (s0) || weight transposes (s2) ----
    cudaEventRecord(eB, s0);
    cudaStreamWaitEvent(s2, eB, 0);
    transpose_bf16_kernel<<<dim3(3*DM/32, DM/32), dim3(32,8), 0, s2>>>(wqkv, wqb, DM, 3*DM);
    cudaEventRecord(e2a, s2);
    transpose_bf16_kernel<<<dim3(FFND/32, DM/32), dim3(32,8), 0, s2>>>(fw1, w1b, DM, FFND);
    transpose_bf16_kernel<<<dim3(DM/32, FFND/32), dim3(32,8), 0, s2>>>(fw2, w2b, FFND, DM);
    cudaEventRecord(e2, s2);

    rmsnorm_kernel<<<BSZ*TOTAL, 256, 0, s0>>>(x, n1w, xn, xnb);
    cudaEventRecord(e0, s0);

    // s1: Q projection -> ns_q -> rope_q
    cudaStreamWaitEvent(s1, e0, 0);
    cudaStreamWaitEvent(s1, e2a, 0);
    mma_gemmB_kernel<64><<<dim3(DM/128, (BSZ*OUTN)/64), 256, SMEMB64, s1>>>(
        xnb + (long)(MAXS-OUTN)*DM, DM, aB, OUTN, wqb, DM, bqkv, q, DM, qB, DM, 0, 1, 0, seq, 0, nullptr);
    ns_split4_kernel<<<dim3(DM/512, NSN, 32), 128, 0, s1>>>(xn + (long)MAXS*DM, aB, DM, wnsq, part2, DM, DM, DM/32);
    ns_reduce_kernel<<<dim3(DM/256, NSN, BSZ), 256, 0, s1>>>(part2, bnsq, q + (long)OUTN*DM, qB, DM, DM, 32, 0, 1, nullptr);
    {
        int totq = BSZ*QLEN*NH*32;
        rope_kernel<<<(totq+255)/256, 256, 0, s1>>>(q, QLEN, TOTAL-QLEN, DM, totq);
    }
    cudaEventRecord(e1, s1);

    // s3: ns_v then ns_k
    cudaStreamWaitEvent(s3, e0, 0);
    ns_split4_kernel<<<dim3(DM/512, NSN, 32), 128, 0, s3>>>(xn + (long)MAXS*DM, aB, DM, wnsv, part, DM, DM, DM/32);
    ns_reduce_kernel<<<dim3(DM/256, NSN, BSZ), 256, 0, s3>>>(part, bnsv, kv + (long)MAXS*2*DM + DM, kvB, 2*DM, DM, 32, 0, 1, nullptr);
    ns_split4_kernel<<<dim3(DM/512, NSN, 32), 128, 0, s3>>>(xn + (long)MAXS*DM, aB, DM, wnsk, part, DM, DM, DM/32);
    ns_reduce_kernel<<<dim3(DM/256, NSN, BSZ), 256, 0, s3>>>(part, bnsk, kv + (long)MAXS*2*DM, kvB, 2*DM, DM, 32, 0, 1, nullptr);
    cudaEventRecord(e3, s3);

    // s0: KV projection, then rope_k
    cudaStreamWaitEvent(s0, e2a, 0);
    mma_gemmB_kernel<128><<<dim3(2*DM/128, (BSZ*MAXS)/128), 256, SMEMB128, s0>>>(xnb, DM, aB, MAXS,
        wqb + (long)DM*DM, DM, bqkv + DM, kv, 2*DM, kvB, DM, 0, 1, 0, seq, 1, nullptr);
    cudaStreamWaitEvent(s0, e3, 0);
    {
        int totk = BSZ*TOTAL*NH*32;
        rope_kernel<<<(totk+255)/256, 256, 0, s0>>>(kv, TOTAL, 0, 2*DM, totk);
    }

    cudaStreamWaitEvent(s0, e1, 0);
    attn_mma_kernel<<<dim3((QLEN+63)/64, NH, BSZ), 256, ATTSMEM, s0>>>(q, kv, attn, seq);

    add_rmsnorm_kernel<<<BSZ*QLEN, 256, 0, s0>>>(x, n2w);
    cudaEventRecord(e4, s0);

    // ---- Phase 2 ----
    // s1: NS FFN; final reduce writes OUT rows 256..271 with fused +h1
    cudaStreamWaitEvent(s1, e4, 0);
    ns_split4_kernel<<<dim3(FFND/512, NSN, 16), 128, 0, s1>>>(hn + (long)OUTN*DM, qB, DM, w1ns, part, DM, FFND, DM/16);
    ns_reduce_kernel<<<dim3(FFND/256, NSN, BSZ), 256, 0, s1>>>(part, b1ns, tns, (long)NSN*FFND, FFND, FFND, 16, 1, 0, nullptr);
    ns_split4_kernel<<<dim3(DM/512, NSN, 32), 128, 0, s1>>>(tns, (long)NSN*FFND, FFND, w2ns, part, FFND, DM, FFND/32);
    ns_reduce_kernel<<<dim3(DM/256, NSN, BSZ), 256, 0, s1>>>(part, b2ns,
        out + (long)OUTN*DM, qB, DM, DM, 32, 0, 0, h1 + (long)OUTN*DM);
    cudaEventRecord(e5, s1);

    // s0: shared FFN; FFN2 writes OUT rows 0..255 with fused +h1
    cudaStreamWaitEvent(s0, e2, 0);
    mma_gemmB_kernel<128><<<dim3(FFND/128, (BSZ*OUTN)/128), 256, SMEMB128, s0>>>(hnb, DM, qB, OUTN,
        w1b, DM, fb1, tsb, FFND, (long)OUTN*FFND, DM, 1, 0, 1, seq, 0, nullptr);
    mma_gemmB_kernel<64><<<dim3(DM/128, (BSZ*OUTN)/64), 256, SMEMB64, s0>>>(tsb, FFND, (long)OUTN*FFND, OUTN,
        w2b, FFND, fb2, out, DM, qB, FFND, 0, 0, 0, seq, 0, h1);

    cudaStreamWaitEvent(s0, e5, 0);
    tail_kernel<<<1, BSZ, 0, s0>>>(out, seq, out_size);
}